// round 1
// baseline (speedup 1.0000x reference)
#include <cuda_runtime.h>
#include <math.h>

#define BB   2
#define Lseq 2048
#define BL   4096      // B*L
#define Dd   2048
#define DCc  1024
#define NHh  16
#define DHh  128
#define DHRr 64
// dq = DH + DHR = 192, scale = 1/sqrt(192)
#define ATTN_SCALE 0.07216878364870322f

// ---------------- scratch (static __device__ — allocation-free) ----------------
__device__ float g_tmp [BL * DCc];            // pre-RMS buffer (reused)
__device__ float g_ckv [BL * DCc];
__device__ float g_cq  [BL * DCc];
__device__ float g_kc  [BL * (NHh * DHh)];    // 4096 x 2048
__device__ float g_v   [BL * (NHh * DHh)];    // 4096 x 2048
__device__ float g_qc  [BL * (2 * NHh * DHh)];// 4096 x 4096
__device__ float g_qr  [BL * (2 * NHh * DHRr)];// 4096 x 2048
__device__ float g_kr  [BL * DHRr];           // 4096 x 64
__device__ float g_lam [BL * NHh];            // 4096 x 16
__device__ float g_attn[(size_t)2 * BB * NHh * Lseq * DHh]; // [b*2+p][n][l][d]
__device__ float g_pre [BL * Dd];             // 4096 x 2048

// ---------------- generic 128x128x8 SGEMM (row-major A[MxK] @ B[KxN]) ----------------
__global__ void sgemm128(int M, int N, int K,
                         const float* __restrict__ A,
                         const float* __restrict__ B,
                         float* __restrict__ C)
{
    const int BM = 128, BN = 128, BKK = 8;
    __shared__ float As[BKK * BM];
    __shared__ float Bs[BKK * BN];
    int tid = threadIdx.x;

    A += (size_t)blockIdx.y * BM * K;
    B += blockIdx.x * BN;
    C += (size_t)blockIdx.y * BM * N + blockIdx.x * BN;

    int aRow = tid >> 1, aCol = (tid & 1) * 4;
    int bRow = tid >> 5, bCol = (tid & 31) * 4;
    int tRow = (tid >> 4) * 8, tCol = (tid & 15) * 8;

    float acc[8][8];
    #pragma unroll
    for (int i = 0; i < 8; i++)
        #pragma unroll
        for (int j = 0; j < 8; j++) acc[i][j] = 0.f;

    for (int k0 = 0; k0 < K; k0 += BKK) {
        float4 av = *(const float4*)(A + (size_t)aRow * K + aCol);
        As[(aCol + 0) * BM + aRow] = av.x;
        As[(aCol + 1) * BM + aRow] = av.y;
        As[(aCol + 2) * BM + aRow] = av.z;
        As[(aCol + 3) * BM + aRow] = av.w;
        *(float4*)(Bs + bRow * BN + bCol) = *(const float4*)(B + (size_t)bRow * N + bCol);
        __syncthreads();
        A += BKK;
        B += (size_t)BKK * N;
        #pragma unroll
        for (int k = 0; k < BKK; k++) {
            float rM[8], rN[8];
            *(float4*)(rM)     = *(const float4*)(As + k * BM + tRow);
            *(float4*)(rM + 4) = *(const float4*)(As + k * BM + tRow + 4);
            *(float4*)(rN)     = *(const float4*)(Bs + k * BN + tCol);
            *(float4*)(rN + 4) = *(const float4*)(Bs + k * BN + tCol + 4);
            #pragma unroll
            for (int i = 0; i < 8; i++)
                #pragma unroll
                for (int j = 0; j < 8; j++) acc[i][j] += rM[i] * rN[j];
        }
        __syncthreads();
    }
    #pragma unroll
    for (int i = 0; i < 8; i++)
        #pragma unroll
        for (int j = 0; j < 8; j += 4) {
            float4 o = make_float4(acc[i][j], acc[i][j+1], acc[i][j+2], acc[i][j+3]);
            *(float4*)(C + (size_t)(tRow + i) * N + tCol + j) = o;
        }
}

// ---------------- RMS norm: one block per row ----------------
__global__ void rms_kernel(const float* __restrict__ in, const float* __restrict__ w,
                           float* __restrict__ out, int N)
{
    int row = blockIdx.x;
    const float* ir = in + (size_t)row * N;
    float s = 0.f;
    for (int i = threadIdx.x; i < N; i += 256) { float v = ir[i]; s += v * v; }
    __shared__ float red[256];
    red[threadIdx.x] = s;
    __syncthreads();
    for (int st = 128; st > 0; st >>= 1) {
        if (threadIdx.x < st) red[threadIdx.x] += red[threadIdx.x + st];
        __syncthreads();
    }
    float rr = rsqrtf(red[0] / (float)N + 1e-6f);
    float* orow = out + (size_t)row * N;
    for (int i = threadIdx.x; i < N; i += 256) orow[i] = ir[i] * rr * w[i];
}

// ---------------- RoPE (in-place), dhr=64, half=32 ----------------
__global__ void rope_kernel(float* __restrict__ t, int heads, int rowstride)
{
    int idx = blockIdx.x * blockDim.x + threadIdx.x; // over BL*heads*32
    int j = idx & 31;
    int h = (idx >> 5) % heads;
    int row = idx / (32 * heads);
    if (row >= BL) return;
    int l = row & (Lseq - 1);
    float inv = powf(10000.f, -(float)(2 * j) / 64.f);
    float ang = (float)l * inv;
    float c = cosf(ang), s = sinf(ang);
    float* base = t + (size_t)row * rowstride + h * 64;
    float x1 = base[j], x2 = base[j + 32];
    base[j]      = x1 * c - x2 * s;
    base[j + 32] = x2 * c + x1 * s;
}

// ---------------- lambda gate: sigmoid(x @ W_lw + b), N=16, one block/row ----------------
__global__ void lam_kernel(const float* __restrict__ x, const float* __restrict__ Wl,
                           const float* __restrict__ bl, float* __restrict__ lam)
{
    int row = blockIdx.x;
    int tid = threadIdx.x; // 128
    const float* xr = x + (size_t)row * Dd;
    float acc[16];
    #pragma unroll
    for (int n = 0; n < 16; n++) acc[n] = 0.f;
    for (int k = tid; k < Dd; k += 128) {
        float xv = xr[k];
        const float* wv = Wl + (size_t)k * 16;
        #pragma unroll
        for (int n = 0; n < 16; n++) acc[n] += xv * wv[n];
    }
    __shared__ float red[16 * 128];
    #pragma unroll
    for (int n = 0; n < 16; n++) red[n * 128 + tid] = acc[n];
    __syncthreads();
    for (int st = 64; st > 0; st >>= 1) {
        if (tid < st) {
            #pragma unroll
            for (int n = 0; n < 16; n++) red[n * 128 + tid] += red[n * 128 + tid + st];
        }
        __syncthreads();
    }
    if (tid < 16) {
        float z = red[tid * 128] + bl[tid];
        lam[(size_t)row * 16 + tid] = 1.f / (1.f + expf(-z));
    }
}

// ---------------- small GEMM N=64 (x @ W_KR) ----------------
__global__ void gemm_n64(const float* __restrict__ A, const float* __restrict__ B,
                         float* __restrict__ C, int K)
{
    int n = threadIdx.x;                       // 0..63
    int m = blockIdx.x * 4 + threadIdx.y;      // 4 rows/block
    float acc = 0.f;
    const float* ar = A + (size_t)m * K;
    #pragma unroll 8
    for (int k = 0; k < K; k++) acc += ar[k] * B[(size_t)k * 64 + n];
    C[(size_t)m * 64 + n] = acc;
}

// ---------------- fused causal flash attention, fp32 ----------------
// grid: (L/32, 32 heads2, B). block 256 = 8 warps, each warp owns 4 query rows.
// q = [qc(128) | qr(64)], k = [kc(128) | kr(64)] per logical head2 = 2n+p.
__global__ void flash_kernel(const float* __restrict__ qc, const float* __restrict__ qr,
                             const float* __restrict__ kc, const float* __restrict__ kr,
                             const float* __restrict__ vv, float* __restrict__ attn)
{
    extern __shared__ float sm[];
    float* qs = sm;                    // 32 * 196
    float* ks = sm + 32 * 196;         // 32 * 196
    float* vs = sm + 2 * 32 * 196;     // 32 * 132
    float* ps = vs + 32 * 132;         // 32 * 33

    const int q0 = blockIdx.x * 32;
    const int head2 = blockIdx.y;
    const int b = blockIdx.z;
    const int n = head2 >> 1, p = head2 & 1;
    const int tid = threadIdx.x;
    const int lane = tid & 31, w = tid >> 5;

    const float* qcb = qc + ((size_t)(b * Lseq + q0)) * 4096 + head2 * 128;
    const float* qrb = qr + ((size_t)(b * Lseq + q0)) * 2048 + head2 * 64;
    for (int i = tid; i < 32 * 128; i += 256) {
        int r = i >> 7, c = i & 127;
        qs[r * 196 + c] = qcb[(size_t)r * 4096 + c];
    }
    for (int i = tid; i < 32 * 64; i += 256) {
        int r = i >> 6, c = i & 63;
        qs[r * 196 + 128 + c] = qrb[(size_t)r * 2048 + c];
    }

    float m_i[4], l_i[4], acc[4][4];
    #pragma unroll
    for (int rr = 0; rr < 4; rr++) {
        m_i[rr] = -INFINITY; l_i[rr] = 0.f;
        #pragma unroll
        for (int dd = 0; dd < 4; dd++) acc[rr][dd] = 0.f;
    }

    const int kend = q0 + 32;
    for (int k0 = 0; k0 < kend; k0 += 32) {
        __syncthreads();
        const float* kcb = kc + ((size_t)(b * Lseq + k0)) * 2048 + n * 128;
        const float* krb = kr + ((size_t)(b * Lseq + k0)) * 64;
        const float* vb  = vv + ((size_t)(b * Lseq + k0)) * 2048 + n * 128;
        for (int i = tid; i < 32 * 128; i += 256) {
            int r = i >> 7, c = i & 127;
            ks[r * 196 + c] = kcb[(size_t)r * 2048 + c];
            vs[r * 132 + c] = vb[(size_t)r * 2048 + c];
        }
        for (int i = tid; i < 32 * 64; i += 256) {
            int r = i >> 6, c = i & 63;
            ks[r * 196 + 128 + c] = krb[(size_t)r * 64 + c];
        }
        __syncthreads();

        // scores: lane = key j, each warp does its 4 rows
        float s0 = 0.f, s1 = 0.f, s2 = 0.f, s3 = 0.f;
        {
            const float4* krow = (const float4*)(ks + lane * 196);
            const float4* q0p = (const float4*)(qs + (w * 4 + 0) * 196);
            const float4* q1p = (const float4*)(qs + (w * 4 + 1) * 196);
            const float4* q2p = (const float4*)(qs + (w * 4 + 2) * 196);
            const float4* q3p = (const float4*)(qs + (w * 4 + 3) * 196);
            #pragma unroll 8
            for (int d4 = 0; d4 < 48; d4++) {
                float4 kv = krow[d4];
                float4 qa = q0p[d4]; s0 += qa.x*kv.x + qa.y*kv.y + qa.z*kv.z + qa.w*kv.w;
                float4 qb = q1p[d4]; s1 += qb.x*kv.x + qb.y*kv.y + qb.z*kv.z + qb.w*kv.w;
                float4 qg = q2p[d4]; s2 += qg.x*kv.x + qg.y*kv.y + qg.z*kv.z + qg.w*kv.w;
                float4 qd = q3p[d4]; s3 += qd.x*kv.x + qd.y*kv.y + qd.z*kv.z + qd.w*kv.w;
            }
        }
        float sc[4] = {s0, s1, s2, s3};

        #pragma unroll
        for (int rr = 0; rr < 4; rr++) {
            int qi = w * 4 + rr;
            int qglob = q0 + qi;
            float s = sc[rr] * ATTN_SCALE;
            if (k0 + lane > qglob) s = -INFINITY;
            float tmax = s;
            #pragma unroll
            for (int o = 16; o; o >>= 1) tmax = fmaxf(tmax, __shfl_xor_sync(0xffffffffu, tmax, o));
            float mnew = fmaxf(m_i[rr], tmax);
            if (mnew == -INFINITY) {
                ps[qi * 33 + lane] = 0.f;   // fully masked tile for this row
            } else {
                float scl = expf(m_i[rr] - mnew);  // m_i=-inf -> 0
                float pe  = expf(s - mnew);        // masked -> 0
                float lsum = pe;
                #pragma unroll
                for (int o = 16; o; o >>= 1) lsum += __shfl_xor_sync(0xffffffffu, lsum, o);
                l_i[rr] = l_i[rr] * scl + lsum;
                m_i[rr] = mnew;
                #pragma unroll
                for (int dd = 0; dd < 4; dd++) acc[rr][dd] *= scl;
                ps[qi * 33 + lane] = pe;
            }
        }
        __syncwarp();

        // p @ v
        #pragma unroll 4
        for (int kj = 0; kj < 32; kj++) {
            float v0 = vs[kj * 132 + lane];
            float v1 = vs[kj * 132 + lane + 32];
            float v2 = vs[kj * 132 + lane + 64];
            float v3 = vs[kj * 132 + lane + 96];
            #pragma unroll
            for (int rr = 0; rr < 4; rr++) {
                float pr = ps[(w * 4 + rr) * 33 + kj];
                acc[rr][0] += pr * v0;
                acc[rr][1] += pr * v1;
                acc[rr][2] += pr * v2;
                acc[rr][3] += pr * v3;
            }
        }
    }

    size_t obase = ((size_t)(b * 2 + p) * NHh + n) * Lseq;
    #pragma unroll
    for (int rr = 0; rr < 4; rr++) {
        int qglob = q0 + w * 4 + rr;
        float inv_l = 1.f / l_i[rr];
        float* op = attn + (obase + qglob) * 128;
        op[lane]      = acc[rr][0] * inv_l;
        op[lane + 32] = acc[rr][1] * inv_l;
        op[lane + 64] = acc[rr][2] * inv_l;
        op[lane + 96] = acc[rr][3] * inv_l;
    }
}

// ---------------- combine: pre = attn1 - lam * attn2, layout [b,l, n*128+d] ----------------
__global__ void combine_kernel(const float* __restrict__ attn, const float* __restrict__ lam,
                               float* __restrict__ pre)
{
    int idx = blockIdx.x * 256 + threadIdx.x;   // over BL*2048
    int c = idx & 2047;
    int row = idx >> 11;        // b*L + l
    int b = row >> 11;
    int l = row & 2047;
    int n = c >> 7, d = c & 127;
    size_t a1 = (((size_t)(b * 2 + 0) * NHh + n) * Lseq + l) * 128 + d;
    size_t a2 = (((size_t)(b * 2 + 1) * NHh + n) * Lseq + l) * 128 + d;
    pre[idx] = attn[a1] - lam[(size_t)row * 16 + n] * attn[a2];
}

// ---------------- launch ----------------
extern "C" void kernel_launch(void* const* d_in, const int* in_sizes, int n_in,
                              void* d_out, int out_size)
{
    const float* x     = (const float*)d_in[0];
    const float* W_DKV = (const float*)d_in[1];
    const float* kv_w  = (const float*)d_in[2];
    const float* W_UK  = (const float*)d_in[3];
    const float* W_UV  = (const float*)d_in[4];
    const float* W_DQ  = (const float*)d_in[5];
    const float* q_w   = (const float*)d_in[6];
    const float* W_UQ  = (const float*)d_in[7];
    const float* W_QR  = (const float*)d_in[8];
    const float* W_KR  = (const float*)d_in[9];
    const float* W_lw  = (const float*)d_in[10];
    const float* W_lb  = (const float*)d_in[11];
    const float* W_out = (const float*)d_in[12];
    float* out = (float*)d_out;

    float *tmp, *ckv, *cq, *kc, *v, *qc, *qr, *kr, *lam, *attn, *pre;
    cudaGetSymbolAddress((void**)&tmp,  g_tmp);
    cudaGetSymbolAddress((void**)&ckv,  g_ckv);
    cudaGetSymbolAddress((void**)&cq,   g_cq);
    cudaGetSymbolAddress((void**)&kc,   g_kc);
    cudaGetSymbolAddress((void**)&v,    g_v);
    cudaGetSymbolAddress((void**)&qc,   g_qc);
    cudaGetSymbolAddress((void**)&qr,   g_qr);
    cudaGetSymbolAddress((void**)&kr,   g_kr);
    cudaGetSymbolAddress((void**)&lam,  g_lam);
    cudaGetSymbolAddress((void**)&attn, g_attn);
    cudaGetSymbolAddress((void**)&pre,  g_pre);

    // KV path
    sgemm128<<<dim3(DCc / 128, BL / 128), 256>>>(BL, DCc, Dd, x, W_DKV, tmp);
    rms_kernel<<<BL, 256>>>(tmp, kv_w, ckv, DCc);
    sgemm128<<<dim3((NHh * DHh) / 128, BL / 128), 256>>>(BL, NHh * DHh, DCc, ckv, W_UK, kc);
    sgemm128<<<dim3((NHh * DHh) / 128, BL / 128), 256>>>(BL, NHh * DHh, DCc, ckv, W_UV, v);

    // Q path
    sgemm128<<<dim3(DCc / 128, BL / 128), 256>>>(BL, DCc, Dd, x, W_DQ, tmp);
    rms_kernel<<<BL, 256>>>(tmp, q_w, cq, DCc);
    sgemm128<<<dim3((2 * NHh * DHh) / 128, BL / 128), 256>>>(BL, 2 * NHh * DHh, DCc, cq, W_UQ, qc);
    sgemm128<<<dim3((2 * NHh * DHRr) / 128, BL / 128), 256>>>(BL, 2 * NHh * DHRr, DCc, cq, W_QR, qr);

    // k_r (N=64) + RoPE
    gemm_n64<<<BL / 4, dim3(64, 4)>>>(x, W_KR, kr, Dd);
    rope_kernel<<<(BL * 32 * 32) / 256, 256>>>(qr, 32, 2 * NHh * DHRr);
    rope_kernel<<<(BL * 1 * 32) / 256, 256>>>(kr, 1, DHRr);

    // lambda gate
    lam_kernel<<<BL, 128>>>(x, W_lw, W_lb, lam);

    // attention
    const int FLASH_SMEM = (2 * 32 * 196 + 32 * 132 + 32 * 33) * 4; // 71296 B
    cudaFuncSetAttribute(flash_kernel, cudaFuncAttributeMaxDynamicSharedMemorySize, FLASH_SMEM);
    flash_kernel<<<dim3(Lseq / 32, 32, BB), 256, FLASH_SMEM>>>(qc, qr, kc, kr, v, attn);

    // combine + output projection
    combine_kernel<<<(BL * Dd) / 256, 256>>>(attn, lam, pre);
    sgemm128<<<dim3(Dd / 128, BL / 128), 256>>>(BL, Dd, Dd, pre, W_out, out);
}

// round 4
// speedup vs baseline: 1.1140x; 1.1140x over previous
#include <cuda_runtime.h>
#include <cuda.h>
#include <math.h>
#include <stdint.h>

#define BB   2
#define Lseq 2048
#define BL   4096      // B*L
#define Dd   2048
#define DCc  1024
#define NHh  16
#define DHh  128
#define DHRr 64
#define ATTN_SCALE 0.07216878364870322f

// ======================= scratch =======================
__device__ float g_tmp [BL * DCc];
__device__ float g_ckv [BL * DCc];
__device__ float g_cq  [BL * DCc];
__device__ float g_kc  [BL * (NHh * DHh)];
__device__ float g_v   [BL * (NHh * DHh)];
__device__ float g_qc  [BL * (2 * NHh * DHh)];
__device__ float g_qr  [BL * (2 * NHh * DHRr)];
__device__ float g_kr  [BL * DHRr];
__device__ float g_lam [BL * NHh];
__device__ float g_attn[(size_t)2 * BB * NHh * Lseq * DHh];
__device__ float g_pre [BL * Dd];
// transposed weights [N,K]
__device__ float g_tDKV[DCc * Dd];
__device__ float g_tUK [(NHh*DHh) * DCc];
__device__ float g_tUV [(NHh*DHh) * DCc];
__device__ float g_tDQ [DCc * Dd];
__device__ float g_tUQ [(2*NHh*DHh) * DCc];
__device__ float g_tQR [(2*NHh*DHRr) * DCc];
__device__ float g_tOUT[Dd * Dd];

// ======================= helpers =======================
__device__ __forceinline__ uint32_t smem_u32(const void* p) {
    uint32_t a;
    asm("{ .reg .u64 t; cvta.to.shared.u64 t, %1; cvt.u32.u64 %0, t; }" : "=r"(a) : "l"(p));
    return a;
}
__device__ __forceinline__ void cp16(uint32_t dst, const void* src) {
    asm volatile("cp.async.cg.shared.global [%0], [%1], 16;" :: "r"(dst), "l"(src));
}
#define CP_COMMIT() asm volatile("cp.async.commit_group;" ::: "memory")
#define CP_WAIT0()  asm volatile("cp.async.wait_group 0;"  ::: "memory")

__device__ __forceinline__ uint32_t tf32_rna(float x) {
    uint32_t u; asm("cvt.rna.tf32.f32 %0, %1;" : "=r"(u) : "f"(x));
    return u;
}

__device__ __forceinline__ void mma_tf32(float c[4],
                                         uint32_t a0, uint32_t a1, uint32_t a2, uint32_t a3,
                                         uint32_t b0, uint32_t b1)
{
    asm volatile(
        "mma.sync.aligned.m16n8k8.row.col.f32.tf32.tf32.f32 "
        "{%0,%1,%2,%3}, {%4,%5,%6,%7}, {%8,%9}, {%0,%1,%2,%3};"
        : "+f"(c[0]), "+f"(c[1]), "+f"(c[2]), "+f"(c[3])
        : "r"(a0), "r"(a1), "r"(a2), "r"(a3), "r"(b0), "r"(b1));
}

// ======================= transpose: in[R][C] -> out[C][R] =======================
__global__ void transpose32(const float* __restrict__ in, float* __restrict__ out, int R, int C)
{
    __shared__ float t[32][33];
    int bx = blockIdx.x * 32, by = blockIdx.y * 32;
    int x = bx + threadIdx.x;
    #pragma unroll
    for (int j = 0; j < 32; j += 8)
        t[threadIdx.y + j][threadIdx.x] = in[(size_t)(by + threadIdx.y + j) * C + x];
    __syncthreads();
    int ox = by + threadIdx.x;
    #pragma unroll
    for (int j = 0; j < 32; j += 8)
        out[(size_t)(bx + threadIdx.y + j) * R + ox] = t[threadIdx.x][threadIdx.y + j];
}

// ======================= tensor-core tf32 GEMM with 2-term error-compensated split ======
// C[M,N] = A[M,K] @ Bt[N,K]^T. Tile 128x128, BK=32, 256 threads (8 warps, 2M x 4N).
// fp32 lives in smem; hi/lo tf32 splits are formed in registers.
// D = Ahi*Bhi + Ahi*Blo + Alo*Bhi  (lo*lo dropped, ~2^-22 relative)
#define TSTR 36
__global__ __launch_bounds__(256)
void mgemm(int N, int K,
           const float* __restrict__ A,
           const float* __restrict__ Bt,
           float* __restrict__ C)
{
    extern __shared__ float sm[];
    float* As[2] = { sm,               sm + 2 * 128 * TSTR };
    float* Bs[2] = { sm + 128 * TSTR,  sm + 3 * 128 * TSTR };

    const int tid = threadIdx.x;
    const int wid = tid >> 5, lane = tid & 31;
    const int m0 = blockIdx.y * 128, n0 = blockIdx.x * 128;
    const int warpM = (wid >> 2) * 64;   // 0 or 64
    const int warpN = (wid & 3) * 32;

    const float* Ab = A  + (size_t)m0 * K;
    const float* Bb = Bt + (size_t)n0 * K;

    const int r_st  = tid >> 3;
    const int c4_st = (tid & 7) * 4;

    auto stage = [&](int kc, int b) {
        uint32_t abase = smem_u32(As[b]);
        uint32_t bbase = smem_u32(Bs[b]);
        #pragma unroll
        for (int i = 0; i < 4; i++) {
            int r = r_st + i * 32;
            uint32_t off = (uint32_t)(r * TSTR + c4_st) * 4u;
            cp16(abase + off, Ab + (size_t)r * K + kc + c4_st);
            cp16(bbase + off, Bb + (size_t)r * K + kc + c4_st);
        }
        CP_COMMIT();
    };

    float acc[4][4][4];
    #pragma unroll
    for (int i = 0; i < 4; i++)
        #pragma unroll
        for (int j = 0; j < 4; j++)
            #pragma unroll
            for (int k = 0; k < 4; k++) acc[i][j][k] = 0.f;

    stage(0, 0);

    const int nch = K >> 5;
    const int lr = lane >> 2;
    const int lc = lane & 3;

    for (int i = 0; i < nch; i++) {
        CP_WAIT0();
        __syncthreads();
        if (i + 1 < nch) stage((i + 1) << 5, (i + 1) & 1);

        const float* Ar = As[i & 1];
        const float* Br = Bs[i & 1];
        #pragma unroll
        for (int kk = 0; kk < 4; kk++) {
            const int kb = kk * 8;
            uint32_t ah[4][4], al[4][4], bh[4][2], blo[4][2];
            #pragma unroll
            for (int ma = 0; ma < 4; ma++) {
                int row = warpM + ma * 16 + lr;
                float f0 = Ar[ row      * TSTR + kb + lc    ];
                float f1 = Ar[(row + 8) * TSTR + kb + lc    ];
                float f2 = Ar[ row      * TSTR + kb + lc + 4];
                float f3 = Ar[(row + 8) * TSTR + kb + lc + 4];
                ah[ma][0] = tf32_rna(f0); al[ma][0] = tf32_rna(f0 - __uint_as_float(ah[ma][0]));
                ah[ma][1] = tf32_rna(f1); al[ma][1] = tf32_rna(f1 - __uint_as_float(ah[ma][1]));
                ah[ma][2] = tf32_rna(f2); al[ma][2] = tf32_rna(f2 - __uint_as_float(ah[ma][2]));
                ah[ma][3] = tf32_rna(f3); al[ma][3] = tf32_rna(f3 - __uint_as_float(ah[ma][3]));
            }
            #pragma unroll
            for (int nb = 0; nb < 4; nb++) {
                int col = warpN + nb * 8 + lr;
                float g0 = Br[col * TSTR + kb + lc    ];
                float g1 = Br[col * TSTR + kb + lc + 4];
                bh[nb][0] = tf32_rna(g0); blo[nb][0] = tf32_rna(g0 - __uint_as_float(bh[nb][0]));
                bh[nb][1] = tf32_rna(g1); blo[nb][1] = tf32_rna(g1 - __uint_as_float(bh[nb][1]));
            }
            #pragma unroll
            for (int ma = 0; ma < 4; ma++)
                #pragma unroll
                for (int nb = 0; nb < 4; nb++) {
                    // correction terms first, big term last (better rounding behavior)
                    mma_tf32(acc[ma][nb], al[ma][0], al[ma][1], al[ma][2], al[ma][3],
                             bh[nb][0], bh[nb][1]);
                    mma_tf32(acc[ma][nb], ah[ma][0], ah[ma][1], ah[ma][2], ah[ma][3],
                             blo[nb][0], blo[nb][1]);
                    mma_tf32(acc[ma][nb], ah[ma][0], ah[ma][1], ah[ma][2], ah[ma][3],
                             bh[nb][0], bh[nb][1]);
                }
        }
        __syncthreads();
    }

    // epilogue
    #pragma unroll
    for (int ma = 0; ma < 4; ma++) {
        int row = m0 + warpM + ma * 16 + lr;
        #pragma unroll
        for (int nb = 0; nb < 4; nb++) {
            int col = n0 + warpN + nb * 8 + lc * 2;
            float2 o0 = make_float2(acc[ma][nb][0], acc[ma][nb][1]);
            float2 o1 = make_float2(acc[ma][nb][2], acc[ma][nb][3]);
            *(float2*)(C + (size_t)row * N + col)       = o0;
            *(float2*)(C + (size_t)(row + 8) * N + col) = o1;
        }
    }
}
#define MGEMM_SMEM (4 * 128 * TSTR * 4)   // 73728 B

// ======================= RMS norm =======================
__global__ void rms_kernel(const float* __restrict__ in, const float* __restrict__ w,
                           float* __restrict__ out, int N)
{
    int row = blockIdx.x;
    const float* ir = in + (size_t)row * N;
    float s = 0.f;
    for (int i = threadIdx.x; i < N; i += 256) { float v = ir[i]; s += v * v; }
    __shared__ float red[256];
    red[threadIdx.x] = s;
    __syncthreads();
    for (int st = 128; st > 0; st >>= 1) {
        if (threadIdx.x < st) red[threadIdx.x] += red[threadIdx.x + st];
        __syncthreads();
    }
    float rr = rsqrtf(red[0] / (float)N + 1e-6f);
    float* orow = out + (size_t)row * N;
    for (int i = threadIdx.x; i < N; i += 256) orow[i] = ir[i] * rr * w[i];
}

// ======================= RoPE (in-place) =======================
__global__ void rope_kernel(float* __restrict__ t, int heads, int rowstride)
{
    int idx = blockIdx.x * blockDim.x + threadIdx.x;
    int j = idx & 31;
    int h = (idx >> 5) % heads;
    int row = idx / (32 * heads);
    if (row >= BL) return;
    int l = row & (Lseq - 1);
    float inv = powf(10000.f, -(float)(2 * j) / 64.f);
    float ang = (float)l * inv;
    float c = cosf(ang), s = sinf(ang);
    float* base = t + (size_t)row * rowstride + h * 64;
    float x1 = base[j], x2 = base[j + 32];
    base[j]      = x1 * c - x2 * s;
    base[j + 32] = x2 * c + x1 * s;
}

// ======================= lambda gate =======================
__global__ void lam_kernel(const float* __restrict__ x, const float* __restrict__ Wl,
                           const float* __restrict__ bl, float* __restrict__ lam)
{
    int row = blockIdx.x;
    int tid = threadIdx.x;
    const float* xr = x + (size_t)row * Dd;
    float acc[16];
    #pragma unroll
    for (int n = 0; n < 16; n++) acc[n] = 0.f;
    for (int k = tid; k < Dd; k += 128) {
        float xv = xr[k];
        const float* wv = Wl + (size_t)k * 16;
        #pragma unroll
        for (int n = 0; n < 16; n++) acc[n] += xv * wv[n];
    }
    __shared__ float red[16 * 128];
    #pragma unroll
    for (int n = 0; n < 16; n++) red[n * 128 + tid] = acc[n];
    __syncthreads();
    for (int st = 64; st > 0; st >>= 1) {
        if (tid < st) {
            #pragma unroll
            for (int n = 0; n < 16; n++) red[n * 128 + tid] += red[n * 128 + tid + st];
        }
        __syncthreads();
    }
    if (tid < 16) {
        float z = red[tid * 128] + bl[tid];
        lam[(size_t)row * 16 + tid] = 1.f / (1.f + expf(-z));
    }
}

// ======================= small GEMM N=64 (x @ W_KR) =======================
__global__ void gemm_n64(const float* __restrict__ A, const float* __restrict__ B,
                         float* __restrict__ C, int K)
{
    int n = threadIdx.x;
    int m = blockIdx.x * 4 + threadIdx.y;
    float acc = 0.f;
    const float* ar = A + (size_t)m * K;
    #pragma unroll 8
    for (int k = 0; k < K; k++) acc += ar[k] * B[(size_t)k * 64 + n];
    C[(size_t)m * 64 + n] = acc;
}

// ======================= fused causal flash attention, fp32 =======================
__global__ void flash_kernel(const float* __restrict__ qc, const float* __restrict__ qr,
                             const float* __restrict__ kc, const float* __restrict__ kr,
                             const float* __restrict__ vv, float* __restrict__ attn)
{
    extern __shared__ float sm[];
    float* qs = sm;
    float* ks = sm + 32 * 196;
    float* vs = sm + 2 * 32 * 196;
    float* ps = vs + 32 * 132;

    const int q0 = blockIdx.x * 32;
    const int head2 = blockIdx.y;
    const int b = blockIdx.z;
    const int n = head2 >> 1, p = head2 & 1;
    const int tid = threadIdx.x;
    const int lane = tid & 31, w = tid >> 5;

    const float* qcb = qc + ((size_t)(b * Lseq + q0)) * 4096 + head2 * 128;
    const float* qrb = qr + ((size_t)(b * Lseq + q0)) * 2048 + head2 * 64;
    for (int i = tid; i < 32 * 128; i += 256) {
        int r = i >> 7, c = i & 127;
        qs[r * 196 + c] = qcb[(size_t)r * 4096 + c];
    }
    for (int i = tid; i < 32 * 64; i += 256) {
        int r = i >> 6, c = i & 63;
        qs[r * 196 + 128 + c] = qrb[(size_t)r * 2048 + c];
    }

    float m_i[4], l_i[4], acc[4][4];
    #pragma unroll
    for (int rr = 0; rr < 4; rr++) {
        m_i[rr] = -INFINITY; l_i[rr] = 0.f;
        #pragma unroll
        for (int dd = 0; dd < 4; dd++) acc[rr][dd] = 0.f;
    }

    const int kend = q0 + 32;
    for (int k0 = 0; k0 < kend; k0 += 32) {
        __syncthreads();
        const float* kcb = kc + ((size_t)(b * Lseq + k0)) * 2048 + n * 128;
        const float* krb = kr + ((size_t)(b * Lseq + k0)) * 64;
        const float* vb  = vv + ((size_t)(b * Lseq + k0)) * 2048 + n * 128;
        for (int i = tid; i < 32 * 128; i += 256) {
            int r = i >> 7, c = i & 127;
            ks[r * 196 + c] = kcb[(size_t)r * 2048 + c];
            vs[r * 132 + c] = vb[(size_t)r * 2048 + c];
        }
        for (int i = tid; i < 32 * 64; i += 256) {
            int r = i >> 6, c = i & 63;
            ks[r * 196 + 128 + c] = krb[(size_t)r * 64 + c];
        }
        __syncthreads();

        float s0 = 0.f, s1 = 0.f, s2 = 0.f, s3 = 0.f;
        {
            const float4* krow = (const float4*)(ks + lane * 196);
            const float4* q0p = (const float4*)(qs + (w * 4 + 0) * 196);
            const float4* q1p = (const float4*)(qs + (w * 4 + 1) * 196);
            const float4* q2p = (const float4*)(qs + (w * 4 + 2) * 196);
            const float4* q3p = (const float4*)(qs + (w * 4 + 3) * 196);
            #pragma unroll 8
            for (int d4 = 0; d4 < 48; d4++) {
                float4 kv = krow[d4];
                float4 qa = q0p[d4]; s0 += qa.x*kv.x + qa.y*kv.y + qa.z*kv.z + qa.w*kv.w;
                float4 qb = q1p[d4]; s1 += qb.x*kv.x + qb.y*kv.y + qb.z*kv.z + qb.w*kv.w;
                float4 qg = q2p[d4]; s2 += qg.x*kv.x + qg.y*kv.y + qg.z*kv.z + qg.w*kv.w;
                float4 qd = q3p[d4]; s3 += qd.x*kv.x + qd.y*kv.y + qd.z*kv.z + qd.w*kv.w;
            }
        }
        float sc[4] = {s0, s1, s2, s3};

        #pragma unroll
        for (int rr = 0; rr < 4; rr++) {
            int qi = w * 4 + rr;
            int qglob = q0 + qi;
            float s = sc[rr] * ATTN_SCALE;
            if (k0 + lane > qglob) s = -INFINITY;
            float tmax = s;
            #pragma unroll
            for (int o = 16; o; o >>= 1) tmax = fmaxf(tmax, __shfl_xor_sync(0xffffffffu, tmax, o));
            float mnew = fmaxf(m_i[rr], tmax);
            if (mnew == -INFINITY) {
                ps[qi * 33 + lane] = 0.f;
            } else {
                float scl = expf(m_i[rr] - mnew);
                float pe  = expf(s - mnew);
                float lsum = pe;
                #pragma unroll
                for (int o = 16; o; o >>= 1) lsum += __shfl_xor_sync(0xffffffffu, lsum, o);
                l_i[rr] = l_i[rr] * scl + lsum;
                m_i[rr] = mnew;
                #pragma unroll
                for (int dd = 0; dd < 4; dd++) acc[rr][dd] *= scl;
                ps[qi * 33 + lane] = pe;
            }
        }
        __syncwarp();

        #pragma unroll 4
        for (int kj = 0; kj < 32; kj++) {
            float v0 = vs[kj * 132 + lane];
            float v1 = vs[kj * 132 + lane + 32];
            float v2 = vs[kj * 132 + lane + 64];
            float v3 = vs[kj * 132 + lane + 96];
            #pragma unroll
            for (int rr = 0; rr < 4; rr++) {
                float pr = ps[(w * 4 + rr) * 33 + kj];
                acc[rr][0] += pr * v0;
                acc[rr][1] += pr * v1;
                acc[rr][2] += pr * v2;
                acc[rr][3] += pr * v3;
            }
        }
    }

    size_t obase = ((size_t)(b * 2 + p) * NHh + n) * Lseq;
    #pragma unroll
    for (int rr = 0; rr < 4; rr++) {
        int qglob = q0 + w * 4 + rr;
        float inv_l = 1.f / l_i[rr];
        float* op = attn + (obase + qglob) * 128;
        op[lane]      = acc[rr][0] * inv_l;
        op[lane + 32] = acc[rr][1] * inv_l;
        op[lane + 64] = acc[rr][2] * inv_l;
        op[lane + 96] = acc[rr][3] * inv_l;
    }
}

// ======================= combine =======================
__global__ void combine_kernel(const float* __restrict__ attn, const float* __restrict__ lam,
                               float* __restrict__ pre)
{
    int idx = blockIdx.x * 256 + threadIdx.x;
    int c = idx & 2047;
    int row = idx >> 11;
    int b = row >> 11;
    int l = row & 2047;
    int n = c >> 7, d = c & 127;
    size_t a1 = (((size_t)(b * 2 + 0) * NHh + n) * Lseq + l) * 128 + d;
    size_t a2 = (((size_t)(b * 2 + 1) * NHh + n) * Lseq + l) * 128 + d;
    pre[idx] = attn[a1] - lam[(size_t)row * 16 + n] * attn[a2];
}

// ======================= launch =======================
extern "C" void kernel_launch(void* const* d_in, const int* in_sizes, int n_in,
                              void* d_out, int out_size)
{
    const float* x     = (const float*)d_in[0];
    const float* W_DKV = (const float*)d_in[1];
    const float* kv_w  = (const float*)d_in[2];
    const float* W_UK  = (const float*)d_in[3];
    const float* W_UV  = (const float*)d_in[4];
    const float* W_DQ  = (const float*)d_in[5];
    const float* q_w   = (const float*)d_in[6];
    const float* W_UQ  = (const float*)d_in[7];
    const float* W_QR  = (const float*)d_in[8];
    const float* W_KR  = (const float*)d_in[9];
    const float* W_lw  = (const float*)d_in[10];
    const float* W_lb  = (const float*)d_in[11];
    const float* W_out = (const float*)d_in[12];
    float* out = (float*)d_out;

    float *tmp, *ckv, *cq, *kc, *v, *qc, *qr, *kr, *lam, *attn, *pre;
    float *tDKV, *tUK, *tUV, *tDQ, *tUQ, *tQR, *tOUT;
    cudaGetSymbolAddress((void**)&tmp,  g_tmp);
    cudaGetSymbolAddress((void**)&ckv,  g_ckv);
    cudaGetSymbolAddress((void**)&cq,   g_cq);
    cudaGetSymbolAddress((void**)&kc,   g_kc);
    cudaGetSymbolAddress((void**)&v,    g_v);
    cudaGetSymbolAddress((void**)&qc,   g_qc);
    cudaGetSymbolAddress((void**)&qr,   g_qr);
    cudaGetSymbolAddress((void**)&kr,   g_kr);
    cudaGetSymbolAddress((void**)&lam,  g_lam);
    cudaGetSymbolAddress((void**)&attn, g_attn);
    cudaGetSymbolAddress((void**)&pre,  g_pre);
    cudaGetSymbolAddress((void**)&tDKV, g_tDKV);
    cudaGetSymbolAddress((void**)&tUK,  g_tUK);
    cudaGetSymbolAddress((void**)&tUV,  g_tUV);
    cudaGetSymbolAddress((void**)&tDQ,  g_tDQ);
    cudaGetSymbolAddress((void**)&tUQ,  g_tUQ);
    cudaGetSymbolAddress((void**)&tQR,  g_tQR);
    cudaGetSymbolAddress((void**)&tOUT, g_tOUT);

    cudaFuncSetAttribute(mgemm, cudaFuncAttributeMaxDynamicSharedMemorySize, MGEMM_SMEM);

    dim3 tb(32, 8);
    // weight transposes ([K,N] -> [N,K])
    transpose32<<<dim3(DCc/32,  Dd/32),  tb>>>(W_DKV, tDKV, Dd,  DCc);
    transpose32<<<dim3((NHh*DHh)/32, DCc/32), tb>>>(W_UK, tUK, DCc, NHh*DHh);
    transpose32<<<dim3((NHh*DHh)/32, DCc/32), tb>>>(W_UV, tUV, DCc, NHh*DHh);
    transpose32<<<dim3(DCc/32,  Dd/32),  tb>>>(W_DQ,  tDQ,  Dd,  DCc);
    transpose32<<<dim3((2*NHh*DHh)/32, DCc/32), tb>>>(W_UQ, tUQ, DCc, 2*NHh*DHh);
    transpose32<<<dim3((2*NHh*DHRr)/32, DCc/32), tb>>>(W_QR, tQR, DCc, 2*NHh*DHRr);
    transpose32<<<dim3(Dd/32,   Dd/32),  tb>>>(W_out, tOUT, Dd,  Dd);

    // KV path
    mgemm<<<dim3(DCc/128, BL/128), 256, MGEMM_SMEM>>>(DCc, Dd, x, tDKV, tmp);
    rms_kernel<<<BL, 256>>>(tmp, kv_w, ckv, DCc);
    mgemm<<<dim3((NHh*DHh)/128, BL/128), 256, MGEMM_SMEM>>>(NHh*DHh, DCc, ckv, tUK, kc);
    mgemm<<<dim3((NHh*DHh)/128, BL/128), 256, MGEMM_SMEM>>>(NHh*DHh, DCc, ckv, tUV, v);

    // Q path
    mgemm<<<dim3(DCc/128, BL/128), 256, MGEMM_SMEM>>>(DCc, Dd, x, tDQ, tmp);
    rms_kernel<<<BL, 256>>>(tmp, q_w, cq, DCc);
    mgemm<<<dim3((2*NHh*DHh)/128, BL/128), 256, MGEMM_SMEM>>>(2*NHh*DHh, DCc, cq, tUQ, qc);
    mgemm<<<dim3((2*NHh*DHRr)/128, BL/128), 256, MGEMM_SMEM>>>(2*NHh*DHRr, DCc, cq, tQR, qr);

    // k_r (N=64) + RoPE
    gemm_n64<<<BL / 4, dim3(64, 4)>>>(x, W_KR, kr, Dd);
    rope_kernel<<<(BL * 32 * 32) / 256, 256>>>(qr, 32, 2 * NHh * DHRr);
    rope_kernel<<<(BL * 1 * 32) / 256, 256>>>(kr, 1, DHRr);

    // lambda gate
    lam_kernel<<<BL, 128>>>(x, W_lw, W_lb, lam);

    // attention
    const int FLASH_SMEM = (2 * 32 * 196 + 32 * 132 + 32 * 33) * 4;
    cudaFuncSetAttribute(flash_kernel, cudaFuncAttributeMaxDynamicSharedMemorySize, FLASH_SMEM);
    flash_kernel<<<dim3(Lseq / 32, 32, BB), 256, FLASH_SMEM>>>(qc, qr, kc, kr, v, attn);

    // combine + output projection
    combine_kernel<<<(BL * Dd) / 256, 256>>>(attn, lam, pre);
    mgemm<<<dim3(Dd/128, BL/128), 256, MGEMM_SMEM>>>(Dd, Dd, pre, tOUT, out);
}

// round 5
// speedup vs baseline: 1.5382x; 1.3808x over previous
#include <cuda_runtime.h>
#include <cuda.h>
#include <math.h>
#include <stdint.h>

#define BB   2
#define Lseq 2048
#define BL   4096      // B*L
#define Dd   2048
#define DCc  1024
#define NHh  16
#define DHh  128
#define DHRr 64
#define ATTN_SCALE 0.07216878364870322f

// ======================= scratch =======================
__device__ float g_tmp [BL * DCc];
__device__ float g_ckv [BL * DCc];
__device__ float g_cq  [BL * DCc];
__device__ float g_kc  [BL * (NHh * DHh)];
__device__ float g_v   [BL * (NHh * DHh)];
__device__ float g_qc  [BL * (2 * NHh * DHh)];
__device__ float g_qr  [BL * (2 * NHh * DHRr)];
__device__ float g_kr  [BL * DHRr];
__device__ float g_lam [BL * NHh];
__device__ float g_attn[(size_t)2 * BB * NHh * Lseq * DHh];
__device__ float g_pre [BL * Dd];
// transposed weights [N,K]
__device__ float g_tDKV[DCc * Dd];
__device__ float g_tUK [(NHh*DHh) * DCc];
__device__ float g_tUV [(NHh*DHh) * DCc];
__device__ float g_tDQ [DCc * Dd];
__device__ float g_tUQ [(2*NHh*DHh) * DCc];
__device__ float g_tQR [(2*NHh*DHRr) * DCc];
__device__ float g_tOUT[Dd * Dd];

// ======================= helpers =======================
__device__ __forceinline__ uint32_t smem_u32(const void* p) {
    uint32_t a;
    asm("{ .reg .u64 t; cvta.to.shared.u64 t, %1; cvt.u32.u64 %0, t; }" : "=r"(a) : "l"(p));
    return a;
}
__device__ __forceinline__ void cp16(uint32_t dst, const void* src) {
    asm volatile("cp.async.cg.shared.global [%0], [%1], 16;" :: "r"(dst), "l"(src));
}
#define CP_COMMIT() asm volatile("cp.async.commit_group;" ::: "memory")
#define CP_WAIT0()  asm volatile("cp.async.wait_group 0;"  ::: "memory")

__device__ __forceinline__ uint32_t tf32_rna(float x) {
    uint32_t u; asm("cvt.rna.tf32.f32 %0, %1;" : "=r"(u) : "f"(x));
    return u;
}
// cheap split: hi = mantissa-truncated fp32 (valid tf32 payload), lo = exact residual
__device__ __forceinline__ uint32_t hi_tf32(float x) {
    return __float_as_uint(x) & 0xFFFFE000u;
}

__device__ __forceinline__ void mma_tf32(float c[4],
                                         uint32_t a0, uint32_t a1, uint32_t a2, uint32_t a3,
                                         uint32_t b0, uint32_t b1)
{
    asm volatile(
        "mma.sync.aligned.m16n8k8.row.col.f32.tf32.tf32.f32 "
        "{%0,%1,%2,%3}, {%4,%5,%6,%7}, {%8,%9}, {%0,%1,%2,%3};"
        : "+f"(c[0]), "+f"(c[1]), "+f"(c[2]), "+f"(c[3])
        : "r"(a0), "r"(a1), "r"(a2), "r"(a3), "r"(b0), "r"(b1));
}

// ======================= transpose: in[R][C] -> out[C][R] =======================
__global__ void transpose32(const float* __restrict__ in, float* __restrict__ out, int R, int C)
{
    __shared__ float t[32][33];
    int bx = blockIdx.x * 32, by = blockIdx.y * 32;
    int x = bx + threadIdx.x;
    #pragma unroll
    for (int j = 0; j < 32; j += 8)
        t[threadIdx.y + j][threadIdx.x] = in[(size_t)(by + threadIdx.y + j) * C + x];
    __syncthreads();
    int ox = by + threadIdx.x;
    #pragma unroll
    for (int j = 0; j < 32; j += 8)
        out[(size_t)(bx + threadIdx.y + j) * R + ox] = t[threadIdx.x][threadIdx.y + j];
}

// ======================= tensor-core tf32 GEMM with 2-term error-compensated split ======
#define TSTR 36
__global__ __launch_bounds__(256)
void mgemm(int N, int K,
           const float* __restrict__ A,
           const float* __restrict__ Bt,
           float* __restrict__ C)
{
    extern __shared__ float sm[];
    float* As[2] = { sm,               sm + 2 * 128 * TSTR };
    float* Bs[2] = { sm + 128 * TSTR,  sm + 3 * 128 * TSTR };

    const int tid = threadIdx.x;
    const int wid = tid >> 5, lane = tid & 31;
    const int m0 = blockIdx.y * 128, n0 = blockIdx.x * 128;
    const int warpM = (wid >> 2) * 64;
    const int warpN = (wid & 3) * 32;

    const float* Ab = A  + (size_t)m0 * K;
    const float* Bb = Bt + (size_t)n0 * K;

    const int r_st  = tid >> 3;
    const int c4_st = (tid & 7) * 4;

    auto stage = [&](int kc, int b) {
        uint32_t abase = smem_u32(As[b]);
        uint32_t bbase = smem_u32(Bs[b]);
        #pragma unroll
        for (int i = 0; i < 4; i++) {
            int r = r_st + i * 32;
            uint32_t off = (uint32_t)(r * TSTR + c4_st) * 4u;
            cp16(abase + off, Ab + (size_t)r * K + kc + c4_st);
            cp16(bbase + off, Bb + (size_t)r * K + kc + c4_st);
        }
        CP_COMMIT();
    };

    float acc[4][4][4];
    #pragma unroll
    for (int i = 0; i < 4; i++)
        #pragma unroll
        for (int j = 0; j < 4; j++)
            #pragma unroll
            for (int k = 0; k < 4; k++) acc[i][j][k] = 0.f;

    stage(0, 0);

    const int nch = K >> 5;
    const int lr = lane >> 2;
    const int lc = lane & 3;

    for (int i = 0; i < nch; i++) {
        CP_WAIT0();
        __syncthreads();
        if (i + 1 < nch) stage((i + 1) << 5, (i + 1) & 1);

        const float* Ar = As[i & 1];
        const float* Br = Bs[i & 1];
        #pragma unroll
        for (int kk = 0; kk < 4; kk++) {
            const int kb = kk * 8;
            uint32_t ah[4][4], al[4][4], bh[4][2], blo[4][2];
            #pragma unroll
            for (int ma = 0; ma < 4; ma++) {
                int row = warpM + ma * 16 + lr;
                float f0 = Ar[ row      * TSTR + kb + lc    ];
                float f1 = Ar[(row + 8) * TSTR + kb + lc    ];
                float f2 = Ar[ row      * TSTR + kb + lc + 4];
                float f3 = Ar[(row + 8) * TSTR + kb + lc + 4];
                ah[ma][0] = tf32_rna(f0); al[ma][0] = __float_as_uint(f0 - __uint_as_float(ah[ma][0]));
                ah[ma][1] = tf32_rna(f1); al[ma][1] = __float_as_uint(f1 - __uint_as_float(ah[ma][1]));
                ah[ma][2] = tf32_rna(f2); al[ma][2] = __float_as_uint(f2 - __uint_as_float(ah[ma][2]));
                ah[ma][3] = tf32_rna(f3); al[ma][3] = __float_as_uint(f3 - __uint_as_float(ah[ma][3]));
            }
            #pragma unroll
            for (int nb = 0; nb < 4; nb++) {
                int col = warpN + nb * 8 + lr;
                float g0 = Br[col * TSTR + kb + lc    ];
                float g1 = Br[col * TSTR + kb + lc + 4];
                bh[nb][0] = tf32_rna(g0); blo[nb][0] = __float_as_uint(g0 - __uint_as_float(bh[nb][0]));
                bh[nb][1] = tf32_rna(g1); blo[nb][1] = __float_as_uint(g1 - __uint_as_float(bh[nb][1]));
            }
            #pragma unroll
            for (int ma = 0; ma < 4; ma++)
                #pragma unroll
                for (int nb = 0; nb < 4; nb++) {
                    mma_tf32(acc[ma][nb], al[ma][0], al[ma][1], al[ma][2], al[ma][3],
                             bh[nb][0], bh[nb][1]);
                    mma_tf32(acc[ma][nb], ah[ma][0], ah[ma][1], ah[ma][2], ah[ma][3],
                             blo[nb][0], blo[nb][1]);
                    mma_tf32(acc[ma][nb], ah[ma][0], ah[ma][1], ah[ma][2], ah[ma][3],
                             bh[nb][0], bh[nb][1]);
                }
        }
        __syncthreads();
    }

    #pragma unroll
    for (int ma = 0; ma < 4; ma++) {
        int row = m0 + warpM + ma * 16 + lr;
        #pragma unroll
        for (int nb = 0; nb < 4; nb++) {
            int col = n0 + warpN + nb * 8 + lc * 2;
            float2 o0 = make_float2(acc[ma][nb][0], acc[ma][nb][1]);
            float2 o1 = make_float2(acc[ma][nb][2], acc[ma][nb][3]);
            *(float2*)(C + (size_t)row * N + col)       = o0;
            *(float2*)(C + (size_t)(row + 8) * N + col) = o1;
        }
    }
}
#define MGEMM_SMEM (4 * 128 * TSTR * 4)   // 73728 B

// ======================= RMS norm =======================
__global__ void rms_kernel(const float* __restrict__ in, const float* __restrict__ w,
                           float* __restrict__ out, int N)
{
    int row = blockIdx.x;
    const float* ir = in + (size_t)row * N;
    float s = 0.f;
    for (int i = threadIdx.x; i < N; i += 256) { float v = ir[i]; s += v * v; }
    __shared__ float red[256];
    red[threadIdx.x] = s;
    __syncthreads();
    for (int st = 128; st > 0; st >>= 1) {
        if (threadIdx.x < st) red[threadIdx.x] += red[threadIdx.x + st];
        __syncthreads();
    }
    float rr = rsqrtf(red[0] / (float)N + 1e-6f);
    float* orow = out + (size_t)row * N;
    for (int i = threadIdx.x; i < N; i += 256) orow[i] = ir[i] * rr * w[i];
}

// ======================= RoPE (in-place) =======================
__global__ void rope_kernel(float* __restrict__ t, int heads, int rowstride)
{
    int idx = blockIdx.x * blockDim.x + threadIdx.x;
    int j = idx & 31;
    int h = (idx >> 5) % heads;
    int row = idx / (32 * heads);
    if (row >= BL) return;
    int l = row & (Lseq - 1);
    float inv = powf(10000.f, -(float)(2 * j) / 64.f);
    float ang = (float)l * inv;
    float c = cosf(ang), s = sinf(ang);
    float* base = t + (size_t)row * rowstride + h * 64;
    float x1 = base[j], x2 = base[j + 32];
    base[j]      = x1 * c - x2 * s;
    base[j + 32] = x2 * c + x1 * s;
}

// ======================= lambda gate =======================
__global__ void lam_kernel(const float* __restrict__ x, const float* __restrict__ Wl,
                           const float* __restrict__ bl, float* __restrict__ lam)
{
    int row = blockIdx.x;
    int tid = threadIdx.x;
    const float* xr = x + (size_t)row * Dd;
    float acc[16];
    #pragma unroll
    for (int n = 0; n < 16; n++) acc[n] = 0.f;
    for (int k = tid; k < Dd; k += 128) {
        float xv = xr[k];
        const float* wv = Wl + (size_t)k * 16;
        #pragma unroll
        for (int n = 0; n < 16; n++) acc[n] += xv * wv[n];
    }
    __shared__ float red[16 * 128];
    #pragma unroll
    for (int n = 0; n < 16; n++) red[n * 128 + tid] = acc[n];
    __syncthreads();
    for (int st = 64; st > 0; st >>= 1) {
        if (tid < st) {
            #pragma unroll
            for (int n = 0; n < 16; n++) red[n * 128 + tid] += red[n * 128 + tid + st];
        }
        __syncthreads();
    }
    if (tid < 16) {
        float z = red[tid * 128] + bl[tid];
        lam[(size_t)row * 16 + tid] = 1.f / (1.f + expf(-z));
    }
}

// ======================= small GEMM N=64 (x @ W_KR) =======================
__global__ void gemm_n64(const float* __restrict__ A, const float* __restrict__ B,
                         float* __restrict__ C, int K)
{
    int n = threadIdx.x;
    int m = blockIdx.x * 4 + threadIdx.y;
    float acc = 0.f;
    const float* ar = A + (size_t)m * K;
    #pragma unroll 8
    for (int k = 0; k < K; k++) acc += ar[k] * B[(size_t)k * 64 + n];
    C[(size_t)m * 64 + n] = acc;
}

// ======================= tensor-core flash attention (3xTF32) =======================
// block = 128 threads (4 warps). Q tile 64 rows (16/warp), K tile 32.
// smem: qs[64][196] | ks[32][196] | vs[32][136] | ps[64][36]  = 101888 B
__global__ __launch_bounds__(128)
void flash_mma(const float* __restrict__ qc, const float* __restrict__ qr,
               const float* __restrict__ kc, const float* __restrict__ kr,
               const float* __restrict__ vv, float* __restrict__ attn)
{
    extern __shared__ float sm[];
    float* qs = sm;                  // [64][196]
    float* ks = qs + 64 * 196;       // [32][196]
    float* vs = ks + 32 * 196;       // [32][136]
    float* ps = vs + 32 * 136;       // [64][36]

    const int Q0 = blockIdx.x * 64;
    const int head2 = blockIdx.y;
    const int b = blockIdx.z;
    const int hn = head2 >> 1, hp = head2 & 1;
    const int tid = threadIdx.x;
    const int lane = tid & 31, w = tid >> 5;
    const int lr = lane >> 2, lc = lane & 3;

    uint32_t qsb = smem_u32(qs), ksb = smem_u32(ks), vsb = smem_u32(vs);

    // ---- stage Q (once): qc 64x128, qr 64x64 ----
    {
        const float* qcb = qc + ((size_t)(b * Lseq + Q0)) * 4096 + head2 * 128;
        const float* qrb = qr + ((size_t)(b * Lseq + Q0)) * 2048 + head2 * 64;
        #pragma unroll
        for (int i = 0; i < 16; i++) {
            int s = tid + i * 128;
            int r = s >> 5, c4 = s & 31;
            cp16(qsb + (uint32_t)(r * 196 + c4 * 4) * 4u, qcb + (size_t)r * 4096 + c4 * 4);
        }
        #pragma unroll
        for (int i = 0; i < 8; i++) {
            int s = tid + i * 128;
            int r = s >> 4, c4 = s & 15;
            cp16(qsb + (uint32_t)(r * 196 + 128 + c4 * 4) * 4u, qrb + (size_t)r * 2048 + c4 * 4);
        }
        CP_COMMIT();
    }

    float o[16][4];
    #pragma unroll
    for (int i = 0; i < 16; i++) { o[i][0] = o[i][1] = o[i][2] = o[i][3] = 0.f; }
    float m0 = -INFINITY, m1 = -INFINITY, l0 = 0.f, l1 = 0.f;

    const int row0g = Q0 + 16 * w + lr;
    const int row1g = row0g + 8;

    const float* qrow0 = qs + (16 * w + lr) * 196;
    const float* qrow1 = qrow0 + 8 * 196;
    float* prow0 = ps + (16 * w + lr) * 36;
    float* prow1 = prow0 + 8 * 36;

    const int ntile = (Q0 + 64) >> 5;
    for (int t = 0; t < ntile; t++) {
        const int k0 = t << 5;
        __syncthreads();
        // ---- stage K (kc|kr) and V tiles ----
        {
            const float* kcb = kc + ((size_t)(b * Lseq + k0)) * 2048 + hn * 128;
            const float* krb = kr + ((size_t)(b * Lseq + k0)) * 64;
            const float* vb  = vv + ((size_t)(b * Lseq + k0)) * 2048 + hn * 128;
            #pragma unroll
            for (int i = 0; i < 8; i++) {
                int s = tid + i * 128;
                int r = s >> 5, c4 = s & 31;
                cp16(ksb + (uint32_t)(r * 196 + c4 * 4) * 4u, kcb + (size_t)r * 2048 + c4 * 4);
                cp16(vsb + (uint32_t)(r * 136 + c4 * 4) * 4u, vb  + (size_t)r * 2048 + c4 * 4);
            }
            #pragma unroll
            for (int i = 0; i < 4; i++) {
                int s = tid + i * 128;
                int r = s >> 4, c4 = s & 15;
                cp16(ksb + (uint32_t)(r * 196 + 128 + c4 * 4) * 4u, krb + (size_t)r * 64 + c4 * 4);
            }
            CP_COMMIT();
            CP_WAIT0();
            __syncthreads();
        }

        // ---- S = Q @ K^T (3xTF32) ----
        float s4[4][4];
        #pragma unroll
        for (int nt = 0; nt < 4; nt++) { s4[nt][0] = s4[nt][1] = s4[nt][2] = s4[nt][3] = 0.f; }

        #pragma unroll 4
        for (int kb8 = 0; kb8 < 24; kb8++) {
            const int kb = kb8 * 8;
            float a0 = qrow0[kb + lc],     a1 = qrow1[kb + lc];
            float a2 = qrow0[kb + lc + 4], a3 = qrow1[kb + lc + 4];
            uint32_t ah0 = hi_tf32(a0), ah1 = hi_tf32(a1), ah2 = hi_tf32(a2), ah3 = hi_tf32(a3);
            uint32_t al0 = __float_as_uint(a0 - __uint_as_float(ah0));
            uint32_t al1 = __float_as_uint(a1 - __uint_as_float(ah1));
            uint32_t al2 = __float_as_uint(a2 - __uint_as_float(ah2));
            uint32_t al3 = __float_as_uint(a3 - __uint_as_float(ah3));
            #pragma unroll
            for (int nt = 0; nt < 4; nt++) {
                const float* krow = ks + (nt * 8 + lr) * 196;
                float b0 = krow[kb + lc], b1 = krow[kb + lc + 4];
                uint32_t bh0 = hi_tf32(b0), bh1 = hi_tf32(b1);
                uint32_t bl0 = __float_as_uint(b0 - __uint_as_float(bh0));
                uint32_t bl1 = __float_as_uint(b1 - __uint_as_float(bh1));
                mma_tf32(s4[nt], al0, al1, al2, al3, bh0, bh1);
                mma_tf32(s4[nt], ah0, ah1, ah2, ah3, bl0, bl1);
                mma_tf32(s4[nt], ah0, ah1, ah2, ah3, bh0, bh1);
            }
        }

        // ---- mask + scale + online softmax ----
        float tmax0 = -INFINITY, tmax1 = -INFINITY;
        #pragma unroll
        for (int nt = 0; nt < 4; nt++) {
            const int colg = k0 + nt * 8 + 2 * lc;
            s4[nt][0] = (colg     <= row0g) ? s4[nt][0] * ATTN_SCALE : -INFINITY;
            s4[nt][1] = (colg + 1 <= row0g) ? s4[nt][1] * ATTN_SCALE : -INFINITY;
            s4[nt][2] = (colg     <= row1g) ? s4[nt][2] * ATTN_SCALE : -INFINITY;
            s4[nt][3] = (colg + 1 <= row1g) ? s4[nt][3] * ATTN_SCALE : -INFINITY;
            tmax0 = fmaxf(tmax0, fmaxf(s4[nt][0], s4[nt][1]));
            tmax1 = fmaxf(tmax1, fmaxf(s4[nt][2], s4[nt][3]));
        }
        tmax0 = fmaxf(tmax0, __shfl_xor_sync(0xffffffffu, tmax0, 1));
        tmax0 = fmaxf(tmax0, __shfl_xor_sync(0xffffffffu, tmax0, 2));
        tmax1 = fmaxf(tmax1, __shfl_xor_sync(0xffffffffu, tmax1, 1));
        tmax1 = fmaxf(tmax1, __shfl_xor_sync(0xffffffffu, tmax1, 2));

        const float mn0 = fmaxf(m0, tmax0), mn1 = fmaxf(m1, tmax1);
        const float scl0 = expf(m0 - mn0);   // m0=-inf at t=0 -> 0 (mn0 finite: col 0 always unmasked)
        const float scl1 = expf(m1 - mn1);

        float p4[4][4];
        float pr0 = 0.f, pr1 = 0.f;
        #pragma unroll
        for (int nt = 0; nt < 4; nt++) {
            p4[nt][0] = expf(s4[nt][0] - mn0);
            p4[nt][1] = expf(s4[nt][1] - mn0);
            p4[nt][2] = expf(s4[nt][2] - mn1);
            p4[nt][3] = expf(s4[nt][3] - mn1);
            pr0 += p4[nt][0] + p4[nt][1];
            pr1 += p4[nt][2] + p4[nt][3];
        }
        pr0 += __shfl_xor_sync(0xffffffffu, pr0, 1);
        pr0 += __shfl_xor_sync(0xffffffffu, pr0, 2);
        pr1 += __shfl_xor_sync(0xffffffffu, pr1, 1);
        pr1 += __shfl_xor_sync(0xffffffffu, pr1, 2);

        l0 = l0 * scl0 + pr0;
        l1 = l1 * scl1 + pr1;
        m0 = mn0; m1 = mn1;

        #pragma unroll
        for (int i = 0; i < 16; i++) {
            o[i][0] *= scl0; o[i][1] *= scl0;
            o[i][2] *= scl1; o[i][3] *= scl1;
        }

        // ---- stash P for A-fragment reshape (per-warp private) ----
        #pragma unroll
        for (int nt = 0; nt < 4; nt++) {
            *(float2*)(prow0 + nt * 8 + 2 * lc) = make_float2(p4[nt][0], p4[nt][1]);
            *(float2*)(prow1 + nt * 8 + 2 * lc) = make_float2(p4[nt][2], p4[nt][3]);
        }
        __syncwarp();

        // ---- O += P @ V (3xTF32) ----
        #pragma unroll
        for (int ks8 = 0; ks8 < 4; ks8++) {
            float a0 = prow0[ks8 * 8 + lc];
            float a1 = prow1[ks8 * 8 + lc];
            float a2 = prow0[ks8 * 8 + lc + 4];
            float a3 = prow1[ks8 * 8 + lc + 4];
            uint32_t ah0 = hi_tf32(a0), ah1 = hi_tf32(a1), ah2 = hi_tf32(a2), ah3 = hi_tf32(a3);
            uint32_t al0 = __float_as_uint(a0 - __uint_as_float(ah0));
            uint32_t al1 = __float_as_uint(a1 - __uint_as_float(ah1));
            uint32_t al2 = __float_as_uint(a2 - __uint_as_float(ah2));
            uint32_t al3 = __float_as_uint(a3 - __uint_as_float(ah3));
            const float* vrow0 = vs + (ks8 * 8 + lc) * 136;
            const float* vrow1 = vs + (ks8 * 8 + lc + 4) * 136;
            #pragma unroll
            for (int nt2 = 0; nt2 < 16; nt2++) {
                float b0 = vrow0[nt2 * 8 + lr];
                float b1 = vrow1[nt2 * 8 + lr];
                uint32_t bh0 = hi_tf32(b0), bh1 = hi_tf32(b1);
                uint32_t bl0 = __float_as_uint(b0 - __uint_as_float(bh0));
                uint32_t bl1 = __float_as_uint(b1 - __uint_as_float(bh1));
                mma_tf32(o[nt2], al0, al1, al2, al3, bh0, bh1);
                mma_tf32(o[nt2], ah0, ah1, ah2, ah3, bl0, bl1);
                mma_tf32(o[nt2], ah0, ah1, ah2, ah3, bh0, bh1);
            }
        }
    }

    // ---- epilogue ----
    const float inv0 = 1.f / l0, inv1 = 1.f / l1;
    const size_t obase = ((size_t)(b * 2 + hp) * NHh + hn) * Lseq;
    float* op0 = attn + (obase + row0g) * 128;
    float* op1 = attn + (obase + row1g) * 128;
    #pragma unroll
    for (int nt2 = 0; nt2 < 16; nt2++) {
        *(float2*)(op0 + nt2 * 8 + 2 * lc) = make_float2(o[nt2][0] * inv0, o[nt2][1] * inv0);
        *(float2*)(op1 + nt2 * 8 + 2 * lc) = make_float2(o[nt2][2] * inv1, o[nt2][3] * inv1);
    }
}
#define FLASH_SMEM ((64 * 196 + 32 * 196 + 32 * 136 + 64 * 36) * 4)   // 101888 B

// ======================= combine =======================
__global__ void combine_kernel(const float* __restrict__ attn, const float* __restrict__ lam,
                               float* __restrict__ pre)
{
    int idx = blockIdx.x * 256 + threadIdx.x;
    int c = idx & 2047;
    int row = idx >> 11;
    int b = row >> 11;
    int l = row & 2047;
    int n = c >> 7, d = c & 127;
    size_t a1 = (((size_t)(b * 2 + 0) * NHh + n) * Lseq + l) * 128 + d;
    size_t a2 = (((size_t)(b * 2 + 1) * NHh + n) * Lseq + l) * 128 + d;
    pre[idx] = attn[a1] - lam[(size_t)row * 16 + n] * attn[a2];
}

// ======================= launch =======================
extern "C" void kernel_launch(void* const* d_in, const int* in_sizes, int n_in,
                              void* d_out, int out_size)
{
    const float* x     = (const float*)d_in[0];
    const float* W_DKV = (const float*)d_in[1];
    const float* kv_w  = (const float*)d_in[2];
    const float* W_UK  = (const float*)d_in[3];
    const float* W_UV  = (const float*)d_in[4];
    const float* W_DQ  = (const float*)d_in[5];
    const float* q_w   = (const float*)d_in[6];
    const float* W_UQ  = (const float*)d_in[7];
    const float* W_QR  = (const float*)d_in[8];
    const float* W_KR  = (const float*)d_in[9];
    const float* W_lw  = (const float*)d_in[10];
    const float* W_lb  = (const float*)d_in[11];
    const float* W_out = (const float*)d_in[12];
    float* out = (float*)d_out;

    float *tmp, *ckv, *cq, *kc, *v, *qc, *qr, *kr, *lam, *attn, *pre;
    float *tDKV, *tUK, *tUV, *tDQ, *tUQ, *tQR, *tOUT;
    cudaGetSymbolAddress((void**)&tmp,  g_tmp);
    cudaGetSymbolAddress((void**)&ckv,  g_ckv);
    cudaGetSymbolAddress((void**)&cq,   g_cq);
    cudaGetSymbolAddress((void**)&kc,   g_kc);
    cudaGetSymbolAddress((void**)&v,    g_v);
    cudaGetSymbolAddress((void**)&qc,   g_qc);
    cudaGetSymbolAddress((void**)&qr,   g_qr);
    cudaGetSymbolAddress((void**)&kr,   g_kr);
    cudaGetSymbolAddress((void**)&lam,  g_lam);
    cudaGetSymbolAddress((void**)&attn, g_attn);
    cudaGetSymbolAddress((void**)&pre,  g_pre);
    cudaGetSymbolAddress((void**)&tDKV, g_tDKV);
    cudaGetSymbolAddress((void**)&tUK,  g_tUK);
    cudaGetSymbolAddress((void**)&tUV,  g_tUV);
    cudaGetSymbolAddress((void**)&tDQ,  g_tDQ);
    cudaGetSymbolAddress((void**)&tUQ,  g_tUQ);
    cudaGetSymbolAddress((void**)&tQR,  g_tQR);
    cudaGetSymbolAddress((void**)&tOUT, g_tOUT);

    cudaFuncSetAttribute(mgemm, cudaFuncAttributeMaxDynamicSharedMemorySize, MGEMM_SMEM);
    cudaFuncSetAttribute(flash_mma, cudaFuncAttributeMaxDynamicSharedMemorySize, FLASH_SMEM);

    dim3 tb(32, 8);
    transpose32<<<dim3(DCc/32,  Dd/32),  tb>>>(W_DKV, tDKV, Dd,  DCc);
    transpose32<<<dim3((NHh*DHh)/32, DCc/32), tb>>>(W_UK, tUK, DCc, NHh*DHh);
    transpose32<<<dim3((NHh*DHh)/32, DCc/32), tb>>>(W_UV, tUV, DCc, NHh*DHh);
    transpose32<<<dim3(DCc/32,  Dd/32),  tb>>>(W_DQ,  tDQ,  Dd,  DCc);
    transpose32<<<dim3((2*NHh*DHh)/32, DCc/32), tb>>>(W_UQ, tUQ, DCc, 2*NHh*DHh);
    transpose32<<<dim3((2*NHh*DHRr)/32, DCc/32), tb>>>(W_QR, tQR, DCc, 2*NHh*DHRr);
    transpose32<<<dim3(Dd/32,   Dd/32),  tb>>>(W_out, tOUT, Dd,  Dd);

    // KV path
    mgemm<<<dim3(DCc/128, BL/128), 256, MGEMM_SMEM>>>(DCc, Dd, x, tDKV, tmp);
    rms_kernel<<<BL, 256>>>(tmp, kv_w, ckv, DCc);
    mgemm<<<dim3((NHh*DHh)/128, BL/128), 256, MGEMM_SMEM>>>(NHh*DHh, DCc, ckv, tUK, kc);
    mgemm<<<dim3((NHh*DHh)/128, BL/128), 256, MGEMM_SMEM>>>(NHh*DHh, DCc, ckv, tUV, v);

    // Q path
    mgemm<<<dim3(DCc/128, BL/128), 256, MGEMM_SMEM>>>(DCc, Dd, x, tDQ, tmp);
    rms_kernel<<<BL, 256>>>(tmp, q_w, cq, DCc);
    mgemm<<<dim3((2*NHh*DHh)/128, BL/128), 256, MGEMM_SMEM>>>(2*NHh*DHh, DCc, cq, tUQ, qc);
    mgemm<<<dim3((2*NHh*DHRr)/128, BL/128), 256, MGEMM_SMEM>>>(2*NHh*DHRr, DCc, cq, tQR, qr);

    // k_r (N=64) + RoPE
    gemm_n64<<<BL / 4, dim3(64, 4)>>>(x, W_KR, kr, Dd);
    rope_kernel<<<(BL * 32 * 32) / 256, 256>>>(qr, 32, 2 * NHh * DHRr);
    rope_kernel<<<(BL * 1 * 32) / 256, 256>>>(kr, 1, DHRr);

    // lambda gate
    lam_kernel<<<BL, 128>>>(x, W_lw, W_lb, lam);

    // attention (tensor-core flash)
    flash_mma<<<dim3(Lseq / 64, 32, BB), 128, FLASH_SMEM>>>(qc, qr, kc, kr, v, attn);

    // combine + output projection
    combine_kernel<<<(BL * Dd) / 256, 256>>>(attn, lam, pre);
    mgemm<<<dim3(Dd/128, BL/128), 256, MGEMM_SMEM>>>(Dd, Dd, pre, tOUT, out);
}

// round 6
// speedup vs baseline: 1.8708x; 1.2162x over previous
#include <cuda_runtime.h>
#include <cuda.h>
#include <cuda_fp16.h>
#include <math.h>
#include <stdint.h>

#define BB   2
#define Lseq 2048
#define BL   4096      // B*L
#define Dd   2048
#define DCc  1024
#define NHh  16
#define DHh  128
#define DHRr 64
#define ATTN_SCALE 0.07216878364870322f

// ======================= scratch =======================
__device__ float g_tmp [BL * DCc];
__device__ float g_kc  [BL * (NHh * DHh)];
__device__ float g_v   [BL * (NHh * DHh)];
__device__ float g_qc  [BL * (2 * NHh * DHh)];
__device__ float g_qr  [BL * (2 * NHh * DHRr)];
__device__ float g_kr  [BL * DHRr];
__device__ float g_lam [BL * NHh];
__device__ float g_attn[(size_t)2 * BB * NHh * Lseq * DHh];

// fp16 split planes (activations)
__device__ __half g_xh  [BL * Dd],  g_xl  [BL * Dd];
__device__ __half g_ckvh[BL * DCc], g_ckvl[BL * DCc];
__device__ __half g_cqh [BL * DCc], g_cql [BL * DCc];
__device__ __half g_preh[BL * Dd],  g_prel[BL * Dd];
// fp16 split planes (transposed weights, [N][K])
__device__ __half g_tDKVh[DCc * Dd],        g_tDKVl[DCc * Dd];
__device__ __half g_tUKh [(NHh*DHh) * DCc], g_tUKl [(NHh*DHh) * DCc];
__device__ __half g_tUVh [(NHh*DHh) * DCc], g_tUVl [(NHh*DHh) * DCc];
__device__ __half g_tDQh [DCc * Dd],        g_tDQl [DCc * Dd];
__device__ __half g_tUQh [(2*NHh*DHh)*DCc], g_tUQl [(2*NHh*DHh)*DCc];
__device__ __half g_tQRh [(2*NHh*DHRr)*DCc],g_tQRl [(2*NHh*DHRr)*DCc];
__device__ __half g_tOUTh[Dd * Dd],         g_tOUTl[Dd * Dd];

// ======================= helpers =======================
__device__ __forceinline__ uint32_t smem_u32(const void* p) {
    uint32_t a;
    asm("{ .reg .u64 t; cvta.to.shared.u64 t, %1; cvt.u32.u64 %0, t; }" : "=r"(a) : "l"(p));
    return a;
}
__device__ __forceinline__ void cp16(uint32_t dst, const void* src) {
    asm volatile("cp.async.cg.shared.global [%0], [%1], 16;" :: "r"(dst), "l"(src));
}
#define CP_COMMIT() asm volatile("cp.async.commit_group;" ::: "memory")
#define CP_WAIT0()  asm volatile("cp.async.wait_group 0;"  ::: "memory")

// tf32 helpers (flash kernel)
__device__ __forceinline__ uint32_t hi_tf32(float x) {
    return __float_as_uint(x) & 0xFFFFE000u;
}
__device__ __forceinline__ void mma_tf32(float c[4],
                                         uint32_t a0, uint32_t a1, uint32_t a2, uint32_t a3,
                                         uint32_t b0, uint32_t b1)
{
    asm volatile(
        "mma.sync.aligned.m16n8k8.row.col.f32.tf32.tf32.f32 "
        "{%0,%1,%2,%3}, {%4,%5,%6,%7}, {%8,%9}, {%0,%1,%2,%3};"
        : "+f"(c[0]), "+f"(c[1]), "+f"(c[2]), "+f"(c[3])
        : "r"(a0), "r"(a1), "r"(a2), "r"(a3), "r"(b0), "r"(b1));
}
// fp16 m16n8k16 MMA
__device__ __forceinline__ void mma_f16(float c[4],
                                        uint32_t a0, uint32_t a1, uint32_t a2, uint32_t a3,
                                        uint32_t b0, uint32_t b1)
{
    asm volatile(
        "mma.sync.aligned.m16n8k16.row.col.f32.f16.f16.f32 "
        "{%0,%1,%2,%3}, {%4,%5,%6,%7}, {%8,%9}, {%0,%1,%2,%3};"
        : "+f"(c[0]), "+f"(c[1]), "+f"(c[2]), "+f"(c[3])
        : "r"(a0), "r"(a1), "r"(a2), "r"(a3), "r"(b0), "r"(b1));
}

__device__ __forceinline__ void split16(float v, __half& h, __half& l) {
    h = __float2half_rn(v);
    l = __float2half_rn(v - __half2float(h));
}

// ======================= transpose + split: in[R][C] -> hi/lo[C][R] =======================
__global__ void transpose32h(const float* __restrict__ in,
                             __half* __restrict__ oh, __half* __restrict__ ol, int R, int C)
{
    __shared__ float t[32][33];
    int bx = blockIdx.x * 32, by = blockIdx.y * 32;
    int x = bx + threadIdx.x;
    #pragma unroll
    for (int j = 0; j < 32; j += 8)
        t[threadIdx.y + j][threadIdx.x] = in[(size_t)(by + threadIdx.y + j) * C + x];
    __syncthreads();
    int ox = by + threadIdx.x;
    #pragma unroll
    for (int j = 0; j < 32; j += 8) {
        float v = t[threadIdx.x][threadIdx.y + j];
        __half h, l; split16(v, h, l);
        size_t o = (size_t)(bx + threadIdx.y + j) * R + ox;
        oh[o] = h; ol[o] = l;
    }
}

// ======================= elementwise split =======================
__global__ void split_kernel(const float* __restrict__ in,
                             __half* __restrict__ oh, __half* __restrict__ ol)
{
    int idx = blockIdx.x * 256 + threadIdx.x;
    float v = in[idx];
    __half h, l; split16(v, h, l);
    oh[idx] = h; ol[idx] = l;
}

// ======================= fp16-split tensor-core GEMM =======================
// C[M,N] = A[M,K] @ Bt[N,K]^T with A,B given as fp16 hi/lo planes.
// Tile 128x128, BK=32, 256 threads (8 warps, 2M x 4N), m16n8k16, 3 MMAs per frag pair.
// smem planes: word rows of WSTR=20 (16 data words + 4 pad) -> conflict-free LDS.32.
#define WSTR 20
#define HGEMM_SMEM (2 * 4 * 128 * WSTR * 4)   // 81920 B
__global__ __launch_bounds__(256)
void hgemm(int N, int K,
           const __half* __restrict__ Ahi, const __half* __restrict__ Alo,
           const __half* __restrict__ Bhi, const __half* __restrict__ Blo,
           float* __restrict__ C)
{
    extern __shared__ float smraw[];
    uint32_t* smw = (uint32_t*)smraw;
    uint32_t* buf[2] = { smw, smw + 4 * 128 * WSTR };

    const int tid = threadIdx.x;
    const int wid = tid >> 5, lane = tid & 31;
    const int m0 = blockIdx.y * 128, n0 = blockIdx.x * 128;
    const int warpM = (wid >> 2) * 64;
    const int warpN = (wid & 3) * 32;
    const int lr = lane >> 2, lc = lane & 3;

    const __half* Ap[2] = { Ahi + (size_t)m0 * K, Alo + (size_t)m0 * K };
    const __half* Bp[2] = { Bhi + (size_t)n0 * K, Blo + (size_t)n0 * K };

    const int r = tid >> 1;        // 0..127
    const int q = (tid & 1) * 2;   // quarters q, q+1 (each 4 words = 16B = 8 halves)

    auto stage = [&](int kc, int b) {
        uint32_t base = smem_u32(buf[b]);
        #pragma unroll
        for (int p = 0; p < 2; p++) {
            uint32_t dA = base + (uint32_t)((p * 128 + r) * WSTR) * 4u;
            const __half* sA = Ap[p] + (size_t)r * K + kc;
            cp16(dA + q * 16,       sA + q * 8);
            cp16(dA + (q + 1) * 16, sA + (q + 1) * 8);
            uint32_t dB = base + (uint32_t)(((2 + p) * 128 + r) * WSTR) * 4u;
            const __half* sB = Bp[p] + (size_t)r * K + kc;
            cp16(dB + q * 16,       sB + q * 8);
            cp16(dB + (q + 1) * 16, sB + (q + 1) * 8);
        }
        CP_COMMIT();
    };

    float acc[4][4][4];
    #pragma unroll
    for (int i = 0; i < 4; i++)
        #pragma unroll
        for (int j = 0; j < 4; j++)
            #pragma unroll
            for (int k = 0; k < 4; k++) acc[i][j][k] = 0.f;

    stage(0, 0);

    const int nch = K >> 5;
    for (int i = 0; i < nch; i++) {
        CP_WAIT0();
        __syncthreads();
        if (i + 1 < nch) stage((i + 1) << 5, (i + 1) & 1);

        const uint32_t* Ah = buf[i & 1];
        const uint32_t* Al = Ah + 128 * WSTR;
        const uint32_t* Bh = Ah + 2 * 128 * WSTR;
        const uint32_t* Bl = Ah + 3 * 128 * WSTR;

        #pragma unroll
        for (int s = 0; s < 2; s++) {
            uint32_t ah[4][4], al[4][4];
            #pragma unroll
            for (int ma = 0; ma < 4; ma++) {
                int rw = (warpM + ma * 16 + lr) * WSTR + s * 8 + lc;
                ah[ma][0] = Ah[rw];
                ah[ma][1] = Ah[rw + 8 * WSTR];
                ah[ma][2] = Ah[rw + 4];
                ah[ma][3] = Ah[rw + 8 * WSTR + 4];
                al[ma][0] = Al[rw];
                al[ma][1] = Al[rw + 8 * WSTR];
                al[ma][2] = Al[rw + 4];
                al[ma][3] = Al[rw + 8 * WSTR + 4];
            }
            #pragma unroll
            for (int nb = 0; nb < 4; nb++) {
                int cw = (warpN + nb * 8 + lr) * WSTR + s * 8 + lc;
                uint32_t bh0 = Bh[cw], bh1 = Bh[cw + 4];
                uint32_t bl0 = Bl[cw], bl1 = Bl[cw + 4];
                #pragma unroll
                for (int ma = 0; ma < 4; ma++) {
                    mma_f16(acc[ma][nb], al[ma][0], al[ma][1], al[ma][2], al[ma][3], bh0, bh1);
                    mma_f16(acc[ma][nb], ah[ma][0], ah[ma][1], ah[ma][2], ah[ma][3], bl0, bl1);
                    mma_f16(acc[ma][nb], ah[ma][0], ah[ma][1], ah[ma][2], ah[ma][3], bh0, bh1);
                }
            }
        }
        __syncthreads();
    }

    #pragma unroll
    for (int ma = 0; ma < 4; ma++) {
        int row = m0 + warpM + ma * 16 + lr;
        #pragma unroll
        for (int nb = 0; nb < 4; nb++) {
            int col = n0 + warpN + nb * 8 + lc * 2;
            float2 o0 = make_float2(acc[ma][nb][0], acc[ma][nb][1]);
            float2 o1 = make_float2(acc[ma][nb][2], acc[ma][nb][3]);
            *(float2*)(C + (size_t)row * N + col)       = o0;
            *(float2*)(C + (size_t)(row + 8) * N + col) = o1;
        }
    }
}

// ======================= RMS norm -> fp16 split planes =======================
__global__ void rms_h(const float* __restrict__ in, const float* __restrict__ w,
                      __half* __restrict__ oh, __half* __restrict__ ol, int N)
{
    int row = blockIdx.x;
    const float* ir = in + (size_t)row * N;
    float s = 0.f;
    for (int i = threadIdx.x; i < N; i += 256) { float v = ir[i]; s += v * v; }
    __shared__ float red[256];
    red[threadIdx.x] = s;
    __syncthreads();
    for (int st = 128; st > 0; st >>= 1) {
        if (threadIdx.x < st) red[threadIdx.x] += red[threadIdx.x + st];
        __syncthreads();
    }
    float rr = rsqrtf(red[0] / (float)N + 1e-6f);
    for (int i = threadIdx.x; i < N; i += 256) {
        float v = ir[i] * rr * w[i];
        __half h, l; split16(v, h, l);
        oh[(size_t)row * N + i] = h;
        ol[(size_t)row * N + i] = l;
    }
}

// ======================= RoPE (in-place) =======================
__global__ void rope_kernel(float* __restrict__ t, int heads, int rowstride)
{
    int idx = blockIdx.x * blockDim.x + threadIdx.x;
    int j = idx & 31;
    int h = (idx >> 5) % heads;
    int row = idx / (32 * heads);
    if (row >= BL) return;
    int l = row & (Lseq - 1);
    float inv = powf(10000.f, -(float)(2 * j) / 64.f);
    float ang = (float)l * inv;
    float c = cosf(ang), s = sinf(ang);
    float* base = t + (size_t)row * rowstride + h * 64;
    float x1 = base[j], x2 = base[j + 32];
    base[j]      = x1 * c - x2 * s;
    base[j + 32] = x2 * c + x1 * s;
}

// ======================= lambda gate =======================
__global__ void lam_kernel(const float* __restrict__ x, const float* __restrict__ Wl,
                           const float* __restrict__ bl, float* __restrict__ lam)
{
    int row = blockIdx.x;
    int tid = threadIdx.x;
    const float* xr = x + (size_t)row * Dd;
    float acc[16];
    #pragma unroll
    for (int n = 0; n < 16; n++) acc[n] = 0.f;
    for (int k = tid; k < Dd; k += 128) {
        float xv = xr[k];
        const float* wv = Wl + (size_t)k * 16;
        #pragma unroll
        for (int n = 0; n < 16; n++) acc[n] += xv * wv[n];
    }
    __shared__ float red[16 * 128];
    #pragma unroll
    for (int n = 0; n < 16; n++) red[n * 128 + tid] = acc[n];
    __syncthreads();
    for (int st = 64; st > 0; st >>= 1) {
        if (tid < st) {
            #pragma unroll
            for (int n = 0; n < 16; n++) red[n * 128 + tid] += red[n * 128 + tid + st];
        }
        __syncthreads();
    }
    if (tid < 16) {
        float z = red[tid * 128] + bl[tid];
        lam[(size_t)row * 16 + tid] = 1.f / (1.f + expf(-z));
    }
}

// ======================= small GEMM N=64 (x @ W_KR) =======================
__global__ void gemm_n64(const float* __restrict__ A, const float* __restrict__ B,
                         float* __restrict__ C, int K)
{
    int n = threadIdx.x;
    int m = blockIdx.x * 4 + threadIdx.y;
    float acc = 0.f;
    const float* ar = A + (size_t)m * K;
    #pragma unroll 8
    for (int k = 0; k < K; k++) acc += ar[k] * B[(size_t)k * 64 + n];
    C[(size_t)m * 64 + n] = acc;
}

// ======================= tensor-core flash attention (3xTF32) =======================
__global__ __launch_bounds__(128)
void flash_mma(const float* __restrict__ qc, const float* __restrict__ qr,
               const float* __restrict__ kc, const float* __restrict__ kr,
               const float* __restrict__ vv, float* __restrict__ attn)
{
    extern __shared__ float sm[];
    float* qs = sm;                  // [64][196]
    float* ks = qs + 64 * 196;       // [32][196]
    float* vs = ks + 32 * 196;       // [32][136]
    float* ps = vs + 32 * 136;       // [64][36]

    const int Q0 = blockIdx.x * 64;
    const int head2 = blockIdx.y;
    const int b = blockIdx.z;
    const int hn = head2 >> 1, hp = head2 & 1;
    const int tid = threadIdx.x;
    const int lane = tid & 31, w = tid >> 5;
    const int lr = lane >> 2, lc = lane & 3;

    uint32_t qsb = smem_u32(qs), ksb = smem_u32(ks), vsb = smem_u32(vs);

    {
        const float* qcb = qc + ((size_t)(b * Lseq + Q0)) * 4096 + head2 * 128;
        const float* qrb = qr + ((size_t)(b * Lseq + Q0)) * 2048 + head2 * 64;
        #pragma unroll
        for (int i = 0; i < 16; i++) {
            int s = tid + i * 128;
            int r = s >> 5, c4 = s & 31;
            cp16(qsb + (uint32_t)(r * 196 + c4 * 4) * 4u, qcb + (size_t)r * 4096 + c4 * 4);
        }
        #pragma unroll
        for (int i = 0; i < 8; i++) {
            int s = tid + i * 128;
            int r = s >> 4, c4 = s & 15;
            cp16(qsb + (uint32_t)(r * 196 + 128 + c4 * 4) * 4u, qrb + (size_t)r * 2048 + c4 * 4);
        }
        CP_COMMIT();
    }

    float o[16][4];
    #pragma unroll
    for (int i = 0; i < 16; i++) { o[i][0] = o[i][1] = o[i][2] = o[i][3] = 0.f; }
    float m0 = -INFINITY, m1 = -INFINITY, l0 = 0.f, l1 = 0.f;

    const int row0g = Q0 + 16 * w + lr;
    const int row1g = row0g + 8;

    const float* qrow0 = qs + (16 * w + lr) * 196;
    const float* qrow1 = qrow0 + 8 * 196;
    float* prow0 = ps + (16 * w + lr) * 36;
    float* prow1 = prow0 + 8 * 36;

    const int ntile = (Q0 + 64) >> 5;
    for (int t = 0; t < ntile; t++) {
        const int k0 = t << 5;
        __syncthreads();
        {
            const float* kcb = kc + ((size_t)(b * Lseq + k0)) * 2048 + hn * 128;
            const float* krb = kr + ((size_t)(b * Lseq + k0)) * 64;
            const float* vb  = vv + ((size_t)(b * Lseq + k0)) * 2048 + hn * 128;
            #pragma unroll
            for (int i = 0; i < 8; i++) {
                int s = tid + i * 128;
                int r = s >> 5, c4 = s & 31;
                cp16(ksb + (uint32_t)(r * 196 + c4 * 4) * 4u, kcb + (size_t)r * 2048 + c4 * 4);
                cp16(vsb + (uint32_t)(r * 136 + c4 * 4) * 4u, vb  + (size_t)r * 2048 + c4 * 4);
            }
            #pragma unroll
            for (int i = 0; i < 4; i++) {
                int s = tid + i * 128;
                int r = s >> 4, c4 = s & 15;
                cp16(ksb + (uint32_t)(r * 196 + 128 + c4 * 4) * 4u, krb + (size_t)r * 64 + c4 * 4);
            }
            CP_COMMIT();
            CP_WAIT0();
            __syncthreads();
        }

        float s4[4][4];
        #pragma unroll
        for (int nt = 0; nt < 4; nt++) { s4[nt][0] = s4[nt][1] = s4[nt][2] = s4[nt][3] = 0.f; }

        #pragma unroll 4
        for (int kb8 = 0; kb8 < 24; kb8++) {
            const int kb = kb8 * 8;
            float a0 = qrow0[kb + lc],     a1 = qrow1[kb + lc];
            float a2 = qrow0[kb + lc + 4], a3 = qrow1[kb + lc + 4];
            uint32_t ah0 = hi_tf32(a0), ah1 = hi_tf32(a1), ah2 = hi_tf32(a2), ah3 = hi_tf32(a3);
            uint32_t al0 = __float_as_uint(a0 - __uint_as_float(ah0));
            uint32_t al1 = __float_as_uint(a1 - __uint_as_float(ah1));
            uint32_t al2 = __float_as_uint(a2 - __uint_as_float(ah2));
            uint32_t al3 = __float_as_uint(a3 - __uint_as_float(ah3));
            #pragma unroll
            for (int nt = 0; nt < 4; nt++) {
                const float* krow = ks + (nt * 8 + lr) * 196;
                float b0 = krow[kb + lc], b1 = krow[kb + lc + 4];
                uint32_t bh0 = hi_tf32(b0), bh1 = hi_tf32(b1);
                uint32_t bl0 = __float_as_uint(b0 - __uint_as_float(bh0));
                uint32_t bl1 = __float_as_uint(b1 - __uint_as_float(bh1));
                mma_tf32(s4[nt], al0, al1, al2, al3, bh0, bh1);
                mma_tf32(s4[nt], ah0, ah1, ah2, ah3, bl0, bl1);
                mma_tf32(s4[nt], ah0, ah1, ah2, ah3, bh0, bh1);
            }
        }

        float tmax0 = -INFINITY, tmax1 = -INFINITY;
        #pragma unroll
        for (int nt = 0; nt < 4; nt++) {
            const int colg = k0 + nt * 8 + 2 * lc;
            s4[nt][0] = (colg     <= row0g) ? s4[nt][0] * ATTN_SCALE : -INFINITY;
            s4[nt][1] = (colg + 1 <= row0g) ? s4[nt][1] * ATTN_SCALE : -INFINITY;
            s4[nt][2] = (colg     <= row1g) ? s4[nt][2] * ATTN_SCALE : -INFINITY;
            s4[nt][3] = (colg + 1 <= row1g) ? s4[nt][3] * ATTN_SCALE : -INFINITY;
            tmax0 = fmaxf(tmax0, fmaxf(s4[nt][0], s4[nt][1]));
            tmax1 = fmaxf(tmax1, fmaxf(s4[nt][2], s4[nt][3]));
        }
        tmax0 = fmaxf(tmax0, __shfl_xor_sync(0xffffffffu, tmax0, 1));
        tmax0 = fmaxf(tmax0, __shfl_xor_sync(0xffffffffu, tmax0, 2));
        tmax1 = fmaxf(tmax1, __shfl_xor_sync(0xffffffffu, tmax1, 1));
        tmax1 = fmaxf(tmax1, __shfl_xor_sync(0xffffffffu, tmax1, 2));

        const float mn0 = fmaxf(m0, tmax0), mn1 = fmaxf(m1, tmax1);
        const float scl0 = expf(m0 - mn0);
        const float scl1 = expf(m1 - mn1);

        float p4[4][4];
        float pr0 = 0.f, pr1 = 0.f;
        #pragma unroll
        for (int nt = 0; nt < 4; nt++) {
            p4[nt][0] = expf(s4[nt][0] - mn0);
            p4[nt][1] = expf(s4[nt][1] - mn0);
            p4[nt][2] = expf(s4[nt][2] - mn1);
            p4[nt][3] = expf(s4[nt][3] - mn1);
            pr0 += p4[nt][0] + p4[nt][1];
            pr1 += p4[nt][2] + p4[nt][3];
        }
        pr0 += __shfl_xor_sync(0xffffffffu, pr0, 1);
        pr0 += __shfl_xor_sync(0xffffffffu, pr0, 2);
        pr1 += __shfl_xor_sync(0xffffffffu, pr1, 1);
        pr1 += __shfl_xor_sync(0xffffffffu, pr1, 2);

        l0 = l0 * scl0 + pr0;
        l1 = l1 * scl1 + pr1;
        m0 = mn0; m1 = mn1;

        #pragma unroll
        for (int i = 0; i < 16; i++) {
            o[i][0] *= scl0; o[i][1] *= scl0;
            o[i][2] *= scl1; o[i][3] *= scl1;
        }

        #pragma unroll
        for (int nt = 0; nt < 4; nt++) {
            *(float2*)(prow0 + nt * 8 + 2 * lc) = make_float2(p4[nt][0], p4[nt][1]);
            *(float2*)(prow1 + nt * 8 + 2 * lc) = make_float2(p4[nt][2], p4[nt][3]);
        }
        __syncwarp();

        #pragma unroll
        for (int ks8 = 0; ks8 < 4; ks8++) {
            float a0 = prow0[ks8 * 8 + lc];
            float a1 = prow1[ks8 * 8 + lc];
            float a2 = prow0[ks8 * 8 + lc + 4];
            float a3 = prow1[ks8 * 8 + lc + 4];
            uint32_t ah0 = hi_tf32(a0), ah1 = hi_tf32(a1), ah2 = hi_tf32(a2), ah3 = hi_tf32(a3);
            uint32_t al0 = __float_as_uint(a0 - __uint_as_float(ah0));
            uint32_t al1 = __float_as_uint(a1 - __uint_as_float(ah1));
            uint32_t al2 = __float_as_uint(a2 - __uint_as_float(ah2));
            uint32_t al3 = __float_as_uint(a3 - __uint_as_float(ah3));
            const float* vrow0 = vs + (ks8 * 8 + lc) * 136;
            const float* vrow1 = vs + (ks8 * 8 + lc + 4) * 136;
            #pragma unroll
            for (int nt2 = 0; nt2 < 16; nt2++) {
                float b0 = vrow0[nt2 * 8 + lr];
                float b1 = vrow1[nt2 * 8 + lr];
                uint32_t bh0 = hi_tf32(b0), bh1 = hi_tf32(b1);
                uint32_t bl0 = __float_as_uint(b0 - __uint_as_float(bh0));
                uint32_t bl1 = __float_as_uint(b1 - __uint_as_float(bh1));
                mma_tf32(o[nt2], al0, al1, al2, al3, bh0, bh1);
                mma_tf32(o[nt2], ah0, ah1, ah2, ah3, bl0, bl1);
                mma_tf32(o[nt2], ah0, ah1, ah2, ah3, bh0, bh1);
            }
        }
    }

    const float inv0 = 1.f / l0, inv1 = 1.f / l1;
    const size_t obase = ((size_t)(b * 2 + hp) * NHh + hn) * Lseq;
    float* op0 = attn + (obase + row0g) * 128;
    float* op1 = attn + (obase + row1g) * 128;
    #pragma unroll
    for (int nt2 = 0; nt2 < 16; nt2++) {
        *(float2*)(op0 + nt2 * 8 + 2 * lc) = make_float2(o[nt2][0] * inv0, o[nt2][1] * inv0);
        *(float2*)(op1 + nt2 * 8 + 2 * lc) = make_float2(o[nt2][2] * inv1, o[nt2][3] * inv1);
    }
}
#define FLASH_SMEM ((64 * 196 + 32 * 196 + 32 * 136 + 64 * 36) * 4)   // 101888 B

// ======================= combine -> fp16 split planes =======================
__global__ void combine_h(const float* __restrict__ attn, const float* __restrict__ lam,
                          __half* __restrict__ oh, __half* __restrict__ ol)
{
    int idx = blockIdx.x * 256 + threadIdx.x;
    int c = idx & 2047;
    int row = idx >> 11;
    int b = row >> 11;
    int l = row & 2047;
    int n = c >> 7, d = c & 127;
    size_t a1 = (((size_t)(b * 2 + 0) * NHh + n) * Lseq + l) * 128 + d;
    size_t a2 = (((size_t)(b * 2 + 1) * NHh + n) * Lseq + l) * 128 + d;
    float v = attn[a1] - lam[(size_t)row * 16 + n] * attn[a2];
    __half h, lo; split16(v, h, lo);
    oh[idx] = h; ol[idx] = lo;
}

// ======================= launch =======================
extern "C" void kernel_launch(void* const* d_in, const int* in_sizes, int n_in,
                              void* d_out, int out_size)
{
    const float* x     = (const float*)d_in[0];
    const float* W_DKV = (const float*)d_in[1];
    const float* kv_w  = (const float*)d_in[2];
    const float* W_UK  = (const float*)d_in[3];
    const float* W_UV  = (const float*)d_in[4];
    const float* W_DQ  = (const float*)d_in[5];
    const float* q_w   = (const float*)d_in[6];
    const float* W_UQ  = (const float*)d_in[7];
    const float* W_QR  = (const float*)d_in[8];
    const float* W_KR  = (const float*)d_in[9];
    const float* W_lw  = (const float*)d_in[10];
    const float* W_lb  = (const float*)d_in[11];
    const float* W_out = (const float*)d_in[12];
    float* out = (float*)d_out;

    float *tmp, *kc, *v, *qc, *qr, *kr, *lam, *attn;
    __half *xh, *xl, *ckvh, *ckvl, *cqh, *cql, *preh, *prel;
    __half *tDKVh, *tDKVl, *tUKh, *tUKl, *tUVh, *tUVl, *tDQh, *tDQl;
    __half *tUQh, *tUQl, *tQRh, *tQRl, *tOUTh, *tOUTl;
    cudaGetSymbolAddress((void**)&tmp,  g_tmp);
    cudaGetSymbolAddress((void**)&kc,   g_kc);
    cudaGetSymbolAddress((void**)&v,    g_v);
    cudaGetSymbolAddress((void**)&qc,   g_qc);
    cudaGetSymbolAddress((void**)&qr,   g_qr);
    cudaGetSymbolAddress((void**)&kr,   g_kr);
    cudaGetSymbolAddress((void**)&lam,  g_lam);
    cudaGetSymbolAddress((void**)&attn, g_attn);
    cudaGetSymbolAddress((void**)&xh,   g_xh);
    cudaGetSymbolAddress((void**)&xl,   g_xl);
    cudaGetSymbolAddress((void**)&ckvh, g_ckvh);
    cudaGetSymbolAddress((void**)&ckvl, g_ckvl);
    cudaGetSymbolAddress((void**)&cqh,  g_cqh);
    cudaGetSymbolAddress((void**)&cql,  g_cql);
    cudaGetSymbolAddress((void**)&preh, g_preh);
    cudaGetSymbolAddress((void**)&prel, g_prel);
    cudaGetSymbolAddress((void**)&tDKVh, g_tDKVh);
    cudaGetSymbolAddress((void**)&tDKVl, g_tDKVl);
    cudaGetSymbolAddress((void**)&tUKh,  g_tUKh);
    cudaGetSymbolAddress((void**)&tUKl,  g_tUKl);
    cudaGetSymbolAddress((void**)&tUVh,  g_tUVh);
    cudaGetSymbolAddress((void**)&tUVl,  g_tUVl);
    cudaGetSymbolAddress((void**)&tDQh,  g_tDQh);
    cudaGetSymbolAddress((void**)&tDQl,  g_tDQl);
    cudaGetSymbolAddress((void**)&tUQh,  g_tUQh);
    cudaGetSymbolAddress((void**)&tUQl,  g_tUQl);
    cudaGetSymbolAddress((void**)&tQRh,  g_tQRh);
    cudaGetSymbolAddress((void**)&tQRl,  g_tQRl);
    cudaGetSymbolAddress((void**)&tOUTh, g_tOUTh);
    cudaGetSymbolAddress((void**)&tOUTl, g_tOUTl);

    cudaFuncSetAttribute(hgemm, cudaFuncAttributeMaxDynamicSharedMemorySize, HGEMM_SMEM);
    cudaFuncSetAttribute(flash_mma, cudaFuncAttributeMaxDynamicSharedMemorySize, FLASH_SMEM);

    dim3 tb(32, 8);
    transpose32h<<<dim3(DCc/32,  Dd/32),  tb>>>(W_DKV, tDKVh, tDKVl, Dd,  DCc);
    transpose32h<<<dim3((NHh*DHh)/32, DCc/32), tb>>>(W_UK, tUKh, tUKl, DCc, NHh*DHh);
    transpose32h<<<dim3((NHh*DHh)/32, DCc/32), tb>>>(W_UV, tUVh, tUVl, DCc, NHh*DHh);
    transpose32h<<<dim3(DCc/32,  Dd/32),  tb>>>(W_DQ,  tDQh,  tDQl,  Dd,  DCc);
    transpose32h<<<dim3((2*NHh*DHh)/32, DCc/32), tb>>>(W_UQ, tUQh, tUQl, DCc, 2*NHh*DHh);
    transpose32h<<<dim3((2*NHh*DHRr)/32, DCc/32), tb>>>(W_QR, tQRh, tQRl, DCc, 2*NHh*DHRr);
    transpose32h<<<dim3(Dd/32,   Dd/32),  tb>>>(W_out, tOUTh, tOUTl, Dd,  Dd);
    split_kernel<<<(BL * Dd) / 256, 256>>>(x, xh, xl);

    // KV path
    hgemm<<<dim3(DCc/128, BL/128), 256, HGEMM_SMEM>>>(DCc, Dd, xh, xl, tDKVh, tDKVl, tmp);
    rms_h<<<BL, 256>>>(tmp, kv_w, ckvh, ckvl, DCc);
    hgemm<<<dim3((NHh*DHh)/128, BL/128), 256, HGEMM_SMEM>>>(NHh*DHh, DCc, ckvh, ckvl, tUKh, tUKl, kc);
    hgemm<<<dim3((NHh*DHh)/128, BL/128), 256, HGEMM_SMEM>>>(NHh*DHh, DCc, ckvh, ckvl, tUVh, tUVl, v);

    // Q path
    hgemm<<<dim3(DCc/128, BL/128), 256, HGEMM_SMEM>>>(DCc, Dd, xh, xl, tDQh, tDQl, tmp);
    rms_h<<<BL, 256>>>(tmp, q_w, cqh, cql, DCc);
    hgemm<<<dim3((2*NHh*DHh)/128, BL/128), 256, HGEMM_SMEM>>>(2*NHh*DHh, DCc, cqh, cql, tUQh, tUQl, qc);
    hgemm<<<dim3((2*NHh*DHRr)/128, BL/128), 256, HGEMM_SMEM>>>(2*NHh*DHRr, DCc, cqh, cql, tQRh, tQRl, qr);

    // k_r (N=64) + RoPE
    gemm_n64<<<BL / 4, dim3(64, 4)>>>(x, W_KR, kr, Dd);
    rope_kernel<<<(BL * 32 * 32) / 256, 256>>>(qr, 32, 2 * NHh * DHRr);
    rope_kernel<<<(BL * 1 * 32) / 256, 256>>>(kr, 1, DHRr);

    // lambda gate
    lam_kernel<<<BL, 128>>>(x, W_lw, W_lb, lam);

    // attention (tensor-core flash)
    flash_mma<<<dim3(Lseq / 64, 32, BB), 128, FLASH_SMEM>>>(qc, qr, kc, kr, v, attn);

    // combine + output projection
    combine_h<<<(BL * Dd) / 256, 256>>>(attn, lam, preh, prel);
    hgemm<<<dim3(Dd/128, BL/128), 256, HGEMM_SMEM>>>(Dd, Dd, preh, prel, tOUTh, tOUTl, out);
}

// round 7
// speedup vs baseline: 2.0980x; 1.1214x over previous
#include <cuda_runtime.h>
#include <cuda.h>
#include <cuda_fp16.h>
#include <math.h>
#include <stdint.h>

#define BB   2
#define Lseq 2048
#define BL   4096      // B*L
#define Dd   2048
#define DCc  1024
#define NHh  16
#define DHh  128
#define DHRr 64
#define ATTN_SCALE 0.07216878364870322f

// ======================= scratch =======================
__device__ float g_tmp [BL * DCc];
__device__ float g_kc  [BL * (NHh * DHh)];
__device__ float g_v   [BL * (NHh * DHh)];
__device__ float g_qc  [BL * (2 * NHh * DHh)];
__device__ float g_qr  [BL * (2 * NHh * DHRr)];
__device__ float g_kr  [BL * DHRr];
__device__ float g_lam [BL * NHh];
__device__ float g_attn[(size_t)2 * BB * NHh * Lseq * DHh];

// fp16 split planes (activations for GEMMs)
__device__ __half g_xh  [BL * Dd],  g_xl  [BL * Dd];
__device__ __half g_ckvh[BL * DCc], g_ckvl[BL * DCc];
__device__ __half g_cqh [BL * DCc], g_cql [BL * DCc];
__device__ __half g_preh[BL * Dd],  g_prel[BL * Dd];
// fp16 split planes (flash operands)
__device__ __half g_qch [BL * (2*NHh*DHh)],  g_qcl [BL * (2*NHh*DHh)];
__device__ __half g_qrh [BL * (2*NHh*DHRr)], g_qrl [BL * (2*NHh*DHRr)];
__device__ __half g_kch [BL * (NHh*DHh)],    g_kcl [BL * (NHh*DHh)];
__device__ __half g_krh [BL * DHRr],         g_krl [BL * DHRr];
__device__ __half g_vhh [BL * (NHh*DHh)],    g_vll [BL * (NHh*DHh)];
// fp16 split planes (transposed weights, [N][K])
__device__ __half g_tDKVh[DCc * Dd],        g_tDKVl[DCc * Dd];
__device__ __half g_tUKh [(NHh*DHh) * DCc], g_tUKl [(NHh*DHh) * DCc];
__device__ __half g_tUVh [(NHh*DHh) * DCc], g_tUVl [(NHh*DHh) * DCc];
__device__ __half g_tDQh [DCc * Dd],        g_tDQl [DCc * Dd];
__device__ __half g_tUQh [(2*NHh*DHh)*DCc], g_tUQl [(2*NHh*DHh)*DCc];
__device__ __half g_tQRh [(2*NHh*DHRr)*DCc],g_tQRl [(2*NHh*DHRr)*DCc];
__device__ __half g_tOUTh[Dd * Dd],         g_tOUTl[Dd * Dd];

// ======================= helpers =======================
__device__ __forceinline__ uint32_t smem_u32(const void* p) {
    uint32_t a;
    asm("{ .reg .u64 t; cvta.to.shared.u64 t, %1; cvt.u32.u64 %0, t; }" : "=r"(a) : "l"(p));
    return a;
}
__device__ __forceinline__ void cp16(uint32_t dst, const void* src) {
    asm volatile("cp.async.cg.shared.global [%0], [%1], 16;" :: "r"(dst), "l"(src));
}
#define CP_COMMIT() asm volatile("cp.async.commit_group;" ::: "memory")
#define CP_WAIT0()  asm volatile("cp.async.wait_group 0;"  ::: "memory")

// fp16 m16n8k16 MMA
__device__ __forceinline__ void mma_f16(float c[4],
                                        uint32_t a0, uint32_t a1, uint32_t a2, uint32_t a3,
                                        uint32_t b0, uint32_t b1)
{
    asm volatile(
        "mma.sync.aligned.m16n8k16.row.col.f32.f16.f16.f32 "
        "{%0,%1,%2,%3}, {%4,%5,%6,%7}, {%8,%9}, {%0,%1,%2,%3};"
        : "+f"(c[0]), "+f"(c[1]), "+f"(c[2]), "+f"(c[3])
        : "r"(a0), "r"(a1), "r"(a2), "r"(a3), "r"(b0), "r"(b1));
}

__device__ __forceinline__ void split16(float v, __half& h, __half& l) {
    h = __float2half_rn(v);
    l = __float2half_rn(v - __half2float(h));
}

// ======================= transpose + split: in[R][C] -> hi/lo[C][R] =======================
__global__ void transpose32h(const float* __restrict__ in,
                             __half* __restrict__ oh, __half* __restrict__ ol, int R, int C)
{
    __shared__ float t[32][33];
    int bx = blockIdx.x * 32, by = blockIdx.y * 32;
    int x = bx + threadIdx.x;
    #pragma unroll
    for (int j = 0; j < 32; j += 8)
        t[threadIdx.y + j][threadIdx.x] = in[(size_t)(by + threadIdx.y + j) * C + x];
    __syncthreads();
    int ox = by + threadIdx.x;
    #pragma unroll
    for (int j = 0; j < 32; j += 8) {
        float v = t[threadIdx.x][threadIdx.y + j];
        __half h, l; split16(v, h, l);
        size_t o = (size_t)(bx + threadIdx.y + j) * R + ox;
        oh[o] = h; ol[o] = l;
    }
}

// ======================= elementwise split =======================
__global__ void split_kernel(const float* __restrict__ in,
                             __half* __restrict__ oh, __half* __restrict__ ol)
{
    int idx = blockIdx.x * 256 + threadIdx.x;
    float v = in[idx];
    __half h, l; split16(v, h, l);
    oh[idx] = h; ol[idx] = l;
}

// ======================= fp16-split tensor-core GEMM =======================
#define WSTR 20
#define HGEMM_SMEM (2 * 4 * 128 * WSTR * 4)   // 81920 B
__global__ __launch_bounds__(256)
void hgemm(int N, int K,
           const __half* __restrict__ Ahi, const __half* __restrict__ Alo,
           const __half* __restrict__ Bhi, const __half* __restrict__ Blo,
           float* __restrict__ C)
{
    extern __shared__ float smraw[];
    uint32_t* smw = (uint32_t*)smraw;
    uint32_t* buf[2] = { smw, smw + 4 * 128 * WSTR };

    const int tid = threadIdx.x;
    const int wid = tid >> 5, lane = tid & 31;
    const int m0 = blockIdx.y * 128, n0 = blockIdx.x * 128;
    const int warpM = (wid >> 2) * 64;
    const int warpN = (wid & 3) * 32;
    const int lr = lane >> 2, lc = lane & 3;

    const __half* Ap[2] = { Ahi + (size_t)m0 * K, Alo + (size_t)m0 * K };
    const __half* Bp[2] = { Bhi + (size_t)n0 * K, Blo + (size_t)n0 * K };

    const int r = tid >> 1;
    const int q = (tid & 1) * 2;

    auto stage = [&](int kc, int b) {
        uint32_t base = smem_u32(buf[b]);
        #pragma unroll
        for (int p = 0; p < 2; p++) {
            uint32_t dA = base + (uint32_t)((p * 128 + r) * WSTR) * 4u;
            const __half* sA = Ap[p] + (size_t)r * K + kc;
            cp16(dA + q * 16,       sA + q * 8);
            cp16(dA + (q + 1) * 16, sA + (q + 1) * 8);
            uint32_t dB = base + (uint32_t)(((2 + p) * 128 + r) * WSTR) * 4u;
            const __half* sB = Bp[p] + (size_t)r * K + kc;
            cp16(dB + q * 16,       sB + q * 8);
            cp16(dB + (q + 1) * 16, sB + (q + 1) * 8);
        }
        CP_COMMIT();
    };

    float acc[4][4][4];
    #pragma unroll
    for (int i = 0; i < 4; i++)
        #pragma unroll
        for (int j = 0; j < 4; j++)
            #pragma unroll
            for (int k = 0; k < 4; k++) acc[i][j][k] = 0.f;

    stage(0, 0);

    const int nch = K >> 5;
    for (int i = 0; i < nch; i++) {
        CP_WAIT0();
        __syncthreads();
        if (i + 1 < nch) stage((i + 1) << 5, (i + 1) & 1);

        const uint32_t* Ah = buf[i & 1];
        const uint32_t* Al = Ah + 128 * WSTR;
        const uint32_t* Bh = Ah + 2 * 128 * WSTR;
        const uint32_t* Bl = Ah + 3 * 128 * WSTR;

        #pragma unroll
        for (int s = 0; s < 2; s++) {
            uint32_t ah[4][4], al[4][4];
            #pragma unroll
            for (int ma = 0; ma < 4; ma++) {
                int rw = (warpM + ma * 16 + lr) * WSTR + s * 8 + lc;
                ah[ma][0] = Ah[rw];
                ah[ma][1] = Ah[rw + 8 * WSTR];
                ah[ma][2] = Ah[rw + 4];
                ah[ma][3] = Ah[rw + 8 * WSTR + 4];
                al[ma][0] = Al[rw];
                al[ma][1] = Al[rw + 8 * WSTR];
                al[ma][2] = Al[rw + 4];
                al[ma][3] = Al[rw + 8 * WSTR + 4];
            }
            #pragma unroll
            for (int nb = 0; nb < 4; nb++) {
                int cw = (warpN + nb * 8 + lr) * WSTR + s * 8 + lc;
                uint32_t bh0 = Bh[cw], bh1 = Bh[cw + 4];
                uint32_t bl0 = Bl[cw], bl1 = Bl[cw + 4];
                #pragma unroll
                for (int ma = 0; ma < 4; ma++) {
                    mma_f16(acc[ma][nb], al[ma][0], al[ma][1], al[ma][2], al[ma][3], bh0, bh1);
                    mma_f16(acc[ma][nb], ah[ma][0], ah[ma][1], ah[ma][2], ah[ma][3], bl0, bl1);
                    mma_f16(acc[ma][nb], ah[ma][0], ah[ma][1], ah[ma][2], ah[ma][3], bh0, bh1);
                }
            }
        }
        __syncthreads();
    }

    #pragma unroll
    for (int ma = 0; ma < 4; ma++) {
        int row = m0 + warpM + ma * 16 + lr;
        #pragma unroll
        for (int nb = 0; nb < 4; nb++) {
            int col = n0 + warpN + nb * 8 + lc * 2;
            float2 o0 = make_float2(acc[ma][nb][0], acc[ma][nb][1]);
            float2 o1 = make_float2(acc[ma][nb][2], acc[ma][nb][3]);
            *(float2*)(C + (size_t)row * N + col)       = o0;
            *(float2*)(C + (size_t)(row + 8) * N + col) = o1;
        }
    }
}

// ======================= RMS norm -> fp16 split planes =======================
__global__ void rms_h(const float* __restrict__ in, const float* __restrict__ w,
                      __half* __restrict__ oh, __half* __restrict__ ol, int N)
{
    int row = blockIdx.x;
    const float* ir = in + (size_t)row * N;
    float s = 0.f;
    for (int i = threadIdx.x; i < N; i += 256) { float v = ir[i]; s += v * v; }
    __shared__ float red[256];
    red[threadIdx.x] = s;
    __syncthreads();
    for (int st = 128; st > 0; st >>= 1) {
        if (threadIdx.x < st) red[threadIdx.x] += red[threadIdx.x + st];
        __syncthreads();
    }
    float rr = rsqrtf(red[0] / (float)N + 1e-6f);
    for (int i = threadIdx.x; i < N; i += 256) {
        float v = ir[i] * rr * w[i];
        __half h, l; split16(v, h, l);
        oh[(size_t)row * N + i] = h;
        ol[(size_t)row * N + i] = l;
    }
}

// ======================= RoPE -> fp16 split planes =======================
__global__ void rope_h(const float* __restrict__ t,
                       __half* __restrict__ oh, __half* __restrict__ ol,
                       int heads, int rowstride)
{
    int idx = blockIdx.x * blockDim.x + threadIdx.x;
    int j = idx & 31;
    int h = (idx >> 5) % heads;
    int row = idx / (32 * heads);
    if (row >= BL) return;
    int l = row & (Lseq - 1);
    float inv = powf(10000.f, -(float)(2 * j) / 64.f);
    float ang = (float)l * inv;
    float c = cosf(ang), s = sinf(ang);
    const float* base = t + (size_t)row * rowstride + h * 64;
    float x1 = base[j], x2 = base[j + 32];
    float y1 = x1 * c - x2 * s;
    float y2 = x2 * c + x1 * s;
    size_t o = (size_t)row * rowstride + h * 64;
    __half hh, ll;
    split16(y1, hh, ll); oh[o + j] = hh;      ol[o + j] = ll;
    split16(y2, hh, ll); oh[o + j + 32] = hh; ol[o + j + 32] = ll;
}

// ======================= lambda gate =======================
__global__ void lam_kernel(const float* __restrict__ x, const float* __restrict__ Wl,
                           const float* __restrict__ bl, float* __restrict__ lam)
{
    int row = blockIdx.x;
    int tid = threadIdx.x;
    const float* xr = x + (size_t)row * Dd;
    float acc[16];
    #pragma unroll
    for (int n = 0; n < 16; n++) acc[n] = 0.f;
    for (int k = tid; k < Dd; k += 128) {
        float xv = xr[k];
        const float* wv = Wl + (size_t)k * 16;
        #pragma unroll
        for (int n = 0; n < 16; n++) acc[n] += xv * wv[n];
    }
    __shared__ float red[16 * 128];
    #pragma unroll
    for (int n = 0; n < 16; n++) red[n * 128 + tid] = acc[n];
    __syncthreads();
    for (int st = 64; st > 0; st >>= 1) {
        if (tid < st) {
            #pragma unroll
            for (int n = 0; n < 16; n++) red[n * 128 + tid] += red[n * 128 + tid + st];
        }
        __syncthreads();
    }
    if (tid < 16) {
        float z = red[tid * 128] + bl[tid];
        lam[(size_t)row * 16 + tid] = 1.f / (1.f + expf(-z));
    }
}

// ======================= small GEMM N=64 (x @ W_KR) =======================
__global__ void gemm_n64(const float* __restrict__ A, const float* __restrict__ B,
                         float* __restrict__ C, int K)
{
    int n = threadIdx.x;
    int m = blockIdx.x * 4 + threadIdx.y;
    float acc = 0.f;
    const float* ar = A + (size_t)m * K;
    #pragma unroll 8
    for (int k = 0; k < K; k++) acc += ar[k] * B[(size_t)k * 64 + n];
    C[(size_t)m * 64 + n] = acc;
}

// ======================= tensor-core flash attention (3xFP16, pre-split planes) =====
// block 128 threads / 4 warps; Q tile 64 (16 rows/warp), K tile 32.
// smem (words): qs 2x6400 | ks 2x3200 | vs 2x2176 | ps 2x1280 = 26112 w = 104448 B
#define FLASH_SMEM (26112 * 4)
__global__ __launch_bounds__(128)
void flash_h(const __half* __restrict__ qch, const __half* __restrict__ qcl,
             const __half* __restrict__ qrh, const __half* __restrict__ qrl,
             const __half* __restrict__ kch, const __half* __restrict__ kcl,
             const __half* __restrict__ krh, const __half* __restrict__ krl,
             const __half* __restrict__ vhh, const __half* __restrict__ vll,
             float* __restrict__ attn)
{
    extern __shared__ uint32_t smw[];
    uint32_t* qs[2] = { smw,         smw + 6400 };
    uint32_t* ks[2] = { smw + 12800, smw + 16000 };
    uint32_t* vs[2] = { smw + 19200, smw + 21376 };
    uint32_t* ps[2] = { smw + 23552, smw + 24832 };

    const int Q0 = blockIdx.x * 64;
    const int head2 = blockIdx.y;
    const int b = blockIdx.z;
    const int hn = head2 >> 1, hp = head2 & 1;
    const int tid = threadIdx.x;
    const int lane = tid & 31, w = tid >> 5;
    const int lr = lane >> 2, lc = lane & 3;

    const size_t tq = (size_t)(b * Lseq + Q0);

    // ---- stage Q (once), both planes ----
    {
        const __half* qcp[2] = { qch + tq * 4096 + head2 * 128, qcl + tq * 4096 + head2 * 128 };
        const __half* qrp[2] = { qrh + tq * 2048 + head2 * 64,  qrl + tq * 2048 + head2 * 64 };
        #pragma unroll
        for (int p = 0; p < 2; p++) {
            uint32_t qb = smem_u32(qs[p]);
            #pragma unroll
            for (int i = 0; i < 8; i++) {
                int s2 = tid + i * 128;
                int r = s2 >> 4, c = s2 & 15;
                cp16(qb + (uint32_t)(r * 100 + c * 4) * 4u, qcp[p] + (size_t)r * 4096 + c * 8);
            }
            #pragma unroll
            for (int i = 0; i < 4; i++) {
                int s2 = tid + i * 128;
                int r = s2 >> 3, c = s2 & 7;
                cp16(qb + (uint32_t)(r * 100 + 64 + c * 4) * 4u, qrp[p] + (size_t)r * 2048 + c * 8);
            }
        }
        CP_COMMIT();
    }

    float o[16][4];
    #pragma unroll
    for (int i = 0; i < 16; i++) { o[i][0] = o[i][1] = o[i][2] = o[i][3] = 0.f; }
    float m0 = -INFINITY, m1 = -INFINITY, l0 = 0.f, l1 = 0.f;

    const int row0g = Q0 + 16 * w + lr;
    const int row1g = row0g + 8;
    const int prow0 = (16 * w + lr) * 20;   // ps word base, row0
    const int arow0 = (16 * w + lr) * 100;  // qs word base, row0

    const int ntile = (Q0 + 64) >> 5;
    for (int t = 0; t < ntile; t++) {
        const int k0 = t << 5;
        __syncthreads();
        // ---- stage K (kc|kr) and V, both planes ----
        {
            const size_t tk = (size_t)(b * Lseq + k0);
            const __half* kcp[2] = { kch + tk * 2048 + hn * 128, kcl + tk * 2048 + hn * 128 };
            const __half* krp[2] = { krh + tk * 64,              krl + tk * 64 };
            const __half* vp[2]  = { vhh + tk * 2048 + hn * 128, vll + tk * 2048 + hn * 128 };
            #pragma unroll
            for (int p = 0; p < 2; p++) {
                uint32_t kb = smem_u32(ks[p]);
                uint32_t vb = smem_u32(vs[p]);
                #pragma unroll
                for (int i = 0; i < 4; i++) {
                    int s2 = tid + i * 128;
                    int r = s2 >> 4, c = s2 & 15;
                    cp16(kb + (uint32_t)(r * 100 + c * 4) * 4u, kcp[p] + (size_t)r * 2048 + c * 8);
                    cp16(vb + (uint32_t)(r * 68 + c * 4) * 4u,  vp[p]  + (size_t)r * 2048 + c * 8);
                }
                #pragma unroll
                for (int i = 0; i < 2; i++) {
                    int s2 = tid + i * 128;
                    int r = s2 >> 3, c = s2 & 7;
                    cp16(kb + (uint32_t)(r * 100 + 64 + c * 4) * 4u, krp[p] + (size_t)r * 64 + c * 8);
                }
            }
            CP_COMMIT();
            CP_WAIT0();
            __syncthreads();
        }

        // ---- S = Q @ K^T (3xFP16) ----
        float s4[4][4];
        #pragma unroll
        for (int nt = 0; nt < 4; nt++) { s4[nt][0] = s4[nt][1] = s4[nt][2] = s4[nt][3] = 0.f; }

        #pragma unroll 4
        for (int s = 0; s < 12; s++) {
            const int ab = arow0 + s * 8 + lc;
            uint32_t ah0 = qs[0][ab],       ah1 = qs[0][ab + 800];
            uint32_t ah2 = qs[0][ab + 4],   ah3 = qs[0][ab + 804];
            uint32_t al0 = qs[1][ab],       al1 = qs[1][ab + 800];
            uint32_t al2 = qs[1][ab + 4],   al3 = qs[1][ab + 804];
            #pragma unroll
            for (int nt = 0; nt < 4; nt++) {
                const int cb = (nt * 8 + lr) * 100 + s * 8 + lc;
                uint32_t bh0 = ks[0][cb], bh1 = ks[0][cb + 4];
                uint32_t bl0 = ks[1][cb], bl1 = ks[1][cb + 4];
                mma_f16(s4[nt], al0, al1, al2, al3, bh0, bh1);
                mma_f16(s4[nt], ah0, ah1, ah2, ah3, bl0, bl1);
                mma_f16(s4[nt], ah0, ah1, ah2, ah3, bh0, bh1);
            }
        }

        // ---- mask + scale + online softmax ----
        float tmax0 = -INFINITY, tmax1 = -INFINITY;
        #pragma unroll
        for (int nt = 0; nt < 4; nt++) {
            const int colg = k0 + nt * 8 + 2 * lc;
            s4[nt][0] = (colg     <= row0g) ? s4[nt][0] * ATTN_SCALE : -INFINITY;
            s4[nt][1] = (colg + 1 <= row0g) ? s4[nt][1] * ATTN_SCALE : -INFINITY;
            s4[nt][2] = (colg     <= row1g) ? s4[nt][2] * ATTN_SCALE : -INFINITY;
            s4[nt][3] = (colg + 1 <= row1g) ? s4[nt][3] * ATTN_SCALE : -INFINITY;
            tmax0 = fmaxf(tmax0, fmaxf(s4[nt][0], s4[nt][1]));
            tmax1 = fmaxf(tmax1, fmaxf(s4[nt][2], s4[nt][3]));
        }
        tmax0 = fmaxf(tmax0, __shfl_xor_sync(0xffffffffu, tmax0, 1));
        tmax0 = fmaxf(tmax0, __shfl_xor_sync(0xffffffffu, tmax0, 2));
        tmax1 = fmaxf(tmax1, __shfl_xor_sync(0xffffffffu, tmax1, 1));
        tmax1 = fmaxf(tmax1, __shfl_xor_sync(0xffffffffu, tmax1, 2));

        const float mn0 = fmaxf(m0, tmax0), mn1 = fmaxf(m1, tmax1);
        const float scl0 = expf(m0 - mn0);
        const float scl1 = expf(m1 - mn1);

        float p4[4][4];
        float pr0 = 0.f, pr1 = 0.f;
        #pragma unroll
        for (int nt = 0; nt < 4; nt++) {
            p4[nt][0] = expf(s4[nt][0] - mn0);
            p4[nt][1] = expf(s4[nt][1] - mn0);
            p4[nt][2] = expf(s4[nt][2] - mn1);
            p4[nt][3] = expf(s4[nt][3] - mn1);
            pr0 += p4[nt][0] + p4[nt][1];
            pr1 += p4[nt][2] + p4[nt][3];
        }
        pr0 += __shfl_xor_sync(0xffffffffu, pr0, 1);
        pr0 += __shfl_xor_sync(0xffffffffu, pr0, 2);
        pr1 += __shfl_xor_sync(0xffffffffu, pr1, 1);
        pr1 += __shfl_xor_sync(0xffffffffu, pr1, 2);

        l0 = l0 * scl0 + pr0;
        l1 = l1 * scl1 + pr1;
        m0 = mn0; m1 = mn1;

        #pragma unroll
        for (int i = 0; i < 16; i++) {
            o[i][0] *= scl0; o[i][1] *= scl0;
            o[i][2] *= scl1; o[i][3] *= scl1;
        }

        // ---- split P into fp16 planes (per-warp private rows) ----
        #pragma unroll
        for (int nt = 0; nt < 4; nt++) {
            __half2 h0 = __floats2half2_rn(p4[nt][0], p4[nt][1]);
            float2 f0 = __half22float2(h0);
            __half2 e0 = __floats2half2_rn(p4[nt][0] - f0.x, p4[nt][1] - f0.y);
            ((__half2*)ps[0])[prow0 + nt * 4 + lc] = h0;
            ((__half2*)ps[1])[prow0 + nt * 4 + lc] = e0;
            __half2 h1 = __floats2half2_rn(p4[nt][2], p4[nt][3]);
            float2 f1 = __half22float2(h1);
            __half2 e1 = __floats2half2_rn(p4[nt][2] - f1.x, p4[nt][3] - f1.y);
            ((__half2*)ps[0])[prow0 + 160 + nt * 4 + lc] = h1;
            ((__half2*)ps[1])[prow0 + 160 + nt * 4 + lc] = e1;
        }
        __syncwarp();

        // ---- O += P @ V (3xFP16) ----
        const uint16_t* vhp = (const uint16_t*)vs[0];
        const uint16_t* vlp = (const uint16_t*)vs[1];
        #pragma unroll
        for (int s = 0; s < 2; s++) {
            const int pb = prow0 + s * 8 + lc;
            uint32_t ah0 = ps[0][pb],     ah1 = ps[0][pb + 160];
            uint32_t ah2 = ps[0][pb + 4], ah3 = ps[0][pb + 164];
            uint32_t al0 = ps[1][pb],     al1 = ps[1][pb + 160];
            uint32_t al2 = ps[1][pb + 4], al3 = ps[1][pb + 164];
            const int kb = s * 16 + 2 * lc;
            #pragma unroll
            for (int nt2 = 0; nt2 < 16; nt2++) {
                const int d = nt2 * 8 + lr;
                uint32_t bh0 = (uint32_t)vhp[kb * 136 + d]       | ((uint32_t)vhp[(kb + 1) * 136 + d] << 16);
                uint32_t bh1 = (uint32_t)vhp[(kb + 8) * 136 + d] | ((uint32_t)vhp[(kb + 9) * 136 + d] << 16);
                uint32_t bl0 = (uint32_t)vlp[kb * 136 + d]       | ((uint32_t)vlp[(kb + 1) * 136 + d] << 16);
                uint32_t bl1 = (uint32_t)vlp[(kb + 8) * 136 + d] | ((uint32_t)vlp[(kb + 9) * 136 + d] << 16);
                mma_f16(o[nt2], al0, al1, al2, al3, bh0, bh1);
                mma_f16(o[nt2], ah0, ah1, ah2, ah3, bl0, bl1);
                mma_f16(o[nt2], ah0, ah1, ah2, ah3, bh0, bh1);
            }
        }
    }

    // ---- epilogue ----
    const float inv0 = 1.f / l0, inv1 = 1.f / l1;
    const size_t obase = ((size_t)(b * 2 + hp) * NHh + hn) * Lseq;
    float* op0 = attn + (obase + row0g) * 128;
    float* op1 = attn + (obase + row1g) * 128;
    #pragma unroll
    for (int nt2 = 0; nt2 < 16; nt2++) {
        *(float2*)(op0 + nt2 * 8 + 2 * lc) = make_float2(o[nt2][0] * inv0, o[nt2][1] * inv0);
        *(float2*)(op1 + nt2 * 8 + 2 * lc) = make_float2(o[nt2][2] * inv1, o[nt2][3] * inv1);
    }
}

// ======================= combine -> fp16 split planes =======================
__global__ void combine_h(const float* __restrict__ attn, const float* __restrict__ lam,
                          __half* __restrict__ oh, __half* __restrict__ ol)
{
    int idx = blockIdx.x * 256 + threadIdx.x;
    int c = idx & 2047;
    int row = idx >> 11;
    int b = row >> 11;
    int l = row & 2047;
    int n = c >> 7, d = c & 127;
    size_t a1 = (((size_t)(b * 2 + 0) * NHh + n) * Lseq + l) * 128 + d;
    size_t a2 = (((size_t)(b * 2 + 1) * NHh + n) * Lseq + l) * 128 + d;
    float v = attn[a1] - lam[(size_t)row * 16 + n] * attn[a2];
    __half h, lo; split16(v, h, lo);
    oh[idx] = h; ol[idx] = lo;
}

// ======================= launch =======================
extern "C" void kernel_launch(void* const* d_in, const int* in_sizes, int n_in,
                              void* d_out, int out_size)
{
    const float* x     = (const float*)d_in[0];
    const float* W_DKV = (const float*)d_in[1];
    const float* kv_w  = (const float*)d_in[2];
    const float* W_UK  = (const float*)d_in[3];
    const float* W_UV  = (const float*)d_in[4];
    const float* W_DQ  = (const float*)d_in[5];
    const float* q_w   = (const float*)d_in[6];
    const float* W_UQ  = (const float*)d_in[7];
    const float* W_QR  = (const float*)d_in[8];
    const float* W_KR  = (const float*)d_in[9];
    const float* W_lw  = (const float*)d_in[10];
    const float* W_lb  = (const float*)d_in[11];
    const float* W_out = (const float*)d_in[12];
    float* out = (float*)d_out;

    float *tmp, *kc, *v, *qc, *qr, *kr, *lam, *attn;
    __half *xh, *xl, *ckvh, *ckvl, *cqh, *cql, *preh, *prel;
    __half *qchp, *qclp, *qrhp, *qrlp, *kchp, *kclp, *krhp, *krlp, *vhp, *vlp;
    __half *tDKVh, *tDKVl, *tUKh, *tUKl, *tUVh, *tUVl, *tDQh, *tDQl;
    __half *tUQh, *tUQl, *tQRh, *tQRl, *tOUTh, *tOUTl;
    cudaGetSymbolAddress((void**)&tmp,  g_tmp);
    cudaGetSymbolAddress((void**)&kc,   g_kc);
    cudaGetSymbolAddress((void**)&v,    g_v);
    cudaGetSymbolAddress((void**)&qc,   g_qc);
    cudaGetSymbolAddress((void**)&qr,   g_qr);
    cudaGetSymbolAddress((void**)&kr,   g_kr);
    cudaGetSymbolAddress((void**)&lam,  g_lam);
    cudaGetSymbolAddress((void**)&attn, g_attn);
    cudaGetSymbolAddress((void**)&xh,   g_xh);
    cudaGetSymbolAddress((void**)&xl,   g_xl);
    cudaGetSymbolAddress((void**)&ckvh, g_ckvh);
    cudaGetSymbolAddress((void**)&ckvl, g_ckvl);
    cudaGetSymbolAddress((void**)&cqh,  g_cqh);
    cudaGetSymbolAddress((void**)&cql,  g_cql);
    cudaGetSymbolAddress((void**)&preh, g_preh);
    cudaGetSymbolAddress((void**)&prel, g_prel);
    cudaGetSymbolAddress((void**)&qchp, g_qch);
    cudaGetSymbolAddress((void**)&qclp, g_qcl);
    cudaGetSymbolAddress((void**)&qrhp, g_qrh);
    cudaGetSymbolAddress((void**)&qrlp, g_qrl);
    cudaGetSymbolAddress((void**)&kchp, g_kch);
    cudaGetSymbolAddress((void**)&kclp, g_kcl);
    cudaGetSymbolAddress((void**)&krhp, g_krh);
    cudaGetSymbolAddress((void**)&krlp, g_krl);
    cudaGetSymbolAddress((void**)&vhp,  g_vhh);
    cudaGetSymbolAddress((void**)&vlp,  g_vll);
    cudaGetSymbolAddress((void**)&tDKVh, g_tDKVh);
    cudaGetSymbolAddress((void**)&tDKVl, g_tDKVl);
    cudaGetSymbolAddress((void**)&tUKh,  g_tUKh);
    cudaGetSymbolAddress((void**)&tUKl,  g_tUKl);
    cudaGetSymbolAddress((void**)&tUVh,  g_tUVh);
    cudaGetSymbolAddress((void**)&tUVl,  g_tUVl);
    cudaGetSymbolAddress((void**)&tDQh,  g_tDQh);
    cudaGetSymbolAddress((void**)&tDQl,  g_tDQl);
    cudaGetSymbolAddress((void**)&tUQh,  g_tUQh);
    cudaGetSymbolAddress((void**)&tUQl,  g_tUQl);
    cudaGetSymbolAddress((void**)&tQRh,  g_tQRh);
    cudaGetSymbolAddress((void**)&tQRl,  g_tQRl);
    cudaGetSymbolAddress((void**)&tOUTh, g_tOUTh);
    cudaGetSymbolAddress((void**)&tOUTl, g_tOUTl);

    cudaFuncSetAttribute(hgemm, cudaFuncAttributeMaxDynamicSharedMemorySize, HGEMM_SMEM);
    cudaFuncSetAttribute(flash_h, cudaFuncAttributeMaxDynamicSharedMemorySize, FLASH_SMEM);

    dim3 tb(32, 8);
    transpose32h<<<dim3(DCc/32,  Dd/32),  tb>>>(W_DKV, tDKVh, tDKVl, Dd,  DCc);
    transpose32h<<<dim3((NHh*DHh)/32, DCc/32), tb>>>(W_UK, tUKh, tUKl, DCc, NHh*DHh);
    transpose32h<<<dim3((NHh*DHh)/32, DCc/32), tb>>>(W_UV, tUVh, tUVl, DCc, NHh*DHh);
    transpose32h<<<dim3(DCc/32,  Dd/32),  tb>>>(W_DQ,  tDQh,  tDQl,  Dd,  DCc);
    transpose32h<<<dim3((2*NHh*DHh)/32, DCc/32), tb>>>(W_UQ, tUQh, tUQl, DCc, 2*NHh*DHh);
    transpose32h<<<dim3((2*NHh*DHRr)/32, DCc/32), tb>>>(W_QR, tQRh, tQRl, DCc, 2*NHh*DHRr);
    transpose32h<<<dim3(Dd/32,   Dd/32),  tb>>>(W_out, tOUTh, tOUTl, Dd,  Dd);
    split_kernel<<<(BL * Dd) / 256, 256>>>(x, xh, xl);

    // KV path
    hgemm<<<dim3(DCc/128, BL/128), 256, HGEMM_SMEM>>>(DCc, Dd, xh, xl, tDKVh, tDKVl, tmp);
    rms_h<<<BL, 256>>>(tmp, kv_w, ckvh, ckvl, DCc);
    hgemm<<<dim3((NHh*DHh)/128, BL/128), 256, HGEMM_SMEM>>>(NHh*DHh, DCc, ckvh, ckvl, tUKh, tUKl, kc);
    hgemm<<<dim3((NHh*DHh)/128, BL/128), 256, HGEMM_SMEM>>>(NHh*DHh, DCc, ckvh, ckvl, tUVh, tUVl, v);

    // Q path
    hgemm<<<dim3(DCc/128, BL/128), 256, HGEMM_SMEM>>>(DCc, Dd, xh, xl, tDQh, tDQl, tmp);
    rms_h<<<BL, 256>>>(tmp, q_w, cqh, cql, DCc);
    hgemm<<<dim3((2*NHh*DHh)/128, BL/128), 256, HGEMM_SMEM>>>(2*NHh*DHh, DCc, cqh, cql, tUQh, tUQl, qc);
    hgemm<<<dim3((2*NHh*DHRr)/128, BL/128), 256, HGEMM_SMEM>>>(2*NHh*DHRr, DCc, cqh, cql, tQRh, tQRl, qr);

    // split flash operands
    split_kernel<<<(BL * 2*NHh*DHh) / 256, 256>>>(qc, qchp, qclp);
    split_kernel<<<(BL * NHh*DHh) / 256, 256>>>(kc, kchp, kclp);
    split_kernel<<<(BL * NHh*DHh) / 256, 256>>>(v, vhp, vlp);

    // k_r (N=64) + RoPE (emit split planes)
    gemm_n64<<<BL / 4, dim3(64, 4)>>>(x, W_KR, kr, Dd);
    rope_h<<<(BL * 32 * 32) / 256, 256>>>(qr, qrhp, qrlp, 32, 2 * NHh * DHRr);
    rope_h<<<(BL * 1 * 32) / 256, 256>>>(kr, krhp, krlp, 1, DHRr);

    // lambda gate
    lam_kernel<<<BL, 128>>>(x, W_lw, W_lb, lam);

    // attention (fp16 tensor-core flash)
    flash_h<<<dim3(Lseq / 64, 32, BB), 128, FLASH_SMEM>>>(
        qchp, qclp, qrhp, qrlp, kchp, kclp, krhp, krlp, vhp, vlp, attn);

    // combine + output projection
    combine_h<<<(BL * Dd) / 256, 256>>>(attn, lam, preh, prel);
    hgemm<<<dim3(Dd/128, BL/128), 256, HGEMM_SMEM>>>(Dd, Dd, preh, prel, tOUTh, tOUTl, out);
}

// round 8
// speedup vs baseline: 2.1691x; 1.0339x over previous
#include <cuda_runtime.h>
#include <cuda.h>
#include <cuda_fp16.h>
#include <math.h>
#include <stdint.h>

#define BB   2
#define Lseq 2048
#define BL   4096      // B*L
#define Dd   2048
#define DCc  1024
#define NHh  16
#define DHh  128
#define DHRr 64
#define ATTN_SCALE 0.07216878364870322f

// ======================= scratch =======================
__device__ float g_tmp [BL * 2048];          // fused [ckv_pre | cq_pre]
__device__ float g_qr  [BL * (2 * NHh * DHRr)];
__device__ float g_kr  [BL * DHRr];
__device__ float g_lam [BL * NHh];
__device__ float g_attn[(size_t)2 * BB * NHh * Lseq * DHh];

// fp16 split planes (activations)
__device__ __half g_xh  [BL * Dd],   g_xl  [BL * Dd];
__device__ __half g_ckvh[BL * DCc],  g_ckvl[BL * DCc];
__device__ __half g_cqh [BL * DCc],  g_cql [BL * DCc];
__device__ __half g_preh[BL * Dd],   g_prel[BL * Dd];
__device__ __half g_qch [BL * 4096], g_qcl [BL * 4096];
__device__ __half g_qrh [BL * 2048], g_qrl [BL * 2048];
__device__ __half g_krh [BL * DHRr], g_krl [BL * DHRr];
__device__ __half g_kvh [BL * 4096], g_kvl [BL * 4096];   // [kc 2048 | v 2048]
// fp16 split planes (transposed weights, [N][K]); fused where A is shared
__device__ __half g_tDKVQh[2048 * Dd],  g_tDKVQl[2048 * Dd];   // rows: [DKV 1024 | DQ 1024]
__device__ __half g_tUKVh [4096 * DCc], g_tUKVl [4096 * DCc];  // rows: [UK 2048 | UV 2048]
__device__ __half g_tUQh  [4096 * DCc], g_tUQl  [4096 * DCc];
__device__ __half g_tQRh  [2048 * DCc], g_tQRl  [2048 * DCc];
__device__ __half g_tOUTh [Dd * Dd],    g_tOUTl [Dd * Dd];

// ======================= helpers =======================
__device__ __forceinline__ uint32_t smem_u32(const void* p) {
    uint32_t a;
    asm("{ .reg .u64 t; cvta.to.shared.u64 t, %1; cvt.u32.u64 %0, t; }" : "=r"(a) : "l"(p));
    return a;
}
__device__ __forceinline__ void cp16(uint32_t dst, const void* src) {
    asm volatile("cp.async.cg.shared.global [%0], [%1], 16;" :: "r"(dst), "l"(src));
}
#define CP_COMMIT() asm volatile("cp.async.commit_group;" ::: "memory")
#define CP_WAIT0()  asm volatile("cp.async.wait_group 0;"  ::: "memory")

__device__ __forceinline__ void mma_f16(float c[4],
                                        uint32_t a0, uint32_t a1, uint32_t a2, uint32_t a3,
                                        uint32_t b0, uint32_t b1)
{
    asm volatile(
        "mma.sync.aligned.m16n8k16.row.col.f32.f16.f16.f32 "
        "{%0,%1,%2,%3}, {%4,%5,%6,%7}, {%8,%9}, {%0,%1,%2,%3};"
        : "+f"(c[0]), "+f"(c[1]), "+f"(c[2]), "+f"(c[3])
        : "r"(a0), "r"(a1), "r"(a2), "r"(a3), "r"(b0), "r"(b1));
}

__device__ __forceinline__ void split16(float v, __half& h, __half& l) {
    h = __float2half_rn(v);
    l = __float2half_rn(v - __half2float(h));
}

// ======================= transpose + split: in[R][C] -> hi/lo[C][R] =======================
__global__ void transpose32h(const float* __restrict__ in,
                             __half* __restrict__ oh, __half* __restrict__ ol, int R, int C)
{
    __shared__ float t[32][33];
    int bx = blockIdx.x * 32, by = blockIdx.y * 32;
    int x = bx + threadIdx.x;
    #pragma unroll
    for (int j = 0; j < 32; j += 8)
        t[threadIdx.y + j][threadIdx.x] = in[(size_t)(by + threadIdx.y + j) * C + x];
    __syncthreads();
    int ox = by + threadIdx.x;
    #pragma unroll
    for (int j = 0; j < 32; j += 8) {
        float v = t[threadIdx.x][threadIdx.y + j];
        __half h, l; split16(v, h, l);
        size_t o = (size_t)(bx + threadIdx.y + j) * R + ox;
        oh[o] = h; ol[o] = l;
    }
}

// ======================= elementwise split =======================
__global__ void split_kernel(const float* __restrict__ in,
                             __half* __restrict__ oh, __half* __restrict__ ol)
{
    int idx = blockIdx.x * 256 + threadIdx.x;
    float v = in[idx];
    __half h, l; split16(v, h, l);
    oh[idx] = h; ol[idx] = l;
}

// ======================= fp16-split tensor-core GEMM (shared mainloop) =======================
#define WSTR 20
#define HGEMM_SMEM (2 * 4 * 128 * WSTR * 4)   // 81920 B

// mainloop macro body via template on epilogue type
template<bool HALF_OUT>
__global__ __launch_bounds__(256)
void hgemm_t(int N, int K,
             const __half* __restrict__ Ahi, const __half* __restrict__ Alo,
             const __half* __restrict__ Bhi, const __half* __restrict__ Blo,
             float* __restrict__ C, __half* __restrict__ Ch, __half* __restrict__ Cl)
{
    extern __shared__ float smraw[];
    uint32_t* smw = (uint32_t*)smraw;
    uint32_t* buf[2] = { smw, smw + 4 * 128 * WSTR };

    const int tid = threadIdx.x;
    const int wid = tid >> 5, lane = tid & 31;
    const int m0 = blockIdx.y * 128, n0 = blockIdx.x * 128;
    const int warpM = (wid >> 2) * 64;
    const int warpN = (wid & 3) * 32;
    const int lr = lane >> 2, lc = lane & 3;

    const __half* Ap[2] = { Ahi + (size_t)m0 * K, Alo + (size_t)m0 * K };
    const __half* Bp[2] = { Bhi + (size_t)n0 * K, Blo + (size_t)n0 * K };

    const int r = tid >> 1;
    const int q = (tid & 1) * 2;

    auto stage = [&](int kc, int b) {
        uint32_t base = smem_u32(buf[b]);
        #pragma unroll
        for (int p = 0; p < 2; p++) {
            uint32_t dA = base + (uint32_t)((p * 128 + r) * WSTR) * 4u;
            const __half* sA = Ap[p] + (size_t)r * K + kc;
            cp16(dA + q * 16,       sA + q * 8);
            cp16(dA + (q + 1) * 16, sA + (q + 1) * 8);
            uint32_t dB = base + (uint32_t)(((2 + p) * 128 + r) * WSTR) * 4u;
            const __half* sB = Bp[p] + (size_t)r * K + kc;
            cp16(dB + q * 16,       sB + q * 8);
            cp16(dB + (q + 1) * 16, sB + (q + 1) * 8);
        }
        CP_COMMIT();
    };

    float acc[4][4][4];
    #pragma unroll
    for (int i = 0; i < 4; i++)
        #pragma unroll
        for (int j = 0; j < 4; j++)
            #pragma unroll
            for (int k = 0; k < 4; k++) acc[i][j][k] = 0.f;

    stage(0, 0);

    const int nch = K >> 5;
    for (int i = 0; i < nch; i++) {
        CP_WAIT0();
        __syncthreads();
        if (i + 1 < nch) stage((i + 1) << 5, (i + 1) & 1);

        const uint32_t* Ah = buf[i & 1];
        const uint32_t* Al = Ah + 128 * WSTR;
        const uint32_t* Bh = Ah + 2 * 128 * WSTR;
        const uint32_t* Bl = Ah + 3 * 128 * WSTR;

        #pragma unroll
        for (int s = 0; s < 2; s++) {
            uint32_t ah[4][4], al[4][4];
            #pragma unroll
            for (int ma = 0; ma < 4; ma++) {
                int rw = (warpM + ma * 16 + lr) * WSTR + s * 8 + lc;
                ah[ma][0] = Ah[rw];
                ah[ma][1] = Ah[rw + 8 * WSTR];
                ah[ma][2] = Ah[rw + 4];
                ah[ma][3] = Ah[rw + 8 * WSTR + 4];
                al[ma][0] = Al[rw];
                al[ma][1] = Al[rw + 8 * WSTR];
                al[ma][2] = Al[rw + 4];
                al[ma][3] = Al[rw + 8 * WSTR + 4];
            }
            #pragma unroll
            for (int nb = 0; nb < 4; nb++) {
                int cw = (warpN + nb * 8 + lr) * WSTR + s * 8 + lc;
                uint32_t bh0 = Bh[cw], bh1 = Bh[cw + 4];
                uint32_t bl0 = Bl[cw], bl1 = Bl[cw + 4];
                #pragma unroll
                for (int ma = 0; ma < 4; ma++) {
                    mma_f16(acc[ma][nb], al[ma][0], al[ma][1], al[ma][2], al[ma][3], bh0, bh1);
                    mma_f16(acc[ma][nb], ah[ma][0], ah[ma][1], ah[ma][2], ah[ma][3], bl0, bl1);
                    mma_f16(acc[ma][nb], ah[ma][0], ah[ma][1], ah[ma][2], ah[ma][3], bh0, bh1);
                }
            }
        }
        __syncthreads();
    }

    #pragma unroll
    for (int ma = 0; ma < 4; ma++) {
        int row = m0 + warpM + ma * 16 + lr;
        #pragma unroll
        for (int nb = 0; nb < 4; nb++) {
            int col = n0 + warpN + nb * 8 + lc * 2;
            if (HALF_OUT) {
                float x0 = acc[ma][nb][0], x1 = acc[ma][nb][1];
                __half2 h2 = __floats2half2_rn(x0, x1);
                float2 hf = __half22float2(h2);
                __half2 l2 = __floats2half2_rn(x0 - hf.x, x1 - hf.y);
                *(__half2*)(Ch + (size_t)row * N + col) = h2;
                *(__half2*)(Cl + (size_t)row * N + col) = l2;
                float y0 = acc[ma][nb][2], y1 = acc[ma][nb][3];
                __half2 h3 = __floats2half2_rn(y0, y1);
                float2 hg = __half22float2(h3);
                __half2 l3 = __floats2half2_rn(y0 - hg.x, y1 - hg.y);
                *(__half2*)(Ch + (size_t)(row + 8) * N + col) = h3;
                *(__half2*)(Cl + (size_t)(row + 8) * N + col) = l3;
            } else {
                float2 o0 = make_float2(acc[ma][nb][0], acc[ma][nb][1]);
                float2 o1 = make_float2(acc[ma][nb][2], acc[ma][nb][3]);
                *(float2*)(C + (size_t)row * N + col)       = o0;
                *(float2*)(C + (size_t)(row + 8) * N + col) = o1;
            }
        }
    }
}

// ======================= RMS norm (strided input) -> fp16 split planes =======================
__global__ void rms_h(const float* __restrict__ in, int instride,
                      const float* __restrict__ w,
                      __half* __restrict__ oh, __half* __restrict__ ol, int N)
{
    int row = blockIdx.x;
    const float* ir = in + (size_t)row * instride;
    float s = 0.f;
    for (int i = threadIdx.x; i < N; i += 256) { float v = ir[i]; s += v * v; }
    __shared__ float red[256];
    red[threadIdx.x] = s;
    __syncthreads();
    for (int st = 128; st > 0; st >>= 1) {
        if (threadIdx.x < st) red[threadIdx.x] += red[threadIdx.x + st];
        __syncthreads();
    }
    float rr = rsqrtf(red[0] / (float)N + 1e-6f);
    for (int i = threadIdx.x; i < N; i += 256) {
        float v = ir[i] * rr * w[i];
        __half h, l; split16(v, h, l);
        oh[(size_t)row * N + i] = h;
        ol[(size_t)row * N + i] = l;
    }
}

// ======================= RoPE -> fp16 split planes =======================
__global__ void rope_h(const float* __restrict__ t,
                       __half* __restrict__ oh, __half* __restrict__ ol,
                       int heads, int rowstride)
{
    int idx = blockIdx.x * blockDim.x + threadIdx.x;
    int j = idx & 31;
    int h = (idx >> 5) % heads;
    int row = idx / (32 * heads);
    if (row >= BL) return;
    int l = row & (Lseq - 1);
    float inv = powf(10000.f, -(float)(2 * j) / 64.f);
    float ang = (float)l * inv;
    float c = cosf(ang), s = sinf(ang);
    const float* base = t + (size_t)row * rowstride + h * 64;
    float x1 = base[j], x2 = base[j + 32];
    float y1 = x1 * c - x2 * s;
    float y2 = x2 * c + x1 * s;
    size_t o = (size_t)row * rowstride + h * 64;
    __half hh, ll;
    split16(y1, hh, ll); oh[o + j] = hh;      ol[o + j] = ll;
    split16(y2, hh, ll); oh[o + j + 32] = hh; ol[o + j + 32] = ll;
}

// ======================= lambda gate =======================
__global__ void lam_kernel(const float* __restrict__ x, const float* __restrict__ Wl,
                           const float* __restrict__ bl, float* __restrict__ lam)
{
    int row = blockIdx.x;
    int tid = threadIdx.x;
    const float* xr = x + (size_t)row * Dd;
    float acc[16];
    #pragma unroll
    for (int n = 0; n < 16; n++) acc[n] = 0.f;
    for (int k = tid; k < Dd; k += 128) {
        float xv = xr[k];
        const float* wv = Wl + (size_t)k * 16;
        #pragma unroll
        for (int n = 0; n < 16; n++) acc[n] += xv * wv[n];
    }
    __shared__ float red[16 * 128];
    #pragma unroll
    for (int n = 0; n < 16; n++) red[n * 128 + tid] = acc[n];
    __syncthreads();
    for (int st = 64; st > 0; st >>= 1) {
        if (tid < st) {
            #pragma unroll
            for (int n = 0; n < 16; n++) red[n * 128 + tid] += red[n * 128 + tid + st];
        }
        __syncthreads();
    }
    if (tid < 16) {
        float z = red[tid * 128] + bl[tid];
        lam[(size_t)row * 16 + tid] = 1.f / (1.f + expf(-z));
    }
}

// ======================= small GEMM N=64 (x @ W_KR) =======================
__global__ void gemm_n64(const float* __restrict__ A, const float* __restrict__ B,
                         float* __restrict__ C, int K)
{
    int n = threadIdx.x;
    int m = blockIdx.x * 4 + threadIdx.y;
    float acc = 0.f;
    const float* ar = A + (size_t)m * K;
    #pragma unroll 8
    for (int k = 0; k < K; k++) acc += ar[k] * B[(size_t)k * 64 + n];
    C[(size_t)m * 64 + n] = acc;
}

// ======================= tensor-core flash attention (3xFP16, pre-split planes) =====
#define FLASH_SMEM (26112 * 4)
__global__ __launch_bounds__(128)
void flash_h(const __half* __restrict__ qch, const __half* __restrict__ qcl,
             const __half* __restrict__ qrh, const __half* __restrict__ qrl,
             const __half* __restrict__ kvh, const __half* __restrict__ kvl,
             const __half* __restrict__ krh, const __half* __restrict__ krl,
             float* __restrict__ attn)
{
    extern __shared__ uint32_t smw[];
    uint32_t* qs[2] = { smw,         smw + 6400 };
    uint32_t* ks[2] = { smw + 12800, smw + 16000 };
    uint32_t* vs[2] = { smw + 19200, smw + 21376 };
    uint32_t* ps[2] = { smw + 23552, smw + 24832 };

    const int Q0 = (gridDim.x - 1 - blockIdx.x) * 64;   // longest work first
    const int head2 = blockIdx.y;
    const int b = blockIdx.z;
    const int hn = head2 >> 1, hp = head2 & 1;
    const int tid = threadIdx.x;
    const int lane = tid & 31, w = tid >> 5;
    const int lr = lane >> 2, lc = lane & 3;

    const size_t tq = (size_t)(b * Lseq + Q0);

    // ---- stage Q (once), both planes ----
    {
        const __half* qcp[2] = { qch + tq * 4096 + head2 * 128, qcl + tq * 4096 + head2 * 128 };
        const __half* qrp[2] = { qrh + tq * 2048 + head2 * 64,  qrl + tq * 2048 + head2 * 64 };
        #pragma unroll
        for (int p = 0; p < 2; p++) {
            uint32_t qb = smem_u32(qs[p]);
            #pragma unroll
            for (int i = 0; i < 8; i++) {
                int s2 = tid + i * 128;
                int r = s2 >> 4, c = s2 & 15;
                cp16(qb + (uint32_t)(r * 100 + c * 4) * 4u, qcp[p] + (size_t)r * 4096 + c * 8);
            }
            #pragma unroll
            for (int i = 0; i < 4; i++) {
                int s2 = tid + i * 128;
                int r = s2 >> 3, c = s2 & 7;
                cp16(qb + (uint32_t)(r * 100 + 64 + c * 4) * 4u, qrp[p] + (size_t)r * 2048 + c * 8);
            }
        }
        CP_COMMIT();
    }

    float o[16][4];
    #pragma unroll
    for (int i = 0; i < 16; i++) { o[i][0] = o[i][1] = o[i][2] = o[i][3] = 0.f; }
    float m0 = -INFINITY, m1 = -INFINITY, l0 = 0.f, l1 = 0.f;

    const int row0g = Q0 + 16 * w + lr;
    const int row1g = row0g + 8;
    const int prow0 = (16 * w + lr) * 20;
    const int arow0 = (16 * w + lr) * 100;

    const int ntile = (Q0 + 64) >> 5;
    for (int t = 0; t < ntile; t++) {
        const int k0 = t << 5;
        __syncthreads();
        // ---- stage K (kc|kr) and V from fused kv planes ----
        {
            const size_t tk = (size_t)(b * Lseq + k0);
            const __half* kcp[2] = { kvh + tk * 4096 + hn * 128,        kvl + tk * 4096 + hn * 128 };
            const __half* vp[2]  = { kvh + tk * 4096 + 2048 + hn * 128, kvl + tk * 4096 + 2048 + hn * 128 };
            const __half* krp[2] = { krh + tk * 64,                     krl + tk * 64 };
            #pragma unroll
            for (int p = 0; p < 2; p++) {
                uint32_t kb = smem_u32(ks[p]);
                uint32_t vb = smem_u32(vs[p]);
                #pragma unroll
                for (int i = 0; i < 4; i++) {
                    int s2 = tid + i * 128;
                    int r = s2 >> 4, c = s2 & 15;
                    cp16(kb + (uint32_t)(r * 100 + c * 4) * 4u, kcp[p] + (size_t)r * 4096 + c * 8);
                    cp16(vb + (uint32_t)(r * 68 + c * 4) * 4u,  vp[p]  + (size_t)r * 4096 + c * 8);
                }
                #pragma unroll
                for (int i = 0; i < 2; i++) {
                    int s2 = tid + i * 128;
                    int r = s2 >> 3, c = s2 & 7;
                    cp16(kb + (uint32_t)(r * 100 + 64 + c * 4) * 4u, krp[p] + (size_t)r * 64 + c * 8);
                }
            }
            CP_COMMIT();
            CP_WAIT0();
            __syncthreads();
        }

        // ---- S = Q @ K^T (3xFP16) ----
        float s4[4][4];
        #pragma unroll
        for (int nt = 0; nt < 4; nt++) { s4[nt][0] = s4[nt][1] = s4[nt][2] = s4[nt][3] = 0.f; }

        #pragma unroll 4
        for (int s = 0; s < 12; s++) {
            const int ab = arow0 + s * 8 + lc;
            uint32_t ah0 = qs[0][ab],       ah1 = qs[0][ab + 800];
            uint32_t ah2 = qs[0][ab + 4],   ah3 = qs[0][ab + 804];
            uint32_t al0 = qs[1][ab],       al1 = qs[1][ab + 800];
            uint32_t al2 = qs[1][ab + 4],   al3 = qs[1][ab + 804];
            #pragma unroll
            for (int nt = 0; nt < 4; nt++) {
                const int cb = (nt * 8 + lr) * 100 + s * 8 + lc;
                uint32_t bh0 = ks[0][cb], bh1 = ks[0][cb + 4];
                uint32_t bl0 = ks[1][cb], bl1 = ks[1][cb + 4];
                mma_f16(s4[nt], al0, al1, al2, al3, bh0, bh1);
                mma_f16(s4[nt], ah0, ah1, ah2, ah3, bl0, bl1);
                mma_f16(s4[nt], ah0, ah1, ah2, ah3, bh0, bh1);
            }
        }

        // ---- mask + scale + online softmax ----
        float tmax0 = -INFINITY, tmax1 = -INFINITY;
        #pragma unroll
        for (int nt = 0; nt < 4; nt++) {
            const int colg = k0 + nt * 8 + 2 * lc;
            s4[nt][0] = (colg     <= row0g) ? s4[nt][0] * ATTN_SCALE : -INFINITY;
            s4[nt][1] = (colg + 1 <= row0g) ? s4[nt][1] * ATTN_SCALE : -INFINITY;
            s4[nt][2] = (colg     <= row1g) ? s4[nt][2] * ATTN_SCALE : -INFINITY;
            s4[nt][3] = (colg + 1 <= row1g) ? s4[nt][3] * ATTN_SCALE : -INFINITY;
            tmax0 = fmaxf(tmax0, fmaxf(s4[nt][0], s4[nt][1]));
            tmax1 = fmaxf(tmax1, fmaxf(s4[nt][2], s4[nt][3]));
        }
        tmax0 = fmaxf(tmax0, __shfl_xor_sync(0xffffffffu, tmax0, 1));
        tmax0 = fmaxf(tmax0, __shfl_xor_sync(0xffffffffu, tmax0, 2));
        tmax1 = fmaxf(tmax1, __shfl_xor_sync(0xffffffffu, tmax1, 1));
        tmax1 = fmaxf(tmax1, __shfl_xor_sync(0xffffffffu, tmax1, 2));

        const float mn0 = fmaxf(m0, tmax0), mn1 = fmaxf(m1, tmax1);
        const float scl0 = expf(m0 - mn0);
        const float scl1 = expf(m1 - mn1);

        float p4[4][4];
        float pr0 = 0.f, pr1 = 0.f;
        #pragma unroll
        for (int nt = 0; nt < 4; nt++) {
            p4[nt][0] = expf(s4[nt][0] - mn0);
            p4[nt][1] = expf(s4[nt][1] - mn0);
            p4[nt][2] = expf(s4[nt][2] - mn1);
            p4[nt][3] = expf(s4[nt][3] - mn1);
            pr0 += p4[nt][0] + p4[nt][1];
            pr1 += p4[nt][2] + p4[nt][3];
        }
        pr0 += __shfl_xor_sync(0xffffffffu, pr0, 1);
        pr0 += __shfl_xor_sync(0xffffffffu, pr0, 2);
        pr1 += __shfl_xor_sync(0xffffffffu, pr1, 1);
        pr1 += __shfl_xor_sync(0xffffffffu, pr1, 2);

        l0 = l0 * scl0 + pr0;
        l1 = l1 * scl1 + pr1;
        m0 = mn0; m1 = mn1;

        #pragma unroll
        for (int i = 0; i < 16; i++) {
            o[i][0] *= scl0; o[i][1] *= scl0;
            o[i][2] *= scl1; o[i][3] *= scl1;
        }

        // ---- split P into fp16 planes (per-warp private rows) ----
        #pragma unroll
        for (int nt = 0; nt < 4; nt++) {
            __half2 h0 = __floats2half2_rn(p4[nt][0], p4[nt][1]);
            float2 f0 = __half22float2(h0);
            __half2 e0 = __floats2half2_rn(p4[nt][0] - f0.x, p4[nt][1] - f0.y);
            ((__half2*)ps[0])[prow0 + nt * 4 + lc] = h0;
            ((__half2*)ps[1])[prow0 + nt * 4 + lc] = e0;
            __half2 h1 = __floats2half2_rn(p4[nt][2], p4[nt][3]);
            float2 f1 = __half22float2(h1);
            __half2 e1 = __floats2half2_rn(p4[nt][2] - f1.x, p4[nt][3] - f1.y);
            ((__half2*)ps[0])[prow0 + 160 + nt * 4 + lc] = h1;
            ((__half2*)ps[1])[prow0 + 160 + nt * 4 + lc] = e1;
        }
        __syncwarp();

        // ---- O += P @ V (3xFP16) ----
        const uint16_t* vhp = (const uint16_t*)vs[0];
        const uint16_t* vlp = (const uint16_t*)vs[1];
        #pragma unroll
        for (int s = 0; s < 2; s++) {
            const int pb = prow0 + s * 8 + lc;
            uint32_t ah0 = ps[0][pb],     ah1 = ps[0][pb + 160];
            uint32_t ah2 = ps[0][pb + 4], ah3 = ps[0][pb + 164];
            uint32_t al0 = ps[1][pb],     al1 = ps[1][pb + 160];
            uint32_t al2 = ps[1][pb + 4], al3 = ps[1][pb + 164];
            const int kb = s * 16 + 2 * lc;
            #pragma unroll
            for (int nt2 = 0; nt2 < 16; nt2++) {
                const int d = nt2 * 8 + lr;
                uint32_t bh0 = (uint32_t)vhp[kb * 136 + d]       | ((uint32_t)vhp[(kb + 1) * 136 + d] << 16);
                uint32_t bh1 = (uint32_t)vhp[(kb + 8) * 136 + d] | ((uint32_t)vhp[(kb + 9) * 136 + d] << 16);
                uint32_t bl0 = (uint32_t)vlp[kb * 136 + d]       | ((uint32_t)vlp[(kb + 1) * 136 + d] << 16);
                uint32_t bl1 = (uint32_t)vlp[(kb + 8) * 136 + d] | ((uint32_t)vlp[(kb + 9) * 136 + d] << 16);
                mma_f16(o[nt2], al0, al1, al2, al3, bh0, bh1);
                mma_f16(o[nt2], ah0, ah1, ah2, ah3, bl0, bl1);
                mma_f16(o[nt2], ah0, ah1, ah2, ah3, bh0, bh1);
            }
        }
    }

    // ---- epilogue ----
    const float inv0 = 1.f / l0, inv1 = 1.f / l1;
    const size_t obase = ((size_t)(b * 2 + hp) * NHh + hn) * Lseq;
    float* op0 = attn + (obase + row0g) * 128;
    float* op1 = attn + (obase + row1g) * 128;
    #pragma unroll
    for (int nt2 = 0; nt2 < 16; nt2++) {
        *(float2*)(op0 + nt2 * 8 + 2 * lc) = make_float2(o[nt2][0] * inv0, o[nt2][1] * inv0);
        *(float2*)(op1 + nt2 * 8 + 2 * lc) = make_float2(o[nt2][2] * inv1, o[nt2][3] * inv1);
    }
}

// ======================= combine -> fp16 split planes =======================
__global__ void combine_h(const float* __restrict__ attn, const float* __restrict__ lam,
                          __half* __restrict__ oh, __half* __restrict__ ol)
{
    int idx = blockIdx.x * 256 + threadIdx.x;
    int c = idx & 2047;
    int row = idx >> 11;
    int b = row >> 11;
    int l = row & 2047;
    int n = c >> 7, d = c & 127;
    size_t a1 = (((size_t)(b * 2 + 0) * NHh + n) * Lseq + l) * 128 + d;
    size_t a2 = (((size_t)(b * 2 + 1) * NHh + n) * Lseq + l) * 128 + d;
    float v = attn[a1] - lam[(size_t)row * 16 + n] * attn[a2];
    __half h, lo; split16(v, h, lo);
    oh[idx] = h; ol[idx] = lo;
}

// ======================= launch =======================
extern "C" void kernel_launch(void* const* d_in, const int* in_sizes, int n_in,
                              void* d_out, int out_size)
{
    const float* x     = (const float*)d_in[0];
    const float* W_DKV = (const float*)d_in[1];
    const float* kv_w  = (const float*)d_in[2];
    const float* W_UK  = (const float*)d_in[3];
    const float* W_UV  = (const float*)d_in[4];
    const float* W_DQ  = (const float*)d_in[5];
    const float* q_w   = (const float*)d_in[6];
    const float* W_UQ  = (const float*)d_in[7];
    const float* W_QR  = (const float*)d_in[8];
    const float* W_KR  = (const float*)d_in[9];
    const float* W_lw  = (const float*)d_in[10];
    const float* W_lb  = (const float*)d_in[11];
    const float* W_out = (const float*)d_in[12];
    float* out = (float*)d_out;

    float *tmp, *qr, *kr, *lam, *attn;
    __half *xh, *xl, *ckvh, *ckvl, *cqh, *cql, *preh, *prel;
    __half *qchp, *qclp, *qrhp, *qrlp, *krhp, *krlp, *kvh, *kvl;
    __half *tDKVQh, *tDKVQl, *tUKVh, *tUKVl, *tUQh, *tUQl, *tQRh, *tQRl, *tOUTh, *tOUTl;
    cudaGetSymbolAddress((void**)&tmp,  g_tmp);
    cudaGetSymbolAddress((void**)&qr,   g_qr);
    cudaGetSymbolAddress((void**)&kr,   g_kr);
    cudaGetSymbolAddress((void**)&lam,  g_lam);
    cudaGetSymbolAddress((void**)&attn, g_attn);
    cudaGetSymbolAddress((void**)&xh,   g_xh);
    cudaGetSymbolAddress((void**)&xl,   g_xl);
    cudaGetSymbolAddress((void**)&ckvh, g_ckvh);
    cudaGetSymbolAddress((void**)&ckvl, g_ckvl);
    cudaGetSymbolAddress((void**)&cqh,  g_cqh);
    cudaGetSymbolAddress((void**)&cql,  g_cql);
    cudaGetSymbolAddress((void**)&preh, g_preh);
    cudaGetSymbolAddress((void**)&prel, g_prel);
    cudaGetSymbolAddress((void**)&qchp, g_qch);
    cudaGetSymbolAddress((void**)&qclp, g_qcl);
    cudaGetSymbolAddress((void**)&qrhp, g_qrh);
    cudaGetSymbolAddress((void**)&qrlp, g_qrl);
    cudaGetSymbolAddress((void**)&krhp, g_krh);
    cudaGetSymbolAddress((void**)&krlp, g_krl);
    cudaGetSymbolAddress((void**)&kvh,  g_kvh);
    cudaGetSymbolAddress((void**)&kvl,  g_kvl);
    cudaGetSymbolAddress((void**)&tDKVQh, g_tDKVQh);
    cudaGetSymbolAddress((void**)&tDKVQl, g_tDKVQl);
    cudaGetSymbolAddress((void**)&tUKVh,  g_tUKVh);
    cudaGetSymbolAddress((void**)&tUKVl,  g_tUKVl);
    cudaGetSymbolAddress((void**)&tUQh,   g_tUQh);
    cudaGetSymbolAddress((void**)&tUQl,   g_tUQl);
    cudaGetSymbolAddress((void**)&tQRh,   g_tQRh);
    cudaGetSymbolAddress((void**)&tQRl,   g_tQRl);
    cudaGetSymbolAddress((void**)&tOUTh,  g_tOUTh);
    cudaGetSymbolAddress((void**)&tOUTl,  g_tOUTl);

    cudaFuncSetAttribute(hgemm_t<false>, cudaFuncAttributeMaxDynamicSharedMemorySize, HGEMM_SMEM);
    cudaFuncSetAttribute(hgemm_t<true>,  cudaFuncAttributeMaxDynamicSharedMemorySize, HGEMM_SMEM);
    cudaFuncSetAttribute(flash_h, cudaFuncAttributeMaxDynamicSharedMemorySize, FLASH_SMEM);

    dim3 tb(32, 8);
    // fused transposed weight planes
    transpose32h<<<dim3(DCc/32,  Dd/32),  tb>>>(W_DKV, tDKVQh,               tDKVQl,               Dd,  DCc);
    transpose32h<<<dim3(DCc/32,  Dd/32),  tb>>>(W_DQ,  tDKVQh + 1024 * Dd,   tDKVQl + 1024 * Dd,   Dd,  DCc);
    transpose32h<<<dim3((NHh*DHh)/32, DCc/32), tb>>>(W_UK, tUKVh,                tUKVl,                DCc, NHh*DHh);
    transpose32h<<<dim3((NHh*DHh)/32, DCc/32), tb>>>(W_UV, tUKVh + 2048 * DCc,   tUKVl + 2048 * DCc,   DCc, NHh*DHh);
    transpose32h<<<dim3((2*NHh*DHh)/32, DCc/32), tb>>>(W_UQ, tUQh, tUQl, DCc, 2*NHh*DHh);
    transpose32h<<<dim3((2*NHh*DHRr)/32, DCc/32), tb>>>(W_QR, tQRh, tQRl, DCc, 2*NHh*DHRr);
    transpose32h<<<dim3(Dd/32,   Dd/32),  tb>>>(W_out, tOUTh, tOUTl, Dd,  Dd);
    split_kernel<<<(BL * Dd) / 256, 256>>>(x, xh, xl);

    // fused down-projections: tmp[row][ ckv_pre 1024 | cq_pre 1024 ]
    hgemm_t<false><<<dim3(2048/128, BL/128), 256, HGEMM_SMEM>>>(2048, Dd, xh, xl, tDKVQh, tDKVQl, tmp, nullptr, nullptr);
    rms_h<<<BL, 256>>>(tmp,        2048, kv_w, ckvh, ckvl, DCc);
    rms_h<<<BL, 256>>>(tmp + 1024, 2048, q_w,  cqh,  cql,  DCc);

    // fused up-projection KV: kv[row][ kc 2048 | v 2048 ] -> split planes directly
    hgemm_t<true><<<dim3(4096/128, BL/128), 256, HGEMM_SMEM>>>(4096, DCc, ckvh, ckvl, tUKVh, tUKVl, nullptr, kvh, kvl);
    // Q up-projection -> split planes directly
    hgemm_t<true><<<dim3(4096/128, BL/128), 256, HGEMM_SMEM>>>(4096, DCc, cqh, cql, tUQh, tUQl, nullptr, qchp, qclp);
    // q_r projection (fp32, rope follows)
    hgemm_t<false><<<dim3(2048/128, BL/128), 256, HGEMM_SMEM>>>(2048, DCc, cqh, cql, tQRh, tQRl, qr, nullptr, nullptr);

    // k_r (N=64) + RoPE (emit split planes)
    gemm_n64<<<BL / 4, dim3(64, 4)>>>(x, W_KR, kr, Dd);
    rope_h<<<(BL * 32 * 32) / 256, 256>>>(qr, qrhp, qrlp, 32, 2 * NHh * DHRr);
    rope_h<<<(BL * 1 * 32) / 256, 256>>>(kr, krhp, krlp, 1, DHRr);

    // lambda gate
    lam_kernel<<<BL, 128>>>(x, W_lw, W_lb, lam);

    // attention (fp16 tensor-core flash, longest-first)
    flash_h<<<dim3(Lseq / 64, 32, BB), 128, FLASH_SMEM>>>(
        qchp, qclp, qrhp, qrlp, kvh, kvl, krhp, krlp, attn);

    // combine + output projection
    combine_h<<<(BL * Dd) / 256, 256>>>(attn, lam, preh, prel);
    hgemm_t<false><<<dim3(Dd/128, BL/128), 256, HGEMM_SMEM>>>(Dd, Dd, preh, prel, tOUTh, tOUTl, out, nullptr, nullptr);
}

// round 9
// speedup vs baseline: 2.2585x; 1.0412x over previous
#include <cuda_runtime.h>
#include <cuda.h>
#include <cuda_fp16.h>
#include <math.h>
#include <stdint.h>

#define BB   2
#define Lseq 2048
#define BL   4096      // B*L
#define Dd   2048
#define DCc  1024
#define NHh  16
#define DHh  128
#define DHRr 64
#define ATTN_SCALE 0.07216878364870322f

// ======================= scratch =======================
__device__ float g_tmp [BL * 2048];          // fused [ckv_pre | cq_pre]
__device__ float g_qr  [BL * (2 * NHh * DHRr)];
__device__ float g_kr  [BL * DHRr];
__device__ float g_lam [BL * NHh];
__device__ float g_attn[(size_t)2 * BB * NHh * Lseq * DHh];

// fp16 split planes (activations)
__device__ __half g_xh  [BL * Dd],   g_xl  [BL * Dd];
__device__ __half g_ckvh[BL * DCc],  g_ckvl[BL * DCc];
__device__ __half g_cqh [BL * DCc],  g_cql [BL * DCc];
__device__ __half g_preh[BL * Dd],   g_prel[BL * Dd];
__device__ __half g_qch [BL * 4096], g_qcl [BL * 4096];
__device__ __half g_qrh [BL * 2048], g_qrl [BL * 2048];
__device__ __half g_krh [BL * DHRr], g_krl [BL * DHRr];
__device__ __half g_kvh [BL * 4096], g_kvl [BL * 4096];   // [kc 2048 | v 2048]
// fp16 split planes (transposed weights, [N][K]); fused where A is shared
__device__ __half g_tDKVQh[2048 * Dd],  g_tDKVQl[2048 * Dd];   // rows: [DKV 1024 | DQ 1024]
__device__ __half g_tUKVh [4096 * DCc], g_tUKVl [4096 * DCc];  // rows: [UK 2048 | UV 2048]
__device__ __half g_tUQh  [4096 * DCc], g_tUQl  [4096 * DCc];
__device__ __half g_tQRh  [2048 * DCc], g_tQRl  [2048 * DCc];
__device__ __half g_tOUTh [Dd * Dd],    g_tOUTl [Dd * Dd];

// ======================= helpers =======================
__device__ __forceinline__ uint32_t smem_u32(const void* p) {
    uint32_t a;
    asm("{ .reg .u64 t; cvta.to.shared.u64 t, %1; cvt.u32.u64 %0, t; }" : "=r"(a) : "l"(p));
    return a;
}
__device__ __forceinline__ void cp16(uint32_t dst, const void* src) {
    asm volatile("cp.async.cg.shared.global [%0], [%1], 16;" :: "r"(dst), "l"(src));
}
#define CP_COMMIT() asm volatile("cp.async.commit_group;" ::: "memory")
#define CP_WAIT0()  asm volatile("cp.async.wait_group 0;"  ::: "memory")

__device__ __forceinline__ void mma_f16(float c[4],
                                        uint32_t a0, uint32_t a1, uint32_t a2, uint32_t a3,
                                        uint32_t b0, uint32_t b1)
{
    asm volatile(
        "mma.sync.aligned.m16n8k16.row.col.f32.f16.f16.f32 "
        "{%0,%1,%2,%3}, {%4,%5,%6,%7}, {%8,%9}, {%0,%1,%2,%3};"
        : "+f"(c[0]), "+f"(c[1]), "+f"(c[2]), "+f"(c[3])
        : "r"(a0), "r"(a1), "r"(a2), "r"(a3), "r"(b0), "r"(b1));
}

__device__ __forceinline__ void split16(float v, __half& h, __half& l) {
    h = __float2half_rn(v);
    l = __float2half_rn(v - __half2float(h));
}

// ======================= transpose + split: in[R][C] -> hi/lo[C][R] =======================
__global__ void transpose32h(const float* __restrict__ in,
                             __half* __restrict__ oh, __half* __restrict__ ol, int R, int C)
{
    __shared__ float t[32][33];
    int bx = blockIdx.x * 32, by = blockIdx.y * 32;
    int x = bx + threadIdx.x;
    #pragma unroll
    for (int j = 0; j < 32; j += 8)
        t[threadIdx.y + j][threadIdx.x] = in[(size_t)(by + threadIdx.y + j) * C + x];
    __syncthreads();
    int ox = by + threadIdx.x;
    #pragma unroll
    for (int j = 0; j < 32; j += 8) {
        float v = t[threadIdx.x][threadIdx.y + j];
        __half h, l; split16(v, h, l);
        size_t o = (size_t)(bx + threadIdx.y + j) * R + ox;
        oh[o] = h; ol[o] = l;
    }
}

// ======================= elementwise split =======================
__global__ void split_kernel(const float* __restrict__ in,
                             __half* __restrict__ oh, __half* __restrict__ ol)
{
    int idx = blockIdx.x * 256 + threadIdx.x;
    float v = in[idx];
    __half h, l; split16(v, h, l);
    oh[idx] = h; ol[idx] = l;
}

// ======================= fp16-split tensor-core GEMM =======================
// 512 threads / 16 warps (4M x 4N), warp tile 32x32, term-major MMA issue.
#define WSTR 20
#define HGEMM_SMEM (2 * 4 * 128 * WSTR * 4)   // 81920 B

template<bool HALF_OUT>
__global__ __launch_bounds__(512)
void hgemm_t(int N, int K,
             const __half* __restrict__ Ahi, const __half* __restrict__ Alo,
             const __half* __restrict__ Bhi, const __half* __restrict__ Blo,
             float* __restrict__ C, __half* __restrict__ Ch, __half* __restrict__ Cl)
{
    extern __shared__ float smraw[];
    uint32_t* smw = (uint32_t*)smraw;
    uint32_t* buf[2] = { smw, smw + 4 * 128 * WSTR };

    const int tid = threadIdx.x;
    const int wid = tid >> 5, lane = tid & 31;
    const int m0 = blockIdx.y * 128, n0 = blockIdx.x * 128;
    const int warpM = (wid >> 2) * 32;   // 4 M groups of 32
    const int warpN = (wid & 3) * 32;    // 4 N groups of 32
    const int lr = lane >> 2, lc = lane & 3;

    const __half* Ap[2] = { Ahi + (size_t)m0 * K, Alo + (size_t)m0 * K };
    const __half* Bp[2] = { Bhi + (size_t)n0 * K, Blo + (size_t)n0 * K };

    const int r = tid >> 2;        // 0..127
    const int q = (tid & 3) * 4;   // word quarter within 16-word row

    auto stage = [&](int kc, int b) {
        uint32_t base = smem_u32(buf[b]);
        #pragma unroll
        for (int p = 0; p < 2; p++) {
            cp16(base + (uint32_t)((p * 128 + r) * WSTR + q) * 4u,
                 Ap[p] + (size_t)r * K + kc + q * 2);
            cp16(base + (uint32_t)(((2 + p) * 128 + r) * WSTR + q) * 4u,
                 Bp[p] + (size_t)r * K + kc + q * 2);
        }
        CP_COMMIT();
    };

    float acc[2][4][4];
    #pragma unroll
    for (int i = 0; i < 2; i++)
        #pragma unroll
        for (int j = 0; j < 4; j++)
            #pragma unroll
            for (int k = 0; k < 4; k++) acc[i][j][k] = 0.f;

    stage(0, 0);

    const int nch = K >> 5;
    for (int i = 0; i < nch; i++) {
        CP_WAIT0();
        __syncthreads();
        if (i + 1 < nch) stage((i + 1) << 5, (i + 1) & 1);

        const uint32_t* Ah = buf[i & 1];
        const uint32_t* Al = Ah + 128 * WSTR;
        const uint32_t* Bh = Ah + 2 * 128 * WSTR;
        const uint32_t* Bl = Ah + 3 * 128 * WSTR;

        #pragma unroll
        for (int s = 0; s < 2; s++) {
            uint32_t ah[2][4], al[2][4], bhf[4][2], blf[4][2];
            #pragma unroll
            for (int ma = 0; ma < 2; ma++) {
                int rw = (warpM + ma * 16 + lr) * WSTR + s * 8 + lc;
                ah[ma][0] = Ah[rw];
                ah[ma][1] = Ah[rw + 8 * WSTR];
                ah[ma][2] = Ah[rw + 4];
                ah[ma][3] = Ah[rw + 8 * WSTR + 4];
                al[ma][0] = Al[rw];
                al[ma][1] = Al[rw + 8 * WSTR];
                al[ma][2] = Al[rw + 4];
                al[ma][3] = Al[rw + 8 * WSTR + 4];
            }
            #pragma unroll
            for (int nb = 0; nb < 4; nb++) {
                int cw = (warpN + nb * 8 + lr) * WSTR + s * 8 + lc;
                bhf[nb][0] = Bh[cw]; bhf[nb][1] = Bh[cw + 4];
                blf[nb][0] = Bl[cw]; blf[nb][1] = Bl[cw + 4];
            }
            // term-major: same-acc reissue distance = 8 MMAs
            #pragma unroll
            for (int nb = 0; nb < 4; nb++)
                #pragma unroll
                for (int ma = 0; ma < 2; ma++)
                    mma_f16(acc[ma][nb], al[ma][0], al[ma][1], al[ma][2], al[ma][3],
                            bhf[nb][0], bhf[nb][1]);
            #pragma unroll
            for (int nb = 0; nb < 4; nb++)
                #pragma unroll
                for (int ma = 0; ma < 2; ma++)
                    mma_f16(acc[ma][nb], ah[ma][0], ah[ma][1], ah[ma][2], ah[ma][3],
                            blf[nb][0], blf[nb][1]);
            #pragma unroll
            for (int nb = 0; nb < 4; nb++)
                #pragma unroll
                for (int ma = 0; ma < 2; ma++)
                    mma_f16(acc[ma][nb], ah[ma][0], ah[ma][1], ah[ma][2], ah[ma][3],
                            bhf[nb][0], bhf[nb][1]);
        }
        __syncthreads();
    }

    #pragma unroll
    for (int ma = 0; ma < 2; ma++) {
        int row = m0 + warpM + ma * 16 + lr;
        #pragma unroll
        for (int nb = 0; nb < 4; nb++) {
            int col = n0 + warpN + nb * 8 + lc * 2;
            if (HALF_OUT) {
                float x0 = acc[ma][nb][0], x1 = acc[ma][nb][1];
                __half2 h2 = __floats2half2_rn(x0, x1);
                float2 hf = __half22float2(h2);
                __half2 l2 = __floats2half2_rn(x0 - hf.x, x1 - hf.y);
                *(__half2*)(Ch + (size_t)row * N + col) = h2;
                *(__half2*)(Cl + (size_t)row * N + col) = l2;
                float y0 = acc[ma][nb][2], y1 = acc[ma][nb][3];
                __half2 h3 = __floats2half2_rn(y0, y1);
                float2 hg = __half22float2(h3);
                __half2 l3 = __floats2half2_rn(y0 - hg.x, y1 - hg.y);
                *(__half2*)(Ch + (size_t)(row + 8) * N + col) = h3;
                *(__half2*)(Cl + (size_t)(row + 8) * N + col) = l3;
            } else {
                float2 o0 = make_float2(acc[ma][nb][0], acc[ma][nb][1]);
                float2 o1 = make_float2(acc[ma][nb][2], acc[ma][nb][3]);
                *(float2*)(C + (size_t)row * N + col)       = o0;
                *(float2*)(C + (size_t)(row + 8) * N + col) = o1;
            }
        }
    }
}

// ======================= RMS norm (strided input) -> fp16 split planes =======================
__global__ void rms_h(const float* __restrict__ in, int instride,
                      const float* __restrict__ w,
                      __half* __restrict__ oh, __half* __restrict__ ol, int N)
{
    int row = blockIdx.x;
    const float* ir = in + (size_t)row * instride;
    float s = 0.f;
    for (int i = threadIdx.x; i < N; i += 256) { float v = ir[i]; s += v * v; }
    __shared__ float red[256];
    red[threadIdx.x] = s;
    __syncthreads();
    for (int st = 128; st > 0; st >>= 1) {
        if (threadIdx.x < st) red[threadIdx.x] += red[threadIdx.x + st];
        __syncthreads();
    }
    float rr = rsqrtf(red[0] / (float)N + 1e-6f);
    for (int i = threadIdx.x; i < N; i += 256) {
        float v = ir[i] * rr * w[i];
        __half h, l; split16(v, h, l);
        oh[(size_t)row * N + i] = h;
        ol[(size_t)row * N + i] = l;
    }
}

// ======================= RoPE -> fp16 split planes =======================
__global__ void rope_h(const float* __restrict__ t,
                       __half* __restrict__ oh, __half* __restrict__ ol,
                       int heads, int rowstride)
{
    int idx = blockIdx.x * blockDim.x + threadIdx.x;
    int j = idx & 31;
    int h = (idx >> 5) % heads;
    int row = idx / (32 * heads);
    if (row >= BL) return;
    int l = row & (Lseq - 1);
    float inv = powf(10000.f, -(float)(2 * j) / 64.f);
    float ang = (float)l * inv;
    float c = cosf(ang), s = sinf(ang);
    const float* base = t + (size_t)row * rowstride + h * 64;
    float x1 = base[j], x2 = base[j + 32];
    float y1 = x1 * c - x2 * s;
    float y2 = x2 * c + x1 * s;
    size_t o = (size_t)row * rowstride + h * 64;
    __half hh, ll;
    split16(y1, hh, ll); oh[o + j] = hh;      ol[o + j] = ll;
    split16(y2, hh, ll); oh[o + j + 32] = hh; ol[o + j + 32] = ll;
}

// ======================= lambda gate =======================
__global__ void lam_kernel(const float* __restrict__ x, const float* __restrict__ Wl,
                           const float* __restrict__ bl, float* __restrict__ lam)
{
    int row = blockIdx.x;
    int tid = threadIdx.x;
    const float* xr = x + (size_t)row * Dd;
    float acc[16];
    #pragma unroll
    for (int n = 0; n < 16; n++) acc[n] = 0.f;
    for (int k = tid; k < Dd; k += 128) {
        float xv = xr[k];
        const float* wv = Wl + (size_t)k * 16;
        #pragma unroll
        for (int n = 0; n < 16; n++) acc[n] += xv * wv[n];
    }
    __shared__ float red[16 * 128];
    #pragma unroll
    for (int n = 0; n < 16; n++) red[n * 128 + tid] = acc[n];
    __syncthreads();
    for (int st = 64; st > 0; st >>= 1) {
        if (tid < st) {
            #pragma unroll
            for (int n = 0; n < 16; n++) red[n * 128 + tid] += red[n * 128 + tid + st];
        }
        __syncthreads();
    }
    if (tid < 16) {
        float z = red[tid * 128] + bl[tid];
        lam[(size_t)row * 16 + tid] = 1.f / (1.f + expf(-z));
    }
}

// ======================= small GEMM N=64 (x @ W_KR) =======================
__global__ void gemm_n64(const float* __restrict__ A, const float* __restrict__ B,
                         float* __restrict__ C, int K)
{
    int n = threadIdx.x;
    int m = blockIdx.x * 4 + threadIdx.y;
    float acc = 0.f;
    const float* ar = A + (size_t)m * K;
    #pragma unroll 8
    for (int k = 0; k < K; k++) acc += ar[k] * B[(size_t)k * 64 + n];
    C[(size_t)m * 64 + n] = acc;
}

// ======================= tensor-core flash attention (3xFP16, pre-split planes) =====
#define FLASH_SMEM (26112 * 4)
__global__ __launch_bounds__(128)
void flash_h(const __half* __restrict__ qch, const __half* __restrict__ qcl,
             const __half* __restrict__ qrh, const __half* __restrict__ qrl,
             const __half* __restrict__ kvh, const __half* __restrict__ kvl,
             const __half* __restrict__ krh, const __half* __restrict__ krl,
             float* __restrict__ attn)
{
    extern __shared__ uint32_t smw[];
    uint32_t* qs[2] = { smw,         smw + 6400 };
    uint32_t* ks[2] = { smw + 12800, smw + 16000 };
    uint32_t* vs[2] = { smw + 19200, smw + 21376 };
    uint32_t* ps[2] = { smw + 23552, smw + 24832 };

    const int Q0 = (gridDim.x - 1 - blockIdx.x) * 64;   // longest work first
    const int head2 = blockIdx.y;
    const int b = blockIdx.z;
    const int hn = head2 >> 1, hp = head2 & 1;
    const int tid = threadIdx.x;
    const int lane = tid & 31, w = tid >> 5;
    const int lr = lane >> 2, lc = lane & 3;

    const size_t tq = (size_t)(b * Lseq + Q0);

    {
        const __half* qcp[2] = { qch + tq * 4096 + head2 * 128, qcl + tq * 4096 + head2 * 128 };
        const __half* qrp[2] = { qrh + tq * 2048 + head2 * 64,  qrl + tq * 2048 + head2 * 64 };
        #pragma unroll
        for (int p = 0; p < 2; p++) {
            uint32_t qb = smem_u32(qs[p]);
            #pragma unroll
            for (int i = 0; i < 8; i++) {
                int s2 = tid + i * 128;
                int r = s2 >> 4, c = s2 & 15;
                cp16(qb + (uint32_t)(r * 100 + c * 4) * 4u, qcp[p] + (size_t)r * 4096 + c * 8);
            }
            #pragma unroll
            for (int i = 0; i < 4; i++) {
                int s2 = tid + i * 128;
                int r = s2 >> 3, c = s2 & 7;
                cp16(qb + (uint32_t)(r * 100 + 64 + c * 4) * 4u, qrp[p] + (size_t)r * 2048 + c * 8);
            }
        }
        CP_COMMIT();
    }

    float o[16][4];
    #pragma unroll
    for (int i = 0; i < 16; i++) { o[i][0] = o[i][1] = o[i][2] = o[i][3] = 0.f; }
    float m0 = -INFINITY, m1 = -INFINITY, l0 = 0.f, l1 = 0.f;

    const int row0g = Q0 + 16 * w + lr;
    const int row1g = row0g + 8;
    const int prow0 = (16 * w + lr) * 20;
    const int arow0 = (16 * w + lr) * 100;

    const int ntile = (Q0 + 64) >> 5;
    for (int t = 0; t < ntile; t++) {
        const int k0 = t << 5;
        __syncthreads();
        {
            const size_t tk = (size_t)(b * Lseq + k0);
            const __half* kcp[2] = { kvh + tk * 4096 + hn * 128,        kvl + tk * 4096 + hn * 128 };
            const __half* vp[2]  = { kvh + tk * 4096 + 2048 + hn * 128, kvl + tk * 4096 + 2048 + hn * 128 };
            const __half* krp[2] = { krh + tk * 64,                     krl + tk * 64 };
            #pragma unroll
            for (int p = 0; p < 2; p++) {
                uint32_t kb = smem_u32(ks[p]);
                uint32_t vb = smem_u32(vs[p]);
                #pragma unroll
                for (int i = 0; i < 4; i++) {
                    int s2 = tid + i * 128;
                    int r = s2 >> 4, c = s2 & 15;
                    cp16(kb + (uint32_t)(r * 100 + c * 4) * 4u, kcp[p] + (size_t)r * 4096 + c * 8);
                    cp16(vb + (uint32_t)(r * 68 + c * 4) * 4u,  vp[p]  + (size_t)r * 4096 + c * 8);
                }
                #pragma unroll
                for (int i = 0; i < 2; i++) {
                    int s2 = tid + i * 128;
                    int r = s2 >> 3, c = s2 & 7;
                    cp16(kb + (uint32_t)(r * 100 + 64 + c * 4) * 4u, krp[p] + (size_t)r * 64 + c * 8);
                }
            }
            CP_COMMIT();
            CP_WAIT0();
            __syncthreads();
        }

        float s4[4][4];
        #pragma unroll
        for (int nt = 0; nt < 4; nt++) { s4[nt][0] = s4[nt][1] = s4[nt][2] = s4[nt][3] = 0.f; }

        #pragma unroll 4
        for (int s = 0; s < 12; s++) {
            const int ab = arow0 + s * 8 + lc;
            uint32_t ah0 = qs[0][ab],       ah1 = qs[0][ab + 800];
            uint32_t ah2 = qs[0][ab + 4],   ah3 = qs[0][ab + 804];
            uint32_t al0 = qs[1][ab],       al1 = qs[1][ab + 800];
            uint32_t al2 = qs[1][ab + 4],   al3 = qs[1][ab + 804];
            #pragma unroll
            for (int nt = 0; nt < 4; nt++) {
                const int cb = (nt * 8 + lr) * 100 + s * 8 + lc;
                uint32_t bh0 = ks[0][cb], bh1 = ks[0][cb + 4];
                uint32_t bl0 = ks[1][cb], bl1 = ks[1][cb + 4];
                mma_f16(s4[nt], al0, al1, al2, al3, bh0, bh1);
                mma_f16(s4[nt], ah0, ah1, ah2, ah3, bl0, bl1);
                mma_f16(s4[nt], ah0, ah1, ah2, ah3, bh0, bh1);
            }
        }

        float tmax0 = -INFINITY, tmax1 = -INFINITY;
        #pragma unroll
        for (int nt = 0; nt < 4; nt++) {
            const int colg = k0 + nt * 8 + 2 * lc;
            s4[nt][0] = (colg     <= row0g) ? s4[nt][0] * ATTN_SCALE : -INFINITY;
            s4[nt][1] = (colg + 1 <= row0g) ? s4[nt][1] * ATTN_SCALE : -INFINITY;
            s4[nt][2] = (colg     <= row1g) ? s4[nt][2] * ATTN_SCALE : -INFINITY;
            s4[nt][3] = (colg + 1 <= row1g) ? s4[nt][3] * ATTN_SCALE : -INFINITY;
            tmax0 = fmaxf(tmax0, fmaxf(s4[nt][0], s4[nt][1]));
            tmax1 = fmaxf(tmax1, fmaxf(s4[nt][2], s4[nt][3]));
        }
        tmax0 = fmaxf(tmax0, __shfl_xor_sync(0xffffffffu, tmax0, 1));
        tmax0 = fmaxf(tmax0, __shfl_xor_sync(0xffffffffu, tmax0, 2));
        tmax1 = fmaxf(tmax1, __shfl_xor_sync(0xffffffffu, tmax1, 1));
        tmax1 = fmaxf(tmax1, __shfl_xor_sync(0xffffffffu, tmax1, 2));

        const float mn0 = fmaxf(m0, tmax0), mn1 = fmaxf(m1, tmax1);
        const float scl0 = expf(m0 - mn0);
        const float scl1 = expf(m1 - mn1);

        float p4[4][4];
        float pr0 = 0.f, pr1 = 0.f;
        #pragma unroll
        for (int nt = 0; nt < 4; nt++) {
            p4[nt][0] = expf(s4[nt][0] - mn0);
            p4[nt][1] = expf(s4[nt][1] - mn0);
            p4[nt][2] = expf(s4[nt][2] - mn1);
            p4[nt][3] = expf(s4[nt][3] - mn1);
            pr0 += p4[nt][0] + p4[nt][1];
            pr1 += p4[nt][2] + p4[nt][3];
        }
        pr0 += __shfl_xor_sync(0xffffffffu, pr0, 1);
        pr0 += __shfl_xor_sync(0xffffffffu, pr0, 2);
        pr1 += __shfl_xor_sync(0xffffffffu, pr1, 1);
        pr1 += __shfl_xor_sync(0xffffffffu, pr1, 2);

        l0 = l0 * scl0 + pr0;
        l1 = l1 * scl1 + pr1;
        m0 = mn0; m1 = mn1;

        #pragma unroll
        for (int i = 0; i < 16; i++) {
            o[i][0] *= scl0; o[i][1] *= scl0;
            o[i][2] *= scl1; o[i][3] *= scl1;
        }

        #pragma unroll
        for (int nt = 0; nt < 4; nt++) {
            __half2 h0 = __floats2half2_rn(p4[nt][0], p4[nt][1]);
            float2 f0 = __half22float2(h0);
            __half2 e0 = __floats2half2_rn(p4[nt][0] - f0.x, p4[nt][1] - f0.y);
            ((__half2*)ps[0])[prow0 + nt * 4 + lc] = h0;
            ((__half2*)ps[1])[prow0 + nt * 4 + lc] = e0;
            __half2 h1 = __floats2half2_rn(p4[nt][2], p4[nt][3]);
            float2 f1 = __half22float2(h1);
            __half2 e1 = __floats2half2_rn(p4[nt][2] - f1.x, p4[nt][3] - f1.y);
            ((__half2*)ps[0])[prow0 + 160 + nt * 4 + lc] = h1;
            ((__half2*)ps[1])[prow0 + 160 + nt * 4 + lc] = e1;
        }
        __syncwarp();

        const uint16_t* vhp = (const uint16_t*)vs[0];
        const uint16_t* vlp = (const uint16_t*)vs[1];
        #pragma unroll
        for (int s = 0; s < 2; s++) {
            const int pb = prow0 + s * 8 + lc;
            uint32_t ah0 = ps[0][pb],     ah1 = ps[0][pb + 160];
            uint32_t ah2 = ps[0][pb + 4], ah3 = ps[0][pb + 164];
            uint32_t al0 = ps[1][pb],     al1 = ps[1][pb + 160];
            uint32_t al2 = ps[1][pb + 4], al3 = ps[1][pb + 164];
            const int kb = s * 16 + 2 * lc;
            #pragma unroll
            for (int nt2 = 0; nt2 < 16; nt2++) {
                const int d = nt2 * 8 + lr;
                uint32_t bh0 = (uint32_t)vhp[kb * 136 + d]       | ((uint32_t)vhp[(kb + 1) * 136 + d] << 16);
                uint32_t bh1 = (uint32_t)vhp[(kb + 8) * 136 + d] | ((uint32_t)vhp[(kb + 9) * 136 + d] << 16);
                uint32_t bl0 = (uint32_t)vlp[kb * 136 + d]       | ((uint32_t)vlp[(kb + 1) * 136 + d] << 16);
                uint32_t bl1 = (uint32_t)vlp[(kb + 8) * 136 + d] | ((uint32_t)vlp[(kb + 9) * 136 + d] << 16);
                mma_f16(o[nt2], al0, al1, al2, al3, bh0, bh1);
                mma_f16(o[nt2], ah0, ah1, ah2, ah3, bl0, bl1);
                mma_f16(o[nt2], ah0, ah1, ah2, ah3, bh0, bh1);
            }
        }
    }

    const float inv0 = 1.f / l0, inv1 = 1.f / l1;
    const size_t obase = ((size_t)(b * 2 + hp) * NHh + hn) * Lseq;
    float* op0 = attn + (obase + row0g) * 128;
    float* op1 = attn + (obase + row1g) * 128;
    #pragma unroll
    for (int nt2 = 0; nt2 < 16; nt2++) {
        *(float2*)(op0 + nt2 * 8 + 2 * lc) = make_float2(o[nt2][0] * inv0, o[nt2][1] * inv0);
        *(float2*)(op1 + nt2 * 8 + 2 * lc) = make_float2(o[nt2][2] * inv1, o[nt2][3] * inv1);
    }
}

// ======================= combine -> fp16 split planes =======================
__global__ void combine_h(const float* __restrict__ attn, const float* __restrict__ lam,
                          __half* __restrict__ oh, __half* __restrict__ ol)
{
    int idx = blockIdx.x * 256 + threadIdx.x;
    int c = idx & 2047;
    int row = idx >> 11;
    int b = row >> 11;
    int l = row & 2047;
    int n = c >> 7, d = c & 127;
    size_t a1 = (((size_t)(b * 2 + 0) * NHh + n) * Lseq + l) * 128 + d;
    size_t a2 = (((size_t)(b * 2 + 1) * NHh + n) * Lseq + l) * 128 + d;
    float v = attn[a1] - lam[(size_t)row * 16 + n] * attn[a2];
    __half h, lo; split16(v, h, lo);
    oh[idx] = h; ol[idx] = lo;
}

// ======================= launch =======================
extern "C" void kernel_launch(void* const* d_in, const int* in_sizes, int n_in,
                              void* d_out, int out_size)
{
    const float* x     = (const float*)d_in[0];
    const float* W_DKV = (const float*)d_in[1];
    const float* kv_w  = (const float*)d_in[2];
    const float* W_UK  = (const float*)d_in[3];
    const float* W_UV  = (const float*)d_in[4];
    const float* W_DQ  = (const float*)d_in[5];
    const float* q_w   = (const float*)d_in[6];
    const float* W_UQ  = (const float*)d_in[7];
    const float* W_QR  = (const float*)d_in[8];
    const float* W_KR  = (const float*)d_in[9];
    const float* W_lw  = (const float*)d_in[10];
    const float* W_lb  = (const float*)d_in[11];
    const float* W_out = (const float*)d_in[12];
    float* out = (float*)d_out;

    float *tmp, *qr, *kr, *lam, *attn;
    __half *xh, *xl, *ckvh, *ckvl, *cqh, *cql, *preh, *prel;
    __half *qchp, *qclp, *qrhp, *qrlp, *krhp, *krlp, *kvh, *kvl;
    __half *tDKVQh, *tDKVQl, *tUKVh, *tUKVl, *tUQh, *tUQl, *tQRh, *tQRl, *tOUTh, *tOUTl;
    cudaGetSymbolAddress((void**)&tmp,  g_tmp);
    cudaGetSymbolAddress((void**)&qr,   g_qr);
    cudaGetSymbolAddress((void**)&kr,   g_kr);
    cudaGetSymbolAddress((void**)&lam,  g_lam);
    cudaGetSymbolAddress((void**)&attn, g_attn);
    cudaGetSymbolAddress((void**)&xh,   g_xh);
    cudaGetSymbolAddress((void**)&xl,   g_xl);
    cudaGetSymbolAddress((void**)&ckvh, g_ckvh);
    cudaGetSymbolAddress((void**)&ckvl, g_ckvl);
    cudaGetSymbolAddress((void**)&cqh,  g_cqh);
    cudaGetSymbolAddress((void**)&cql,  g_cql);
    cudaGetSymbolAddress((void**)&preh, g_preh);
    cudaGetSymbolAddress((void**)&prel, g_prel);
    cudaGetSymbolAddress((void**)&qchp, g_qch);
    cudaGetSymbolAddress((void**)&qclp, g_qcl);
    cudaGetSymbolAddress((void**)&qrhp, g_qrh);
    cudaGetSymbolAddress((void**)&qrlp, g_qrl);
    cudaGetSymbolAddress((void**)&krhp, g_krh);
    cudaGetSymbolAddress((void**)&krlp, g_krl);
    cudaGetSymbolAddress((void**)&kvh,  g_kvh);
    cudaGetSymbolAddress((void**)&kvl,  g_kvl);
    cudaGetSymbolAddress((void**)&tDKVQh, g_tDKVQh);
    cudaGetSymbolAddress((void**)&tDKVQl, g_tDKVQl);
    cudaGetSymbolAddress((void**)&tUKVh,  g_tUKVh);
    cudaGetSymbolAddress((void**)&tUKVl,  g_tUKVl);
    cudaGetSymbolAddress((void**)&tUQh,   g_tUQh);
    cudaGetSymbolAddress((void**)&tUQl,   g_tUQl);
    cudaGetSymbolAddress((void**)&tQRh,   g_tQRh);
    cudaGetSymbolAddress((void**)&tQRl,   g_tQRl);
    cudaGetSymbolAddress((void**)&tOUTh,  g_tOUTh);
    cudaGetSymbolAddress((void**)&tOUTl,  g_tOUTl);

    cudaFuncSetAttribute(hgemm_t<false>, cudaFuncAttributeMaxDynamicSharedMemorySize, HGEMM_SMEM);
    cudaFuncSetAttribute(hgemm_t<true>,  cudaFuncAttributeMaxDynamicSharedMemorySize, HGEMM_SMEM);
    cudaFuncSetAttribute(flash_h, cudaFuncAttributeMaxDynamicSharedMemorySize, FLASH_SMEM);

    dim3 tb(32, 8);
    transpose32h<<<dim3(DCc/32,  Dd/32),  tb>>>(W_DKV, tDKVQh,             tDKVQl,             Dd,  DCc);
    transpose32h<<<dim3(DCc/32,  Dd/32),  tb>>>(W_DQ,  tDKVQh + 1024 * Dd, tDKVQl + 1024 * Dd, Dd,  DCc);
    transpose32h<<<dim3((NHh*DHh)/32, DCc/32), tb>>>(W_UK, tUKVh,              tUKVl,              DCc, NHh*DHh);
    transpose32h<<<dim3((NHh*DHh)/32, DCc/32), tb>>>(W_UV, tUKVh + 2048 * DCc, tUKVl + 2048 * DCc, DCc, NHh*DHh);
    transpose32h<<<dim3((2*NHh*DHh)/32, DCc/32), tb>>>(W_UQ, tUQh, tUQl, DCc, 2*NHh*DHh);
    transpose32h<<<dim3((2*NHh*DHRr)/32, DCc/32), tb>>>(W_QR, tQRh, tQRl, DCc, 2*NHh*DHRr);
    transpose32h<<<dim3(Dd/32,   Dd/32),  tb>>>(W_out, tOUTh, tOUTl, Dd,  Dd);
    split_kernel<<<(BL * Dd) / 256, 256>>>(x, xh, xl);

    // fused down-projections: tmp[row][ ckv_pre 1024 | cq_pre 1024 ]
    hgemm_t<false><<<dim3(2048/128, BL/128), 512, HGEMM_SMEM>>>(2048, Dd, xh, xl, tDKVQh, tDKVQl, tmp, nullptr, nullptr);
    rms_h<<<BL, 256>>>(tmp,        2048, kv_w, ckvh, ckvl, DCc);
    rms_h<<<BL, 256>>>(tmp + 1024, 2048, q_w,  cqh,  cql,  DCc);

    // fused up-projection KV: kv[row][ kc 2048 | v 2048 ] -> split planes directly
    hgemm_t<true><<<dim3(4096/128, BL/128), 512, HGEMM_SMEM>>>(4096, DCc, ckvh, ckvl, tUKVh, tUKVl, nullptr, kvh, kvl);
    // Q up-projection -> split planes directly
    hgemm_t<true><<<dim3(4096/128, BL/128), 512, HGEMM_SMEM>>>(4096, DCc, cqh, cql, tUQh, tUQl, nullptr, qchp, qclp);
    // q_r projection (fp32, rope follows)
    hgemm_t<false><<<dim3(2048/128, BL/128), 512, HGEMM_SMEM>>>(2048, DCc, cqh, cql, tQRh, tQRl, qr, nullptr, nullptr);

    // k_r (N=64) + RoPE (emit split planes)
    gemm_n64<<<BL / 4, dim3(64, 4)>>>(x, W_KR, kr, Dd);
    rope_h<<<(BL * 32 * 32) / 256, 256>>>(qr, qrhp, qrlp, 32, 2 * NHh * DHRr);
    rope_h<<<(BL * 1 * 32) / 256, 256>>>(kr, krhp, krlp, 1, DHRr);

    // lambda gate
    lam_kernel<<<BL, 128>>>(x, W_lw, W_lb, lam);

    // attention (fp16 tensor-core flash, longest-first)
    flash_h<<<dim3(Lseq / 64, 32, BB), 128, FLASH_SMEM>>>(
        qchp, qclp, qrhp, qrlp, kvh, kvl, krhp, krlp, attn);

    // combine + output projection
    combine_h<<<(BL * Dd) / 256, 256>>>(attn, lam, preh, prel);
    hgemm_t<false><<<dim3(Dd/128, BL/128), 512, HGEMM_SMEM>>>(Dd, Dd, preh, prel, tOUTh, tOUTl, out, nullptr, nullptr);
}

// round 10
// speedup vs baseline: 2.5910x; 1.1472x over previous
#include <cuda_runtime.h>
#include <cuda.h>
#include <cuda_fp16.h>
#include <math.h>
#include <stdint.h>

#define BB   2
#define Lseq 2048
#define BL   4096      // B*L
#define Dd   2048
#define DCc  1024
#define NHh  16
#define DHh  128
#define DHRr 64
#define ATTN_SCALE 0.07216878364870322f
#define NX   2176      // fused down-proj width: [ckv 1024 | cq 1024 | kr 64 | lam 16 | pad 48]

// ======================= scratch =======================
__device__ float g_tmp [BL * NX];
__device__ float g_lam [BL * NHh];
__device__ float g_attn[(size_t)2 * BB * NHh * Lseq * DHh];

// fp16 split planes (activations)
__device__ __half g_xh  [BL * Dd],   g_xl  [BL * Dd];
__device__ __half g_ckvh[BL * DCc],  g_ckvl[BL * DCc];
__device__ __half g_cqh [BL * DCc],  g_cql [BL * DCc];
__device__ __half g_preh[BL * Dd],   g_prel[BL * Dd];
__device__ __half g_qch [BL * 4096], g_qcl [BL * 4096];
__device__ __half g_qrh [BL * 2048], g_qrl [BL * 2048];
__device__ __half g_krh [BL * DHRr], g_krl [BL * DHRr];
__device__ __half g_kvh [BL * 4096], g_kvl [BL * 4096];   // [kc 2048 | v 2048]
// fp16 split planes (transposed weights, [N][K])
__device__ __half g_tXh  [NX * Dd],     g_tXl  [NX * Dd];     // [DKV|DQ|KR|lw|pad0]
__device__ __half g_tUKVh[4096 * DCc],  g_tUKVl[4096 * DCc];  // [UK 2048 | UV 2048]
__device__ __half g_tUQh [4096 * DCc],  g_tUQl [4096 * DCc];
__device__ __half g_tQRh [2048 * DCc],  g_tQRl [2048 * DCc];
__device__ __half g_tOUTh[Dd * Dd],     g_tOUTl[Dd * Dd];

// ======================= helpers =======================
__device__ __forceinline__ uint32_t smem_u32(const void* p) {
    uint32_t a;
    asm("{ .reg .u64 t; cvta.to.shared.u64 t, %1; cvt.u32.u64 %0, t; }" : "=r"(a) : "l"(p));
    return a;
}
__device__ __forceinline__ void cp16(uint32_t dst, const void* src) {
    asm volatile("cp.async.cg.shared.global [%0], [%1], 16;" :: "r"(dst), "l"(src));
}
#define CP_COMMIT() asm volatile("cp.async.commit_group;" ::: "memory")
#define CP_WAIT0()  asm volatile("cp.async.wait_group 0;"  ::: "memory")

__device__ __forceinline__ void mma_f16(float c[4],
                                        uint32_t a0, uint32_t a1, uint32_t a2, uint32_t a3,
                                        uint32_t b0, uint32_t b1)
{
    asm volatile(
        "mma.sync.aligned.m16n8k16.row.col.f32.f16.f16.f32 "
        "{%0,%1,%2,%3}, {%4,%5,%6,%7}, {%8,%9}, {%0,%1,%2,%3};"
        : "+f"(c[0]), "+f"(c[1]), "+f"(c[2]), "+f"(c[3])
        : "r"(a0), "r"(a1), "r"(a2), "r"(a3), "r"(b0), "r"(b1));
}

__device__ __forceinline__ void split16(float v, __half& h, __half& l) {
    h = __float2half_rn(v);
    l = __float2half_rn(v - __half2float(h));
}

// ======================= transpose + split: in[R][C] -> hi/lo[C][R] =======================
__global__ void transpose32h(const float* __restrict__ in,
                             __half* __restrict__ oh, __half* __restrict__ ol, int R, int C)
{
    __shared__ float t[32][33];
    int bx = blockIdx.x * 32, by = blockIdx.y * 32;
    int x = bx + threadIdx.x;
    #pragma unroll
    for (int j = 0; j < 32; j += 8)
        t[threadIdx.y + j][threadIdx.x] = in[(size_t)(by + threadIdx.y + j) * C + x];
    __syncthreads();
    int ox = by + threadIdx.x;
    #pragma unroll
    for (int j = 0; j < 32; j += 8) {
        float v = t[threadIdx.x][threadIdx.y + j];
        __half h, l; split16(v, h, l);
        size_t o = (size_t)(bx + threadIdx.y + j) * R + ox;
        oh[o] = h; ol[o] = l;
    }
}

// W_lw [2048][16] -> rows 2112..2127 of tX planes
__global__ void lwT_kernel(const float* __restrict__ Wl,
                           __half* __restrict__ oh, __half* __restrict__ ol)
{
    int idx = blockIdx.x * 256 + threadIdx.x;   // 2048*16
    int k = idx >> 4, n = idx & 15;
    float v = Wl[idx];
    __half h, l; split16(v, h, l);
    size_t o = (size_t)(2112 + n) * Dd + k;
    oh[o] = h; ol[o] = l;
}

// ======================= elementwise split =======================
__global__ void split_kernel(const float* __restrict__ in,
                             __half* __restrict__ oh, __half* __restrict__ ol)
{
    int idx = blockIdx.x * 256 + threadIdx.x;
    float v = in[idx];
    __half h, l; split16(v, h, l);
    oh[idx] = h; ol[idx] = l;
}

// ======================= fp16-split tensor-core GEMM (fp32 out) =======================
#define WSTR 20
#define HGEMM_SMEM (2 * 4 * 128 * WSTR * 4)   // 81920 B

__device__ __forceinline__ void hgemm_body(
    int N, int K, int m0, int n0,
    const __half* __restrict__ Ahi, const __half* __restrict__ Alo,
    const __half* __restrict__ Bhi, const __half* __restrict__ Blo,
    uint32_t* smw, float acc[2][4][4])
{
    uint32_t* buf[2] = { smw, smw + 4 * 128 * WSTR };
    const int tid = threadIdx.x;
    const int wid = tid >> 5, lane = tid & 31;
    const int warpM = (wid >> 2) * 32;
    const int warpN = (wid & 3) * 32;
    const int lr = lane >> 2, lc = lane & 3;

    const __half* Ap[2] = { Ahi + (size_t)m0 * K, Alo + (size_t)m0 * K };
    const __half* Bp[2] = { Bhi + (size_t)n0 * K, Blo + (size_t)n0 * K };

    const int r = tid >> 2;
    const int q = (tid & 3) * 4;

    auto stage = [&](int kc, int b) {
        uint32_t base = smem_u32(buf[b]);
        #pragma unroll
        for (int p = 0; p < 2; p++) {
            cp16(base + (uint32_t)((p * 128 + r) * WSTR + q) * 4u,
                 Ap[p] + (size_t)r * K + kc + q * 2);
            cp16(base + (uint32_t)(((2 + p) * 128 + r) * WSTR + q) * 4u,
                 Bp[p] + (size_t)r * K + kc + q * 2);
        }
        CP_COMMIT();
    };

    #pragma unroll
    for (int i = 0; i < 2; i++)
        #pragma unroll
        for (int j = 0; j < 4; j++)
            #pragma unroll
            for (int k = 0; k < 4; k++) acc[i][j][k] = 0.f;

    stage(0, 0);

    const int nch = K >> 5;
    for (int i = 0; i < nch; i++) {
        CP_WAIT0();
        __syncthreads();
        if (i + 1 < nch) stage((i + 1) << 5, (i + 1) & 1);

        const uint32_t* Ah = buf[i & 1];
        const uint32_t* Al = Ah + 128 * WSTR;
        const uint32_t* Bh = Ah + 2 * 128 * WSTR;
        const uint32_t* Bl = Ah + 3 * 128 * WSTR;

        #pragma unroll
        for (int s = 0; s < 2; s++) {
            uint32_t ah[2][4], al[2][4], bhf[4][2], blf[4][2];
            #pragma unroll
            for (int ma = 0; ma < 2; ma++) {
                int rw = (warpM + ma * 16 + lr) * WSTR + s * 8 + lc;
                ah[ma][0] = Ah[rw];
                ah[ma][1] = Ah[rw + 8 * WSTR];
                ah[ma][2] = Ah[rw + 4];
                ah[ma][3] = Ah[rw + 8 * WSTR + 4];
                al[ma][0] = Al[rw];
                al[ma][1] = Al[rw + 8 * WSTR];
                al[ma][2] = Al[rw + 4];
                al[ma][3] = Al[rw + 8 * WSTR + 4];
            }
            #pragma unroll
            for (int nb = 0; nb < 4; nb++) {
                int cw = (warpN + nb * 8 + lr) * WSTR + s * 8 + lc;
                bhf[nb][0] = Bh[cw]; bhf[nb][1] = Bh[cw + 4];
                blf[nb][0] = Bl[cw]; blf[nb][1] = Bl[cw + 4];
            }
            #pragma unroll
            for (int nb = 0; nb < 4; nb++)
                #pragma unroll
                for (int ma = 0; ma < 2; ma++)
                    mma_f16(acc[ma][nb], al[ma][0], al[ma][1], al[ma][2], al[ma][3],
                            bhf[nb][0], bhf[nb][1]);
            #pragma unroll
            for (int nb = 0; nb < 4; nb++)
                #pragma unroll
                for (int ma = 0; ma < 2; ma++)
                    mma_f16(acc[ma][nb], ah[ma][0], ah[ma][1], ah[ma][2], ah[ma][3],
                            blf[nb][0], blf[nb][1]);
            #pragma unroll
            for (int nb = 0; nb < 4; nb++)
                #pragma unroll
                for (int ma = 0; ma < 2; ma++)
                    mma_f16(acc[ma][nb], ah[ma][0], ah[ma][1], ah[ma][2], ah[ma][3],
                            bhf[nb][0], bhf[nb][1]);
        }
        __syncthreads();
    }
}

__global__ __launch_bounds__(512)
void hgemm_f(int N, int K,
             const __half* __restrict__ Ahi, const __half* __restrict__ Alo,
             const __half* __restrict__ Bhi, const __half* __restrict__ Blo,
             float* __restrict__ C)
{
    extern __shared__ float smraw[];
    float acc[2][4][4];
    const int m0 = blockIdx.y * 128, n0 = blockIdx.x * 128;
    hgemm_body(N, K, m0, n0, Ahi, Alo, Bhi, Blo, (uint32_t*)smraw, acc);

    const int wid = threadIdx.x >> 5, lane = threadIdx.x & 31;
    const int warpM = (wid >> 2) * 32, warpN = (wid & 3) * 32;
    const int lr = lane >> 2, lc = lane & 3;
    #pragma unroll
    for (int ma = 0; ma < 2; ma++) {
        int row = m0 + warpM + ma * 16 + lr;
        #pragma unroll
        for (int nb = 0; nb < 4; nb++) {
            int col = n0 + warpN + nb * 8 + lc * 2;
            *(float2*)(C + (size_t)row * N + col)       = make_float2(acc[ma][nb][0], acc[ma][nb][1]);
            *(float2*)(C + (size_t)(row + 8) * N + col) = make_float2(acc[ma][nb][2], acc[ma][nb][3]);
        }
    }
}

// merged K=1024 launch: seg0 (32 tiles) ckv@UKV->kv, seg1 (32) cq@UQ->qc, seg2 (16) cq@QR->qr
__global__ __launch_bounds__(512)
void hgemm_multi(const __half* __restrict__ ckvh, const __half* __restrict__ ckvl,
                 const __half* __restrict__ cqh,  const __half* __restrict__ cql,
                 const __half* __restrict__ tUKVh, const __half* __restrict__ tUKVl,
                 const __half* __restrict__ tUQh,  const __half* __restrict__ tUQl,
                 const __half* __restrict__ tQRh,  const __half* __restrict__ tQRl,
                 __half* __restrict__ kvh, __half* __restrict__ kvl,
                 __half* __restrict__ qch, __half* __restrict__ qcl,
                 __half* __restrict__ qrh, __half* __restrict__ qrl)
{
    extern __shared__ float smraw[];
    const int bx = blockIdx.x;
    const __half *Ahp, *Alp, *Bhp, *Blp;
    __half *Chp, *Clp;
    int N, nloc;
    if (bx < 32)      { Ahp = ckvh; Alp = ckvl; Bhp = tUKVh; Blp = tUKVl; Chp = kvh; Clp = kvl; N = 4096; nloc = bx; }
    else if (bx < 64) { Ahp = cqh;  Alp = cql;  Bhp = tUQh;  Blp = tUQl;  Chp = qch; Clp = qcl; N = 4096; nloc = bx - 32; }
    else              { Ahp = cqh;  Alp = cql;  Bhp = tQRh;  Blp = tQRl;  Chp = qrh; Clp = qrl; N = 2048; nloc = bx - 64; }

    float acc[2][4][4];
    const int m0 = blockIdx.y * 128, n0 = nloc * 128;
    hgemm_body(N, 1024, m0, n0, Ahp, Alp, Bhp, Blp, (uint32_t*)smraw, acc);

    const int wid = threadIdx.x >> 5, lane = threadIdx.x & 31;
    const int warpM = (wid >> 2) * 32, warpN = (wid & 3) * 32;
    const int lr = lane >> 2, lc = lane & 3;
    #pragma unroll
    for (int ma = 0; ma < 2; ma++) {
        int row = m0 + warpM + ma * 16 + lr;
        #pragma unroll
        for (int nb = 0; nb < 4; nb++) {
            int col = n0 + warpN + nb * 8 + lc * 2;
            float x0 = acc[ma][nb][0], x1 = acc[ma][nb][1];
            __half2 h2 = __floats2half2_rn(x0, x1);
            float2 hf = __half22float2(h2);
            __half2 l2 = __floats2half2_rn(x0 - hf.x, x1 - hf.y);
            *(__half2*)(Chp + (size_t)row * N + col) = h2;
            *(__half2*)(Clp + (size_t)row * N + col) = l2;
            float y0 = acc[ma][nb][2], y1 = acc[ma][nb][3];
            __half2 h3 = __floats2half2_rn(y0, y1);
            float2 hg = __half22float2(h3);
            __half2 l3 = __floats2half2_rn(y0 - hg.x, y1 - hg.y);
            *(__half2*)(Chp + (size_t)(row + 8) * N + col) = h3;
            *(__half2*)(Clp + (size_t)(row + 8) * N + col) = l3;
        }
    }
}

// ======================= RMS norm (strided input) -> fp16 split planes =======================
__global__ void rms_h(const float* __restrict__ in, int instride,
                      const float* __restrict__ w,
                      __half* __restrict__ oh, __half* __restrict__ ol, int N)
{
    int row = blockIdx.x;
    const float* ir = in + (size_t)row * instride;
    float s = 0.f;
    for (int i = threadIdx.x; i < N; i += 256) { float v = ir[i]; s += v * v; }
    __shared__ float red[256];
    red[threadIdx.x] = s;
    __syncthreads();
    for (int st = 128; st > 0; st >>= 1) {
        if (threadIdx.x < st) red[threadIdx.x] += red[threadIdx.x + st];
        __syncthreads();
    }
    float rr = rsqrtf(red[0] / (float)N + 1e-6f);
    for (int i = threadIdx.x; i < N; i += 256) {
        float v = ir[i] * rr * w[i];
        __half h, l; split16(v, h, l);
        oh[(size_t)row * N + i] = h;
        ol[(size_t)row * N + i] = l;
    }
}

// ======================= lambda sigmoid (from fused tmp cols) =======================
__global__ void lam_sig(const float* __restrict__ tmp, const float* __restrict__ bl,
                        float* __restrict__ lam)
{
    int idx = blockIdx.x * 256 + threadIdx.x;   // BL*16
    int row = idx >> 4, n = idx & 15;
    float z = tmp[(size_t)row * NX + 2112 + n] + bl[n];
    lam[idx] = 1.f / (1.f + expf(-z));
}

// ======================= RoPE kr (from fused tmp cols) -> planes =======================
__global__ void rope_kr(const float* __restrict__ tmp,
                        __half* __restrict__ oh, __half* __restrict__ ol)
{
    int idx = blockIdx.x * 256 + threadIdx.x;   // BL*32
    int j = idx & 31, row = idx >> 5;
    int l = row & (Lseq - 1);
    float inv = powf(10000.f, -(float)(2 * j) / 64.f);
    float ang = (float)l * inv;
    float c = cosf(ang), s = sinf(ang);
    const float* base = tmp + (size_t)row * NX + 2048;
    float x1 = base[j], x2 = base[j + 32];
    float y1 = x1 * c - x2 * s;
    float y2 = x2 * c + x1 * s;
    size_t o = (size_t)row * 64;
    __half hh, ll;
    split16(y1, hh, ll); oh[o + j] = hh;      ol[o + j] = ll;
    split16(y2, hh, ll); oh[o + j + 32] = hh; ol[o + j + 32] = ll;
}

// ======================= RoPE qr (in-place on split planes) =======================
__global__ void rope_qp(__half* __restrict__ ph, __half* __restrict__ pl)
{
    int idx = blockIdx.x * 256 + threadIdx.x;   // BL*32*32
    int j = idx & 31;
    int h = (idx >> 5) & 31;
    int row = idx >> 10;
    int l = row & (Lseq - 1);
    float inv = powf(10000.f, -(float)(2 * j) / 64.f);
    float ang = (float)l * inv;
    float c = cosf(ang), s = sinf(ang);
    size_t o = (size_t)row * 2048 + h * 64;
    float x1 = __half2float(ph[o + j])      + __half2float(pl[o + j]);
    float x2 = __half2float(ph[o + j + 32]) + __half2float(pl[o + j + 32]);
    float y1 = x1 * c - x2 * s;
    float y2 = x2 * c + x1 * s;
    __half hh, ll;
    split16(y1, hh, ll); ph[o + j] = hh;      pl[o + j] = ll;
    split16(y2, hh, ll); ph[o + j + 32] = hh; pl[o + j + 32] = ll;
}

// ======================= tensor-core flash attention (3xFP16, pre-split planes) =====
#define FLASH_SMEM (26112 * 4)
__global__ __launch_bounds__(128)
void flash_h(const __half* __restrict__ qch, const __half* __restrict__ qcl,
             const __half* __restrict__ qrh, const __half* __restrict__ qrl,
             const __half* __restrict__ kvh, const __half* __restrict__ kvl,
             const __half* __restrict__ krh, const __half* __restrict__ krl,
             float* __restrict__ attn)
{
    extern __shared__ uint32_t smw[];
    uint32_t* qs[2] = { smw,         smw + 6400 };
    uint32_t* ks[2] = { smw + 12800, smw + 16000 };
    uint32_t* vs[2] = { smw + 19200, smw + 21376 };
    uint32_t* ps[2] = { smw + 23552, smw + 24832 };

    const int Q0 = (gridDim.x - 1 - blockIdx.x) * 64;
    const int head2 = blockIdx.y;
    const int b = blockIdx.z;
    const int hn = head2 >> 1, hp = head2 & 1;
    const int tid = threadIdx.x;
    const int lane = tid & 31, w = tid >> 5;
    const int lr = lane >> 2, lc = lane & 3;

    const size_t tq = (size_t)(b * Lseq + Q0);

    {
        const __half* qcp[2] = { qch + tq * 4096 + head2 * 128, qcl + tq * 4096 + head2 * 128 };
        const __half* qrp[2] = { qrh + tq * 2048 + head2 * 64,  qrl + tq * 2048 + head2 * 64 };
        #pragma unroll
        for (int p = 0; p < 2; p++) {
            uint32_t qb = smem_u32(qs[p]);
            #pragma unroll
            for (int i = 0; i < 8; i++) {
                int s2 = tid + i * 128;
                int r = s2 >> 4, c = s2 & 15;
                cp16(qb + (uint32_t)(r * 100 + c * 4) * 4u, qcp[p] + (size_t)r * 4096 + c * 8);
            }
            #pragma unroll
            for (int i = 0; i < 4; i++) {
                int s2 = tid + i * 128;
                int r = s2 >> 3, c = s2 & 7;
                cp16(qb + (uint32_t)(r * 100 + 64 + c * 4) * 4u, qrp[p] + (size_t)r * 2048 + c * 8);
            }
        }
        CP_COMMIT();
    }

    float o[16][4];
    #pragma unroll
    for (int i = 0; i < 16; i++) { o[i][0] = o[i][1] = o[i][2] = o[i][3] = 0.f; }
    float m0 = -INFINITY, m1 = -INFINITY, l0 = 0.f, l1 = 0.f;

    const int row0g = Q0 + 16 * w + lr;
    const int row1g = row0g + 8;
    const int prow0 = (16 * w + lr) * 20;
    const int arow0 = (16 * w + lr) * 100;

    const int ntile = (Q0 + 64) >> 5;
    for (int t = 0; t < ntile; t++) {
        const int k0 = t << 5;
        __syncthreads();
        {
            const size_t tk = (size_t)(b * Lseq + k0);
            const __half* kcp[2] = { kvh + tk * 4096 + hn * 128,        kvl + tk * 4096 + hn * 128 };
            const __half* vp[2]  = { kvh + tk * 4096 + 2048 + hn * 128, kvl + tk * 4096 + 2048 + hn * 128 };
            const __half* krp[2] = { krh + tk * 64,                     krl + tk * 64 };
            #pragma unroll
            for (int p = 0; p < 2; p++) {
                uint32_t kb = smem_u32(ks[p]);
                uint32_t vb = smem_u32(vs[p]);
                #pragma unroll
                for (int i = 0; i < 4; i++) {
                    int s2 = tid + i * 128;
                    int r = s2 >> 4, c = s2 & 15;
                    cp16(kb + (uint32_t)(r * 100 + c * 4) * 4u, kcp[p] + (size_t)r * 4096 + c * 8);
                    cp16(vb + (uint32_t)(r * 68 + c * 4) * 4u,  vp[p]  + (size_t)r * 4096 + c * 8);
                }
                #pragma unroll
                for (int i = 0; i < 2; i++) {
                    int s2 = tid + i * 128;
                    int r = s2 >> 3, c = s2 & 7;
                    cp16(kb + (uint32_t)(r * 100 + 64 + c * 4) * 4u, krp[p] + (size_t)r * 64 + c * 8);
                }
            }
            CP_COMMIT();
            CP_WAIT0();
            __syncthreads();
        }

        float s4[4][4];
        #pragma unroll
        for (int nt = 0; nt < 4; nt++) { s4[nt][0] = s4[nt][1] = s4[nt][2] = s4[nt][3] = 0.f; }

        #pragma unroll 4
        for (int s = 0; s < 12; s++) {
            const int ab = arow0 + s * 8 + lc;
            uint32_t ah0 = qs[0][ab],       ah1 = qs[0][ab + 800];
            uint32_t ah2 = qs[0][ab + 4],   ah3 = qs[0][ab + 804];
            uint32_t al0 = qs[1][ab],       al1 = qs[1][ab + 800];
            uint32_t al2 = qs[1][ab + 4],   al3 = qs[1][ab + 804];
            #pragma unroll
            for (int nt = 0; nt < 4; nt++) {
                const int cb = (nt * 8 + lr) * 100 + s * 8 + lc;
                uint32_t bh0 = ks[0][cb], bh1 = ks[0][cb + 4];
                uint32_t bl0 = ks[1][cb], bl1 = ks[1][cb + 4];
                mma_f16(s4[nt], al0, al1, al2, al3, bh0, bh1);
                mma_f16(s4[nt], ah0, ah1, ah2, ah3, bl0, bl1);
                mma_f16(s4[nt], ah0, ah1, ah2, ah3, bh0, bh1);
            }
        }

        float tmax0 = -INFINITY, tmax1 = -INFINITY;
        #pragma unroll
        for (int nt = 0; nt < 4; nt++) {
            const int colg = k0 + nt * 8 + 2 * lc;
            s4[nt][0] = (colg     <= row0g) ? s4[nt][0] * ATTN_SCALE : -INFINITY;
            s4[nt][1] = (colg + 1 <= row0g) ? s4[nt][1] * ATTN_SCALE : -INFINITY;
            s4[nt][2] = (colg     <= row1g) ? s4[nt][2] * ATTN_SCALE : -INFINITY;
            s4[nt][3] = (colg + 1 <= row1g) ? s4[nt][3] * ATTN_SCALE : -INFINITY;
            tmax0 = fmaxf(tmax0, fmaxf(s4[nt][0], s4[nt][1]));
            tmax1 = fmaxf(tmax1, fmaxf(s4[nt][2], s4[nt][3]));
        }
        tmax0 = fmaxf(tmax0, __shfl_xor_sync(0xffffffffu, tmax0, 1));
        tmax0 = fmaxf(tmax0, __shfl_xor_sync(0xffffffffu, tmax0, 2));
        tmax1 = fmaxf(tmax1, __shfl_xor_sync(0xffffffffu, tmax1, 1));
        tmax1 = fmaxf(tmax1, __shfl_xor_sync(0xffffffffu, tmax1, 2));

        const float mn0 = fmaxf(m0, tmax0), mn1 = fmaxf(m1, tmax1);
        const float scl0 = expf(m0 - mn0);
        const float scl1 = expf(m1 - mn1);

        float p4[4][4];
        float pr0 = 0.f, pr1 = 0.f;
        #pragma unroll
        for (int nt = 0; nt < 4; nt++) {
            p4[nt][0] = expf(s4[nt][0] - mn0);
            p4[nt][1] = expf(s4[nt][1] - mn0);
            p4[nt][2] = expf(s4[nt][2] - mn1);
            p4[nt][3] = expf(s4[nt][3] - mn1);
            pr0 += p4[nt][0] + p4[nt][1];
            pr1 += p4[nt][2] + p4[nt][3];
        }
        pr0 += __shfl_xor_sync(0xffffffffu, pr0, 1);
        pr0 += __shfl_xor_sync(0xffffffffu, pr0, 2);
        pr1 += __shfl_xor_sync(0xffffffffu, pr1, 1);
        pr1 += __shfl_xor_sync(0xffffffffu, pr1, 2);

        l0 = l0 * scl0 + pr0;
        l1 = l1 * scl1 + pr1;
        m0 = mn0; m1 = mn1;

        #pragma unroll
        for (int i = 0; i < 16; i++) {
            o[i][0] *= scl0; o[i][1] *= scl0;
            o[i][2] *= scl1; o[i][3] *= scl1;
        }

        #pragma unroll
        for (int nt = 0; nt < 4; nt++) {
            __half2 h0 = __floats2half2_rn(p4[nt][0], p4[nt][1]);
            float2 f0 = __half22float2(h0);
            __half2 e0 = __floats2half2_rn(p4[nt][0] - f0.x, p4[nt][1] - f0.y);
            ((__half2*)ps[0])[prow0 + nt * 4 + lc] = h0;
            ((__half2*)ps[1])[prow0 + nt * 4 + lc] = e0;
            __half2 h1 = __floats2half2_rn(p4[nt][2], p4[nt][3]);
            float2 f1 = __half22float2(h1);
            __half2 e1 = __floats2half2_rn(p4[nt][2] - f1.x, p4[nt][3] - f1.y);
            ((__half2*)ps[0])[prow0 + 160 + nt * 4 + lc] = h1;
            ((__half2*)ps[1])[prow0 + 160 + nt * 4 + lc] = e1;
        }
        __syncwarp();

        const uint16_t* vhp = (const uint16_t*)vs[0];
        const uint16_t* vlp = (const uint16_t*)vs[1];
        #pragma unroll
        for (int s = 0; s < 2; s++) {
            const int pb = prow0 + s * 8 + lc;
            uint32_t ah0 = ps[0][pb],     ah1 = ps[0][pb + 160];
            uint32_t ah2 = ps[0][pb + 4], ah3 = ps[0][pb + 164];
            uint32_t al0 = ps[1][pb],     al1 = ps[1][pb + 160];
            uint32_t al2 = ps[1][pb + 4], al3 = ps[1][pb + 164];
            const int kb = s * 16 + 2 * lc;
            #pragma unroll
            for (int nt2 = 0; nt2 < 16; nt2++) {
                const int d = nt2 * 8 + lr;
                uint32_t bh0 = (uint32_t)vhp[kb * 136 + d]       | ((uint32_t)vhp[(kb + 1) * 136 + d] << 16);
                uint32_t bh1 = (uint32_t)vhp[(kb + 8) * 136 + d] | ((uint32_t)vhp[(kb + 9) * 136 + d] << 16);
                uint32_t bl0 = (uint32_t)vlp[kb * 136 + d]       | ((uint32_t)vlp[(kb + 1) * 136 + d] << 16);
                uint32_t bl1 = (uint32_t)vlp[(kb + 8) * 136 + d] | ((uint32_t)vlp[(kb + 9) * 136 + d] << 16);
                mma_f16(o[nt2], al0, al1, al2, al3, bh0, bh1);
                mma_f16(o[nt2], ah0, ah1, ah2, ah3, bl0, bl1);
                mma_f16(o[nt2], ah0, ah1, ah2, ah3, bh0, bh1);
            }
        }
    }

    const float inv0 = 1.f / l0, inv1 = 1.f / l1;
    const size_t obase = ((size_t)(b * 2 + hp) * NHh + hn) * Lseq;
    float* op0 = attn + (obase + row0g) * 128;
    float* op1 = attn + (obase + row1g) * 128;
    #pragma unroll
    for (int nt2 = 0; nt2 < 16; nt2++) {
        *(float2*)(op0 + nt2 * 8 + 2 * lc) = make_float2(o[nt2][0] * inv0, o[nt2][1] * inv0);
        *(float2*)(op1 + nt2 * 8 + 2 * lc) = make_float2(o[nt2][2] * inv1, o[nt2][3] * inv1);
    }
}

// ======================= combine -> fp16 split planes =======================
__global__ void combine_h(const float* __restrict__ attn, const float* __restrict__ lam,
                          __half* __restrict__ oh, __half* __restrict__ ol)
{
    int idx = blockIdx.x * 256 + threadIdx.x;
    int c = idx & 2047;
    int row = idx >> 11;
    int b = row >> 11;
    int l = row & 2047;
    int n = c >> 7, d = c & 127;
    size_t a1 = (((size_t)(b * 2 + 0) * NHh + n) * Lseq + l) * 128 + d;
    size_t a2 = (((size_t)(b * 2 + 1) * NHh + n) * Lseq + l) * 128 + d;
    float v = attn[a1] - lam[(size_t)row * 16 + n] * attn[a2];
    __half h, lo; split16(v, h, lo);
    oh[idx] = h; ol[idx] = lo;
}

// ======================= launch =======================
extern "C" void kernel_launch(void* const* d_in, const int* in_sizes, int n_in,
                              void* d_out, int out_size)
{
    const float* x     = (const float*)d_in[0];
    const float* W_DKV = (const float*)d_in[1];
    const float* kv_w  = (const float*)d_in[2];
    const float* W_UK  = (const float*)d_in[3];
    const float* W_UV  = (const float*)d_in[4];
    const float* W_DQ  = (const float*)d_in[5];
    const float* q_w   = (const float*)d_in[6];
    const float* W_UQ  = (const float*)d_in[7];
    const float* W_QR  = (const float*)d_in[8];
    const float* W_KR  = (const float*)d_in[9];
    const float* W_lw  = (const float*)d_in[10];
    const float* W_lb  = (const float*)d_in[11];
    const float* W_out = (const float*)d_in[12];
    float* out = (float*)d_out;

    float *tmp, *lam, *attn;
    __half *xh, *xl, *ckvh, *ckvl, *cqh, *cql, *preh, *prel;
    __half *qchp, *qclp, *qrhp, *qrlp, *krhp, *krlp, *kvh, *kvl;
    __half *tXh, *tXl, *tUKVh, *tUKVl, *tUQh, *tUQl, *tQRh, *tQRl, *tOUTh, *tOUTl;
    cudaGetSymbolAddress((void**)&tmp,  g_tmp);
    cudaGetSymbolAddress((void**)&lam,  g_lam);
    cudaGetSymbolAddress((void**)&attn, g_attn);
    cudaGetSymbolAddress((void**)&xh,   g_xh);
    cudaGetSymbolAddress((void**)&xl,   g_xl);
    cudaGetSymbolAddress((void**)&ckvh, g_ckvh);
    cudaGetSymbolAddress((void**)&ckvl, g_ckvl);
    cudaGetSymbolAddress((void**)&cqh,  g_cqh);
    cudaGetSymbolAddress((void**)&cql,  g_cql);
    cudaGetSymbolAddress((void**)&preh, g_preh);
    cudaGetSymbolAddress((void**)&prel, g_prel);
    cudaGetSymbolAddress((void**)&qchp, g_qch);
    cudaGetSymbolAddress((void**)&qclp, g_qcl);
    cudaGetSymbolAddress((void**)&qrhp, g_qrh);
    cudaGetSymbolAddress((void**)&qrlp, g_qrl);
    cudaGetSymbolAddress((void**)&krhp, g_krh);
    cudaGetSymbolAddress((void**)&krlp, g_krl);
    cudaGetSymbolAddress((void**)&kvh,  g_kvh);
    cudaGetSymbolAddress((void**)&kvl,  g_kvl);
    cudaGetSymbolAddress((void**)&tXh,  g_tXh);
    cudaGetSymbolAddress((void**)&tXl,  g_tXl);
    cudaGetSymbolAddress((void**)&tUKVh, g_tUKVh);
    cudaGetSymbolAddress((void**)&tUKVl, g_tUKVl);
    cudaGetSymbolAddress((void**)&tUQh,  g_tUQh);
    cudaGetSymbolAddress((void**)&tUQl,  g_tUQl);
    cudaGetSymbolAddress((void**)&tQRh,  g_tQRh);
    cudaGetSymbolAddress((void**)&tQRl,  g_tQRl);
    cudaGetSymbolAddress((void**)&tOUTh, g_tOUTh);
    cudaGetSymbolAddress((void**)&tOUTl, g_tOUTl);

    cudaFuncSetAttribute(hgemm_f,     cudaFuncAttributeMaxDynamicSharedMemorySize, HGEMM_SMEM);
    cudaFuncSetAttribute(hgemm_multi, cudaFuncAttributeMaxDynamicSharedMemorySize, HGEMM_SMEM);
    cudaFuncSetAttribute(flash_h,     cudaFuncAttributeMaxDynamicSharedMemorySize, FLASH_SMEM);

    dim3 tb(32, 8);
    // fused tX planes: rows [DKV 0..1023 | DQ 1024..2047 | KR 2048..2111 | lw 2112..2127 | pad]
    transpose32h<<<dim3(DCc/32, Dd/32), tb>>>(W_DKV, tXh,              tXl,              Dd, DCc);
    transpose32h<<<dim3(DCc/32, Dd/32), tb>>>(W_DQ,  tXh + 1024 * Dd,  tXl + 1024 * Dd,  Dd, DCc);
    transpose32h<<<dim3(DHRr/32, Dd/32), tb>>>(W_KR, tXh + 2048 * Dd,  tXl + 2048 * Dd,  Dd, DHRr);
    lwT_kernel<<<(Dd * 16) / 256, 256>>>(W_lw, tXh, tXl);
    transpose32h<<<dim3((NHh*DHh)/32, DCc/32), tb>>>(W_UK, tUKVh,              tUKVl,              DCc, NHh*DHh);
    transpose32h<<<dim3((NHh*DHh)/32, DCc/32), tb>>>(W_UV, tUKVh + 2048 * DCc, tUKVl + 2048 * DCc, DCc, NHh*DHh);
    transpose32h<<<dim3((2*NHh*DHh)/32, DCc/32), tb>>>(W_UQ, tUQh, tUQl, DCc, 2*NHh*DHh);
    transpose32h<<<dim3((2*NHh*DHRr)/32, DCc/32), tb>>>(W_QR, tQRh, tQRl, DCc, 2*NHh*DHRr);
    transpose32h<<<dim3(Dd/32, Dd/32), tb>>>(W_out, tOUTh, tOUTl, Dd, Dd);
    split_kernel<<<(BL * Dd) / 256, 256>>>(x, xh, xl);

    // fused down-projection + kr + lambda-pre: tmp[row][NX]
    hgemm_f<<<dim3(NX/128, BL/128), 512, HGEMM_SMEM>>>(NX, Dd, xh, xl, tXh, tXl, tmp);
    rms_h<<<BL, 256>>>(tmp,        NX, kv_w, ckvh, ckvl, DCc);
    rms_h<<<BL, 256>>>(tmp + 1024, NX, q_w,  cqh,  cql,  DCc);
    lam_sig<<<(BL * 16) / 256, 256>>>(tmp, W_lb, lam);
    rope_kr<<<(BL * 32) / 256, 256>>>(tmp, krhp, krlp);

    // merged up-projections (UKV + UQ + QR), all K=1024
    hgemm_multi<<<dim3(80, BL/128), 512, HGEMM_SMEM>>>(
        ckvh, ckvl, cqh, cql,
        tUKVh, tUKVl, tUQh, tUQl, tQRh, tQRl,
        kvh, kvl, qchp, qclp, qrhp, qrlp);

    // RoPE on qr planes (in-place)
    rope_qp<<<(BL * 1024) / 256, 256>>>(qrhp, qrlp);

    // attention (fp16 tensor-core flash, longest-first)
    flash_h<<<dim3(Lseq / 64, 32, BB), 128, FLASH_SMEM>>>(
        qchp, qclp, qrhp, qrlp, kvh, kvl, krhp, krlp, attn);

    // combine + output projection
    combine_h<<<(BL * Dd) / 256, 256>>>(attn, lam, preh, prel);
    hgemm_f<<<dim3(Dd/128, BL/128), 512, HGEMM_SMEM>>>(Dd, Dd, preh, prel, tOUTh, tOUTl, out);
}

// round 11
// speedup vs baseline: 2.7708x; 1.0694x over previous
#include <cuda_runtime.h>
#include <cuda.h>
#include <cuda_fp16.h>
#include <math.h>
#include <stdint.h>

#define BB   2
#define Lseq 2048
#define BL   4096      // B*L
#define Dd   2048
#define DCc  1024
#define NHh  16
#define DHh  128
#define DHRr 64
#define ATTN_SCALE 0.07216878364870322f
#define NX   2176      // fused down-proj width: [ckv 1024 | cq 1024 | kr 64 | lam 16 | pad 48]

// ======================= scratch =======================
__device__ float g_tmp [BL * NX];
__device__ float g_lam [BL * NHh];
__device__ float g_attn[(size_t)2 * BB * NHh * Lseq * DHh];

// fp16 split planes (activations)
__device__ __half g_xh  [BL * Dd],   g_xl  [BL * Dd];
__device__ __half g_ckvh[BL * DCc],  g_ckvl[BL * DCc];
__device__ __half g_cqh [BL * DCc],  g_cql [BL * DCc];
__device__ __half g_preh[BL * Dd],   g_prel[BL * Dd];
__device__ __half g_qch [BL * 4096], g_qcl [BL * 4096];
__device__ __half g_qrh [BL * 2048], g_qrl [BL * 2048];
__device__ __half g_krh [BL * DHRr], g_krl [BL * DHRr];
__device__ __half g_kvh [BL * 4096], g_kvl [BL * 4096];   // [kc 2048 | v 2048]
// fp16 split planes (transposed weights, [N][K])
__device__ __half g_tXh  [NX * Dd],     g_tXl  [NX * Dd];     // [DKV|DQ|KR|lw|pad0]
__device__ __half g_tUKVh[4096 * DCc],  g_tUKVl[4096 * DCc];  // [UK 2048 | UV 2048]
__device__ __half g_tUQh [4096 * DCc],  g_tUQl [4096 * DCc];
__device__ __half g_tQRh [2048 * DCc],  g_tQRl [2048 * DCc];
__device__ __half g_tOUTh[Dd * Dd],     g_tOUTl[Dd * Dd];

// ======================= helpers =======================
__device__ __forceinline__ uint32_t smem_u32(const void* p) {
    uint32_t a;
    asm("{ .reg .u64 t; cvta.to.shared.u64 t, %1; cvt.u32.u64 %0, t; }" : "=r"(a) : "l"(p));
    return a;
}
__device__ __forceinline__ void cp16(uint32_t dst, const void* src) {
    asm volatile("cp.async.cg.shared.global [%0], [%1], 16;" :: "r"(dst), "l"(src));
}
#define CP_COMMIT() asm volatile("cp.async.commit_group;" ::: "memory")
#define CP_WAIT0()  asm volatile("cp.async.wait_group 0;"  ::: "memory")

__device__ __forceinline__ void mma_f16(float c[4],
                                        uint32_t a0, uint32_t a1, uint32_t a2, uint32_t a3,
                                        uint32_t b0, uint32_t b1)
{
    asm volatile(
        "mma.sync.aligned.m16n8k16.row.col.f32.f16.f16.f32 "
        "{%0,%1,%2,%3}, {%4,%5,%6,%7}, {%8,%9}, {%0,%1,%2,%3};"
        : "+f"(c[0]), "+f"(c[1]), "+f"(c[2]), "+f"(c[3])
        : "r"(a0), "r"(a1), "r"(a2), "r"(a3), "r"(b0), "r"(b1));
}

__device__ __forceinline__ void split16(float v, __half& h, __half& l) {
    h = __float2half_rn(v);
    l = __float2half_rn(v - __half2float(h));
}

// ======================= transpose + split: in[R][C] -> hi/lo[C][R] =======================
__global__ void transpose32h(const float* __restrict__ in,
                             __half* __restrict__ oh, __half* __restrict__ ol, int R, int C)
{
    __shared__ float t[32][33];
    int bx = blockIdx.x * 32, by = blockIdx.y * 32;
    int x = bx + threadIdx.x;
    #pragma unroll
    for (int j = 0; j < 32; j += 8)
        t[threadIdx.y + j][threadIdx.x] = in[(size_t)(by + threadIdx.y + j) * C + x];
    __syncthreads();
    int ox = by + threadIdx.x;
    #pragma unroll
    for (int j = 0; j < 32; j += 8) {
        float v = t[threadIdx.x][threadIdx.y + j];
        __half h, l; split16(v, h, l);
        size_t o = (size_t)(bx + threadIdx.y + j) * R + ox;
        oh[o] = h; ol[o] = l;
    }
}

// W_lw [2048][16] -> rows 2112..2127 of tX planes
__global__ void lwT_kernel(const float* __restrict__ Wl,
                           __half* __restrict__ oh, __half* __restrict__ ol)
{
    int idx = blockIdx.x * 256 + threadIdx.x;   // 2048*16
    int k = idx >> 4, n = idx & 15;
    float v = Wl[idx];
    __half h, l; split16(v, h, l);
    size_t o = (size_t)(2112 + n) * Dd + k;
    oh[o] = h; ol[o] = l;
}

// ======================= elementwise split =======================
__global__ void split_kernel(const float* __restrict__ in,
                             __half* __restrict__ oh, __half* __restrict__ ol)
{
    int idx = blockIdx.x * 256 + threadIdx.x;
    float v = in[idx];
    __half h, l; split16(v, h, l);
    oh[idx] = h; ol[idx] = l;
}

// ======================= fp16-split tensor-core GEMM =======================
// TERMS=3: D = al*bh + ah*bl + ah*bh (err ~2^-22)
// TERMS=2: D = al*bh + ah*bh          (err ~2^-12, B-lo plane not staged)
#define WSTR 20
#define HGEMM_SMEM (2 * 4 * 128 * WSTR * 4)   // 81920 B

template<int TERMS>
__device__ __forceinline__ void hgemm_body(
    int N, int K, int m0, int n0,
    const __half* __restrict__ Ahi, const __half* __restrict__ Alo,
    const __half* __restrict__ Bhi, const __half* __restrict__ Blo,
    uint32_t* smw, float acc[2][4][4])
{
    uint32_t* buf[2] = { smw, smw + 4 * 128 * WSTR };
    const int tid = threadIdx.x;
    const int wid = tid >> 5, lane = tid & 31;
    const int warpM = (wid >> 2) * 32;
    const int warpN = (wid & 3) * 32;
    const int lr = lane >> 2, lc = lane & 3;

    const __half* Ap[2] = { Ahi + (size_t)m0 * K, Alo + (size_t)m0 * K };
    const __half* Bp[2] = { Bhi + (size_t)n0 * K, Blo + (size_t)n0 * K };

    const int r = tid >> 2;
    const int q = (tid & 3) * 4;

    auto stage = [&](int kc, int b) {
        uint32_t base = smem_u32(buf[b]);
        cp16(base + (uint32_t)((r) * WSTR + q) * 4u,
             Ap[0] + (size_t)r * K + kc + q * 2);
        cp16(base + (uint32_t)((128 + r) * WSTR + q) * 4u,
             Ap[1] + (size_t)r * K + kc + q * 2);
        cp16(base + (uint32_t)((2 * 128 + r) * WSTR + q) * 4u,
             Bp[0] + (size_t)r * K + kc + q * 2);
        if (TERMS == 3)
            cp16(base + (uint32_t)((3 * 128 + r) * WSTR + q) * 4u,
                 Bp[1] + (size_t)r * K + kc + q * 2);
        CP_COMMIT();
    };

    #pragma unroll
    for (int i = 0; i < 2; i++)
        #pragma unroll
        for (int j = 0; j < 4; j++)
            #pragma unroll
            for (int k = 0; k < 4; k++) acc[i][j][k] = 0.f;

    stage(0, 0);

    const int nch = K >> 5;
    for (int i = 0; i < nch; i++) {
        CP_WAIT0();
        __syncthreads();
        if (i + 1 < nch) stage((i + 1) << 5, (i + 1) & 1);

        const uint32_t* Ah = buf[i & 1];
        const uint32_t* Al = Ah + 128 * WSTR;
        const uint32_t* Bh = Ah + 2 * 128 * WSTR;
        const uint32_t* Bl = Ah + 3 * 128 * WSTR;

        #pragma unroll
        for (int s = 0; s < 2; s++) {
            uint32_t ah[2][4], al[2][4], bhf[4][2], blf[4][2];
            #pragma unroll
            for (int ma = 0; ma < 2; ma++) {
                int rw = (warpM + ma * 16 + lr) * WSTR + s * 8 + lc;
                ah[ma][0] = Ah[rw];
                ah[ma][1] = Ah[rw + 8 * WSTR];
                ah[ma][2] = Ah[rw + 4];
                ah[ma][3] = Ah[rw + 8 * WSTR + 4];
                al[ma][0] = Al[rw];
                al[ma][1] = Al[rw + 8 * WSTR];
                al[ma][2] = Al[rw + 4];
                al[ma][3] = Al[rw + 8 * WSTR + 4];
            }
            #pragma unroll
            for (int nb = 0; nb < 4; nb++) {
                int cw = (warpN + nb * 8 + lr) * WSTR + s * 8 + lc;
                bhf[nb][0] = Bh[cw]; bhf[nb][1] = Bh[cw + 4];
                if (TERMS == 3) { blf[nb][0] = Bl[cw]; blf[nb][1] = Bl[cw + 4]; }
            }
            #pragma unroll
            for (int nb = 0; nb < 4; nb++)
                #pragma unroll
                for (int ma = 0; ma < 2; ma++)
                    mma_f16(acc[ma][nb], al[ma][0], al[ma][1], al[ma][2], al[ma][3],
                            bhf[nb][0], bhf[nb][1]);
            if (TERMS == 3) {
                #pragma unroll
                for (int nb = 0; nb < 4; nb++)
                    #pragma unroll
                    for (int ma = 0; ma < 2; ma++)
                        mma_f16(acc[ma][nb], ah[ma][0], ah[ma][1], ah[ma][2], ah[ma][3],
                                blf[nb][0], blf[nb][1]);
            }
            #pragma unroll
            for (int nb = 0; nb < 4; nb++)
                #pragma unroll
                for (int ma = 0; ma < 2; ma++)
                    mma_f16(acc[ma][nb], ah[ma][0], ah[ma][1], ah[ma][2], ah[ma][3],
                            bhf[nb][0], bhf[nb][1]);
        }
        __syncthreads();
    }
}

template<int TERMS>
__global__ __launch_bounds__(512)
void hgemm_f(int N, int K,
             const __half* __restrict__ Ahi, const __half* __restrict__ Alo,
             const __half* __restrict__ Bhi, const __half* __restrict__ Blo,
             float* __restrict__ C)
{
    extern __shared__ float smraw[];
    float acc[2][4][4];
    const int m0 = blockIdx.y * 128, n0 = blockIdx.x * 128;
    hgemm_body<TERMS>(N, K, m0, n0, Ahi, Alo, Bhi, Blo, (uint32_t*)smraw, acc);

    const int wid = threadIdx.x >> 5, lane = threadIdx.x & 31;
    const int warpM = (wid >> 2) * 32, warpN = (wid & 3) * 32;
    const int lr = lane >> 2, lc = lane & 3;
    #pragma unroll
    for (int ma = 0; ma < 2; ma++) {
        int row = m0 + warpM + ma * 16 + lr;
        #pragma unroll
        for (int nb = 0; nb < 4; nb++) {
            int col = n0 + warpN + nb * 8 + lc * 2;
            *(float2*)(C + (size_t)row * N + col)       = make_float2(acc[ma][nb][0], acc[ma][nb][1]);
            *(float2*)(C + (size_t)(row + 8) * N + col) = make_float2(acc[ma][nb][2], acc[ma][nb][3]);
        }
    }
}

// merged K=1024 launch: seg0 (32 tiles) ckv@UKV->kv, seg1 (32) cq@UQ->qc, seg2 (16) cq@QR->qr
__global__ __launch_bounds__(512)
void hgemm_multi(const __half* __restrict__ ckvh, const __half* __restrict__ ckvl,
                 const __half* __restrict__ cqh,  const __half* __restrict__ cql,
                 const __half* __restrict__ tUKVh, const __half* __restrict__ tUKVl,
                 const __half* __restrict__ tUQh,  const __half* __restrict__ tUQl,
                 const __half* __restrict__ tQRh,  const __half* __restrict__ tQRl,
                 __half* __restrict__ kvh, __half* __restrict__ kvl,
                 __half* __restrict__ qch, __half* __restrict__ qcl,
                 __half* __restrict__ qrh, __half* __restrict__ qrl)
{
    extern __shared__ float smraw[];
    const int bx = blockIdx.x;
    const __half *Ahp, *Alp, *Bhp, *Blp;
    __half *Chp, *Clp;
    int N, nloc;
    if (bx < 32)      { Ahp = ckvh; Alp = ckvl; Bhp = tUKVh; Blp = tUKVl; Chp = kvh; Clp = kvl; N = 4096; nloc = bx; }
    else if (bx < 64) { Ahp = cqh;  Alp = cql;  Bhp = tUQh;  Blp = tUQl;  Chp = qch; Clp = qcl; N = 4096; nloc = bx - 32; }
    else              { Ahp = cqh;  Alp = cql;  Bhp = tQRh;  Blp = tQRl;  Chp = qrh; Clp = qrl; N = 2048; nloc = bx - 64; }

    float acc[2][4][4];
    const int m0 = blockIdx.y * 128, n0 = nloc * 128;
    hgemm_body<3>(N, 1024, m0, n0, Ahp, Alp, Bhp, Blp, (uint32_t*)smraw, acc);

    const int wid = threadIdx.x >> 5, lane = threadIdx.x & 31;
    const int warpM = (wid >> 2) * 32, warpN = (wid & 3) * 32;
    const int lr = lane >> 2, lc = lane & 3;
    #pragma unroll
    for (int ma = 0; ma < 2; ma++) {
        int row = m0 + warpM + ma * 16 + lr;
        #pragma unroll
        for (int nb = 0; nb < 4; nb++) {
            int col = n0 + warpN + nb * 8 + lc * 2;
            float x0 = acc[ma][nb][0], x1 = acc[ma][nb][1];
            __half2 h2 = __floats2half2_rn(x0, x1);
            float2 hf = __half22float2(h2);
            __half2 l2 = __floats2half2_rn(x0 - hf.x, x1 - hf.y);
            *(__half2*)(Chp + (size_t)row * N + col) = h2;
            *(__half2*)(Clp + (size_t)row * N + col) = l2;
            float y0 = acc[ma][nb][2], y1 = acc[ma][nb][3];
            __half2 h3 = __floats2half2_rn(y0, y1);
            float2 hg = __half22float2(h3);
            __half2 l3 = __floats2half2_rn(y0 - hg.x, y1 - hg.y);
            *(__half2*)(Chp + (size_t)(row + 8) * N + col) = h3;
            *(__half2*)(Clp + (size_t)(row + 8) * N + col) = l3;
        }
    }
}

// ======================= RMS norm (strided input) -> fp16 split planes =======================
__global__ void rms_h(const float* __restrict__ in, int instride,
                      const float* __restrict__ w,
                      __half* __restrict__ oh, __half* __restrict__ ol, int N)
{
    int row = blockIdx.x;
    const float* ir = in + (size_t)row * instride;
    float s = 0.f;
    for (int i = threadIdx.x; i < N; i += 256) { float v = ir[i]; s += v * v; }
    __shared__ float red[256];
    red[threadIdx.x] = s;
    __syncthreads();
    for (int st = 128; st > 0; st >>= 1) {
        if (threadIdx.x < st) red[threadIdx.x] += red[threadIdx.x + st];
        __syncthreads();
    }
    float rr = rsqrtf(red[0] / (float)N + 1e-6f);
    for (int i = threadIdx.x; i < N; i += 256) {
        float v = ir[i] * rr * w[i];
        __half h, l; split16(v, h, l);
        oh[(size_t)row * N + i] = h;
        ol[(size_t)row * N + i] = l;
    }
}

// ======================= lambda sigmoid (from fused tmp cols) =======================
__global__ void lam_sig(const float* __restrict__ tmp, const float* __restrict__ bl,
                        float* __restrict__ lam)
{
    int idx = blockIdx.x * 256 + threadIdx.x;   // BL*16
    int row = idx >> 4, n = idx & 15;
    float z = tmp[(size_t)row * NX + 2112 + n] + bl[n];
    lam[idx] = 1.f / (1.f + expf(-z));
}

// ======================= RoPE kr (from fused tmp cols) -> planes =======================
__global__ void rope_kr(const float* __restrict__ tmp,
                        __half* __restrict__ oh, __half* __restrict__ ol)
{
    int idx = blockIdx.x * 256 + threadIdx.x;   // BL*32
    int j = idx & 31, row = idx >> 5;
    int l = row & (Lseq - 1);
    float inv = powf(10000.f, -(float)(2 * j) / 64.f);
    float ang = (float)l * inv;
    float c = cosf(ang), s = sinf(ang);
    const float* base = tmp + (size_t)row * NX + 2048;
    float x1 = base[j], x2 = base[j + 32];
    float y1 = x1 * c - x2 * s;
    float y2 = x2 * c + x1 * s;
    size_t o = (size_t)row * 64;
    __half hh, ll;
    split16(y1, hh, ll); oh[o + j] = hh;      ol[o + j] = ll;
    split16(y2, hh, ll); oh[o + j + 32] = hh; ol[o + j + 32] = ll;
}

// ======================= RoPE qr (in-place on split planes) =======================
__global__ void rope_qp(__half* __restrict__ ph, __half* __restrict__ pl)
{
    int idx = blockIdx.x * 256 + threadIdx.x;   // BL*32*32
    int j = idx & 31;
    int h = (idx >> 5) & 31;
    int row = idx >> 10;
    int l = row & (Lseq - 1);
    float inv = powf(10000.f, -(float)(2 * j) / 64.f);
    float ang = (float)l * inv;
    float c = cosf(ang), s = sinf(ang);
    size_t o = (size_t)row * 2048 + h * 64;
    float x1 = __half2float(ph[o + j])      + __half2float(pl[o + j]);
    float x2 = __half2float(ph[o + j + 32]) + __half2float(pl[o + j + 32]);
    float y1 = x1 * c - x2 * s;
    float y2 = x2 * c + x1 * s;
    __half hh, ll;
    split16(y1, hh, ll); ph[o + j] = hh;      pl[o + j] = ll;
    split16(y2, hh, ll); ph[o + j + 32] = hh; pl[o + j + 32] = ll;
}

// ======================= tensor-core flash attention (3xFP16, pre-split planes) =====
#define FLASH_SMEM (26112 * 4)
__global__ __launch_bounds__(128)
void flash_h(const __half* __restrict__ qch, const __half* __restrict__ qcl,
             const __half* __restrict__ qrh, const __half* __restrict__ qrl,
             const __half* __restrict__ kvh, const __half* __restrict__ kvl,
             const __half* __restrict__ krh, const __half* __restrict__ krl,
             float* __restrict__ attn)
{
    extern __shared__ uint32_t smw[];
    uint32_t* qs[2] = { smw,         smw + 6400 };
    uint32_t* ks[2] = { smw + 12800, smw + 16000 };
    uint32_t* vs[2] = { smw + 19200, smw + 21376 };
    uint32_t* ps[2] = { smw + 23552, smw + 24832 };

    const int Q0 = (gridDim.x - 1 - blockIdx.x) * 64;
    const int head2 = blockIdx.y;
    const int b = blockIdx.z;
    const int hn = head2 >> 1, hp = head2 & 1;
    const int tid = threadIdx.x;
    const int lane = tid & 31, w = tid >> 5;
    const int lr = lane >> 2, lc = lane & 3;

    const size_t tq = (size_t)(b * Lseq + Q0);

    {
        const __half* qcp[2] = { qch + tq * 4096 + head2 * 128, qcl + tq * 4096 + head2 * 128 };
        const __half* qrp[2] = { qrh + tq * 2048 + head2 * 64,  qrl + tq * 2048 + head2 * 64 };
        #pragma unroll
        for (int p = 0; p < 2; p++) {
            uint32_t qb = smem_u32(qs[p]);
            #pragma unroll
            for (int i = 0; i < 8; i++) {
                int s2 = tid + i * 128;
                int r = s2 >> 4, c = s2 & 15;
                cp16(qb + (uint32_t)(r * 100 + c * 4) * 4u, qcp[p] + (size_t)r * 4096 + c * 8);
            }
            #pragma unroll
            for (int i = 0; i < 4; i++) {
                int s2 = tid + i * 128;
                int r = s2 >> 3, c = s2 & 7;
                cp16(qb + (uint32_t)(r * 100 + 64 + c * 4) * 4u, qrp[p] + (size_t)r * 2048 + c * 8);
            }
        }
        CP_COMMIT();
    }

    float o[16][4];
    #pragma unroll
    for (int i = 0; i < 16; i++) { o[i][0] = o[i][1] = o[i][2] = o[i][3] = 0.f; }
    float m0 = -INFINITY, m1 = -INFINITY, l0 = 0.f, l1 = 0.f;

    const int row0g = Q0 + 16 * w + lr;
    const int row1g = row0g + 8;
    const int prow0 = (16 * w + lr) * 20;
    const int arow0 = (16 * w + lr) * 100;

    const int ntile = (Q0 + 64) >> 5;
    for (int t = 0; t < ntile; t++) {
        const int k0 = t << 5;
        __syncthreads();
        {
            const size_t tk = (size_t)(b * Lseq + k0);
            const __half* kcp[2] = { kvh + tk * 4096 + hn * 128,        kvl + tk * 4096 + hn * 128 };
            const __half* vp[2]  = { kvh + tk * 4096 + 2048 + hn * 128, kvl + tk * 4096 + 2048 + hn * 128 };
            const __half* krp[2] = { krh + tk * 64,                     krl + tk * 64 };
            #pragma unroll
            for (int p = 0; p < 2; p++) {
                uint32_t kb = smem_u32(ks[p]);
                uint32_t vb = smem_u32(vs[p]);
                #pragma unroll
                for (int i = 0; i < 4; i++) {
                    int s2 = tid + i * 128;
                    int r = s2 >> 4, c = s2 & 15;
                    cp16(kb + (uint32_t)(r * 100 + c * 4) * 4u, kcp[p] + (size_t)r * 4096 + c * 8);
                    cp16(vb + (uint32_t)(r * 68 + c * 4) * 4u,  vp[p]  + (size_t)r * 4096 + c * 8);
                }
                #pragma unroll
                for (int i = 0; i < 2; i++) {
                    int s2 = tid + i * 128;
                    int r = s2 >> 3, c = s2 & 7;
                    cp16(kb + (uint32_t)(r * 100 + 64 + c * 4) * 4u, krp[p] + (size_t)r * 64 + c * 8);
                }
            }
            CP_COMMIT();
            CP_WAIT0();
            __syncthreads();
        }

        float s4[4][4];
        #pragma unroll
        for (int nt = 0; nt < 4; nt++) { s4[nt][0] = s4[nt][1] = s4[nt][2] = s4[nt][3] = 0.f; }

        #pragma unroll 4
        for (int s = 0; s < 12; s++) {
            const int ab = arow0 + s * 8 + lc;
            uint32_t ah0 = qs[0][ab],       ah1 = qs[0][ab + 800];
            uint32_t ah2 = qs[0][ab + 4],   ah3 = qs[0][ab + 804];
            uint32_t al0 = qs[1][ab],       al1 = qs[1][ab + 800];
            uint32_t al2 = qs[1][ab + 4],   al3 = qs[1][ab + 804];
            #pragma unroll
            for (int nt = 0; nt < 4; nt++) {
                const int cb = (nt * 8 + lr) * 100 + s * 8 + lc;
                uint32_t bh0 = ks[0][cb], bh1 = ks[0][cb + 4];
                uint32_t bl0 = ks[1][cb], bl1 = ks[1][cb + 4];
                mma_f16(s4[nt], al0, al1, al2, al3, bh0, bh1);
                mma_f16(s4[nt], ah0, ah1, ah2, ah3, bl0, bl1);
                mma_f16(s4[nt], ah0, ah1, ah2, ah3, bh0, bh1);
            }
        }

        float tmax0 = -INFINITY, tmax1 = -INFINITY;
        #pragma unroll
        for (int nt = 0; nt < 4; nt++) {
            const int colg = k0 + nt * 8 + 2 * lc;
            s4[nt][0] = (colg     <= row0g) ? s4[nt][0] * ATTN_SCALE : -INFINITY;
            s4[nt][1] = (colg + 1 <= row0g) ? s4[nt][1] * ATTN_SCALE : -INFINITY;
            s4[nt][2] = (colg     <= row1g) ? s4[nt][2] * ATTN_SCALE : -INFINITY;
            s4[nt][3] = (colg + 1 <= row1g) ? s4[nt][3] * ATTN_SCALE : -INFINITY;
            tmax0 = fmaxf(tmax0, fmaxf(s4[nt][0], s4[nt][1]));
            tmax1 = fmaxf(tmax1, fmaxf(s4[nt][2], s4[nt][3]));
        }
        tmax0 = fmaxf(tmax0, __shfl_xor_sync(0xffffffffu, tmax0, 1));
        tmax0 = fmaxf(tmax0, __shfl_xor_sync(0xffffffffu, tmax0, 2));
        tmax1 = fmaxf(tmax1, __shfl_xor_sync(0xffffffffu, tmax1, 1));
        tmax1 = fmaxf(tmax1, __shfl_xor_sync(0xffffffffu, tmax1, 2));

        const float mn0 = fmaxf(m0, tmax0), mn1 = fmaxf(m1, tmax1);
        const float scl0 = expf(m0 - mn0);
        const float scl1 = expf(m1 - mn1);

        float p4[4][4];
        float pr0 = 0.f, pr1 = 0.f;
        #pragma unroll
        for (int nt = 0; nt < 4; nt++) {
            p4[nt][0] = expf(s4[nt][0] - mn0);
            p4[nt][1] = expf(s4[nt][1] - mn0);
            p4[nt][2] = expf(s4[nt][2] - mn1);
            p4[nt][3] = expf(s4[nt][3] - mn1);
            pr0 += p4[nt][0] + p4[nt][1];
            pr1 += p4[nt][2] + p4[nt][3];
        }
        pr0 += __shfl_xor_sync(0xffffffffu, pr0, 1);
        pr0 += __shfl_xor_sync(0xffffffffu, pr0, 2);
        pr1 += __shfl_xor_sync(0xffffffffu, pr1, 1);
        pr1 += __shfl_xor_sync(0xffffffffu, pr1, 2);

        l0 = l0 * scl0 + pr0;
        l1 = l1 * scl1 + pr1;
        m0 = mn0; m1 = mn1;

        #pragma unroll
        for (int i = 0; i < 16; i++) {
            o[i][0] *= scl0; o[i][1] *= scl0;
            o[i][2] *= scl1; o[i][3] *= scl1;
        }

        #pragma unroll
        for (int nt = 0; nt < 4; nt++) {
            __half2 h0 = __floats2half2_rn(p4[nt][0], p4[nt][1]);
            float2 f0 = __half22float2(h0);
            __half2 e0 = __floats2half2_rn(p4[nt][0] - f0.x, p4[nt][1] - f0.y);
            ((__half2*)ps[0])[prow0 + nt * 4 + lc] = h0;
            ((__half2*)ps[1])[prow0 + nt * 4 + lc] = e0;
            __half2 h1 = __floats2half2_rn(p4[nt][2], p4[nt][3]);
            float2 f1 = __half22float2(h1);
            __half2 e1 = __floats2half2_rn(p4[nt][2] - f1.x, p4[nt][3] - f1.y);
            ((__half2*)ps[0])[prow0 + 160 + nt * 4 + lc] = h1;
            ((__half2*)ps[1])[prow0 + 160 + nt * 4 + lc] = e1;
        }
        __syncwarp();

        const uint16_t* vhp = (const uint16_t*)vs[0];
        const uint16_t* vlp = (const uint16_t*)vs[1];
        #pragma unroll
        for (int s = 0; s < 2; s++) {
            const int pb = prow0 + s * 8 + lc;
            uint32_t ah0 = ps[0][pb],     ah1 = ps[0][pb + 160];
            uint32_t ah2 = ps[0][pb + 4], ah3 = ps[0][pb + 164];
            uint32_t al0 = ps[1][pb],     al1 = ps[1][pb + 160];
            uint32_t al2 = ps[1][pb + 4], al3 = ps[1][pb + 164];
            const int kb = s * 16 + 2 * lc;
            #pragma unroll
            for (int nt2 = 0; nt2 < 16; nt2++) {
                const int d = nt2 * 8 + lr;
                uint32_t bh0 = (uint32_t)vhp[kb * 136 + d]       | ((uint32_t)vhp[(kb + 1) * 136 + d] << 16);
                uint32_t bh1 = (uint32_t)vhp[(kb + 8) * 136 + d] | ((uint32_t)vhp[(kb + 9) * 136 + d] << 16);
                uint32_t bl0 = (uint32_t)vlp[kb * 136 + d]       | ((uint32_t)vlp[(kb + 1) * 136 + d] << 16);
                uint32_t bl1 = (uint32_t)vlp[(kb + 8) * 136 + d] | ((uint32_t)vlp[(kb + 9) * 136 + d] << 16);
                mma_f16(o[nt2], al0, al1, al2, al3, bh0, bh1);
                mma_f16(o[nt2], ah0, ah1, ah2, ah3, bl0, bl1);
                mma_f16(o[nt2], ah0, ah1, ah2, ah3, bh0, bh1);
            }
        }
    }

    const float inv0 = 1.f / l0, inv1 = 1.f / l1;
    const size_t obase = ((size_t)(b * 2 + hp) * NHh + hn) * Lseq;
    float* op0 = attn + (obase + row0g) * 128;
    float* op1 = attn + (obase + row1g) * 128;
    #pragma unroll
    for (int nt2 = 0; nt2 < 16; nt2++) {
        *(float2*)(op0 + nt2 * 8 + 2 * lc) = make_float2(o[nt2][0] * inv0, o[nt2][1] * inv0);
        *(float2*)(op1 + nt2 * 8 + 2 * lc) = make_float2(o[nt2][2] * inv1, o[nt2][3] * inv1);
    }
}

// ======================= combine -> fp16 split planes =======================
__global__ void combine_h(const float* __restrict__ attn, const float* __restrict__ lam,
                          __half* __restrict__ oh, __half* __restrict__ ol)
{
    int idx = blockIdx.x * 256 + threadIdx.x;
    int c = idx & 2047;
    int row = idx >> 11;
    int b = row >> 11;
    int l = row & 2047;
    int n = c >> 7, d = c & 127;
    size_t a1 = (((size_t)(b * 2 + 0) * NHh + n) * Lseq + l) * 128 + d;
    size_t a2 = (((size_t)(b * 2 + 1) * NHh + n) * Lseq + l) * 128 + d;
    float v = attn[a1] - lam[(size_t)row * 16 + n] * attn[a2];
    __half h, lo; split16(v, h, lo);
    oh[idx] = h; ol[idx] = lo;
}

// ======================= launch =======================
extern "C" void kernel_launch(void* const* d_in, const int* in_sizes, int n_in,
                              void* d_out, int out_size)
{
    const float* x     = (const float*)d_in[0];
    const float* W_DKV = (const float*)d_in[1];
    const float* kv_w  = (const float*)d_in[2];
    const float* W_UK  = (const float*)d_in[3];
    const float* W_UV  = (const float*)d_in[4];
    const float* W_DQ  = (const float*)d_in[5];
    const float* q_w   = (const float*)d_in[6];
    const float* W_UQ  = (const float*)d_in[7];
    const float* W_QR  = (const float*)d_in[8];
    const float* W_KR  = (const float*)d_in[9];
    const float* W_lw  = (const float*)d_in[10];
    const float* W_lb  = (const float*)d_in[11];
    const float* W_out = (const float*)d_in[12];
    float* out = (float*)d_out;

    float *tmp, *lam, *attn;
    __half *xh, *xl, *ckvh, *ckvl, *cqh, *cql, *preh, *prel;
    __half *qchp, *qclp, *qrhp, *qrlp, *krhp, *krlp, *kvh, *kvl;
    __half *tXh, *tXl, *tUKVh, *tUKVl, *tUQh, *tUQl, *tQRh, *tQRl, *tOUTh, *tOUTl;
    cudaGetSymbolAddress((void**)&tmp,  g_tmp);
    cudaGetSymbolAddress((void**)&lam,  g_lam);
    cudaGetSymbolAddress((void**)&attn, g_attn);
    cudaGetSymbolAddress((void**)&xh,   g_xh);
    cudaGetSymbolAddress((void**)&xl,   g_xl);
    cudaGetSymbolAddress((void**)&ckvh, g_ckvh);
    cudaGetSymbolAddress((void**)&ckvl, g_ckvl);
    cudaGetSymbolAddress((void**)&cqh,  g_cqh);
    cudaGetSymbolAddress((void**)&cql,  g_cql);
    cudaGetSymbolAddress((void**)&preh, g_preh);
    cudaGetSymbolAddress((void**)&prel, g_prel);
    cudaGetSymbolAddress((void**)&qchp, g_qch);
    cudaGetSymbolAddress((void**)&qclp, g_qcl);
    cudaGetSymbolAddress((void**)&qrhp, g_qrh);
    cudaGetSymbolAddress((void**)&qrlp, g_qrl);
    cudaGetSymbolAddress((void**)&krhp, g_krh);
    cudaGetSymbolAddress((void**)&krlp, g_krl);
    cudaGetSymbolAddress((void**)&kvh,  g_kvh);
    cudaGetSymbolAddress((void**)&kvl,  g_kvl);
    cudaGetSymbolAddress((void**)&tXh,  g_tXh);
    cudaGetSymbolAddress((void**)&tXl,  g_tXl);
    cudaGetSymbolAddress((void**)&tUKVh, g_tUKVh);
    cudaGetSymbolAddress((void**)&tUKVl, g_tUKVl);
    cudaGetSymbolAddress((void**)&tUQh,  g_tUQh);
    cudaGetSymbolAddress((void**)&tUQl,  g_tUQl);
    cudaGetSymbolAddress((void**)&tQRh,  g_tQRh);
    cudaGetSymbolAddress((void**)&tQRl,  g_tQRl);
    cudaGetSymbolAddress((void**)&tOUTh, g_tOUTh);
    cudaGetSymbolAddress((void**)&tOUTl, g_tOUTl);

    cudaFuncSetAttribute(hgemm_f<2>,  cudaFuncAttributeMaxDynamicSharedMemorySize, HGEMM_SMEM);
    cudaFuncSetAttribute(hgemm_f<3>,  cudaFuncAttributeMaxDynamicSharedMemorySize, HGEMM_SMEM);
    cudaFuncSetAttribute(hgemm_multi, cudaFuncAttributeMaxDynamicSharedMemorySize, HGEMM_SMEM);
    cudaFuncSetAttribute(flash_h,     cudaFuncAttributeMaxDynamicSharedMemorySize, FLASH_SMEM);

    dim3 tb(32, 8);
    // fused tX planes: rows [DKV 0..1023 | DQ 1024..2047 | KR 2048..2111 | lw 2112..2127 | pad]
    transpose32h<<<dim3(DCc/32, Dd/32), tb>>>(W_DKV, tXh,              tXl,              Dd, DCc);
    transpose32h<<<dim3(DCc/32, Dd/32), tb>>>(W_DQ,  tXh + 1024 * Dd,  tXl + 1024 * Dd,  Dd, DCc);
    transpose32h<<<dim3(DHRr/32, Dd/32), tb>>>(W_KR, tXh + 2048 * Dd,  tXl + 2048 * Dd,  Dd, DHRr);
    lwT_kernel<<<(Dd * 16) / 256, 256>>>(W_lw, tXh, tXl);
    transpose32h<<<dim3((NHh*DHh)/32, DCc/32), tb>>>(W_UK, tUKVh,              tUKVl,              DCc, NHh*DHh);
    transpose32h<<<dim3((NHh*DHh)/32, DCc/32), tb>>>(W_UV, tUKVh + 2048 * DCc, tUKVl + 2048 * DCc, DCc, NHh*DHh);
    transpose32h<<<dim3((2*NHh*DHh)/32, DCc/32), tb>>>(W_UQ, tUQh, tUQl, DCc, 2*NHh*DHh);
    transpose32h<<<dim3((2*NHh*DHRr)/32, DCc/32), tb>>>(W_QR, tQRh, tQRl, DCc, 2*NHh*DHRr);
    transpose32h<<<dim3(Dd/32, Dd/32), tb>>>(W_out, tOUTh, tOUTl, Dd, Dd);
    split_kernel<<<(BL * Dd) / 256, 256>>>(x, xh, xl);

    // fused down-projection + kr + lambda-pre (2-term split): tmp[row][NX]
    hgemm_f<2><<<dim3(NX/128, BL/128), 512, HGEMM_SMEM>>>(NX, Dd, xh, xl, tXh, tXl, tmp);
    rms_h<<<BL, 256>>>(tmp,        NX, kv_w, ckvh, ckvl, DCc);
    rms_h<<<BL, 256>>>(tmp + 1024, NX, q_w,  cqh,  cql,  DCc);
    lam_sig<<<(BL * 16) / 256, 256>>>(tmp, W_lb, lam);
    rope_kr<<<(BL * 32) / 256, 256>>>(tmp, krhp, krlp);

    // merged up-projections (UKV + UQ + QR), all K=1024, 3-term (feeds attention)
    hgemm_multi<<<dim3(80, BL/128), 512, HGEMM_SMEM>>>(
        ckvh, ckvl, cqh, cql,
        tUKVh, tUKVl, tUQh, tUQl, tQRh, tQRl,
        kvh, kvl, qchp, qclp, qrhp, qrlp);

    // RoPE on qr planes (in-place)
    rope_qp<<<(BL * 1024) / 256, 256>>>(qrhp, qrlp);

    // attention (fp16 tensor-core flash, longest-first)
    flash_h<<<dim3(Lseq / 64, 32, BB), 128, FLASH_SMEM>>>(
        qchp, qclp, qrhp, qrlp, kvh, kvl, krhp, krlp, attn);

    // combine + output projection (2-term split)
    combine_h<<<(BL * Dd) / 256, 256>>>(attn, lam, preh, prel);
    hgemm_f<2><<<dim3(Dd/128, BL/128), 512, HGEMM_SMEM>>>(Dd, Dd, preh, prel, tOUTh, tOUTl, out);
}

// round 12
// speedup vs baseline: 2.9868x; 1.0780x over previous
#include <cuda_runtime.h>
#include <cuda.h>
#include <cuda_fp16.h>
#include <math.h>
#include <stdint.h>

#define BB   2
#define Lseq 2048
#define BL   4096      // B*L
#define Dd   2048
#define DCc  1024
#define NHh  16
#define DHh  128
#define DHRr 64
#define ATTN_SCALE 0.07216878364870322f
#define NX   2176      // fused down-proj width: [ckv 1024 | cq 1024 | kr 64 | lam 16 | pad 48]

// ======================= scratch =======================
__device__ float g_tmp [BL * NX];
__device__ float g_lam [BL * NHh];
__device__ float g_attn[(size_t)2 * BB * NHh * Lseq * DHh];

// fp16 split planes (activations)
__device__ __half g_xh  [BL * Dd],   g_xl  [BL * Dd];
__device__ __half g_ckvh[BL * DCc],  g_ckvl[BL * DCc];
__device__ __half g_cqh [BL * DCc],  g_cql [BL * DCc];
__device__ __half g_preh[BL * Dd],   g_prel[BL * Dd];
__device__ __half g_qch [BL * 4096], g_qcl [BL * 4096];
__device__ __half g_qrh [BL * 2048], g_qrl [BL * 2048];
__device__ __half g_krh [BL * DHRr], g_krl [BL * DHRr];
__device__ __half g_kvh [BL * 4096], g_kvl [BL * 4096];   // [kc 2048 | v 2048]
// fp16 split planes (transposed weights, [N][K])
__device__ __half g_tXh  [NX * Dd],     g_tXl  [NX * Dd];     // [DKV|DQ|KR|lw|pad0]
__device__ __half g_tUKVh[4096 * DCc],  g_tUKVl[4096 * DCc];  // [UK 2048 | UV 2048]
__device__ __half g_tUQh [4096 * DCc],  g_tUQl [4096 * DCc];
__device__ __half g_tQRh [2048 * DCc],  g_tQRl [2048 * DCc];
__device__ __half g_tOUTh[Dd * Dd],     g_tOUTl[Dd * Dd];

// ======================= helpers =======================
__device__ __forceinline__ uint32_t smem_u32(const void* p) {
    uint32_t a;
    asm("{ .reg .u64 t; cvta.to.shared.u64 t, %1; cvt.u32.u64 %0, t; }" : "=r"(a) : "l"(p));
    return a;
}
__device__ __forceinline__ void cp16(uint32_t dst, const void* src) {
    asm volatile("cp.async.cg.shared.global [%0], [%1], 16;" :: "r"(dst), "l"(src));
}
#define CP_COMMIT() asm volatile("cp.async.commit_group;" ::: "memory")
#define CP_WAIT0()  asm volatile("cp.async.wait_group 0;"  ::: "memory")

__device__ __forceinline__ void mma_f16(float c[4],
                                        uint32_t a0, uint32_t a1, uint32_t a2, uint32_t a3,
                                        uint32_t b0, uint32_t b1)
{
    asm volatile(
        "mma.sync.aligned.m16n8k16.row.col.f32.f16.f16.f32 "
        "{%0,%1,%2,%3}, {%4,%5,%6,%7}, {%8,%9}, {%0,%1,%2,%3};"
        : "+f"(c[0]), "+f"(c[1]), "+f"(c[2]), "+f"(c[3])
        : "r"(a0), "r"(a1), "r"(a2), "r"(a3), "r"(b0), "r"(b1));
}

__device__ __forceinline__ void split16(float v, __half& h, __half& l) {
    h = __float2half_rn(v);
    l = __float2half_rn(v - __half2float(h));
}

// ======================= transpose + split: in[R][C] -> hi/lo[C][R] =======================
__global__ void transpose32h(const float* __restrict__ in,
                             __half* __restrict__ oh, __half* __restrict__ ol, int R, int C)
{
    __shared__ float t[32][33];
    int bx = blockIdx.x * 32, by = blockIdx.y * 32;
    int x = bx + threadIdx.x;
    #pragma unroll
    for (int j = 0; j < 32; j += 8)
        t[threadIdx.y + j][threadIdx.x] = in[(size_t)(by + threadIdx.y + j) * C + x];
    __syncthreads();
    int ox = by + threadIdx.x;
    #pragma unroll
    for (int j = 0; j < 32; j += 8) {
        float v = t[threadIdx.x][threadIdx.y + j];
        __half h, l; split16(v, h, l);
        size_t o = (size_t)(bx + threadIdx.y + j) * R + ox;
        oh[o] = h; ol[o] = l;
    }
}

// W_lw [2048][16] -> rows 2112..2127 of tX planes
__global__ void lwT_kernel(const float* __restrict__ Wl,
                           __half* __restrict__ oh, __half* __restrict__ ol)
{
    int idx = blockIdx.x * 256 + threadIdx.x;   // 2048*16
    int k = idx >> 4, n = idx & 15;
    float v = Wl[idx];
    __half h, l; split16(v, h, l);
    size_t o = (size_t)(2112 + n) * Dd + k;
    oh[o] = h; ol[o] = l;
}

// ======================= elementwise split =======================
__global__ void split_kernel(const float* __restrict__ in,
                             __half* __restrict__ oh, __half* __restrict__ ol)
{
    int idx = blockIdx.x * 256 + threadIdx.x;
    float v = in[idx];
    __half h, l; split16(v, h, l);
    oh[idx] = h; ol[idx] = l;
}

// ======================= fp16-split tensor-core GEMM =======================
// TERMS=3: D = al*bh + ah*bl + ah*bh (err ~2^-22)
// TERMS=2: D = al*bh + ah*bh          (err ~2^-12, B-lo plane not staged)
#define WSTR 20
#define HGEMM_SMEM (2 * 4 * 128 * WSTR * 4)   // 81920 B

template<int TERMS>
__device__ __forceinline__ void hgemm_body(
    int N, int K, int m0, int n0,
    const __half* __restrict__ Ahi, const __half* __restrict__ Alo,
    const __half* __restrict__ Bhi, const __half* __restrict__ Blo,
    uint32_t* smw, float acc[2][4][4])
{
    uint32_t* buf[2] = { smw, smw + 4 * 128 * WSTR };
    const int tid = threadIdx.x;
    const int wid = tid >> 5, lane = tid & 31;
    const int warpM = (wid >> 2) * 32;
    const int warpN = (wid & 3) * 32;
    const int lr = lane >> 2, lc = lane & 3;

    const __half* Ap[2] = { Ahi + (size_t)m0 * K, Alo + (size_t)m0 * K };
    const __half* Bp[2] = { Bhi + (size_t)n0 * K, Blo + (size_t)n0 * K };

    const int r = tid >> 2;
    const int q = (tid & 3) * 4;

    auto stage = [&](int kc, int b) {
        uint32_t base = smem_u32(buf[b]);
        cp16(base + (uint32_t)((r) * WSTR + q) * 4u,
             Ap[0] + (size_t)r * K + kc + q * 2);
        cp16(base + (uint32_t)((128 + r) * WSTR + q) * 4u,
             Ap[1] + (size_t)r * K + kc + q * 2);
        cp16(base + (uint32_t)((2 * 128 + r) * WSTR + q) * 4u,
             Bp[0] + (size_t)r * K + kc + q * 2);
        if (TERMS == 3)
            cp16(base + (uint32_t)((3 * 128 + r) * WSTR + q) * 4u,
                 Bp[1] + (size_t)r * K + kc + q * 2);
        CP_COMMIT();
    };

    #pragma unroll
    for (int i = 0; i < 2; i++)
        #pragma unroll
        for (int j = 0; j < 4; j++)
            #pragma unroll
            for (int k = 0; k < 4; k++) acc[i][j][k] = 0.f;

    stage(0, 0);

    const int nch = K >> 5;
    for (int i = 0; i < nch; i++) {
        CP_WAIT0();
        __syncthreads();
        if (i + 1 < nch) stage((i + 1) << 5, (i + 1) & 1);

        const uint32_t* Ah = buf[i & 1];
        const uint32_t* Al = Ah + 128 * WSTR;
        const uint32_t* Bh = Ah + 2 * 128 * WSTR;
        const uint32_t* Bl = Ah + 3 * 128 * WSTR;

        #pragma unroll
        for (int s = 0; s < 2; s++) {
            uint32_t ah[2][4], al[2][4], bhf[4][2], blf[4][2];
            #pragma unroll
            for (int ma = 0; ma < 2; ma++) {
                int rw = (warpM + ma * 16 + lr) * WSTR + s * 8 + lc;
                ah[ma][0] = Ah[rw];
                ah[ma][1] = Ah[rw + 8 * WSTR];
                ah[ma][2] = Ah[rw + 4];
                ah[ma][3] = Ah[rw + 8 * WSTR + 4];
                al[ma][0] = Al[rw];
                al[ma][1] = Al[rw + 8 * WSTR];
                al[ma][2] = Al[rw + 4];
                al[ma][3] = Al[rw + 8 * WSTR + 4];
            }
            #pragma unroll
            for (int nb = 0; nb < 4; nb++) {
                int cw = (warpN + nb * 8 + lr) * WSTR + s * 8 + lc;
                bhf[nb][0] = Bh[cw]; bhf[nb][1] = Bh[cw + 4];
                if (TERMS == 3) { blf[nb][0] = Bl[cw]; blf[nb][1] = Bl[cw + 4]; }
            }
            #pragma unroll
            for (int nb = 0; nb < 4; nb++)
                #pragma unroll
                for (int ma = 0; ma < 2; ma++)
                    mma_f16(acc[ma][nb], al[ma][0], al[ma][1], al[ma][2], al[ma][3],
                            bhf[nb][0], bhf[nb][1]);
            if (TERMS == 3) {
                #pragma unroll
                for (int nb = 0; nb < 4; nb++)
                    #pragma unroll
                    for (int ma = 0; ma < 2; ma++)
                        mma_f16(acc[ma][nb], ah[ma][0], ah[ma][1], ah[ma][2], ah[ma][3],
                                blf[nb][0], blf[nb][1]);
            }
            #pragma unroll
            for (int nb = 0; nb < 4; nb++)
                #pragma unroll
                for (int ma = 0; ma < 2; ma++)
                    mma_f16(acc[ma][nb], ah[ma][0], ah[ma][1], ah[ma][2], ah[ma][3],
                            bhf[nb][0], bhf[nb][1]);
        }
        __syncthreads();
    }
}

template<int TERMS>
__global__ __launch_bounds__(512)
void hgemm_f(int N, int K,
             const __half* __restrict__ Ahi, const __half* __restrict__ Alo,
             const __half* __restrict__ Bhi, const __half* __restrict__ Blo,
             float* __restrict__ C)
{
    extern __shared__ float smraw[];
    float acc[2][4][4];
    const int m0 = blockIdx.y * 128, n0 = blockIdx.x * 128;
    hgemm_body<TERMS>(N, K, m0, n0, Ahi, Alo, Bhi, Blo, (uint32_t*)smraw, acc);

    const int wid = threadIdx.x >> 5, lane = threadIdx.x & 31;
    const int warpM = (wid >> 2) * 32, warpN = (wid & 3) * 32;
    const int lr = lane >> 2, lc = lane & 3;
    #pragma unroll
    for (int ma = 0; ma < 2; ma++) {
        int row = m0 + warpM + ma * 16 + lr;
        #pragma unroll
        for (int nb = 0; nb < 4; nb++) {
            int col = n0 + warpN + nb * 8 + lc * 2;
            *(float2*)(C + (size_t)row * N + col)       = make_float2(acc[ma][nb][0], acc[ma][nb][1]);
            *(float2*)(C + (size_t)(row + 8) * N + col) = make_float2(acc[ma][nb][2], acc[ma][nb][3]);
        }
    }
}

// merged K=1024 launch: seg0 (32 tiles) ckv@UKV->kv, seg1 (32) cq@UQ->qc, seg2 (16) cq@QR->qr
__global__ __launch_bounds__(512)
void hgemm_multi(const __half* __restrict__ ckvh, const __half* __restrict__ ckvl,
                 const __half* __restrict__ cqh,  const __half* __restrict__ cql,
                 const __half* __restrict__ tUKVh, const __half* __restrict__ tUKVl,
                 const __half* __restrict__ tUQh,  const __half* __restrict__ tUQl,
                 const __half* __restrict__ tQRh,  const __half* __restrict__ tQRl,
                 __half* __restrict__ kvh, __half* __restrict__ kvl,
                 __half* __restrict__ qch, __half* __restrict__ qcl,
                 __half* __restrict__ qrh, __half* __restrict__ qrl)
{
    extern __shared__ float smraw[];
    const int bx = blockIdx.x;
    const __half *Ahp, *Alp, *Bhp, *Blp;
    __half *Chp, *Clp;
    int N, nloc;
    if (bx < 32)      { Ahp = ckvh; Alp = ckvl; Bhp = tUKVh; Blp = tUKVl; Chp = kvh; Clp = kvl; N = 4096; nloc = bx; }
    else if (bx < 64) { Ahp = cqh;  Alp = cql;  Bhp = tUQh;  Blp = tUQl;  Chp = qch; Clp = qcl; N = 4096; nloc = bx - 32; }
    else              { Ahp = cqh;  Alp = cql;  Bhp = tQRh;  Blp = tQRl;  Chp = qrh; Clp = qrl; N = 2048; nloc = bx - 64; }

    float acc[2][4][4];
    const int m0 = blockIdx.y * 128, n0 = nloc * 128;
    hgemm_body<2>(N, 1024, m0, n0, Ahp, Alp, Bhp, Blp, (uint32_t*)smraw, acc);

    const int wid = threadIdx.x >> 5, lane = threadIdx.x & 31;
    const int warpM = (wid >> 2) * 32, warpN = (wid & 3) * 32;
    const int lr = lane >> 2, lc = lane & 3;
    #pragma unroll
    for (int ma = 0; ma < 2; ma++) {
        int row = m0 + warpM + ma * 16 + lr;
        #pragma unroll
        for (int nb = 0; nb < 4; nb++) {
            int col = n0 + warpN + nb * 8 + lc * 2;
            float x0 = acc[ma][nb][0], x1 = acc[ma][nb][1];
            __half2 h2 = __floats2half2_rn(x0, x1);
            float2 hf = __half22float2(h2);
            __half2 l2 = __floats2half2_rn(x0 - hf.x, x1 - hf.y);
            *(__half2*)(Chp + (size_t)row * N + col) = h2;
            *(__half2*)(Clp + (size_t)row * N + col) = l2;
            float y0 = acc[ma][nb][2], y1 = acc[ma][nb][3];
            __half2 h3 = __floats2half2_rn(y0, y1);
            float2 hg = __half22float2(h3);
            __half2 l3 = __floats2half2_rn(y0 - hg.x, y1 - hg.y);
            *(__half2*)(Chp + (size_t)(row + 8) * N + col) = h3;
            *(__half2*)(Clp + (size_t)(row + 8) * N + col) = l3;
        }
    }
}

// ======================= RMS norm (strided input) -> fp16 split planes =======================
__global__ void rms_h(const float* __restrict__ in, int instride,
                      const float* __restrict__ w,
                      __half* __restrict__ oh, __half* __restrict__ ol, int N)
{
    int row = blockIdx.x;
    const float* ir = in + (size_t)row * instride;
    float s = 0.f;
    for (int i = threadIdx.x; i < N; i += 256) { float v = ir[i]; s += v * v; }
    __shared__ float red[256];
    red[threadIdx.x] = s;
    __syncthreads();
    for (int st = 128; st > 0; st >>= 1) {
        if (threadIdx.x < st) red[threadIdx.x] += red[threadIdx.x + st];
        __syncthreads();
    }
    float rr = rsqrtf(red[0] / (float)N + 1e-6f);
    for (int i = threadIdx.x; i < N; i += 256) {
        float v = ir[i] * rr * w[i];
        __half h, l; split16(v, h, l);
        oh[(size_t)row * N + i] = h;
        ol[(size_t)row * N + i] = l;
    }
}

// ======================= lambda sigmoid (from fused tmp cols) =======================
__global__ void lam_sig(const float* __restrict__ tmp, const float* __restrict__ bl,
                        float* __restrict__ lam)
{
    int idx = blockIdx.x * 256 + threadIdx.x;   // BL*16
    int row = idx >> 4, n = idx & 15;
    float z = tmp[(size_t)row * NX + 2112 + n] + bl[n];
    lam[idx] = 1.f / (1.f + expf(-z));
}

// ======================= RoPE kr (from fused tmp cols) -> planes =======================
__global__ void rope_kr(const float* __restrict__ tmp,
                        __half* __restrict__ oh, __half* __restrict__ ol)
{
    int idx = blockIdx.x * 256 + threadIdx.x;   // BL*32
    int j = idx & 31, row = idx >> 5;
    int l = row & (Lseq - 1);
    float inv = powf(10000.f, -(float)(2 * j) / 64.f);
    float ang = (float)l * inv;
    float c = cosf(ang), s = sinf(ang);
    const float* base = tmp + (size_t)row * NX + 2048;
    float x1 = base[j], x2 = base[j + 32];
    float y1 = x1 * c - x2 * s;
    float y2 = x2 * c + x1 * s;
    size_t o = (size_t)row * 64;
    __half hh, ll;
    split16(y1, hh, ll); oh[o + j] = hh;      ol[o + j] = ll;
    split16(y2, hh, ll); oh[o + j + 32] = hh; ol[o + j + 32] = ll;
}

// ======================= RoPE qr (in-place on split planes) =======================
__global__ void rope_qp(__half* __restrict__ ph, __half* __restrict__ pl)
{
    int idx = blockIdx.x * 256 + threadIdx.x;   // BL*32*32
    int j = idx & 31;
    int h = (idx >> 5) & 31;
    int row = idx >> 10;
    int l = row & (Lseq - 1);
    float inv = powf(10000.f, -(float)(2 * j) / 64.f);
    float ang = (float)l * inv;
    float c = cosf(ang), s = sinf(ang);
    size_t o = (size_t)row * 2048 + h * 64;
    float x1 = __half2float(ph[o + j])      + __half2float(pl[o + j]);
    float x2 = __half2float(ph[o + j + 32]) + __half2float(pl[o + j + 32]);
    float y1 = x1 * c - x2 * s;
    float y2 = x2 * c + x1 * s;
    __half hh, ll;
    split16(y1, hh, ll); ph[o + j] = hh;      pl[o + j] = ll;
    split16(y2, hh, ll); ph[o + j + 32] = hh; pl[o + j + 32] = ll;
}

// ======================= tensor-core flash attention (3xFP16, pre-split planes) =====
#define FLASH_SMEM (26112 * 4)
__global__ __launch_bounds__(128)
void flash_h(const __half* __restrict__ qch, const __half* __restrict__ qcl,
             const __half* __restrict__ qrh, const __half* __restrict__ qrl,
             const __half* __restrict__ kvh, const __half* __restrict__ kvl,
             const __half* __restrict__ krh, const __half* __restrict__ krl,
             float* __restrict__ attn)
{
    extern __shared__ uint32_t smw[];
    uint32_t* qs[2] = { smw,         smw + 6400 };
    uint32_t* ks[2] = { smw + 12800, smw + 16000 };
    uint32_t* vs[2] = { smw + 19200, smw + 21376 };
    uint32_t* ps[2] = { smw + 23552, smw + 24832 };

    const int Q0 = (gridDim.x - 1 - blockIdx.x) * 64;
    const int head2 = blockIdx.y;
    const int b = blockIdx.z;
    const int hn = head2 >> 1, hp = head2 & 1;
    const int tid = threadIdx.x;
    const int lane = tid & 31, w = tid >> 5;
    const int lr = lane >> 2, lc = lane & 3;

    const size_t tq = (size_t)(b * Lseq + Q0);

    {
        const __half* qcp[2] = { qch + tq * 4096 + head2 * 128, qcl + tq * 4096 + head2 * 128 };
        const __half* qrp[2] = { qrh + tq * 2048 + head2 * 64,  qrl + tq * 2048 + head2 * 64 };
        #pragma unroll
        for (int p = 0; p < 2; p++) {
            uint32_t qb = smem_u32(qs[p]);
            #pragma unroll
            for (int i = 0; i < 8; i++) {
                int s2 = tid + i * 128;
                int r = s2 >> 4, c = s2 & 15;
                cp16(qb + (uint32_t)(r * 100 + c * 4) * 4u, qcp[p] + (size_t)r * 4096 + c * 8);
            }
            #pragma unroll
            for (int i = 0; i < 4; i++) {
                int s2 = tid + i * 128;
                int r = s2 >> 3, c = s2 & 7;
                cp16(qb + (uint32_t)(r * 100 + 64 + c * 4) * 4u, qrp[p] + (size_t)r * 2048 + c * 8);
            }
        }
        CP_COMMIT();
    }

    float o[16][4];
    #pragma unroll
    for (int i = 0; i < 16; i++) { o[i][0] = o[i][1] = o[i][2] = o[i][3] = 0.f; }
    float m0 = -INFINITY, m1 = -INFINITY, l0 = 0.f, l1 = 0.f;

    const int row0g = Q0 + 16 * w + lr;
    const int row1g = row0g + 8;
    const int prow0 = (16 * w + lr) * 20;
    const int arow0 = (16 * w + lr) * 100;

    const int ntile = (Q0 + 64) >> 5;
    for (int t = 0; t < ntile; t++) {
        const int k0 = t << 5;
        __syncthreads();
        {
            const size_t tk = (size_t)(b * Lseq + k0);
            const __half* kcp[2] = { kvh + tk * 4096 + hn * 128,        kvl + tk * 4096 + hn * 128 };
            const __half* vp[2]  = { kvh + tk * 4096 + 2048 + hn * 128, kvl + tk * 4096 + 2048 + hn * 128 };
            const __half* krp[2] = { krh + tk * 64,                     krl + tk * 64 };
            #pragma unroll
            for (int p = 0; p < 2; p++) {
                uint32_t kb = smem_u32(ks[p]);
                uint32_t vb = smem_u32(vs[p]);
                #pragma unroll
                for (int i = 0; i < 4; i++) {
                    int s2 = tid + i * 128;
                    int r = s2 >> 4, c = s2 & 15;
                    cp16(kb + (uint32_t)(r * 100 + c * 4) * 4u, kcp[p] + (size_t)r * 4096 + c * 8);
                    cp16(vb + (uint32_t)(r * 68 + c * 4) * 4u,  vp[p]  + (size_t)r * 4096 + c * 8);
                }
                #pragma unroll
                for (int i = 0; i < 2; i++) {
                    int s2 = tid + i * 128;
                    int r = s2 >> 3, c = s2 & 7;
                    cp16(kb + (uint32_t)(r * 100 + 64 + c * 4) * 4u, krp[p] + (size_t)r * 64 + c * 8);
                }
            }
            CP_COMMIT();
            CP_WAIT0();
            __syncthreads();
        }

        float s4[4][4];
        #pragma unroll
        for (int nt = 0; nt < 4; nt++) { s4[nt][0] = s4[nt][1] = s4[nt][2] = s4[nt][3] = 0.f; }

        #pragma unroll 4
        for (int s = 0; s < 12; s++) {
            const int ab = arow0 + s * 8 + lc;
            uint32_t ah0 = qs[0][ab],       ah1 = qs[0][ab + 800];
            uint32_t ah2 = qs[0][ab + 4],   ah3 = qs[0][ab + 804];
            uint32_t al0 = qs[1][ab],       al1 = qs[1][ab + 800];
            uint32_t al2 = qs[1][ab + 4],   al3 = qs[1][ab + 804];
            #pragma unroll
            for (int nt = 0; nt < 4; nt++) {
                const int cb = (nt * 8 + lr) * 100 + s * 8 + lc;
                uint32_t bh0 = ks[0][cb], bh1 = ks[0][cb + 4];
                uint32_t bl0 = ks[1][cb], bl1 = ks[1][cb + 4];
                mma_f16(s4[nt], al0, al1, al2, al3, bh0, bh1);
                mma_f16(s4[nt], ah0, ah1, ah2, ah3, bl0, bl1);
                mma_f16(s4[nt], ah0, ah1, ah2, ah3, bh0, bh1);
            }
        }

        float tmax0 = -INFINITY, tmax1 = -INFINITY;
        #pragma unroll
        for (int nt = 0; nt < 4; nt++) {
            const int colg = k0 + nt * 8 + 2 * lc;
            s4[nt][0] = (colg     <= row0g) ? s4[nt][0] * ATTN_SCALE : -INFINITY;
            s4[nt][1] = (colg + 1 <= row0g) ? s4[nt][1] * ATTN_SCALE : -INFINITY;
            s4[nt][2] = (colg     <= row1g) ? s4[nt][2] * ATTN_SCALE : -INFINITY;
            s4[nt][3] = (colg + 1 <= row1g) ? s4[nt][3] * ATTN_SCALE : -INFINITY;
            tmax0 = fmaxf(tmax0, fmaxf(s4[nt][0], s4[nt][1]));
            tmax1 = fmaxf(tmax1, fmaxf(s4[nt][2], s4[nt][3]));
        }
        tmax0 = fmaxf(tmax0, __shfl_xor_sync(0xffffffffu, tmax0, 1));
        tmax0 = fmaxf(tmax0, __shfl_xor_sync(0xffffffffu, tmax0, 2));
        tmax1 = fmaxf(tmax1, __shfl_xor_sync(0xffffffffu, tmax1, 1));
        tmax1 = fmaxf(tmax1, __shfl_xor_sync(0xffffffffu, tmax1, 2));

        const float mn0 = fmaxf(m0, tmax0), mn1 = fmaxf(m1, tmax1);
        const float scl0 = expf(m0 - mn0);
        const float scl1 = expf(m1 - mn1);

        float p4[4][4];
        float pr0 = 0.f, pr1 = 0.f;
        #pragma unroll
        for (int nt = 0; nt < 4; nt++) {
            p4[nt][0] = expf(s4[nt][0] - mn0);
            p4[nt][1] = expf(s4[nt][1] - mn0);
            p4[nt][2] = expf(s4[nt][2] - mn1);
            p4[nt][3] = expf(s4[nt][3] - mn1);
            pr0 += p4[nt][0] + p4[nt][1];
            pr1 += p4[nt][2] + p4[nt][3];
        }
        pr0 += __shfl_xor_sync(0xffffffffu, pr0, 1);
        pr0 += __shfl_xor_sync(0xffffffffu, pr0, 2);
        pr1 += __shfl_xor_sync(0xffffffffu, pr1, 1);
        pr1 += __shfl_xor_sync(0xffffffffu, pr1, 2);

        l0 = l0 * scl0 + pr0;
        l1 = l1 * scl1 + pr1;
        m0 = mn0; m1 = mn1;

        #pragma unroll
        for (int i = 0; i < 16; i++) {
            o[i][0] *= scl0; o[i][1] *= scl0;
            o[i][2] *= scl1; o[i][3] *= scl1;
        }

        #pragma unroll
        for (int nt = 0; nt < 4; nt++) {
            __half2 h0 = __floats2half2_rn(p4[nt][0], p4[nt][1]);
            float2 f0 = __half22float2(h0);
            __half2 e0 = __floats2half2_rn(p4[nt][0] - f0.x, p4[nt][1] - f0.y);
            ((__half2*)ps[0])[prow0 + nt * 4 + lc] = h0;
            ((__half2*)ps[1])[prow0 + nt * 4 + lc] = e0;
            __half2 h1 = __floats2half2_rn(p4[nt][2], p4[nt][3]);
            float2 f1 = __half22float2(h1);
            __half2 e1 = __floats2half2_rn(p4[nt][2] - f1.x, p4[nt][3] - f1.y);
            ((__half2*)ps[0])[prow0 + 160 + nt * 4 + lc] = h1;
            ((__half2*)ps[1])[prow0 + 160 + nt * 4 + lc] = e1;
        }
        __syncwarp();

        const uint16_t* vhp = (const uint16_t*)vs[0];
        const uint16_t* vlp = (const uint16_t*)vs[1];
        #pragma unroll
        for (int s = 0; s < 2; s++) {
            const int pb = prow0 + s * 8 + lc;
            uint32_t ah0 = ps[0][pb],     ah1 = ps[0][pb + 160];
            uint32_t ah2 = ps[0][pb + 4], ah3 = ps[0][pb + 164];
            uint32_t al0 = ps[1][pb],     al1 = ps[1][pb + 160];
            uint32_t al2 = ps[1][pb + 4], al3 = ps[1][pb + 164];
            const int kb = s * 16 + 2 * lc;
            #pragma unroll
            for (int nt2 = 0; nt2 < 16; nt2++) {
                const int d = nt2 * 8 + lr;
                uint32_t bh0 = (uint32_t)vhp[kb * 136 + d]       | ((uint32_t)vhp[(kb + 1) * 136 + d] << 16);
                uint32_t bh1 = (uint32_t)vhp[(kb + 8) * 136 + d] | ((uint32_t)vhp[(kb + 9) * 136 + d] << 16);
                uint32_t bl0 = (uint32_t)vlp[kb * 136 + d]       | ((uint32_t)vlp[(kb + 1) * 136 + d] << 16);
                uint32_t bl1 = (uint32_t)vlp[(kb + 8) * 136 + d] | ((uint32_t)vlp[(kb + 9) * 136 + d] << 16);
                mma_f16(o[nt2], al0, al1, al2, al3, bh0, bh1);
                mma_f16(o[nt2], ah0, ah1, ah2, ah3, bl0, bl1);
                mma_f16(o[nt2], ah0, ah1, ah2, ah3, bh0, bh1);
            }
        }
    }

    const float inv0 = 1.f / l0, inv1 = 1.f / l1;
    const size_t obase = ((size_t)(b * 2 + hp) * NHh + hn) * Lseq;
    float* op0 = attn + (obase + row0g) * 128;
    float* op1 = attn + (obase + row1g) * 128;
    #pragma unroll
    for (int nt2 = 0; nt2 < 16; nt2++) {
        *(float2*)(op0 + nt2 * 8 + 2 * lc) = make_float2(o[nt2][0] * inv0, o[nt2][1] * inv0);
        *(float2*)(op1 + nt2 * 8 + 2 * lc) = make_float2(o[nt2][2] * inv1, o[nt2][3] * inv1);
    }
}

// ======================= combine -> fp16 split planes =======================
__global__ void combine_h(const float* __restrict__ attn, const float* __restrict__ lam,
                          __half* __restrict__ oh, __half* __restrict__ ol)
{
    int idx = blockIdx.x * 256 + threadIdx.x;
    int c = idx & 2047;
    int row = idx >> 11;
    int b = row >> 11;
    int l = row & 2047;
    int n = c >> 7, d = c & 127;
    size_t a1 = (((size_t)(b * 2 + 0) * NHh + n) * Lseq + l) * 128 + d;
    size_t a2 = (((size_t)(b * 2 + 1) * NHh + n) * Lseq + l) * 128 + d;
    float v = attn[a1] - lam[(size_t)row * 16 + n] * attn[a2];
    __half h, lo; split16(v, h, lo);
    oh[idx] = h; ol[idx] = lo;
}

// ======================= launch =======================
extern "C" void kernel_launch(void* const* d_in, const int* in_sizes, int n_in,
                              void* d_out, int out_size)
{
    const float* x     = (const float*)d_in[0];
    const float* W_DKV = (const float*)d_in[1];
    const float* kv_w  = (const float*)d_in[2];
    const float* W_UK  = (const float*)d_in[3];
    const float* W_UV  = (const float*)d_in[4];
    const float* W_DQ  = (const float*)d_in[5];
    const float* q_w   = (const float*)d_in[6];
    const float* W_UQ  = (const float*)d_in[7];
    const float* W_QR  = (const float*)d_in[8];
    const float* W_KR  = (const float*)d_in[9];
    const float* W_lw  = (const float*)d_in[10];
    const float* W_lb  = (const float*)d_in[11];
    const float* W_out = (const float*)d_in[12];
    float* out = (float*)d_out;

    float *tmp, *lam, *attn;
    __half *xh, *xl, *ckvh, *ckvl, *cqh, *cql, *preh, *prel;
    __half *qchp, *qclp, *qrhp, *qrlp, *krhp, *krlp, *kvh, *kvl;
    __half *tXh, *tXl, *tUKVh, *tUKVl, *tUQh, *tUQl, *tQRh, *tQRl, *tOUTh, *tOUTl;
    cudaGetSymbolAddress((void**)&tmp,  g_tmp);
    cudaGetSymbolAddress((void**)&lam,  g_lam);
    cudaGetSymbolAddress((void**)&attn, g_attn);
    cudaGetSymbolAddress((void**)&xh,   g_xh);
    cudaGetSymbolAddress((void**)&xl,   g_xl);
    cudaGetSymbolAddress((void**)&ckvh, g_ckvh);
    cudaGetSymbolAddress((void**)&ckvl, g_ckvl);
    cudaGetSymbolAddress((void**)&cqh,  g_cqh);
    cudaGetSymbolAddress((void**)&cql,  g_cql);
    cudaGetSymbolAddress((void**)&preh, g_preh);
    cudaGetSymbolAddress((void**)&prel, g_prel);
    cudaGetSymbolAddress((void**)&qchp, g_qch);
    cudaGetSymbolAddress((void**)&qclp, g_qcl);
    cudaGetSymbolAddress((void**)&qrhp, g_qrh);
    cudaGetSymbolAddress((void**)&qrlp, g_qrl);
    cudaGetSymbolAddress((void**)&krhp, g_krh);
    cudaGetSymbolAddress((void**)&krlp, g_krl);
    cudaGetSymbolAddress((void**)&kvh,  g_kvh);
    cudaGetSymbolAddress((void**)&kvl,  g_kvl);
    cudaGetSymbolAddress((void**)&tXh,  g_tXh);
    cudaGetSymbolAddress((void**)&tXl,  g_tXl);
    cudaGetSymbolAddress((void**)&tUKVh, g_tUKVh);
    cudaGetSymbolAddress((void**)&tUKVl, g_tUKVl);
    cudaGetSymbolAddress((void**)&tUQh,  g_tUQh);
    cudaGetSymbolAddress((void**)&tUQl,  g_tUQl);
    cudaGetSymbolAddress((void**)&tQRh,  g_tQRh);
    cudaGetSymbolAddress((void**)&tQRl,  g_tQRl);
    cudaGetSymbolAddress((void**)&tOUTh, g_tOUTh);
    cudaGetSymbolAddress((void**)&tOUTl, g_tOUTl);

    cudaFuncSetAttribute(hgemm_f<2>,  cudaFuncAttributeMaxDynamicSharedMemorySize, HGEMM_SMEM);
    cudaFuncSetAttribute(hgemm_f<3>,  cudaFuncAttributeMaxDynamicSharedMemorySize, HGEMM_SMEM);
    cudaFuncSetAttribute(hgemm_multi, cudaFuncAttributeMaxDynamicSharedMemorySize, HGEMM_SMEM);
    cudaFuncSetAttribute(flash_h,     cudaFuncAttributeMaxDynamicSharedMemorySize, FLASH_SMEM);

    dim3 tb(32, 8);
    // fused tX planes: rows [DKV 0..1023 | DQ 1024..2047 | KR 2048..2111 | lw 2112..2127 | pad]
    transpose32h<<<dim3(DCc/32, Dd/32), tb>>>(W_DKV, tXh,              tXl,              Dd, DCc);
    transpose32h<<<dim3(DCc/32, Dd/32), tb>>>(W_DQ,  tXh + 1024 * Dd,  tXl + 1024 * Dd,  Dd, DCc);
    transpose32h<<<dim3(DHRr/32, Dd/32), tb>>>(W_KR, tXh + 2048 * Dd,  tXl + 2048 * Dd,  Dd, DHRr);
    lwT_kernel<<<(Dd * 16) / 256, 256>>>(W_lw, tXh, tXl);
    transpose32h<<<dim3((NHh*DHh)/32, DCc/32), tb>>>(W_UK, tUKVh,              tUKVl,              DCc, NHh*DHh);
    transpose32h<<<dim3((NHh*DHh)/32, DCc/32), tb>>>(W_UV, tUKVh + 2048 * DCc, tUKVl + 2048 * DCc, DCc, NHh*DHh);
    transpose32h<<<dim3((2*NHh*DHh)/32, DCc/32), tb>>>(W_UQ, tUQh, tUQl, DCc, 2*NHh*DHh);
    transpose32h<<<dim3((2*NHh*DHRr)/32, DCc/32), tb>>>(W_QR, tQRh, tQRl, DCc, 2*NHh*DHRr);
    transpose32h<<<dim3(Dd/32, Dd/32), tb>>>(W_out, tOUTh, tOUTl, Dd, Dd);
    split_kernel<<<(BL * Dd) / 256, 256>>>(x, xh, xl);

    // fused down-projection + kr + lambda-pre (2-term split): tmp[row][NX]
    hgemm_f<2><<<dim3(NX/128, BL/128), 512, HGEMM_SMEM>>>(NX, Dd, xh, xl, tXh, tXl, tmp);
    rms_h<<<BL, 256>>>(tmp,        NX, kv_w, ckvh, ckvl, DCc);
    rms_h<<<BL, 256>>>(tmp + 1024, NX, q_w,  cqh,  cql,  DCc);
    lam_sig<<<(BL * 16) / 256, 256>>>(tmp, W_lb, lam);
    rope_kr<<<(BL * 32) / 256, 256>>>(tmp, krhp, krlp);

    // merged up-projections (UKV + UQ + QR), all K=1024, 2-term split
    hgemm_multi<<<dim3(80, BL/128), 512, HGEMM_SMEM>>>(
        ckvh, ckvl, cqh, cql,
        tUKVh, tUKVl, tUQh, tUQl, tQRh, tQRl,
        kvh, kvl, qchp, qclp, qrhp, qrlp);

    // RoPE on qr planes (in-place)
    rope_qp<<<(BL * 1024) / 256, 256>>>(qrhp, qrlp);

    // attention (fp16 tensor-core flash, longest-first)
    flash_h<<<dim3(Lseq / 64, 32, BB), 128, FLASH_SMEM>>>(
        qchp, qclp, qrhp, qrlp, kvh, kvl, krhp, krlp, attn);

    // combine + output projection (2-term split)
    combine_h<<<(BL * Dd) / 256, 256>>>(attn, lam, preh, prel);
    hgemm_f<2><<<dim3(Dd/128, BL/128), 512, HGEMM_SMEM>>>(Dd, Dd, preh, prel, tOUTh, tOUTl, out);
}

// round 13
// speedup vs baseline: 3.8621x; 1.2930x over previous
#include <cuda_runtime.h>
#include <cuda.h>
#include <cuda_fp16.h>
#include <math.h>
#include <stdint.h>

#define BB   2
#define Lseq 2048
#define BL   4096      // B*L
#define Dd   2048
#define DCc  1024
#define NHh  16
#define DHh  128
#define DHRr 64
#define ATTN_SCALE 0.07216878364870322f
#define NX   2176      // fused down-proj width: [ckv 1024 | cq 1024 | kr 64 | lam 16 | pad 48]

// ======================= scratch =======================
__device__ float g_tmp [BL * NX];
__device__ float g_lam [BL * NHh];
__device__ float g_attn[(size_t)2 * BB * NHh * Lseq * DHh];

// fp16 split planes (activations)
__device__ __half g_xh  [BL * Dd],   g_xl  [BL * Dd];
__device__ __half g_ckvh[BL * DCc],  g_ckvl[BL * DCc];
__device__ __half g_cqh [BL * DCc],  g_cql [BL * DCc];
__device__ __half g_preh[BL * Dd],   g_prel[BL * Dd];
__device__ __half g_qch [BL * 4096], g_qcl [BL * 4096];
__device__ __half g_qrh [BL * 2048], g_qrl [BL * 2048];
__device__ __half g_krh [BL * DHRr], g_krl [BL * DHRr];
__device__ __half g_kvh [BL * 4096], g_kvl [BL * 4096];   // [kc 2048 | v 2048]
// fp16 split planes (transposed weights, [N][K])
__device__ __half g_tXh  [NX * Dd],     g_tXl  [NX * Dd];     // [DKV|DQ|KR|lw|pad0]
__device__ __half g_tUKVh[4096 * DCc],  g_tUKVl[4096 * DCc];  // [UK 2048 | UV 2048]
__device__ __half g_tUQh [4096 * DCc],  g_tUQl [4096 * DCc];
__device__ __half g_tQRh [2048 * DCc],  g_tQRl [2048 * DCc];
__device__ __half g_tOUTh[Dd * Dd],     g_tOUTl[Dd * Dd];

// ======================= helpers =======================
__device__ __forceinline__ uint32_t smem_u32(const void* p) {
    uint32_t a;
    asm("{ .reg .u64 t; cvta.to.shared.u64 t, %1; cvt.u32.u64 %0, t; }" : "=r"(a) : "l"(p));
    return a;
}
__device__ __forceinline__ void cp16(uint32_t dst, const void* src) {
    asm volatile("cp.async.cg.shared.global [%0], [%1], 16;" :: "r"(dst), "l"(src));
}
#define CP_COMMIT() asm volatile("cp.async.commit_group;" ::: "memory")
#define CP_WAIT0()  asm volatile("cp.async.wait_group 0;"  ::: "memory")

__device__ __forceinline__ void mma_f16(float c[4],
                                        uint32_t a0, uint32_t a1, uint32_t a2, uint32_t a3,
                                        uint32_t b0, uint32_t b1)
{
    asm volatile(
        "mma.sync.aligned.m16n8k16.row.col.f32.f16.f16.f32 "
        "{%0,%1,%2,%3}, {%4,%5,%6,%7}, {%8,%9}, {%0,%1,%2,%3};"
        : "+f"(c[0]), "+f"(c[1]), "+f"(c[2]), "+f"(c[3])
        : "r"(a0), "r"(a1), "r"(a2), "r"(a3), "r"(b0), "r"(b1));
}

__device__ __forceinline__ void split16(float v, __half& h, __half& l) {
    h = __float2half_rn(v);
    l = __float2half_rn(v - __half2float(h));
}

// ======================= transpose + split: in[R][C] -> hi/lo[C][R] =======================
__global__ void transpose32h(const float* __restrict__ in,
                             __half* __restrict__ oh, __half* __restrict__ ol, int R, int C)
{
    __shared__ float t[32][33];
    int bx = blockIdx.x * 32, by = blockIdx.y * 32;
    int x = bx + threadIdx.x;
    #pragma unroll
    for (int j = 0; j < 32; j += 8)
        t[threadIdx.y + j][threadIdx.x] = in[(size_t)(by + threadIdx.y + j) * C + x];
    __syncthreads();
    int ox = by + threadIdx.x;
    #pragma unroll
    for (int j = 0; j < 32; j += 8) {
        float v = t[threadIdx.x][threadIdx.y + j];
        __half h, l; split16(v, h, l);
        size_t o = (size_t)(bx + threadIdx.y + j) * R + ox;
        oh[o] = h; ol[o] = l;
    }
}

// W_lw [2048][16] -> rows 2112..2127 of tX planes
__global__ void lwT_kernel(const float* __restrict__ Wl,
                           __half* __restrict__ oh, __half* __restrict__ ol)
{
    int idx = blockIdx.x * 256 + threadIdx.x;   // 2048*16
    int k = idx >> 4, n = idx & 15;
    float v = Wl[idx];
    __half h, l; split16(v, h, l);
    size_t o = (size_t)(2112 + n) * Dd + k;
    oh[o] = h; ol[o] = l;
}

// ======================= elementwise split =======================
__global__ void split_kernel(const float* __restrict__ in,
                             __half* __restrict__ oh, __half* __restrict__ ol)
{
    int idx = blockIdx.x * 256 + threadIdx.x;
    float v = in[idx];
    __half h, l; split16(v, h, l);
    oh[idx] = h; ol[idx] = l;
}

// ======================= fp16-split tensor-core GEMM =======================
// TERMS=3: D = al*bh + ah*bl + ah*bh (err ~2^-22)
// TERMS=2: D = al*bh + ah*bh          (err ~2^-12, B-lo plane not staged)
#define WSTR 20
#define HGEMM_SMEM (2 * 4 * 128 * WSTR * 4)   // 81920 B

template<int TERMS>
__device__ __forceinline__ void hgemm_body(
    int N, int K, int m0, int n0,
    const __half* __restrict__ Ahi, const __half* __restrict__ Alo,
    const __half* __restrict__ Bhi, const __half* __restrict__ Blo,
    uint32_t* smw, float acc[2][4][4])
{
    uint32_t* buf[2] = { smw, smw + 4 * 128 * WSTR };
    const int tid = threadIdx.x;
    const int wid = tid >> 5, lane = tid & 31;
    const int warpM = (wid >> 2) * 32;
    const int warpN = (wid & 3) * 32;
    const int lr = lane >> 2, lc = lane & 3;

    const __half* Ap[2] = { Ahi + (size_t)m0 * K, Alo + (size_t)m0 * K };
    const __half* Bp[2] = { Bhi + (size_t)n0 * K, Blo + (size_t)n0 * K };

    const int r = tid >> 2;
    const int q = (tid & 3) * 4;

    auto stage = [&](int kc, int b) {
        uint32_t base = smem_u32(buf[b]);
        cp16(base + (uint32_t)((r) * WSTR + q) * 4u,
             Ap[0] + (size_t)r * K + kc + q * 2);
        cp16(base + (uint32_t)((128 + r) * WSTR + q) * 4u,
             Ap[1] + (size_t)r * K + kc + q * 2);
        cp16(base + (uint32_t)((2 * 128 + r) * WSTR + q) * 4u,
             Bp[0] + (size_t)r * K + kc + q * 2);
        if (TERMS == 3)
            cp16(base + (uint32_t)((3 * 128 + r) * WSTR + q) * 4u,
                 Bp[1] + (size_t)r * K + kc + q * 2);
        CP_COMMIT();
    };

    #pragma unroll
    for (int i = 0; i < 2; i++)
        #pragma unroll
        for (int j = 0; j < 4; j++)
            #pragma unroll
            for (int k = 0; k < 4; k++) acc[i][j][k] = 0.f;

    stage(0, 0);

    const int nch = K >> 5;
    for (int i = 0; i < nch; i++) {
        CP_WAIT0();
        __syncthreads();
        if (i + 1 < nch) stage((i + 1) << 5, (i + 1) & 1);

        const uint32_t* Ah = buf[i & 1];
        const uint32_t* Al = Ah + 128 * WSTR;
        const uint32_t* Bh = Ah + 2 * 128 * WSTR;
        const uint32_t* Bl = Ah + 3 * 128 * WSTR;

        #pragma unroll
        for (int s = 0; s < 2; s++) {
            uint32_t ah[2][4], al[2][4], bhf[4][2], blf[4][2];
            #pragma unroll
            for (int ma = 0; ma < 2; ma++) {
                int rw = (warpM + ma * 16 + lr) * WSTR + s * 8 + lc;
                ah[ma][0] = Ah[rw];
                ah[ma][1] = Ah[rw + 8 * WSTR];
                ah[ma][2] = Ah[rw + 4];
                ah[ma][3] = Ah[rw + 8 * WSTR + 4];
                al[ma][0] = Al[rw];
                al[ma][1] = Al[rw + 8 * WSTR];
                al[ma][2] = Al[rw + 4];
                al[ma][3] = Al[rw + 8 * WSTR + 4];
            }
            #pragma unroll
            for (int nb = 0; nb < 4; nb++) {
                int cw = (warpN + nb * 8 + lr) * WSTR + s * 8 + lc;
                bhf[nb][0] = Bh[cw]; bhf[nb][1] = Bh[cw + 4];
                if (TERMS == 3) { blf[nb][0] = Bl[cw]; blf[nb][1] = Bl[cw + 4]; }
            }
            #pragma unroll
            for (int nb = 0; nb < 4; nb++)
                #pragma unroll
                for (int ma = 0; ma < 2; ma++)
                    mma_f16(acc[ma][nb], al[ma][0], al[ma][1], al[ma][2], al[ma][3],
                            bhf[nb][0], bhf[nb][1]);
            if (TERMS == 3) {
                #pragma unroll
                for (int nb = 0; nb < 4; nb++)
                    #pragma unroll
                    for (int ma = 0; ma < 2; ma++)
                        mma_f16(acc[ma][nb], ah[ma][0], ah[ma][1], ah[ma][2], ah[ma][3],
                                blf[nb][0], blf[nb][1]);
            }
            #pragma unroll
            for (int nb = 0; nb < 4; nb++)
                #pragma unroll
                for (int ma = 0; ma < 2; ma++)
                    mma_f16(acc[ma][nb], ah[ma][0], ah[ma][1], ah[ma][2], ah[ma][3],
                            bhf[nb][0], bhf[nb][1]);
        }
        __syncthreads();
    }
}

template<int TERMS>
__global__ __launch_bounds__(512)
void hgemm_f(int N, int K,
             const __half* __restrict__ Ahi, const __half* __restrict__ Alo,
             const __half* __restrict__ Bhi, const __half* __restrict__ Blo,
             float* __restrict__ C)
{
    extern __shared__ float smraw[];
    float acc[2][4][4];
    const int m0 = blockIdx.y * 128, n0 = blockIdx.x * 128;
    hgemm_body<TERMS>(N, K, m0, n0, Ahi, Alo, Bhi, Blo, (uint32_t*)smraw, acc);

    const int wid = threadIdx.x >> 5, lane = threadIdx.x & 31;
    const int warpM = (wid >> 2) * 32, warpN = (wid & 3) * 32;
    const int lr = lane >> 2, lc = lane & 3;
    #pragma unroll
    for (int ma = 0; ma < 2; ma++) {
        int row = m0 + warpM + ma * 16 + lr;
        #pragma unroll
        for (int nb = 0; nb < 4; nb++) {
            int col = n0 + warpN + nb * 8 + lc * 2;
            *(float2*)(C + (size_t)row * N + col)       = make_float2(acc[ma][nb][0], acc[ma][nb][1]);
            *(float2*)(C + (size_t)(row + 8) * N + col) = make_float2(acc[ma][nb][2], acc[ma][nb][3]);
        }
    }
}

// merged K=1024 launch: seg0 (32 tiles) ckv@UKV->kv, seg1 (32) cq@UQ->qc, seg2 (16) cq@QR->qr
__global__ __launch_bounds__(512)
void hgemm_multi(const __half* __restrict__ ckvh, const __half* __restrict__ ckvl,
                 const __half* __restrict__ cqh,  const __half* __restrict__ cql,
                 const __half* __restrict__ tUKVh, const __half* __restrict__ tUKVl,
                 const __half* __restrict__ tUQh,  const __half* __restrict__ tUQl,
                 const __half* __restrict__ tQRh,  const __half* __restrict__ tQRl,
                 __half* __restrict__ kvh, __half* __restrict__ kvl,
                 __half* __restrict__ qch, __half* __restrict__ qcl,
                 __half* __restrict__ qrh, __half* __restrict__ qrl)
{
    extern __shared__ float smraw[];
    const int bx = blockIdx.x;
    const __half *Ahp, *Alp, *Bhp, *Blp;
    __half *Chp, *Clp;
    int N, nloc;
    if (bx < 32)      { Ahp = ckvh; Alp = ckvl; Bhp = tUKVh; Blp = tUKVl; Chp = kvh; Clp = kvl; N = 4096; nloc = bx; }
    else if (bx < 64) { Ahp = cqh;  Alp = cql;  Bhp = tUQh;  Blp = tUQl;  Chp = qch; Clp = qcl; N = 4096; nloc = bx - 32; }
    else              { Ahp = cqh;  Alp = cql;  Bhp = tQRh;  Blp = tQRl;  Chp = qrh; Clp = qrl; N = 2048; nloc = bx - 64; }

    float acc[2][4][4];
    const int m0 = blockIdx.y * 128, n0 = nloc * 128;
    hgemm_body<2>(N, 1024, m0, n0, Ahp, Alp, Bhp, Blp, (uint32_t*)smraw, acc);

    const int wid = threadIdx.x >> 5, lane = threadIdx.x & 31;
    const int warpM = (wid >> 2) * 32, warpN = (wid & 3) * 32;
    const int lr = lane >> 2, lc = lane & 3;
    #pragma unroll
    for (int ma = 0; ma < 2; ma++) {
        int row = m0 + warpM + ma * 16 + lr;
        #pragma unroll
        for (int nb = 0; nb < 4; nb++) {
            int col = n0 + warpN + nb * 8 + lc * 2;
            float x0 = acc[ma][nb][0], x1 = acc[ma][nb][1];
            __half2 h2 = __floats2half2_rn(x0, x1);
            float2 hf = __half22float2(h2);
            __half2 l2 = __floats2half2_rn(x0 - hf.x, x1 - hf.y);
            *(__half2*)(Chp + (size_t)row * N + col) = h2;
            *(__half2*)(Clp + (size_t)row * N + col) = l2;
            float y0 = acc[ma][nb][2], y1 = acc[ma][nb][3];
            __half2 h3 = __floats2half2_rn(y0, y1);
            float2 hg = __half22float2(h3);
            __half2 l3 = __floats2half2_rn(y0 - hg.x, y1 - hg.y);
            *(__half2*)(Chp + (size_t)(row + 8) * N + col) = h3;
            *(__half2*)(Clp + (size_t)(row + 8) * N + col) = l3;
        }
    }
}

// ======================= RMS norm (strided input) -> fp16 split planes =======================
__global__ void rms_h(const float* __restrict__ in, int instride,
                      const float* __restrict__ w,
                      __half* __restrict__ oh, __half* __restrict__ ol, int N)
{
    int row = blockIdx.x;
    const float* ir = in + (size_t)row * instride;
    float s = 0.f;
    for (int i = threadIdx.x; i < N; i += 256) { float v = ir[i]; s += v * v; }
    __shared__ float red[256];
    red[threadIdx.x] = s;
    __syncthreads();
    for (int st = 128; st > 0; st >>= 1) {
        if (threadIdx.x < st) red[threadIdx.x] += red[threadIdx.x + st];
        __syncthreads();
    }
    float rr = rsqrtf(red[0] / (float)N + 1e-6f);
    for (int i = threadIdx.x; i < N; i += 256) {
        float v = ir[i] * rr * w[i];
        __half h, l; split16(v, h, l);
        oh[(size_t)row * N + i] = h;
        ol[(size_t)row * N + i] = l;
    }
}

// ======================= lambda sigmoid (from fused tmp cols) =======================
__global__ void lam_sig(const float* __restrict__ tmp, const float* __restrict__ bl,
                        float* __restrict__ lam)
{
    int idx = blockIdx.x * 256 + threadIdx.x;   // BL*16
    int row = idx >> 4, n = idx & 15;
    float z = tmp[(size_t)row * NX + 2112 + n] + bl[n];
    lam[idx] = 1.f / (1.f + expf(-z));
}

// ======================= RoPE kr (from fused tmp cols) -> planes =======================
__global__ void rope_kr(const float* __restrict__ tmp,
                        __half* __restrict__ oh, __half* __restrict__ ol)
{
    int idx = blockIdx.x * 256 + threadIdx.x;   // BL*32
    int j = idx & 31, row = idx >> 5;
    int l = row & (Lseq - 1);
    float inv = powf(10000.f, -(float)(2 * j) / 64.f);
    float ang = (float)l * inv;
    float c = cosf(ang), s = sinf(ang);
    const float* base = tmp + (size_t)row * NX + 2048;
    float x1 = base[j], x2 = base[j + 32];
    float y1 = x1 * c - x2 * s;
    float y2 = x2 * c + x1 * s;
    size_t o = (size_t)row * 64;
    __half hh, ll;
    split16(y1, hh, ll); oh[o + j] = hh;      ol[o + j] = ll;
    split16(y2, hh, ll); oh[o + j + 32] = hh; ol[o + j + 32] = ll;
}

// ======================= RoPE qr (in-place on split planes) =======================
__global__ void rope_qp(__half* __restrict__ ph, __half* __restrict__ pl)
{
    int idx = blockIdx.x * 256 + threadIdx.x;   // BL*32*32
    int j = idx & 31;
    int h = (idx >> 5) & 31;
    int row = idx >> 10;
    int l = row & (Lseq - 1);
    float inv = powf(10000.f, -(float)(2 * j) / 64.f);
    float ang = (float)l * inv;
    float c = cosf(ang), s = sinf(ang);
    size_t o = (size_t)row * 2048 + h * 64;
    float x1 = __half2float(ph[o + j])      + __half2float(pl[o + j]);
    float x2 = __half2float(ph[o + j + 32]) + __half2float(pl[o + j + 32]);
    float y1 = x1 * c - x2 * s;
    float y2 = x2 * c + x1 * s;
    __half hh, ll;
    split16(y1, hh, ll); ph[o + j] = hh;      pl[o + j] = ll;
    split16(y2, hh, ll); ph[o + j + 32] = hh; pl[o + j + 32] = ll;
}

// ======================= tensor-core flash attention (2xFP16, pre-split planes) =====
// smem words: qs0 6400 | qs1 6400 | ks 3200 | vs 2176 | ps0 1280 | ps1 1280 = 20736
#define FLASH_SMEM (20736 * 4)   // 82944 B -> 2 CTAs/SM
__global__ __launch_bounds__(128)
void flash_h(const __half* __restrict__ qch, const __half* __restrict__ qcl,
             const __half* __restrict__ qrh, const __half* __restrict__ qrl,
             const __half* __restrict__ kvh, const __half* __restrict__ kvl,
             const __half* __restrict__ krh, const __half* __restrict__ krl,
             float* __restrict__ attn)
{
    extern __shared__ uint32_t smw[];
    uint32_t* qs[2] = { smw,         smw + 6400 };
    uint32_t* ks    = smw + 12800;
    uint32_t* vs    = smw + 16000;
    uint32_t* ps[2] = { smw + 18176, smw + 19456 };

    const int Q0 = (gridDim.x - 1 - blockIdx.x) * 64;
    const int head2 = blockIdx.y;
    const int b = blockIdx.z;
    const int hn = head2 >> 1, hp = head2 & 1;
    const int tid = threadIdx.x;
    const int lane = tid & 31, w = tid >> 5;
    const int lr = lane >> 2, lc = lane & 3;

    const size_t tq = (size_t)(b * Lseq + Q0);

    {
        const __half* qcp[2] = { qch + tq * 4096 + head2 * 128, qcl + tq * 4096 + head2 * 128 };
        const __half* qrp[2] = { qrh + tq * 2048 + head2 * 64,  qrl + tq * 2048 + head2 * 64 };
        #pragma unroll
        for (int p = 0; p < 2; p++) {
            uint32_t qb = smem_u32(qs[p]);
            #pragma unroll
            for (int i = 0; i < 8; i++) {
                int s2 = tid + i * 128;
                int r = s2 >> 4, c = s2 & 15;
                cp16(qb + (uint32_t)(r * 100 + c * 4) * 4u, qcp[p] + (size_t)r * 4096 + c * 8);
            }
            #pragma unroll
            for (int i = 0; i < 4; i++) {
                int s2 = tid + i * 128;
                int r = s2 >> 3, c = s2 & 7;
                cp16(qb + (uint32_t)(r * 100 + 64 + c * 4) * 4u, qrp[p] + (size_t)r * 2048 + c * 8);
            }
        }
        CP_COMMIT();
    }

    float o[16][4];
    #pragma unroll
    for (int i = 0; i < 16; i++) { o[i][0] = o[i][1] = o[i][2] = o[i][3] = 0.f; }
    float m0 = -INFINITY, m1 = -INFINITY, l0 = 0.f, l1 = 0.f;

    const int row0g = Q0 + 16 * w + lr;
    const int row1g = row0g + 8;
    const int prow0 = (16 * w + lr) * 20;
    const int arow0 = (16 * w + lr) * 100;

    const int ntile = (Q0 + 64) >> 5;
    for (int t = 0; t < ntile; t++) {
        const int k0 = t << 5;
        __syncthreads();
        // ---- stage K (hi only: kc|kr) and V (hi only) ----
        {
            const size_t tk = (size_t)(b * Lseq + k0);
            const __half* kcp = kvh + tk * 4096 + hn * 128;
            const __half* vp  = kvh + tk * 4096 + 2048 + hn * 128;
            const __half* krp = krh + tk * 64;
            uint32_t kb = smem_u32(ks);
            uint32_t vb = smem_u32(vs);
            #pragma unroll
            for (int i = 0; i < 4; i++) {
                int s2 = tid + i * 128;
                int r = s2 >> 4, c = s2 & 15;
                cp16(kb + (uint32_t)(r * 100 + c * 4) * 4u, kcp + (size_t)r * 4096 + c * 8);
                cp16(vb + (uint32_t)(r * 68 + c * 4) * 4u,  vp  + (size_t)r * 4096 + c * 8);
            }
            #pragma unroll
            for (int i = 0; i < 2; i++) {
                int s2 = tid + i * 128;
                int r = s2 >> 3, c = s2 & 7;
                cp16(kb + (uint32_t)(r * 100 + 64 + c * 4) * 4u, krp + (size_t)r * 64 + c * 8);
            }
            CP_COMMIT();
            CP_WAIT0();
            __syncthreads();
        }

        // ---- S = Q @ K^T (2xFP16: al*bh + ah*bh) ----
        float s4[4][4];
        #pragma unroll
        for (int nt = 0; nt < 4; nt++) { s4[nt][0] = s4[nt][1] = s4[nt][2] = s4[nt][3] = 0.f; }

        #pragma unroll 4
        for (int s = 0; s < 12; s++) {
            const int ab = arow0 + s * 8 + lc;
            uint32_t ah0 = qs[0][ab],       ah1 = qs[0][ab + 800];
            uint32_t ah2 = qs[0][ab + 4],   ah3 = qs[0][ab + 804];
            uint32_t al0 = qs[1][ab],       al1 = qs[1][ab + 800];
            uint32_t al2 = qs[1][ab + 4],   al3 = qs[1][ab + 804];
            #pragma unroll
            for (int nt = 0; nt < 4; nt++) {
                const int cb = (nt * 8 + lr) * 100 + s * 8 + lc;
                uint32_t bh0 = ks[cb], bh1 = ks[cb + 4];
                mma_f16(s4[nt], al0, al1, al2, al3, bh0, bh1);
                mma_f16(s4[nt], ah0, ah1, ah2, ah3, bh0, bh1);
            }
        }

        // ---- mask + scale + online softmax ----
        float tmax0 = -INFINITY, tmax1 = -INFINITY;
        #pragma unroll
        for (int nt = 0; nt < 4; nt++) {
            const int colg = k0 + nt * 8 + 2 * lc;
            s4[nt][0] = (colg     <= row0g) ? s4[nt][0] * ATTN_SCALE : -INFINITY;
            s4[nt][1] = (colg + 1 <= row0g) ? s4[nt][1] * ATTN_SCALE : -INFINITY;
            s4[nt][2] = (colg     <= row1g) ? s4[nt][2] * ATTN_SCALE : -INFINITY;
            s4[nt][3] = (colg + 1 <= row1g) ? s4[nt][3] * ATTN_SCALE : -INFINITY;
            tmax0 = fmaxf(tmax0, fmaxf(s4[nt][0], s4[nt][1]));
            tmax1 = fmaxf(tmax1, fmaxf(s4[nt][2], s4[nt][3]));
        }
        tmax0 = fmaxf(tmax0, __shfl_xor_sync(0xffffffffu, tmax0, 1));
        tmax0 = fmaxf(tmax0, __shfl_xor_sync(0xffffffffu, tmax0, 2));
        tmax1 = fmaxf(tmax1, __shfl_xor_sync(0xffffffffu, tmax1, 1));
        tmax1 = fmaxf(tmax1, __shfl_xor_sync(0xffffffffu, tmax1, 2));

        const float mn0 = fmaxf(m0, tmax0), mn1 = fmaxf(m1, tmax1);
        const float scl0 = expf(m0 - mn0);
        const float scl1 = expf(m1 - mn1);

        float p4[4][4];
        float pr0 = 0.f, pr1 = 0.f;
        #pragma unroll
        for (int nt = 0; nt < 4; nt++) {
            p4[nt][0] = expf(s4[nt][0] - mn0);
            p4[nt][1] = expf(s4[nt][1] - mn0);
            p4[nt][2] = expf(s4[nt][2] - mn1);
            p4[nt][3] = expf(s4[nt][3] - mn1);
            pr0 += p4[nt][0] + p4[nt][1];
            pr1 += p4[nt][2] + p4[nt][3];
        }
        pr0 += __shfl_xor_sync(0xffffffffu, pr0, 1);
        pr0 += __shfl_xor_sync(0xffffffffu, pr0, 2);
        pr1 += __shfl_xor_sync(0xffffffffu, pr1, 1);
        pr1 += __shfl_xor_sync(0xffffffffu, pr1, 2);

        l0 = l0 * scl0 + pr0;
        l1 = l1 * scl1 + pr1;
        m0 = mn0; m1 = mn1;

        #pragma unroll
        for (int i = 0; i < 16; i++) {
            o[i][0] *= scl0; o[i][1] *= scl0;
            o[i][2] *= scl1; o[i][3] *= scl1;
        }

        // ---- split P into fp16 planes (per-warp private rows) ----
        #pragma unroll
        for (int nt = 0; nt < 4; nt++) {
            __half2 h0 = __floats2half2_rn(p4[nt][0], p4[nt][1]);
            float2 f0 = __half22float2(h0);
            __half2 e0 = __floats2half2_rn(p4[nt][0] - f0.x, p4[nt][1] - f0.y);
            ((__half2*)ps[0])[prow0 + nt * 4 + lc] = h0;
            ((__half2*)ps[1])[prow0 + nt * 4 + lc] = e0;
            __half2 h1 = __floats2half2_rn(p4[nt][2], p4[nt][3]);
            float2 f1 = __half22float2(h1);
            __half2 e1 = __floats2half2_rn(p4[nt][2] - f1.x, p4[nt][3] - f1.y);
            ((__half2*)ps[0])[prow0 + 160 + nt * 4 + lc] = h1;
            ((__half2*)ps[1])[prow0 + 160 + nt * 4 + lc] = e1;
        }
        __syncwarp();

        // ---- O += P @ V (2xFP16: pl*vh + ph*vh) ----
        const uint16_t* vhp = (const uint16_t*)vs;
        #pragma unroll
        for (int s = 0; s < 2; s++) {
            const int pb = prow0 + s * 8 + lc;
            uint32_t ah0 = ps[0][pb],     ah1 = ps[0][pb + 160];
            uint32_t ah2 = ps[0][pb + 4], ah3 = ps[0][pb + 164];
            uint32_t al0 = ps[1][pb],     al1 = ps[1][pb + 160];
            uint32_t al2 = ps[1][pb + 4], al3 = ps[1][pb + 164];
            const int kb = s * 16 + 2 * lc;
            #pragma unroll
            for (int nt2 = 0; nt2 < 16; nt2++) {
                const int d = nt2 * 8 + lr;
                uint32_t bh0 = (uint32_t)vhp[kb * 136 + d]       | ((uint32_t)vhp[(kb + 1) * 136 + d] << 16);
                uint32_t bh1 = (uint32_t)vhp[(kb + 8) * 136 + d] | ((uint32_t)vhp[(kb + 9) * 136 + d] << 16);
                mma_f16(o[nt2], al0, al1, al2, al3, bh0, bh1);
                mma_f16(o[nt2], ah0, ah1, ah2, ah3, bh0, bh1);
            }
        }
    }

    const float inv0 = 1.f / l0, inv1 = 1.f / l1;
    const size_t obase = ((size_t)(b * 2 + hp) * NHh + hn) * Lseq;
    float* op0 = attn + (obase + row0g) * 128;
    float* op1 = attn + (obase + row1g) * 128;
    #pragma unroll
    for (int nt2 = 0; nt2 < 16; nt2++) {
        *(float2*)(op0 + nt2 * 8 + 2 * lc) = make_float2(o[nt2][0] * inv0, o[nt2][1] * inv0);
        *(float2*)(op1 + nt2 * 8 + 2 * lc) = make_float2(o[nt2][2] * inv1, o[nt2][3] * inv1);
    }
}

// ======================= combine -> fp16 split planes =======================
__global__ void combine_h(const float* __restrict__ attn, const float* __restrict__ lam,
                          __half* __restrict__ oh, __half* __restrict__ ol)
{
    int idx = blockIdx.x * 256 + threadIdx.x;
    int c = idx & 2047;
    int row = idx >> 11;
    int b = row >> 11;
    int l = row & 2047;
    int n = c >> 7, d = c & 127;
    size_t a1 = (((size_t)(b * 2 + 0) * NHh + n) * Lseq + l) * 128 + d;
    size_t a2 = (((size_t)(b * 2 + 1) * NHh + n) * Lseq + l) * 128 + d;
    float v = attn[a1] - lam[(size_t)row * 16 + n] * attn[a2];
    __half h, lo; split16(v, h, lo);
    oh[idx] = h; ol[idx] = lo;
}

// ======================= launch =======================
extern "C" void kernel_launch(void* const* d_in, const int* in_sizes, int n_in,
                              void* d_out, int out_size)
{
    const float* x     = (const float*)d_in[0];
    const float* W_DKV = (const float*)d_in[1];
    const float* kv_w  = (const float*)d_in[2];
    const float* W_UK  = (const float*)d_in[3];
    const float* W_UV  = (const float*)d_in[4];
    const float* W_DQ  = (const float*)d_in[5];
    const float* q_w   = (const float*)d_in[6];
    const float* W_UQ  = (const float*)d_in[7];
    const float* W_QR  = (const float*)d_in[8];
    const float* W_KR  = (const float*)d_in[9];
    const float* W_lw  = (const float*)d_in[10];
    const float* W_lb  = (const float*)d_in[11];
    const float* W_out = (const float*)d_in[12];
    float* out = (float*)d_out;

    float *tmp, *lam, *attn;
    __half *xh, *xl, *ckvh, *ckvl, *cqh, *cql, *preh, *prel;
    __half *qchp, *qclp, *qrhp, *qrlp, *krhp, *krlp, *kvh, *kvl;
    __half *tXh, *tXl, *tUKVh, *tUKVl, *tUQh, *tUQl, *tQRh, *tQRl, *tOUTh, *tOUTl;
    cudaGetSymbolAddress((void**)&tmp,  g_tmp);
    cudaGetSymbolAddress((void**)&lam,  g_lam);
    cudaGetSymbolAddress((void**)&attn, g_attn);
    cudaGetSymbolAddress((void**)&xh,   g_xh);
    cudaGetSymbolAddress((void**)&xl,   g_xl);
    cudaGetSymbolAddress((void**)&ckvh, g_ckvh);
    cudaGetSymbolAddress((void**)&ckvl, g_ckvl);
    cudaGetSymbolAddress((void**)&cqh,  g_cqh);
    cudaGetSymbolAddress((void**)&cql,  g_cql);
    cudaGetSymbolAddress((void**)&preh, g_preh);
    cudaGetSymbolAddress((void**)&prel, g_prel);
    cudaGetSymbolAddress((void**)&qchp, g_qch);
    cudaGetSymbolAddress((void**)&qclp, g_qcl);
    cudaGetSymbolAddress((void**)&qrhp, g_qrh);
    cudaGetSymbolAddress((void**)&qrlp, g_qrl);
    cudaGetSymbolAddress((void**)&krhp, g_krh);
    cudaGetSymbolAddress((void**)&krlp, g_krl);
    cudaGetSymbolAddress((void**)&kvh,  g_kvh);
    cudaGetSymbolAddress((void**)&kvl,  g_kvl);
    cudaGetSymbolAddress((void**)&tXh,  g_tXh);
    cudaGetSymbolAddress((void**)&tXl,  g_tXl);
    cudaGetSymbolAddress((void**)&tUKVh, g_tUKVh);
    cudaGetSymbolAddress((void**)&tUKVl, g_tUKVl);
    cudaGetSymbolAddress((void**)&tUQh,  g_tUQh);
    cudaGetSymbolAddress((void**)&tUQl,  g_tUQl);
    cudaGetSymbolAddress((void**)&tQRh,  g_tQRh);
    cudaGetSymbolAddress((void**)&tQRl,  g_tQRl);
    cudaGetSymbolAddress((void**)&tOUTh, g_tOUTh);
    cudaGetSymbolAddress((void**)&tOUTl, g_tOUTl);

    cudaFuncSetAttribute(hgemm_f<2>,  cudaFuncAttributeMaxDynamicSharedMemorySize, HGEMM_SMEM);
    cudaFuncSetAttribute(hgemm_multi, cudaFuncAttributeMaxDynamicSharedMemorySize, HGEMM_SMEM);
    cudaFuncSetAttribute(flash_h,     cudaFuncAttributeMaxDynamicSharedMemorySize, FLASH_SMEM);

    dim3 tb(32, 8);
    // fused tX planes: rows [DKV 0..1023 | DQ 1024..2047 | KR 2048..2111 | lw 2112..2127 | pad]
    transpose32h<<<dim3(DCc/32, Dd/32), tb>>>(W_DKV, tXh,              tXl,              Dd, DCc);
    transpose32h<<<dim3(DCc/32, Dd/32), tb>>>(W_DQ,  tXh + 1024 * Dd,  tXl + 1024 * Dd,  Dd, DCc);
    transpose32h<<<dim3(DHRr/32, Dd/32), tb>>>(W_KR, tXh + 2048 * Dd,  tXl + 2048 * Dd,  Dd, DHRr);
    lwT_kernel<<<(Dd * 16) / 256, 256>>>(W_lw, tXh, tXl);
    transpose32h<<<dim3((NHh*DHh)/32, DCc/32), tb>>>(W_UK, tUKVh,              tUKVl,              DCc, NHh*DHh);
    transpose32h<<<dim3((NHh*DHh)/32, DCc/32), tb>>>(W_UV, tUKVh + 2048 * DCc, tUKVl + 2048 * DCc, DCc, NHh*DHh);
    transpose32h<<<dim3((2*NHh*DHh)/32, DCc/32), tb>>>(W_UQ, tUQh, tUQl, DCc, 2*NHh*DHh);
    transpose32h<<<dim3((2*NHh*DHRr)/32, DCc/32), tb>>>(W_QR, tQRh, tQRl, DCc, 2*NHh*DHRr);
    transpose32h<<<dim3(Dd/32, Dd/32), tb>>>(W_out, tOUTh, tOUTl, Dd, Dd);
    split_kernel<<<(BL * Dd) / 256, 256>>>(x, xh, xl);

    // fused down-projection + kr + lambda-pre (2-term split): tmp[row][NX]
    hgemm_f<2><<<dim3(NX/128, BL/128), 512, HGEMM_SMEM>>>(NX, Dd, xh, xl, tXh, tXl, tmp);
    rms_h<<<BL, 256>>>(tmp,        NX, kv_w, ckvh, ckvl, DCc);
    rms_h<<<BL, 256>>>(tmp + 1024, NX, q_w,  cqh,  cql,  DCc);
    lam_sig<<<(BL * 16) / 256, 256>>>(tmp, W_lb, lam);
    rope_kr<<<(BL * 32) / 256, 256>>>(tmp, krhp, krlp);

    // merged up-projections (UKV + UQ + QR), all K=1024, 2-term split
    hgemm_multi<<<dim3(80, BL/128), 512, HGEMM_SMEM>>>(
        ckvh, ckvl, cqh, cql,
        tUKVh, tUKVl, tUQh, tUQl, tQRh, tQRl,
        kvh, kvl, qchp, qclp, qrhp, qrlp);

    // RoPE on qr planes (in-place)
    rope_qp<<<(BL * 1024) / 256, 256>>>(qrhp, qrlp);

    // attention (fp16 tensor-core flash, 2-term, longest-first)
    flash_h<<<dim3(Lseq / 64, 32, BB), 128, FLASH_SMEM>>>(
        qchp, qclp, qrhp, qrlp, kvh, kvl, krhp, krlp, attn);

    // combine + output projection (2-term split)
    combine_h<<<(BL * Dd) / 256, 256>>>(attn, lam, preh, prel);
    hgemm_f<2><<<dim3(Dd/128, BL/128), 512, HGEMM_SMEM>>>(Dd, Dd, preh, prel, tOUTh, tOUTl, out);
}

// round 14
// speedup vs baseline: 3.8679x; 1.0015x over previous
#include <cuda_runtime.h>
#include <cuda.h>
#include <cuda_fp16.h>
#include <math.h>
#include <stdint.h>

#define BB   2
#define Lseq 2048
#define BL   4096      // B*L
#define Dd   2048
#define DCc  1024
#define NHh  16
#define DHh  128
#define DHRr 64
#define ATTN_SCALE 0.07216878364870322f
#define NX   2176      // fused down-proj width: [ckv 1024 | cq 1024 | kr 64 | lam 16 | pad 48]

// ======================= scratch =======================
__device__ float g_tmp [BL * NX];
__device__ float g_lam [BL * NHh];
__device__ float g_attn[(size_t)2 * BB * NHh * Lseq * DHh];

// fp16 split planes (activations)
__device__ __half g_xh  [BL * Dd],   g_xl  [BL * Dd];
__device__ __half g_ckvh[BL * DCc],  g_ckvl[BL * DCc];
__device__ __half g_cqh [BL * DCc],  g_cql [BL * DCc];
__device__ __half g_preh[BL * Dd],   g_prel[BL * Dd];
__device__ __half g_qch [BL * 4096], g_qcl [BL * 4096];
__device__ __half g_qrh [BL * 2048], g_qrl [BL * 2048];
__device__ __half g_krh [BL * DHRr], g_krl [BL * DHRr];
__device__ __half g_kvh [BL * 4096], g_kvl [BL * 4096];   // [kc 2048 | v 2048]
// fp16 split planes (transposed weights, [N][K])
__device__ __half g_tXh  [NX * Dd],     g_tXl  [NX * Dd];     // [DKV|DQ|KR|lw|pad0]
__device__ __half g_tUKVh[4096 * DCc],  g_tUKVl[4096 * DCc];  // [UK 2048 | UV 2048]
__device__ __half g_tUQh [4096 * DCc],  g_tUQl [4096 * DCc];
__device__ __half g_tQRh [2048 * DCc],  g_tQRl [2048 * DCc];
__device__ __half g_tOUTh[Dd * Dd],     g_tOUTl[Dd * Dd];

// ======================= helpers =======================
__device__ __forceinline__ uint32_t smem_u32(const void* p) {
    uint32_t a;
    asm("{ .reg .u64 t; cvta.to.shared.u64 t, %1; cvt.u32.u64 %0, t; }" : "=r"(a) : "l"(p));
    return a;
}
__device__ __forceinline__ void cp16(uint32_t dst, const void* src) {
    asm volatile("cp.async.cg.shared.global [%0], [%1], 16;" :: "r"(dst), "l"(src));
}
#define CP_COMMIT() asm volatile("cp.async.commit_group;" ::: "memory")
#define CP_WAIT0()  asm volatile("cp.async.wait_group 0;"  ::: "memory")

__device__ __forceinline__ void mma_f16(float c[4],
                                        uint32_t a0, uint32_t a1, uint32_t a2, uint32_t a3,
                                        uint32_t b0, uint32_t b1)
{
    asm volatile(
        "mma.sync.aligned.m16n8k16.row.col.f32.f16.f16.f32 "
        "{%0,%1,%2,%3}, {%4,%5,%6,%7}, {%8,%9}, {%0,%1,%2,%3};"
        : "+f"(c[0]), "+f"(c[1]), "+f"(c[2]), "+f"(c[3])
        : "r"(a0), "r"(a1), "r"(a2), "r"(a3), "r"(b0), "r"(b1));
}
// fp16-accumulator HMMA (lo-term correction path)
__device__ __forceinline__ void mma_h16(uint32_t c[2],
                                        uint32_t a0, uint32_t a1, uint32_t a2, uint32_t a3,
                                        uint32_t b0, uint32_t b1)
{
    asm volatile(
        "mma.sync.aligned.m16n8k16.row.col.f16.f16.f16.f16 "
        "{%0,%1}, {%2,%3,%4,%5}, {%6,%7}, {%0,%1};"
        : "+r"(c[0]), "+r"(c[1])
        : "r"(a0), "r"(a1), "r"(a2), "r"(a3), "r"(b0), "r"(b1));
}

__device__ __forceinline__ void split16(float v, __half& h, __half& l) {
    h = __float2half_rn(v);
    l = __float2half_rn(v - __half2float(h));
}

// ======================= transpose + split: in[R][C] -> hi/lo[C][R] =======================
__global__ void transpose32h(const float* __restrict__ in,
                             __half* __restrict__ oh, __half* __restrict__ ol, int R, int C)
{
    __shared__ float t[32][33];
    int bx = blockIdx.x * 32, by = blockIdx.y * 32;
    int x = bx + threadIdx.x;
    #pragma unroll
    for (int j = 0; j < 32; j += 8)
        t[threadIdx.y + j][threadIdx.x] = in[(size_t)(by + threadIdx.y + j) * C + x];
    __syncthreads();
    int ox = by + threadIdx.x;
    #pragma unroll
    for (int j = 0; j < 32; j += 8) {
        float v = t[threadIdx.x][threadIdx.y + j];
        __half h, l; split16(v, h, l);
        size_t o = (size_t)(bx + threadIdx.y + j) * R + ox;
        oh[o] = h; ol[o] = l;
    }
}

// W_lw [2048][16] -> rows 2112..2127 of tX planes
__global__ void lwT_kernel(const float* __restrict__ Wl,
                           __half* __restrict__ oh, __half* __restrict__ ol)
{
    int idx = blockIdx.x * 256 + threadIdx.x;   // 2048*16
    int k = idx >> 4, n = idx & 15;
    float v = Wl[idx];
    __half h, l; split16(v, h, l);
    size_t o = (size_t)(2112 + n) * Dd + k;
    oh[o] = h; ol[o] = l;
}

// ======================= elementwise split =======================
__global__ void split_kernel(const float* __restrict__ in,
                             __half* __restrict__ oh, __half* __restrict__ ol)
{
    int idx = blockIdx.x * 256 + threadIdx.x;
    float v = in[idx];
    __half h, l; split16(v, h, l);
    oh[idx] = h; ol[idx] = l;
}

// ======================= fp16-split tensor-core GEMM (2-term) =======================
// D = al*bh (fp16 acc, separate regs) + ah*bh (f32 acc); lo-sum folded at epilogue.
#define WSTR 20
#define HGEMM_SMEM (2 * 4 * 128 * WSTR * 4)   // 81920 B

__device__ __forceinline__ void hgemm_body(
    int N, int K, int m0, int n0,
    const __half* __restrict__ Ahi, const __half* __restrict__ Alo,
    const __half* __restrict__ Bhi,
    uint32_t* smw, float acc[2][4][4])
{
    uint32_t* buf[2] = { smw, smw + 4 * 128 * WSTR };
    const int tid = threadIdx.x;
    const int wid = tid >> 5, lane = tid & 31;
    const int warpM = (wid >> 2) * 32;
    const int warpN = (wid & 3) * 32;
    const int lr = lane >> 2, lc = lane & 3;

    const __half* Ap[2] = { Ahi + (size_t)m0 * K, Alo + (size_t)m0 * K };
    const __half* Bp = Bhi + (size_t)n0 * K;

    const int r = tid >> 2;
    const int q = (tid & 3) * 4;

    auto stage = [&](int kc, int b) {
        uint32_t base = smem_u32(buf[b]);
        cp16(base + (uint32_t)((r) * WSTR + q) * 4u,
             Ap[0] + (size_t)r * K + kc + q * 2);
        cp16(base + (uint32_t)((128 + r) * WSTR + q) * 4u,
             Ap[1] + (size_t)r * K + kc + q * 2);
        cp16(base + (uint32_t)((2 * 128 + r) * WSTR + q) * 4u,
             Bp + (size_t)r * K + kc + q * 2);
        CP_COMMIT();
    };

    uint32_t accl[2][4][2];
    #pragma unroll
    for (int i = 0; i < 2; i++)
        #pragma unroll
        for (int j = 0; j < 4; j++) {
            #pragma unroll
            for (int k = 0; k < 4; k++) acc[i][j][k] = 0.f;
            accl[i][j][0] = 0u; accl[i][j][1] = 0u;
        }

    stage(0, 0);

    const int nch = K >> 5;
    for (int i = 0; i < nch; i++) {
        CP_WAIT0();
        __syncthreads();
        if (i + 1 < nch) stage((i + 1) << 5, (i + 1) & 1);

        const uint32_t* Ah = buf[i & 1];
        const uint32_t* Al = Ah + 128 * WSTR;
        const uint32_t* Bh = Ah + 2 * 128 * WSTR;

        #pragma unroll
        for (int s = 0; s < 2; s++) {
            uint32_t ah[2][4], al[2][4], bhf[4][2];
            #pragma unroll
            for (int ma = 0; ma < 2; ma++) {
                int rw = (warpM + ma * 16 + lr) * WSTR + s * 8 + lc;
                ah[ma][0] = Ah[rw];
                ah[ma][1] = Ah[rw + 8 * WSTR];
                ah[ma][2] = Ah[rw + 4];
                ah[ma][3] = Ah[rw + 8 * WSTR + 4];
                al[ma][0] = Al[rw];
                al[ma][1] = Al[rw + 8 * WSTR];
                al[ma][2] = Al[rw + 4];
                al[ma][3] = Al[rw + 8 * WSTR + 4];
            }
            #pragma unroll
            for (int nb = 0; nb < 4; nb++) {
                int cw = (warpN + nb * 8 + lr) * WSTR + s * 8 + lc;
                bhf[nb][0] = Bh[cw]; bhf[nb][1] = Bh[cw + 4];
            }
            // lo-term on the fp16-accumulator path
            #pragma unroll
            for (int nb = 0; nb < 4; nb++)
                #pragma unroll
                for (int ma = 0; ma < 2; ma++)
                    mma_h16(accl[ma][nb], al[ma][0], al[ma][1], al[ma][2], al[ma][3],
                            bhf[nb][0], bhf[nb][1]);
            // main term, f32 accumulation
            #pragma unroll
            for (int nb = 0; nb < 4; nb++)
                #pragma unroll
                for (int ma = 0; ma < 2; ma++)
                    mma_f16(acc[ma][nb], ah[ma][0], ah[ma][1], ah[ma][2], ah[ma][3],
                            bhf[nb][0], bhf[nb][1]);
        }
        __syncthreads();
    }

    // fold lo-term corrections into f32 accumulators
    #pragma unroll
    for (int ma = 0; ma < 2; ma++)
        #pragma unroll
        for (int nb = 0; nb < 4; nb++) {
            float2 c01 = __half22float2(*(__half2*)&accl[ma][nb][0]);
            float2 c23 = __half22float2(*(__half2*)&accl[ma][nb][1]);
            acc[ma][nb][0] += c01.x;
            acc[ma][nb][1] += c01.y;
            acc[ma][nb][2] += c23.x;
            acc[ma][nb][3] += c23.y;
        }
}

__global__ __launch_bounds__(512)
void hgemm_f(int N, int K,
             const __half* __restrict__ Ahi, const __half* __restrict__ Alo,
             const __half* __restrict__ Bhi,
             float* __restrict__ C)
{
    extern __shared__ float smraw[];
    float acc[2][4][4];
    const int m0 = blockIdx.y * 128, n0 = blockIdx.x * 128;
    hgemm_body(N, K, m0, n0, Ahi, Alo, Bhi, (uint32_t*)smraw, acc);

    const int wid = threadIdx.x >> 5, lane = threadIdx.x & 31;
    const int warpM = (wid >> 2) * 32, warpN = (wid & 3) * 32;
    const int lr = lane >> 2, lc = lane & 3;
    #pragma unroll
    for (int ma = 0; ma < 2; ma++) {
        int row = m0 + warpM + ma * 16 + lr;
        #pragma unroll
        for (int nb = 0; nb < 4; nb++) {
            int col = n0 + warpN + nb * 8 + lc * 2;
            *(float2*)(C + (size_t)row * N + col)       = make_float2(acc[ma][nb][0], acc[ma][nb][1]);
            *(float2*)(C + (size_t)(row + 8) * N + col) = make_float2(acc[ma][nb][2], acc[ma][nb][3]);
        }
    }
}

// merged K=1024 launch: seg0 (32 tiles) ckv@UKV->kv, seg1 (32) cq@UQ->qc, seg2 (16) cq@QR->qr
__global__ __launch_bounds__(512)
void hgemm_multi(const __half* __restrict__ ckvh, const __half* __restrict__ ckvl,
                 const __half* __restrict__ cqh,  const __half* __restrict__ cql,
                 const __half* __restrict__ tUKVh,
                 const __half* __restrict__ tUQh,
                 const __half* __restrict__ tQRh,
                 __half* __restrict__ kvh, __half* __restrict__ kvl,
                 __half* __restrict__ qch, __half* __restrict__ qcl,
                 __half* __restrict__ qrh, __half* __restrict__ qrl)
{
    extern __shared__ float smraw[];
    const int bx = blockIdx.x;
    const __half *Ahp, *Alp, *Bhp;
    __half *Chp, *Clp;
    int N, nloc;
    if (bx < 32)      { Ahp = ckvh; Alp = ckvl; Bhp = tUKVh; Chp = kvh; Clp = kvl; N = 4096; nloc = bx; }
    else if (bx < 64) { Ahp = cqh;  Alp = cql;  Bhp = tUQh;  Chp = qch; Clp = qcl; N = 4096; nloc = bx - 32; }
    else              { Ahp = cqh;  Alp = cql;  Bhp = tQRh;  Chp = qrh; Clp = qrl; N = 2048; nloc = bx - 64; }

    float acc[2][4][4];
    const int m0 = blockIdx.y * 128, n0 = nloc * 128;
    hgemm_body(N, 1024, m0, n0, Ahp, Alp, Bhp, (uint32_t*)smraw, acc);

    const int wid = threadIdx.x >> 5, lane = threadIdx.x & 31;
    const int warpM = (wid >> 2) * 32, warpN = (wid & 3) * 32;
    const int lr = lane >> 2, lc = lane & 3;
    #pragma unroll
    for (int ma = 0; ma < 2; ma++) {
        int row = m0 + warpM + ma * 16 + lr;
        #pragma unroll
        for (int nb = 0; nb < 4; nb++) {
            int col = n0 + warpN + nb * 8 + lc * 2;
            float x0 = acc[ma][nb][0], x1 = acc[ma][nb][1];
            __half2 h2 = __floats2half2_rn(x0, x1);
            float2 hf = __half22float2(h2);
            __half2 l2 = __floats2half2_rn(x0 - hf.x, x1 - hf.y);
            *(__half2*)(Chp + (size_t)row * N + col) = h2;
            *(__half2*)(Clp + (size_t)row * N + col) = l2;
            float y0 = acc[ma][nb][2], y1 = acc[ma][nb][3];
            __half2 h3 = __floats2half2_rn(y0, y1);
            float2 hg = __half22float2(h3);
            __half2 l3 = __floats2half2_rn(y0 - hg.x, y1 - hg.y);
            *(__half2*)(Chp + (size_t)(row + 8) * N + col) = h3;
            *(__half2*)(Clp + (size_t)(row + 8) * N + col) = l3;
        }
    }
}

// ======================= RMS norm (strided input) -> fp16 split planes =======================
__global__ void rms_h(const float* __restrict__ in, int instride,
                      const float* __restrict__ w,
                      __half* __restrict__ oh, __half* __restrict__ ol, int N)
{
    int row = blockIdx.x;
    const float* ir = in + (size_t)row * instride;
    float s = 0.f;
    for (int i = threadIdx.x; i < N; i += 256) { float v = ir[i]; s += v * v; }
    __shared__ float red[256];
    red[threadIdx.x] = s;
    __syncthreads();
    for (int st = 128; st > 0; st >>= 1) {
        if (threadIdx.x < st) red[threadIdx.x] += red[threadIdx.x + st];
        __syncthreads();
    }
    float rr = rsqrtf(red[0] / (float)N + 1e-6f);
    for (int i = threadIdx.x; i < N; i += 256) {
        float v = ir[i] * rr * w[i];
        __half h, l; split16(v, h, l);
        oh[(size_t)row * N + i] = h;
        ol[(size_t)row * N + i] = l;
    }
}

// ======================= lambda sigmoid (from fused tmp cols) =======================
__global__ void lam_sig(const float* __restrict__ tmp, const float* __restrict__ bl,
                        float* __restrict__ lam)
{
    int idx = blockIdx.x * 256 + threadIdx.x;   // BL*16
    int row = idx >> 4, n = idx & 15;
    float z = tmp[(size_t)row * NX + 2112 + n] + bl[n];
    lam[idx] = 1.f / (1.f + expf(-z));
}

// ======================= RoPE kr (from fused tmp cols) -> planes =======================
__global__ void rope_kr(const float* __restrict__ tmp,
                        __half* __restrict__ oh, __half* __restrict__ ol)
{
    int idx = blockIdx.x * 256 + threadIdx.x;   // BL*32
    int j = idx & 31, row = idx >> 5;
    int l = row & (Lseq - 1);
    float inv = powf(10000.f, -(float)(2 * j) / 64.f);
    float ang = (float)l * inv;
    float c = cosf(ang), s = sinf(ang);
    const float* base = tmp + (size_t)row * NX + 2048;
    float x1 = base[j], x2 = base[j + 32];
    float y1 = x1 * c - x2 * s;
    float y2 = x2 * c + x1 * s;
    size_t o = (size_t)row * 64;
    __half hh, ll;
    split16(y1, hh, ll); oh[o + j] = hh;      ol[o + j] = ll;
    split16(y2, hh, ll); oh[o + j + 32] = hh; ol[o + j + 32] = ll;
}

// ======================= RoPE qr (in-place on split planes) =======================
__global__ void rope_qp(__half* __restrict__ ph, __half* __restrict__ pl)
{
    int idx = blockIdx.x * 256 + threadIdx.x;   // BL*32*32
    int j = idx & 31;
    int h = (idx >> 5) & 31;
    int row = idx >> 10;
    int l = row & (Lseq - 1);
    float inv = powf(10000.f, -(float)(2 * j) / 64.f);
    float ang = (float)l * inv;
    float c = cosf(ang), s = sinf(ang);
    size_t o = (size_t)row * 2048 + h * 64;
    float x1 = __half2float(ph[o + j])      + __half2float(pl[o + j]);
    float x2 = __half2float(ph[o + j + 32]) + __half2float(pl[o + j + 32]);
    float y1 = x1 * c - x2 * s;
    float y2 = x2 * c + x1 * s;
    __half hh, ll;
    split16(y1, hh, ll); ph[o + j] = hh;      pl[o + j] = ll;
    split16(y2, hh, ll); ph[o + j + 32] = hh; pl[o + j + 32] = ll;
}

// ======================= tensor-core flash attention (2xFP16, pre-split planes) =====
// smem words: qs0 6400 | qs1 6400 | ks 3200 | vs 2176 | ps0 1280 | ps1 1280 = 20736
#define FLASH_SMEM (20736 * 4)   // 82944 B -> 2 CTAs/SM
__global__ __launch_bounds__(128)
void flash_h(const __half* __restrict__ qch, const __half* __restrict__ qcl,
             const __half* __restrict__ qrh, const __half* __restrict__ qrl,
             const __half* __restrict__ kvh, const __half* __restrict__ kvl,
             const __half* __restrict__ krh, const __half* __restrict__ krl,
             float* __restrict__ attn)
{
    extern __shared__ uint32_t smw[];
    uint32_t* qs[2] = { smw,         smw + 6400 };
    uint32_t* ks    = smw + 12800;
    uint32_t* vs    = smw + 16000;
    uint32_t* ps[2] = { smw + 18176, smw + 19456 };

    const int Q0 = (gridDim.x - 1 - blockIdx.x) * 64;
    const int head2 = blockIdx.y;
    const int b = blockIdx.z;
    const int hn = head2 >> 1, hp = head2 & 1;
    const int tid = threadIdx.x;
    const int lane = tid & 31, w = tid >> 5;
    const int lr = lane >> 2, lc = lane & 3;

    const size_t tq = (size_t)(b * Lseq + Q0);

    {
        const __half* qcp[2] = { qch + tq * 4096 + head2 * 128, qcl + tq * 4096 + head2 * 128 };
        const __half* qrp[2] = { qrh + tq * 2048 + head2 * 64,  qrl + tq * 2048 + head2 * 64 };
        #pragma unroll
        for (int p = 0; p < 2; p++) {
            uint32_t qb = smem_u32(qs[p]);
            #pragma unroll
            for (int i = 0; i < 8; i++) {
                int s2 = tid + i * 128;
                int r = s2 >> 4, c = s2 & 15;
                cp16(qb + (uint32_t)(r * 100 + c * 4) * 4u, qcp[p] + (size_t)r * 4096 + c * 8);
            }
            #pragma unroll
            for (int i = 0; i < 4; i++) {
                int s2 = tid + i * 128;
                int r = s2 >> 3, c = s2 & 7;
                cp16(qb + (uint32_t)(r * 100 + 64 + c * 4) * 4u, qrp[p] + (size_t)r * 2048 + c * 8);
            }
        }
        CP_COMMIT();
    }

    float o[16][4];
    #pragma unroll
    for (int i = 0; i < 16; i++) { o[i][0] = o[i][1] = o[i][2] = o[i][3] = 0.f; }
    float m0 = -INFINITY, m1 = -INFINITY, l0 = 0.f, l1 = 0.f;

    const int row0g = Q0 + 16 * w + lr;
    const int row1g = row0g + 8;
    const int prow0 = (16 * w + lr) * 20;
    const int arow0 = (16 * w + lr) * 100;

    const int ntile = (Q0 + 64) >> 5;
    for (int t = 0; t < ntile; t++) {
        const int k0 = t << 5;
        __syncthreads();
        {
            const size_t tk = (size_t)(b * Lseq + k0);
            const __half* kcp = kvh + tk * 4096 + hn * 128;
            const __half* vp  = kvh + tk * 4096 + 2048 + hn * 128;
            const __half* krp = krh + tk * 64;
            uint32_t kb = smem_u32(ks);
            uint32_t vb = smem_u32(vs);
            #pragma unroll
            for (int i = 0; i < 4; i++) {
                int s2 = tid + i * 128;
                int r = s2 >> 4, c = s2 & 15;
                cp16(kb + (uint32_t)(r * 100 + c * 4) * 4u, kcp + (size_t)r * 4096 + c * 8);
                cp16(vb + (uint32_t)(r * 68 + c * 4) * 4u,  vp  + (size_t)r * 4096 + c * 8);
            }
            #pragma unroll
            for (int i = 0; i < 2; i++) {
                int s2 = tid + i * 128;
                int r = s2 >> 3, c = s2 & 7;
                cp16(kb + (uint32_t)(r * 100 + 64 + c * 4) * 4u, krp + (size_t)r * 64 + c * 8);
            }
            CP_COMMIT();
            CP_WAIT0();
            __syncthreads();
        }

        float s4[4][4];
        #pragma unroll
        for (int nt = 0; nt < 4; nt++) { s4[nt][0] = s4[nt][1] = s4[nt][2] = s4[nt][3] = 0.f; }

        #pragma unroll 4
        for (int s = 0; s < 12; s++) {
            const int ab = arow0 + s * 8 + lc;
            uint32_t ah0 = qs[0][ab],       ah1 = qs[0][ab + 800];
            uint32_t ah2 = qs[0][ab + 4],   ah3 = qs[0][ab + 804];
            uint32_t al0 = qs[1][ab],       al1 = qs[1][ab + 800];
            uint32_t al2 = qs[1][ab + 4],   al3 = qs[1][ab + 804];
            #pragma unroll
            for (int nt = 0; nt < 4; nt++) {
                const int cb = (nt * 8 + lr) * 100 + s * 8 + lc;
                uint32_t bh0 = ks[cb], bh1 = ks[cb + 4];
                mma_f16(s4[nt], al0, al1, al2, al3, bh0, bh1);
                mma_f16(s4[nt], ah0, ah1, ah2, ah3, bh0, bh1);
            }
        }

        float tmax0 = -INFINITY, tmax1 = -INFINITY;
        #pragma unroll
        for (int nt = 0; nt < 4; nt++) {
            const int colg = k0 + nt * 8 + 2 * lc;
            s4[nt][0] = (colg     <= row0g) ? s4[nt][0] * ATTN_SCALE : -INFINITY;
            s4[nt][1] = (colg + 1 <= row0g) ? s4[nt][1] * ATTN_SCALE : -INFINITY;
            s4[nt][2] = (colg     <= row1g) ? s4[nt][2] * ATTN_SCALE : -INFINITY;
            s4[nt][3] = (colg + 1 <= row1g) ? s4[nt][3] * ATTN_SCALE : -INFINITY;
            tmax0 = fmaxf(tmax0, fmaxf(s4[nt][0], s4[nt][1]));
            tmax1 = fmaxf(tmax1, fmaxf(s4[nt][2], s4[nt][3]));
        }
        tmax0 = fmaxf(tmax0, __shfl_xor_sync(0xffffffffu, tmax0, 1));
        tmax0 = fmaxf(tmax0, __shfl_xor_sync(0xffffffffu, tmax0, 2));
        tmax1 = fmaxf(tmax1, __shfl_xor_sync(0xffffffffu, tmax1, 1));
        tmax1 = fmaxf(tmax1, __shfl_xor_sync(0xffffffffu, tmax1, 2));

        const float mn0 = fmaxf(m0, tmax0), mn1 = fmaxf(m1, tmax1);
        const float scl0 = expf(m0 - mn0);
        const float scl1 = expf(m1 - mn1);

        float p4[4][4];
        float pr0 = 0.f, pr1 = 0.f;
        #pragma unroll
        for (int nt = 0; nt < 4; nt++) {
            p4[nt][0] = expf(s4[nt][0] - mn0);
            p4[nt][1] = expf(s4[nt][1] - mn0);
            p4[nt][2] = expf(s4[nt][2] - mn1);
            p4[nt][3] = expf(s4[nt][3] - mn1);
            pr0 += p4[nt][0] + p4[nt][1];
            pr1 += p4[nt][2] + p4[nt][3];
        }
        pr0 += __shfl_xor_sync(0xffffffffu, pr0, 1);
        pr0 += __shfl_xor_sync(0xffffffffu, pr0, 2);
        pr1 += __shfl_xor_sync(0xffffffffu, pr1, 1);
        pr1 += __shfl_xor_sync(0xffffffffu, pr1, 2);

        l0 = l0 * scl0 + pr0;
        l1 = l1 * scl1 + pr1;
        m0 = mn0; m1 = mn1;

        #pragma unroll
        for (int i = 0; i < 16; i++) {
            o[i][0] *= scl0; o[i][1] *= scl0;
            o[i][2] *= scl1; o[i][3] *= scl1;
        }

        #pragma unroll
        for (int nt = 0; nt < 4; nt++) {
            __half2 h0 = __floats2half2_rn(p4[nt][0], p4[nt][1]);
            float2 f0 = __half22float2(h0);
            __half2 e0 = __floats2half2_rn(p4[nt][0] - f0.x, p4[nt][1] - f0.y);
            ((__half2*)ps[0])[prow0 + nt * 4 + lc] = h0;
            ((__half2*)ps[1])[prow0 + nt * 4 + lc] = e0;
            __half2 h1 = __floats2half2_rn(p4[nt][2], p4[nt][3]);
            float2 f1 = __half22float2(h1);
            __half2 e1 = __floats2half2_rn(p4[nt][2] - f1.x, p4[nt][3] - f1.y);
            ((__half2*)ps[0])[prow0 + 160 + nt * 4 + lc] = h1;
            ((__half2*)ps[1])[prow0 + 160 + nt * 4 + lc] = e1;
        }
        __syncwarp();

        const uint16_t* vhp = (const uint16_t*)vs;
        #pragma unroll
        for (int s = 0; s < 2; s++) {
            const int pb = prow0 + s * 8 + lc;
            uint32_t ah0 = ps[0][pb],     ah1 = ps[0][pb + 160];
            uint32_t ah2 = ps[0][pb + 4], ah3 = ps[0][pb + 164];
            uint32_t al0 = ps[1][pb],     al1 = ps[1][pb + 160];
            uint32_t al2 = ps[1][pb + 4], al3 = ps[1][pb + 164];
            const int kb = s * 16 + 2 * lc;
            #pragma unroll
            for (int nt2 = 0; nt2 < 16; nt2++) {
                const int d = nt2 * 8 + lr;
                uint32_t bh0 = (uint32_t)vhp[kb * 136 + d]       | ((uint32_t)vhp[(kb + 1) * 136 + d] << 16);
                uint32_t bh1 = (uint32_t)vhp[(kb + 8) * 136 + d] | ((uint32_t)vhp[(kb + 9) * 136 + d] << 16);
                mma_f16(o[nt2], al0, al1, al2, al3, bh0, bh1);
                mma_f16(o[nt2], ah0, ah1, ah2, ah3, bh0, bh1);
            }
        }
    }

    const float inv0 = 1.f / l0, inv1 = 1.f / l1;
    const size_t obase = ((size_t)(b * 2 + hp) * NHh + hn) * Lseq;
    float* op0 = attn + (obase + row0g) * 128;
    float* op1 = attn + (obase + row1g) * 128;
    #pragma unroll
    for (int nt2 = 0; nt2 < 16; nt2++) {
        *(float2*)(op0 + nt2 * 8 + 2 * lc) = make_float2(o[nt2][0] * inv0, o[nt2][1] * inv0);
        *(float2*)(op1 + nt2 * 8 + 2 * lc) = make_float2(o[nt2][2] * inv1, o[nt2][3] * inv1);
    }
}

// ======================= combine -> fp16 split planes =======================
__global__ void combine_h(const float* __restrict__ attn, const float* __restrict__ lam,
                          __half* __restrict__ oh, __half* __restrict__ ol)
{
    int idx = blockIdx.x * 256 + threadIdx.x;
    int c = idx & 2047;
    int row = idx >> 11;
    int b = row >> 11;
    int l = row & 2047;
    int n = c >> 7, d = c & 127;
    size_t a1 = (((size_t)(b * 2 + 0) * NHh + n) * Lseq + l) * 128 + d;
    size_t a2 = (((size_t)(b * 2 + 1) * NHh + n) * Lseq + l) * 128 + d;
    float v = attn[a1] - lam[(size_t)row * 16 + n] * attn[a2];
    __half h, lo; split16(v, h, lo);
    oh[idx] = h; ol[idx] = lo;
}

// ======================= launch =======================
extern "C" void kernel_launch(void* const* d_in, const int* in_sizes, int n_in,
                              void* d_out, int out_size)
{
    const float* x     = (const float*)d_in[0];
    const float* W_DKV = (const float*)d_in[1];
    const float* kv_w  = (const float*)d_in[2];
    const float* W_UK  = (const float*)d_in[3];
    const float* W_UV  = (const float*)d_in[4];
    const float* W_DQ  = (const float*)d_in[5];
    const float* q_w   = (const float*)d_in[6];
    const float* W_UQ  = (const float*)d_in[7];
    const float* W_QR  = (const float*)d_in[8];
    const float* W_KR  = (const float*)d_in[9];
    const float* W_lw  = (const float*)d_in[10];
    const float* W_lb  = (const float*)d_in[11];
    const float* W_out = (const float*)d_in[12];
    float* out = (float*)d_out;

    float *tmp, *lam, *attn;
    __half *xh, *xl, *ckvh, *ckvl, *cqh, *cql, *preh, *prel;
    __half *qchp, *qclp, *qrhp, *qrlp, *krhp, *krlp, *kvh, *kvl;
    __half *tXh, *tXl, *tUKVh, *tUKVl, *tUQh, *tUQl, *tQRh, *tQRl, *tOUTh, *tOUTl;
    cudaGetSymbolAddress((void**)&tmp,  g_tmp);
    cudaGetSymbolAddress((void**)&lam,  g_lam);
    cudaGetSymbolAddress((void**)&attn, g_attn);
    cudaGetSymbolAddress((void**)&xh,   g_xh);
    cudaGetSymbolAddress((void**)&xl,   g_xl);
    cudaGetSymbolAddress((void**)&ckvh, g_ckvh);
    cudaGetSymbolAddress((void**)&ckvl, g_ckvl);
    cudaGetSymbolAddress((void**)&cqh,  g_cqh);
    cudaGetSymbolAddress((void**)&cql,  g_cql);
    cudaGetSymbolAddress((void**)&preh, g_preh);
    cudaGetSymbolAddress((void**)&prel, g_prel);
    cudaGetSymbolAddress((void**)&qchp, g_qch);
    cudaGetSymbolAddress((void**)&qclp, g_qcl);
    cudaGetSymbolAddress((void**)&qrhp, g_qrh);
    cudaGetSymbolAddress((void**)&qrlp, g_qrl);
    cudaGetSymbolAddress((void**)&krhp, g_krh);
    cudaGetSymbolAddress((void**)&krlp, g_krl);
    cudaGetSymbolAddress((void**)&kvh,  g_kvh);
    cudaGetSymbolAddress((void**)&kvl,  g_kvl);
    cudaGetSymbolAddress((void**)&tXh,  g_tXh);
    cudaGetSymbolAddress((void**)&tXl,  g_tXl);
    cudaGetSymbolAddress((void**)&tUKVh, g_tUKVh);
    cudaGetSymbolAddress((void**)&tUKVl, g_tUKVl);
    cudaGetSymbolAddress((void**)&tUQh,  g_tUQh);
    cudaGetSymbolAddress((void**)&tUQl,  g_tUQl);
    cudaGetSymbolAddress((void**)&tQRh,  g_tQRh);
    cudaGetSymbolAddress((void**)&tQRl,  g_tQRl);
    cudaGetSymbolAddress((void**)&tOUTh, g_tOUTh);
    cudaGetSymbolAddress((void**)&tOUTl, g_tOUTl);

    cudaFuncSetAttribute(hgemm_f,     cudaFuncAttributeMaxDynamicSharedMemorySize, HGEMM_SMEM);
    cudaFuncSetAttribute(hgemm_multi, cudaFuncAttributeMaxDynamicSharedMemorySize, HGEMM_SMEM);
    cudaFuncSetAttribute(flash_h,     cudaFuncAttributeMaxDynamicSharedMemorySize, FLASH_SMEM);

    dim3 tb(32, 8);
    // fused tX planes: rows [DKV 0..1023 | DQ 1024..2047 | KR 2048..2111 | lw 2112..2127 | pad]
    transpose32h<<<dim3(DCc/32, Dd/32), tb>>>(W_DKV, tXh,              tXl,              Dd, DCc);
    transpose32h<<<dim3(DCc/32, Dd/32), tb>>>(W_DQ,  tXh + 1024 * Dd,  tXl + 1024 * Dd,  Dd, DCc);
    transpose32h<<<dim3(DHRr/32, Dd/32), tb>>>(W_KR, tXh + 2048 * Dd,  tXl + 2048 * Dd,  Dd, DHRr);
    lwT_kernel<<<(Dd * 16) / 256, 256>>>(W_lw, tXh, tXl);
    transpose32h<<<dim3((NHh*DHh)/32, DCc/32), tb>>>(W_UK, tUKVh,              tUKVl,              DCc, NHh*DHh);
    transpose32h<<<dim3((NHh*DHh)/32, DCc/32), tb>>>(W_UV, tUKVh + 2048 * DCc, tUKVl + 2048 * DCc, DCc, NHh*DHh);
    transpose32h<<<dim3((2*NHh*DHh)/32, DCc/32), tb>>>(W_UQ, tUQh, tUQl, DCc, 2*NHh*DHh);
    transpose32h<<<dim3((2*NHh*DHRr)/32, DCc/32), tb>>>(W_QR, tQRh, tQRl, DCc, 2*NHh*DHRr);
    transpose32h<<<dim3(Dd/32, Dd/32), tb>>>(W_out, tOUTh, tOUTl, Dd, Dd);
    split_kernel<<<(BL * Dd) / 256, 256>>>(x, xh, xl);

    // fused down-projection + kr + lambda-pre (2-term split): tmp[row][NX]
    hgemm_f<<<dim3(NX/128, BL/128), 512, HGEMM_SMEM>>>(NX, Dd, xh, xl, tXh, tmp);
    rms_h<<<BL, 256>>>(tmp,        NX, kv_w, ckvh, ckvl, DCc);
    rms_h<<<BL, 256>>>(tmp + 1024, NX, q_w,  cqh,  cql,  DCc);
    lam_sig<<<(BL * 16) / 256, 256>>>(tmp, W_lb, lam);
    rope_kr<<<(BL * 32) / 256, 256>>>(tmp, krhp, krlp);

    // merged up-projections (UKV + UQ + QR), all K=1024, 2-term split
    hgemm_multi<<<dim3(80, BL/128), 512, HGEMM_SMEM>>>(
        ckvh, ckvl, cqh, cql,
        tUKVh, tUQh, tQRh,
        kvh, kvl, qchp, qclp, qrhp, qrlp);

    // RoPE on qr planes (in-place)
    rope_qp<<<(BL * 1024) / 256, 256>>>(qrhp, qrlp);

    // attention (fp16 tensor-core flash, 2-term, longest-first)
    flash_h<<<dim3(Lseq / 64, 32, BB), 128, FLASH_SMEM>>>(
        qchp, qclp, qrhp, qrlp, kvh, kvl, krhp, krlp, attn);

    // combine + output projection (2-term split)
    combine_h<<<(BL * Dd) / 256, 256>>>(attn, lam, preh, prel);
    hgemm_f<<<dim3(Dd/128, BL/128), 512, HGEMM_SMEM>>>(Dd, Dd, preh, prel, tOUTh, out);
}

// round 15
// speedup vs baseline: 4.4852x; 1.1596x over previous
#include <cuda_runtime.h>
#include <cuda.h>
#include <cuda_fp16.h>
#include <math.h>
#include <stdint.h>

#define BB   2
#define Lseq 2048
#define BL   4096      // B*L
#define Dd   2048
#define DCc  1024
#define NHh  16
#define DHh  128
#define DHRr 64
#define ATTN_SCALE 0.07216878364870322f
#define NX   2176      // fused down-proj width: [ckv 1024 | cq 1024 | kr 64 | lam 16 | pad 48]

// ======================= scratch =======================
__device__ float g_tmp [BL * NX];
__device__ float g_lam [BL * NHh];
__device__ float g_attn[(size_t)2 * BB * NHh * Lseq * DHh];

// fp16 split planes (activations)
__device__ __half g_xh  [BL * Dd],   g_xl  [BL * Dd];
__device__ __half g_ckvh[BL * DCc],  g_ckvl[BL * DCc];
__device__ __half g_cqh [BL * DCc],  g_cql [BL * DCc];
__device__ __half g_preh[BL * Dd],   g_prel[BL * Dd];
__device__ __half g_qch [BL * 4096];
__device__ __half g_qrh [BL * 2048];
__device__ __half g_krh [BL * DHRr];
__device__ __half g_kvh [BL * 4096];   // [kc 2048 | v 2048]
// fp16 split planes (transposed weights, [N][K])
__device__ __half g_tXh  [NX * Dd],     g_tXl  [NX * Dd];     // [DKV|DQ|KR|lw|pad0]
__device__ __half g_tUKVh[4096 * DCc];
__device__ __half g_tUQh [4096 * DCc];
__device__ __half g_tQRh [2048 * DCc];
__device__ __half g_tOUTh[Dd * Dd];

// ======================= helpers =======================
__device__ __forceinline__ uint32_t smem_u32(const void* p) {
    uint32_t a;
    asm("{ .reg .u64 t; cvta.to.shared.u64 t, %1; cvt.u32.u64 %0, t; }" : "=r"(a) : "l"(p));
    return a;
}
__device__ __forceinline__ void cp16(uint32_t dst, const void* src) {
    asm volatile("cp.async.cg.shared.global [%0], [%1], 16;" :: "r"(dst), "l"(src));
}
#define CP_COMMIT() asm volatile("cp.async.commit_group;" ::: "memory")
#define CP_WAIT0()  asm volatile("cp.async.wait_group 0;"  ::: "memory")

__device__ __forceinline__ void mma_f16(float c[4],
                                        uint32_t a0, uint32_t a1, uint32_t a2, uint32_t a3,
                                        uint32_t b0, uint32_t b1)
{
    asm volatile(
        "mma.sync.aligned.m16n8k16.row.col.f32.f16.f16.f32 "
        "{%0,%1,%2,%3}, {%4,%5,%6,%7}, {%8,%9}, {%0,%1,%2,%3};"
        : "+f"(c[0]), "+f"(c[1]), "+f"(c[2]), "+f"(c[3])
        : "r"(a0), "r"(a1), "r"(a2), "r"(a3), "r"(b0), "r"(b1));
}
// fp16-accumulator HMMA (lo-term correction path)
__device__ __forceinline__ void mma_h16(uint32_t c[2],
                                        uint32_t a0, uint32_t a1, uint32_t a2, uint32_t a3,
                                        uint32_t b0, uint32_t b1)
{
    asm volatile(
        "mma.sync.aligned.m16n8k16.row.col.f16.f16.f16.f16 "
        "{%0,%1}, {%2,%3,%4,%5}, {%6,%7}, {%0,%1};"
        : "+r"(c[0]), "+r"(c[1])
        : "r"(a0), "r"(a1), "r"(a2), "r"(a3), "r"(b0), "r"(b1));
}

__device__ __forceinline__ void split16(float v, __half& h, __half& l) {
    h = __float2half_rn(v);
    l = __float2half_rn(v - __half2float(h));
}

// ======================= transpose + split: in[R][C] -> hi/lo[C][R] =======================
__global__ void transpose32h(const float* __restrict__ in,
                             __half* __restrict__ oh, __half* __restrict__ ol, int R, int C)
{
    __shared__ float t[32][33];
    int bx = blockIdx.x * 32, by = blockIdx.y * 32;
    int x = bx + threadIdx.x;
    #pragma unroll
    for (int j = 0; j < 32; j += 8)
        t[threadIdx.y + j][threadIdx.x] = in[(size_t)(by + threadIdx.y + j) * C + x];
    __syncthreads();
    int ox = by + threadIdx.x;
    #pragma unroll
    for (int j = 0; j < 32; j += 8) {
        float v = t[threadIdx.x][threadIdx.y + j];
        size_t o = (size_t)(bx + threadIdx.y + j) * R + ox;
        if (ol) {
            __half h, l; split16(v, h, l);
            oh[o] = h; ol[o] = l;
        } else {
            oh[o] = __float2half_rn(v);
        }
    }
}

// W_lw [2048][16] -> rows 2112..2127 of tX planes
__global__ void lwT_kernel(const float* __restrict__ Wl,
                           __half* __restrict__ oh, __half* __restrict__ ol)
{
    int idx = blockIdx.x * 256 + threadIdx.x;   // 2048*16
    int k = idx >> 4, n = idx & 15;
    float v = Wl[idx];
    __half h, l; split16(v, h, l);
    size_t o = (size_t)(2112 + n) * Dd + k;
    oh[o] = h; ol[o] = l;
}

// ======================= elementwise split =======================
__global__ void split_kernel(const float* __restrict__ in,
                             __half* __restrict__ oh, __half* __restrict__ ol)
{
    int idx = blockIdx.x * 256 + threadIdx.x;
    float v = in[idx];
    __half h, l; split16(v, h, l);
    oh[idx] = h; ol[idx] = l;
}

// ======================= fp16-split tensor-core GEMM (2-term) =======================
// D = al*bh (fp16 acc, separate regs) + ah*bh (f32 acc); lo-sum folded at epilogue.
#define WSTR 20
#define HGEMM_SMEM (2 * 4 * 128 * WSTR * 4)   // 81920 B

__device__ __forceinline__ void hgemm_body(
    int N, int K, int m0, int n0,
    const __half* __restrict__ Ahi, const __half* __restrict__ Alo,
    const __half* __restrict__ Bhi,
    uint32_t* smw, float acc[2][4][4])
{
    uint32_t* buf[2] = { smw, smw + 4 * 128 * WSTR };
    const int tid = threadIdx.x;
    const int wid = tid >> 5, lane = tid & 31;
    const int warpM = (wid >> 2) * 32;
    const int warpN = (wid & 3) * 32;
    const int lr = lane >> 2, lc = lane & 3;

    const __half* Ap[2] = { Ahi + (size_t)m0 * K, Alo + (size_t)m0 * K };
    const __half* Bp = Bhi + (size_t)n0 * K;

    const int r = tid >> 2;
    const int q = (tid & 3) * 4;

    auto stage = [&](int kc, int b) {
        uint32_t base = smem_u32(buf[b]);
        cp16(base + (uint32_t)((r) * WSTR + q) * 4u,
             Ap[0] + (size_t)r * K + kc + q * 2);
        cp16(base + (uint32_t)((128 + r) * WSTR + q) * 4u,
             Ap[1] + (size_t)r * K + kc + q * 2);
        cp16(base + (uint32_t)((2 * 128 + r) * WSTR + q) * 4u,
             Bp + (size_t)r * K + kc + q * 2);
        CP_COMMIT();
    };

    uint32_t accl[2][4][2];
    #pragma unroll
    for (int i = 0; i < 2; i++)
        #pragma unroll
        for (int j = 0; j < 4; j++) {
            #pragma unroll
            for (int k = 0; k < 4; k++) acc[i][j][k] = 0.f;
            accl[i][j][0] = 0u; accl[i][j][1] = 0u;
        }

    stage(0, 0);

    const int nch = K >> 5;
    for (int i = 0; i < nch; i++) {
        CP_WAIT0();
        __syncthreads();
        if (i + 1 < nch) stage((i + 1) << 5, (i + 1) & 1);

        const uint32_t* Ah = buf[i & 1];
        const uint32_t* Al = Ah + 128 * WSTR;
        const uint32_t* Bh = Ah + 2 * 128 * WSTR;

        #pragma unroll
        for (int s = 0; s < 2; s++) {
            uint32_t ah[2][4], al[2][4], bhf[4][2];
            #pragma unroll
            for (int ma = 0; ma < 2; ma++) {
                int rw = (warpM + ma * 16 + lr) * WSTR + s * 8 + lc;
                ah[ma][0] = Ah[rw];
                ah[ma][1] = Ah[rw + 8 * WSTR];
                ah[ma][2] = Ah[rw + 4];
                ah[ma][3] = Ah[rw + 8 * WSTR + 4];
                al[ma][0] = Al[rw];
                al[ma][1] = Al[rw + 8 * WSTR];
                al[ma][2] = Al[rw + 4];
                al[ma][3] = Al[rw + 8 * WSTR + 4];
            }
            #pragma unroll
            for (int nb = 0; nb < 4; nb++) {
                int cw = (warpN + nb * 8 + lr) * WSTR + s * 8 + lc;
                bhf[nb][0] = Bh[cw]; bhf[nb][1] = Bh[cw + 4];
            }
            // lo-term on the fp16-accumulator path
            #pragma unroll
            for (int nb = 0; nb < 4; nb++)
                #pragma unroll
                for (int ma = 0; ma < 2; ma++)
                    mma_h16(accl[ma][nb], al[ma][0], al[ma][1], al[ma][2], al[ma][3],
                            bhf[nb][0], bhf[nb][1]);
            // main term, f32 accumulation
            #pragma unroll
            for (int nb = 0; nb < 4; nb++)
                #pragma unroll
                for (int ma = 0; ma < 2; ma++)
                    mma_f16(acc[ma][nb], ah[ma][0], ah[ma][1], ah[ma][2], ah[ma][3],
                            bhf[nb][0], bhf[nb][1]);
        }
        __syncthreads();
    }

    // fold lo-term corrections into f32 accumulators
    #pragma unroll
    for (int ma = 0; ma < 2; ma++)
        #pragma unroll
        for (int nb = 0; nb < 4; nb++) {
            float2 c01 = __half22float2(*(__half2*)&accl[ma][nb][0]);
            float2 c23 = __half22float2(*(__half2*)&accl[ma][nb][1]);
            acc[ma][nb][0] += c01.x;
            acc[ma][nb][1] += c01.y;
            acc[ma][nb][2] += c23.x;
            acc[ma][nb][3] += c23.y;
        }
}

__global__ __launch_bounds__(512)
void hgemm_f(int N, int K,
             const __half* __restrict__ Ahi, const __half* __restrict__ Alo,
             const __half* __restrict__ Bhi,
             float* __restrict__ C)
{
    extern __shared__ float smraw[];
    float acc[2][4][4];
    const int m0 = blockIdx.y * 128, n0 = blockIdx.x * 128;
    hgemm_body(N, K, m0, n0, Ahi, Alo, Bhi, (uint32_t*)smraw, acc);

    const int wid = threadIdx.x >> 5, lane = threadIdx.x & 31;
    const int warpM = (wid >> 2) * 32, warpN = (wid & 3) * 32;
    const int lr = lane >> 2, lc = lane & 3;
    #pragma unroll
    for (int ma = 0; ma < 2; ma++) {
        int row = m0 + warpM + ma * 16 + lr;
        #pragma unroll
        for (int nb = 0; nb < 4; nb++) {
            int col = n0 + warpN + nb * 8 + lc * 2;
            *(float2*)(C + (size_t)row * N + col)       = make_float2(acc[ma][nb][0], acc[ma][nb][1]);
            *(float2*)(C + (size_t)(row + 8) * N + col) = make_float2(acc[ma][nb][2], acc[ma][nb][3]);
        }
    }
}

// merged K=1024 launch: seg0 (32 tiles) ckv@UKV->kv, seg1 (32) cq@UQ->qc, seg2 (16) cq@QR->qr
// Outputs: fp16 hi planes only (consumed by 1-term flash).
__global__ __launch_bounds__(512)
void hgemm_multi(const __half* __restrict__ ckvh, const __half* __restrict__ ckvl,
                 const __half* __restrict__ cqh,  const __half* __restrict__ cql,
                 const __half* __restrict__ tUKVh,
                 const __half* __restrict__ tUQh,
                 const __half* __restrict__ tQRh,
                 __half* __restrict__ kvh,
                 __half* __restrict__ qch,
                 __half* __restrict__ qrh)
{
    extern __shared__ float smraw[];
    const int bx = blockIdx.x;
    const __half *Ahp, *Alp, *Bhp;
    __half *Chp;
    int N, nloc;
    if (bx < 32)      { Ahp = ckvh; Alp = ckvl; Bhp = tUKVh; Chp = kvh; N = 4096; nloc = bx; }
    else if (bx < 64) { Ahp = cqh;  Alp = cql;  Bhp = tUQh;  Chp = qch; N = 4096; nloc = bx - 32; }
    else              { Ahp = cqh;  Alp = cql;  Bhp = tQRh;  Chp = qrh; N = 2048; nloc = bx - 64; }

    float acc[2][4][4];
    const int m0 = blockIdx.y * 128, n0 = nloc * 128;
    hgemm_body(N, 1024, m0, n0, Ahp, Alp, Bhp, (uint32_t*)smraw, acc);

    const int wid = threadIdx.x >> 5, lane = threadIdx.x & 31;
    const int warpM = (wid >> 2) * 32, warpN = (wid & 3) * 32;
    const int lr = lane >> 2, lc = lane & 3;
    #pragma unroll
    for (int ma = 0; ma < 2; ma++) {
        int row = m0 + warpM + ma * 16 + lr;
        #pragma unroll
        for (int nb = 0; nb < 4; nb++) {
            int col = n0 + warpN + nb * 8 + lc * 2;
            *(__half2*)(Chp + (size_t)row * N + col)       = __floats2half2_rn(acc[ma][nb][0], acc[ma][nb][1]);
            *(__half2*)(Chp + (size_t)(row + 8) * N + col) = __floats2half2_rn(acc[ma][nb][2], acc[ma][nb][3]);
        }
    }
}

// ======================= RMS norm (strided input) -> fp16 split planes =======================
__global__ void rms_h(const float* __restrict__ in, int instride,
                      const float* __restrict__ w,
                      __half* __restrict__ oh, __half* __restrict__ ol, int N)
{
    int row = blockIdx.x;
    const float* ir = in + (size_t)row * instride;
    float s = 0.f;
    for (int i = threadIdx.x; i < N; i += 256) { float v = ir[i]; s += v * v; }
    __shared__ float red[256];
    red[threadIdx.x] = s;
    __syncthreads();
    for (int st = 128; st > 0; st >>= 1) {
        if (threadIdx.x < st) red[threadIdx.x] += red[threadIdx.x + st];
        __syncthreads();
    }
    float rr = rsqrtf(red[0] / (float)N + 1e-6f);
    for (int i = threadIdx.x; i < N; i += 256) {
        float v = ir[i] * rr * w[i];
        __half h, l; split16(v, h, l);
        oh[(size_t)row * N + i] = h;
        ol[(size_t)row * N + i] = l;
    }
}

// ======================= lambda sigmoid (from fused tmp cols) =======================
__global__ void lam_sig(const float* __restrict__ tmp, const float* __restrict__ bl,
                        float* __restrict__ lam)
{
    int idx = blockIdx.x * 256 + threadIdx.x;   // BL*16
    int row = idx >> 4, n = idx & 15;
    float z = tmp[(size_t)row * NX + 2112 + n] + bl[n];
    lam[idx] = 1.f / (1.f + expf(-z));
}

// ======================= RoPE kr (from fused tmp cols) -> hi plane =======================
__global__ void rope_kr(const float* __restrict__ tmp, __half* __restrict__ oh)
{
    int idx = blockIdx.x * 256 + threadIdx.x;   // BL*32
    int j = idx & 31, row = idx >> 5;
    int l = row & (Lseq - 1);
    float inv = powf(10000.f, -(float)(2 * j) / 64.f);
    float ang = (float)l * inv;
    float c = cosf(ang), s = sinf(ang);
    const float* base = tmp + (size_t)row * NX + 2048;
    float x1 = base[j], x2 = base[j + 32];
    size_t o = (size_t)row * 64;
    oh[o + j]      = __float2half_rn(x1 * c - x2 * s);
    oh[o + j + 32] = __float2half_rn(x2 * c + x1 * s);
}

// ======================= RoPE qr (in-place on hi plane) =======================
__global__ void rope_qp(__half* __restrict__ ph)
{
    int idx = blockIdx.x * 256 + threadIdx.x;   // BL*32*32
    int j = idx & 31;
    int h = (idx >> 5) & 31;
    int row = idx >> 10;
    int l = row & (Lseq - 1);
    float inv = powf(10000.f, -(float)(2 * j) / 64.f);
    float ang = (float)l * inv;
    float c = cosf(ang), s = sinf(ang);
    size_t o = (size_t)row * 2048 + h * 64;
    float x1 = __half2float(ph[o + j]);
    float x2 = __half2float(ph[o + j + 32]);
    ph[o + j]      = __float2half_rn(x1 * c - x2 * s);
    ph[o + j + 32] = __float2half_rn(x2 * c + x1 * s);
}

// ======================= tensor-core flash attention (1-term fp16) =====
// smem words: qs 6400 | ks 3200 | vs 2176 | ps 1280 = 13056 -> 52224 B -> 4 CTAs/SM
#define FLASH_SMEM (13056 * 4)
__global__ __launch_bounds__(128)
void flash_h(const __half* __restrict__ qch,
             const __half* __restrict__ qrh,
             const __half* __restrict__ kvh,
             const __half* __restrict__ krh,
             float* __restrict__ attn)
{
    extern __shared__ uint32_t smw[];
    uint32_t* qs = smw;            // 6400
    uint32_t* ks = smw + 6400;     // 3200
    uint32_t* vs = smw + 9600;     // 2176
    uint32_t* ps = smw + 11776;    // 1280

    const int Q0 = (gridDim.x - 1 - blockIdx.x) * 64;
    const int head2 = blockIdx.y;
    const int b = blockIdx.z;
    const int hn = head2 >> 1, hp = head2 & 1;
    const int tid = threadIdx.x;
    const int lane = tid & 31, w = tid >> 5;
    const int lr = lane >> 2, lc = lane & 3;

    const size_t tq = (size_t)(b * Lseq + Q0);

    {
        const __half* qcp = qch + tq * 4096 + head2 * 128;
        const __half* qrp = qrh + tq * 2048 + head2 * 64;
        uint32_t qb = smem_u32(qs);
        #pragma unroll
        for (int i = 0; i < 8; i++) {
            int s2 = tid + i * 128;
            int r = s2 >> 4, c = s2 & 15;
            cp16(qb + (uint32_t)(r * 100 + c * 4) * 4u, qcp + (size_t)r * 4096 + c * 8);
        }
        #pragma unroll
        for (int i = 0; i < 4; i++) {
            int s2 = tid + i * 128;
            int r = s2 >> 3, c = s2 & 7;
            cp16(qb + (uint32_t)(r * 100 + 64 + c * 4) * 4u, qrp + (size_t)r * 2048 + c * 8);
        }
        CP_COMMIT();
    }

    float o[16][4];
    #pragma unroll
    for (int i = 0; i < 16; i++) { o[i][0] = o[i][1] = o[i][2] = o[i][3] = 0.f; }
    float m0 = -INFINITY, m1 = -INFINITY, l0 = 0.f, l1 = 0.f;

    const int row0g = Q0 + 16 * w + lr;
    const int row1g = row0g + 8;
    const int prow0 = (16 * w + lr) * 20;
    const int arow0 = (16 * w + lr) * 100;

    const int ntile = (Q0 + 64) >> 5;
    for (int t = 0; t < ntile; t++) {
        const int k0 = t << 5;
        __syncthreads();
        {
            const size_t tk = (size_t)(b * Lseq + k0);
            const __half* kcp = kvh + tk * 4096 + hn * 128;
            const __half* vp  = kvh + tk * 4096 + 2048 + hn * 128;
            const __half* krp = krh + tk * 64;
            uint32_t kb = smem_u32(ks);
            uint32_t vb = smem_u32(vs);
            #pragma unroll
            for (int i = 0; i < 4; i++) {
                int s2 = tid + i * 128;
                int r = s2 >> 4, c = s2 & 15;
                cp16(kb + (uint32_t)(r * 100 + c * 4) * 4u, kcp + (size_t)r * 4096 + c * 8);
                cp16(vb + (uint32_t)(r * 68 + c * 4) * 4u,  vp  + (size_t)r * 4096 + c * 8);
            }
            #pragma unroll
            for (int i = 0; i < 2; i++) {
                int s2 = tid + i * 128;
                int r = s2 >> 3, c = s2 & 7;
                cp16(kb + (uint32_t)(r * 100 + 64 + c * 4) * 4u, krp + (size_t)r * 64 + c * 8);
            }
            CP_COMMIT();
            CP_WAIT0();
            __syncthreads();
        }

        // ---- S = Q @ K^T (fp16-hi) ----
        float s4[4][4];
        #pragma unroll
        for (int nt = 0; nt < 4; nt++) { s4[nt][0] = s4[nt][1] = s4[nt][2] = s4[nt][3] = 0.f; }

        #pragma unroll 4
        for (int s = 0; s < 12; s++) {
            const int ab = arow0 + s * 8 + lc;
            uint32_t ah0 = qs[ab],     ah1 = qs[ab + 800];
            uint32_t ah2 = qs[ab + 4], ah3 = qs[ab + 804];
            #pragma unroll
            for (int nt = 0; nt < 4; nt++) {
                const int cb = (nt * 8 + lr) * 100 + s * 8 + lc;
                mma_f16(s4[nt], ah0, ah1, ah2, ah3, ks[cb], ks[cb + 4]);
            }
        }

        // ---- mask + scale + online softmax ----
        float tmax0 = -INFINITY, tmax1 = -INFINITY;
        #pragma unroll
        for (int nt = 0; nt < 4; nt++) {
            const int colg = k0 + nt * 8 + 2 * lc;
            s4[nt][0] = (colg     <= row0g) ? s4[nt][0] * ATTN_SCALE : -INFINITY;
            s4[nt][1] = (colg + 1 <= row0g) ? s4[nt][1] * ATTN_SCALE : -INFINITY;
            s4[nt][2] = (colg     <= row1g) ? s4[nt][2] * ATTN_SCALE : -INFINITY;
            s4[nt][3] = (colg + 1 <= row1g) ? s4[nt][3] * ATTN_SCALE : -INFINITY;
            tmax0 = fmaxf(tmax0, fmaxf(s4[nt][0], s4[nt][1]));
            tmax1 = fmaxf(tmax1, fmaxf(s4[nt][2], s4[nt][3]));
        }
        tmax0 = fmaxf(tmax0, __shfl_xor_sync(0xffffffffu, tmax0, 1));
        tmax0 = fmaxf(tmax0, __shfl_xor_sync(0xffffffffu, tmax0, 2));
        tmax1 = fmaxf(tmax1, __shfl_xor_sync(0xffffffffu, tmax1, 1));
        tmax1 = fmaxf(tmax1, __shfl_xor_sync(0xffffffffu, tmax1, 2));

        const float mn0 = fmaxf(m0, tmax0), mn1 = fmaxf(m1, tmax1);
        const float scl0 = expf(m0 - mn0);
        const float scl1 = expf(m1 - mn1);

        float p4[4][4];
        float pr0 = 0.f, pr1 = 0.f;
        #pragma unroll
        for (int nt = 0; nt < 4; nt++) {
            p4[nt][0] = expf(s4[nt][0] - mn0);
            p4[nt][1] = expf(s4[nt][1] - mn0);
            p4[nt][2] = expf(s4[nt][2] - mn1);
            p4[nt][3] = expf(s4[nt][3] - mn1);
            pr0 += p4[nt][0] + p4[nt][1];
            pr1 += p4[nt][2] + p4[nt][3];
        }
        pr0 += __shfl_xor_sync(0xffffffffu, pr0, 1);
        pr0 += __shfl_xor_sync(0xffffffffu, pr0, 2);
        pr1 += __shfl_xor_sync(0xffffffffu, pr1, 1);
        pr1 += __shfl_xor_sync(0xffffffffu, pr1, 2);

        l0 = l0 * scl0 + pr0;
        l1 = l1 * scl1 + pr1;
        m0 = mn0; m1 = mn1;

        #pragma unroll
        for (int i = 0; i < 16; i++) {
            o[i][0] *= scl0; o[i][1] *= scl0;
            o[i][2] *= scl1; o[i][3] *= scl1;
        }

        // ---- P -> fp16 (per-warp private rows) ----
        #pragma unroll
        for (int nt = 0; nt < 4; nt++) {
            ((__half2*)ps)[prow0 + nt * 4 + lc]       = __floats2half2_rn(p4[nt][0], p4[nt][1]);
            ((__half2*)ps)[prow0 + 160 + nt * 4 + lc] = __floats2half2_rn(p4[nt][2], p4[nt][3]);
        }
        __syncwarp();

        // ---- O += P @ V (fp16-hi) ----
        const uint16_t* vhp = (const uint16_t*)vs;
        #pragma unroll
        for (int s = 0; s < 2; s++) {
            const int pb = prow0 + s * 8 + lc;
            uint32_t ah0 = ps[pb],     ah1 = ps[pb + 160];
            uint32_t ah2 = ps[pb + 4], ah3 = ps[pb + 164];
            const int kb = s * 16 + 2 * lc;
            #pragma unroll
            for (int nt2 = 0; nt2 < 16; nt2++) {
                const int d = nt2 * 8 + lr;
                uint32_t bh0 = (uint32_t)vhp[kb * 136 + d]       | ((uint32_t)vhp[(kb + 1) * 136 + d] << 16);
                uint32_t bh1 = (uint32_t)vhp[(kb + 8) * 136 + d] | ((uint32_t)vhp[(kb + 9) * 136 + d] << 16);
                mma_f16(o[nt2], ah0, ah1, ah2, ah3, bh0, bh1);
            }
        }
    }

    const float inv0 = 1.f / l0, inv1 = 1.f / l1;
    const size_t obase = ((size_t)(b * 2 + hp) * NHh + hn) * Lseq;
    float* op0 = attn + (obase + row0g) * 128;
    float* op1 = attn + (obase + row1g) * 128;
    #pragma unroll
    for (int nt2 = 0; nt2 < 16; nt2++) {
        *(float2*)(op0 + nt2 * 8 + 2 * lc) = make_float2(o[nt2][0] * inv0, o[nt2][1] * inv0);
        *(float2*)(op1 + nt2 * 8 + 2 * lc) = make_float2(o[nt2][2] * inv1, o[nt2][3] * inv1);
    }
}

// ======================= combine -> fp16 split planes =======================
__global__ void combine_h(const float* __restrict__ attn, const float* __restrict__ lam,
                          __half* __restrict__ oh, __half* __restrict__ ol)
{
    int idx = blockIdx.x * 256 + threadIdx.x;
    int c = idx & 2047;
    int row = idx >> 11;
    int b = row >> 11;
    int l = row & 2047;
    int n = c >> 7, d = c & 127;
    size_t a1 = (((size_t)(b * 2 + 0) * NHh + n) * Lseq + l) * 128 + d;
    size_t a2 = (((size_t)(b * 2 + 1) * NHh + n) * Lseq + l) * 128 + d;
    float v = attn[a1] - lam[(size_t)row * 16 + n] * attn[a2];
    __half h, lo; split16(v, h, lo);
    oh[idx] = h; ol[idx] = lo;
}

// ======================= launch =======================
extern "C" void kernel_launch(void* const* d_in, const int* in_sizes, int n_in,
                              void* d_out, int out_size)
{
    const float* x     = (const float*)d_in[0];
    const float* W_DKV = (const float*)d_in[1];
    const float* kv_w  = (const float*)d_in[2];
    const float* W_UK  = (const float*)d_in[3];
    const float* W_UV  = (const float*)d_in[4];
    const float* W_DQ  = (const float*)d_in[5];
    const float* q_w   = (const float*)d_in[6];
    const float* W_UQ  = (const float*)d_in[7];
    const float* W_QR  = (const float*)d_in[8];
    const float* W_KR  = (const float*)d_in[9];
    const float* W_lw  = (const float*)d_in[10];
    const float* W_lb  = (const float*)d_in[11];
    const float* W_out = (const float*)d_in[12];
    float* out = (float*)d_out;

    float *tmp, *lam, *attn;
    __half *xh, *xl, *ckvh, *ckvl, *cqh, *cql, *preh, *prel;
    __half *qchp, *qrhp, *krhp, *kvh;
    __half *tXh, *tXl, *tUKVh, *tUQh, *tQRh, *tOUTh;
    cudaGetSymbolAddress((void**)&tmp,  g_tmp);
    cudaGetSymbolAddress((void**)&lam,  g_lam);
    cudaGetSymbolAddress((void**)&attn, g_attn);
    cudaGetSymbolAddress((void**)&xh,   g_xh);
    cudaGetSymbolAddress((void**)&xl,   g_xl);
    cudaGetSymbolAddress((void**)&ckvh, g_ckvh);
    cudaGetSymbolAddress((void**)&ckvl, g_ckvl);
    cudaGetSymbolAddress((void**)&cqh,  g_cqh);
    cudaGetSymbolAddress((void**)&cql,  g_cql);
    cudaGetSymbolAddress((void**)&preh, g_preh);
    cudaGetSymbolAddress((void**)&prel, g_prel);
    cudaGetSymbolAddress((void**)&qchp, g_qch);
    cudaGetSymbolAddress((void**)&qrhp, g_qrh);
    cudaGetSymbolAddress((void**)&krhp, g_krh);
    cudaGetSymbolAddress((void**)&kvh,  g_kvh);
    cudaGetSymbolAddress((void**)&tXh,  g_tXh);
    cudaGetSymbolAddress((void**)&tXl,  g_tXl);
    cudaGetSymbolAddress((void**)&tUKVh, g_tUKVh);
    cudaGetSymbolAddress((void**)&tUQh,  g_tUQh);
    cudaGetSymbolAddress((void**)&tQRh,  g_tQRh);
    cudaGetSymbolAddress((void**)&tOUTh, g_tOUTh);

    cudaFuncSetAttribute(hgemm_f,     cudaFuncAttributeMaxDynamicSharedMemorySize, HGEMM_SMEM);
    cudaFuncSetAttribute(hgemm_multi, cudaFuncAttributeMaxDynamicSharedMemorySize, HGEMM_SMEM);
    cudaFuncSetAttribute(flash_h,     cudaFuncAttributeMaxDynamicSharedMemorySize, FLASH_SMEM);

    dim3 tb(32, 8);
    // fused tX planes: rows [DKV 0..1023 | DQ 1024..2047 | KR 2048..2111 | lw 2112..2127 | pad]
    transpose32h<<<dim3(DCc/32, Dd/32), tb>>>(W_DKV, tXh,              tXl,              Dd, DCc);
    transpose32h<<<dim3(DCc/32, Dd/32), tb>>>(W_DQ,  tXh + 1024 * Dd,  tXl + 1024 * Dd,  Dd, DCc);
    transpose32h<<<dim3(DHRr/32, Dd/32), tb>>>(W_KR, tXh + 2048 * Dd,  tXl + 2048 * Dd,  Dd, DHRr);
    lwT_kernel<<<(Dd * 16) / 256, 256>>>(W_lw, tXh, tXl);
    // up-proj / out-proj weights: hi plane only (B-lo unused in 2-term scheme)
    transpose32h<<<dim3((NHh*DHh)/32, DCc/32), tb>>>(W_UK, tUKVh,              nullptr, DCc, NHh*DHh);
    transpose32h<<<dim3((NHh*DHh)/32, DCc/32), tb>>>(W_UV, tUKVh + 2048 * DCc, nullptr, DCc, NHh*DHh);
    transpose32h<<<dim3((2*NHh*DHh)/32, DCc/32), tb>>>(W_UQ, tUQh, nullptr, DCc, 2*NHh*DHh);
    transpose32h<<<dim3((2*NHh*DHRr)/32, DCc/32), tb>>>(W_QR, tQRh, nullptr, DCc, 2*NHh*DHRr);
    transpose32h<<<dim3(Dd/32, Dd/32), tb>>>(W_out, tOUTh, nullptr, Dd, Dd);
    split_kernel<<<(BL * Dd) / 256, 256>>>(x, xh, xl);

    // fused down-projection + kr + lambda-pre (2-term split): tmp[row][NX]
    hgemm_f<<<dim3(NX/128, BL/128), 512, HGEMM_SMEM>>>(NX, Dd, xh, xl, tXh, tmp);
    rms_h<<<BL, 256>>>(tmp,        NX, kv_w, ckvh, ckvl, DCc);
    rms_h<<<BL, 256>>>(tmp + 1024, NX, q_w,  cqh,  cql,  DCc);
    lam_sig<<<(BL * 16) / 256, 256>>>(tmp, W_lb, lam);
    rope_kr<<<(BL * 32) / 256, 256>>>(tmp, krhp);

    // merged up-projections (UKV + UQ + QR), K=1024, 2-term split, hi-only outputs
    hgemm_multi<<<dim3(80, BL/128), 512, HGEMM_SMEM>>>(
        ckvh, ckvl, cqh, cql,
        tUKVh, tUQh, tQRh,
        kvh, qchp, qrhp);

    // RoPE on qr hi plane (in-place)
    rope_qp<<<(BL * 1024) / 256, 256>>>(qrhp);

    // attention (1-term fp16 flash, longest-first)
    flash_h<<<dim3(Lseq / 64, 32, BB), 128, FLASH_SMEM>>>(
        qchp, qrhp, kvh, krhp, attn);

    // combine + output projection (2-term split)
    combine_h<<<(BL * Dd) / 256, 256>>>(attn, lam, preh, prel);
    hgemm_f<<<dim3(Dd/128, BL/128), 512, HGEMM_SMEM>>>(Dd, Dd, preh, prel, tOUTh, out);
}

// round 16
// speedup vs baseline: 4.7935x; 1.0687x over previous
#include <cuda_runtime.h>
#include <cuda.h>
#include <cuda_fp16.h>
#include <math.h>
#include <stdint.h>

#define BB   2
#define Lseq 2048
#define BL   4096      // B*L
#define Dd   2048
#define DCc  1024
#define NHh  16
#define DHh  128
#define DHRr 64
#define ATTN_SCALE 0.07216878364870322f
#define NX   2176      // fused down-proj width: [ckv 1024 | cq 1024 | kr 64 | lam 16 | pad 48]

// ======================= scratch =======================
__device__ float  g_tmp [BL * NX];
__device__ float  g_lam [BL * NHh];
__device__ __half g_attn[(size_t)2 * BB * NHh * Lseq * DHh];   // fp16 attention output

// fp16 split planes (activations)
__device__ __half g_xh  [BL * Dd],   g_xl  [BL * Dd];
__device__ __half g_ckvh[BL * DCc],  g_ckvl[BL * DCc];
__device__ __half g_cqh [BL * DCc],  g_cql [BL * DCc];
__device__ __half g_preh[BL * Dd];
__device__ __half g_qch [BL * 4096];
__device__ __half g_qrh [BL * 2048];
__device__ __half g_krh [BL * DHRr];
__device__ __half g_kvh [BL * 4096];   // [kc 2048 | v 2048]
// fp16 split planes (transposed weights, [N][K])
__device__ __half g_tXh  [NX * Dd],     g_tXl  [NX * Dd];     // [DKV|DQ|KR|lw|pad0]
__device__ __half g_tUKVh[4096 * DCc];
__device__ __half g_tUQh [4096 * DCc];
__device__ __half g_tQRh [2048 * DCc];
__device__ __half g_tOUTh[Dd * Dd];

// ======================= helpers =======================
__device__ __forceinline__ uint32_t smem_u32(const void* p) {
    uint32_t a;
    asm("{ .reg .u64 t; cvta.to.shared.u64 t, %1; cvt.u32.u64 %0, t; }" : "=r"(a) : "l"(p));
    return a;
}
__device__ __forceinline__ void cp16(uint32_t dst, const void* src) {
    asm volatile("cp.async.cg.shared.global [%0], [%1], 16;" :: "r"(dst), "l"(src));
}
#define CP_COMMIT() asm volatile("cp.async.commit_group;" ::: "memory")
#define CP_WAIT0()  asm volatile("cp.async.wait_group 0;"  ::: "memory")

__device__ __forceinline__ void mma_f16(float c[4],
                                        uint32_t a0, uint32_t a1, uint32_t a2, uint32_t a3,
                                        uint32_t b0, uint32_t b1)
{
    asm volatile(
        "mma.sync.aligned.m16n8k16.row.col.f32.f16.f16.f32 "
        "{%0,%1,%2,%3}, {%4,%5,%6,%7}, {%8,%9}, {%0,%1,%2,%3};"
        : "+f"(c[0]), "+f"(c[1]), "+f"(c[2]), "+f"(c[3])
        : "r"(a0), "r"(a1), "r"(a2), "r"(a3), "r"(b0), "r"(b1));
}
// fp16-accumulator HMMA (lo-term correction path)
__device__ __forceinline__ void mma_h16(uint32_t c[2],
                                        uint32_t a0, uint32_t a1, uint32_t a2, uint32_t a3,
                                        uint32_t b0, uint32_t b1)
{
    asm volatile(
        "mma.sync.aligned.m16n8k16.row.col.f16.f16.f16.f16 "
        "{%0,%1}, {%2,%3,%4,%5}, {%6,%7}, {%0,%1};"
        : "+r"(c[0]), "+r"(c[1])
        : "r"(a0), "r"(a1), "r"(a2), "r"(a3), "r"(b0), "r"(b1));
}

__device__ __forceinline__ void split16(float v, __half& h, __half& l) {
    h = __float2half_rn(v);
    l = __float2half_rn(v - __half2float(h));
}

// ======================= transpose + split: in[R][C] -> hi/lo[C][R] =======================
__global__ void transpose32h(const float* __restrict__ in,
                             __half* __restrict__ oh, __half* __restrict__ ol, int R, int C)
{
    __shared__ float t[32][33];
    int bx = blockIdx.x * 32, by = blockIdx.y * 32;
    int x = bx + threadIdx.x;
    #pragma unroll
    for (int j = 0; j < 32; j += 8)
        t[threadIdx.y + j][threadIdx.x] = in[(size_t)(by + threadIdx.y + j) * C + x];
    __syncthreads();
    int ox = by + threadIdx.x;
    #pragma unroll
    for (int j = 0; j < 32; j += 8) {
        float v = t[threadIdx.x][threadIdx.y + j];
        size_t o = (size_t)(bx + threadIdx.y + j) * R + ox;
        if (ol) {
            __half h, l; split16(v, h, l);
            oh[o] = h; ol[o] = l;
        } else {
            oh[o] = __float2half_rn(v);
        }
    }
}

// W_lw [2048][16] -> rows 2112..2127 of tX planes
__global__ void lwT_kernel(const float* __restrict__ Wl,
                           __half* __restrict__ oh, __half* __restrict__ ol)
{
    int idx = blockIdx.x * 256 + threadIdx.x;   // 2048*16
    int k = idx >> 4, n = idx & 15;
    float v = Wl[idx];
    __half h, l; split16(v, h, l);
    size_t o = (size_t)(2112 + n) * Dd + k;
    oh[o] = h; ol[o] = l;
}

// ======================= elementwise split =======================
__global__ void split_kernel(const float* __restrict__ in,
                             __half* __restrict__ oh, __half* __restrict__ ol)
{
    int idx = blockIdx.x * 256 + threadIdx.x;
    float v = in[idx];
    __half h, l; split16(v, h, l);
    oh[idx] = h; ol[idx] = l;
}

// ======================= fp16-split tensor-core GEMM =======================
// TERMS=2: D = al*bh (fp16 acc) + ah*bh (f32 acc), lo folded at epilogue.
// TERMS=1: D = ah*bh only (A-lo not staged).
#define WSTR 20
#define HGEMM_SMEM (2 * 4 * 128 * WSTR * 4)   // 81920 B

template<int TERMS>
__device__ __forceinline__ void hgemm_body(
    int N, int K, int m0, int n0,
    const __half* __restrict__ Ahi, const __half* __restrict__ Alo,
    const __half* __restrict__ Bhi,
    uint32_t* smw, float acc[2][4][4])
{
    uint32_t* buf[2] = { smw, smw + 4 * 128 * WSTR };
    const int tid = threadIdx.x;
    const int wid = tid >> 5, lane = tid & 31;
    const int warpM = (wid >> 2) * 32;
    const int warpN = (wid & 3) * 32;
    const int lr = lane >> 2, lc = lane & 3;

    const __half* Ap0 = Ahi + (size_t)m0 * K;
    const __half* Ap1 = (TERMS == 2) ? (Alo + (size_t)m0 * K) : nullptr;
    const __half* Bp  = Bhi + (size_t)n0 * K;

    const int r = tid >> 2;
    const int q = (tid & 3) * 4;

    auto stage = [&](int kc, int b) {
        uint32_t base = smem_u32(buf[b]);
        cp16(base + (uint32_t)((r) * WSTR + q) * 4u,
             Ap0 + (size_t)r * K + kc + q * 2);
        if (TERMS == 2)
            cp16(base + (uint32_t)((128 + r) * WSTR + q) * 4u,
                 Ap1 + (size_t)r * K + kc + q * 2);
        cp16(base + (uint32_t)((2 * 128 + r) * WSTR + q) * 4u,
             Bp + (size_t)r * K + kc + q * 2);
        CP_COMMIT();
    };

    uint32_t accl[2][4][2];
    #pragma unroll
    for (int i = 0; i < 2; i++)
        #pragma unroll
        for (int j = 0; j < 4; j++) {
            #pragma unroll
            for (int k = 0; k < 4; k++) acc[i][j][k] = 0.f;
            accl[i][j][0] = 0u; accl[i][j][1] = 0u;
        }

    stage(0, 0);

    const int nch = K >> 5;
    for (int i = 0; i < nch; i++) {
        CP_WAIT0();
        __syncthreads();
        if (i + 1 < nch) stage((i + 1) << 5, (i + 1) & 1);

        const uint32_t* Ah = buf[i & 1];
        const uint32_t* Al = Ah + 128 * WSTR;
        const uint32_t* Bh = Ah + 2 * 128 * WSTR;

        #pragma unroll
        for (int s = 0; s < 2; s++) {
            uint32_t ah[2][4], al[2][4], bhf[4][2];
            #pragma unroll
            for (int ma = 0; ma < 2; ma++) {
                int rw = (warpM + ma * 16 + lr) * WSTR + s * 8 + lc;
                ah[ma][0] = Ah[rw];
                ah[ma][1] = Ah[rw + 8 * WSTR];
                ah[ma][2] = Ah[rw + 4];
                ah[ma][3] = Ah[rw + 8 * WSTR + 4];
                if (TERMS == 2) {
                    al[ma][0] = Al[rw];
                    al[ma][1] = Al[rw + 8 * WSTR];
                    al[ma][2] = Al[rw + 4];
                    al[ma][3] = Al[rw + 8 * WSTR + 4];
                }
            }
            #pragma unroll
            for (int nb = 0; nb < 4; nb++) {
                int cw = (warpN + nb * 8 + lr) * WSTR + s * 8 + lc;
                bhf[nb][0] = Bh[cw]; bhf[nb][1] = Bh[cw + 4];
            }
            if (TERMS == 2) {
                #pragma unroll
                for (int nb = 0; nb < 4; nb++)
                    #pragma unroll
                    for (int ma = 0; ma < 2; ma++)
                        mma_h16(accl[ma][nb], al[ma][0], al[ma][1], al[ma][2], al[ma][3],
                                bhf[nb][0], bhf[nb][1]);
            }
            #pragma unroll
            for (int nb = 0; nb < 4; nb++)
                #pragma unroll
                for (int ma = 0; ma < 2; ma++)
                    mma_f16(acc[ma][nb], ah[ma][0], ah[ma][1], ah[ma][2], ah[ma][3],
                            bhf[nb][0], bhf[nb][1]);
        }
        __syncthreads();
    }

    if (TERMS == 2) {
        #pragma unroll
        for (int ma = 0; ma < 2; ma++)
            #pragma unroll
            for (int nb = 0; nb < 4; nb++) {
                float2 c01 = __half22float2(*(__half2*)&accl[ma][nb][0]);
                float2 c23 = __half22float2(*(__half2*)&accl[ma][nb][1]);
                acc[ma][nb][0] += c01.x;
                acc[ma][nb][1] += c01.y;
                acc[ma][nb][2] += c23.x;
                acc[ma][nb][3] += c23.y;
            }
    }
}

template<int TERMS>
__global__ __launch_bounds__(512)
void hgemm_f(int N, int K,
             const __half* __restrict__ Ahi, const __half* __restrict__ Alo,
             const __half* __restrict__ Bhi,
             float* __restrict__ C)
{
    extern __shared__ float smraw[];
    float acc[2][4][4];
    const int m0 = blockIdx.y * 128, n0 = blockIdx.x * 128;
    hgemm_body<TERMS>(N, K, m0, n0, Ahi, Alo, Bhi, (uint32_t*)smraw, acc);

    const int wid = threadIdx.x >> 5, lane = threadIdx.x & 31;
    const int warpM = (wid >> 2) * 32, warpN = (wid & 3) * 32;
    const int lr = lane >> 2, lc = lane & 3;
    #pragma unroll
    for (int ma = 0; ma < 2; ma++) {
        int row = m0 + warpM + ma * 16 + lr;
        #pragma unroll
        for (int nb = 0; nb < 4; nb++) {
            int col = n0 + warpN + nb * 8 + lc * 2;
            *(float2*)(C + (size_t)row * N + col)       = make_float2(acc[ma][nb][0], acc[ma][nb][1]);
            *(float2*)(C + (size_t)(row + 8) * N + col) = make_float2(acc[ma][nb][2], acc[ma][nb][3]);
        }
    }
}

// merged K=1024 launch: seg0 (32 tiles) ckv@UKV->kv, seg1 (32) cq@UQ->qc, seg2 (16) cq@QR->qr
// Outputs: fp16 hi planes only (consumed by 1-term flash).
__global__ __launch_bounds__(512)
void hgemm_multi(const __half* __restrict__ ckvh, const __half* __restrict__ ckvl,
                 const __half* __restrict__ cqh,  const __half* __restrict__ cql,
                 const __half* __restrict__ tUKVh,
                 const __half* __restrict__ tUQh,
                 const __half* __restrict__ tQRh,
                 __half* __restrict__ kvh,
                 __half* __restrict__ qch,
                 __half* __restrict__ qrh)
{
    extern __shared__ float smraw[];
    const int bx = blockIdx.x;
    const __half *Ahp, *Alp, *Bhp;
    __half *Chp;
    int N, nloc;
    if (bx < 32)      { Ahp = ckvh; Alp = ckvl; Bhp = tUKVh; Chp = kvh; N = 4096; nloc = bx; }
    else if (bx < 64) { Ahp = cqh;  Alp = cql;  Bhp = tUQh;  Chp = qch; N = 4096; nloc = bx - 32; }
    else              { Ahp = cqh;  Alp = cql;  Bhp = tQRh;  Chp = qrh; N = 2048; nloc = bx - 64; }

    float acc[2][4][4];
    const int m0 = blockIdx.y * 128, n0 = nloc * 128;
    hgemm_body<2>(N, 1024, m0, n0, Ahp, Alp, Bhp, (uint32_t*)smraw, acc);

    const int wid = threadIdx.x >> 5, lane = threadIdx.x & 31;
    const int warpM = (wid >> 2) * 32, warpN = (wid & 3) * 32;
    const int lr = lane >> 2, lc = lane & 3;
    #pragma unroll
    for (int ma = 0; ma < 2; ma++) {
        int row = m0 + warpM + ma * 16 + lr;
        #pragma unroll
        for (int nb = 0; nb < 4; nb++) {
            int col = n0 + warpN + nb * 8 + lc * 2;
            *(__half2*)(Chp + (size_t)row * N + col)       = __floats2half2_rn(acc[ma][nb][0], acc[ma][nb][1]);
            *(__half2*)(Chp + (size_t)(row + 8) * N + col) = __floats2half2_rn(acc[ma][nb][2], acc[ma][nb][3]);
        }
    }
}

// ======================= RMS norm (strided input) -> fp16 split planes =======================
__global__ void rms_h(const float* __restrict__ in, int instride,
                      const float* __restrict__ w,
                      __half* __restrict__ oh, __half* __restrict__ ol, int N)
{
    int row = blockIdx.x;
    const float* ir = in + (size_t)row * instride;
    float s = 0.f;
    for (int i = threadIdx.x; i < N; i += 256) { float v = ir[i]; s += v * v; }
    __shared__ float red[256];
    red[threadIdx.x] = s;
    __syncthreads();
    for (int st = 128; st > 0; st >>= 1) {
        if (threadIdx.x < st) red[threadIdx.x] += red[threadIdx.x + st];
        __syncthreads();
    }
    float rr = rsqrtf(red[0] / (float)N + 1e-6f);
    for (int i = threadIdx.x; i < N; i += 256) {
        float v = ir[i] * rr * w[i];
        __half h, l; split16(v, h, l);
        oh[(size_t)row * N + i] = h;
        ol[(size_t)row * N + i] = l;
    }
}

// ======================= lambda sigmoid (from fused tmp cols) =======================
__global__ void lam_sig(const float* __restrict__ tmp, const float* __restrict__ bl,
                        float* __restrict__ lam)
{
    int idx = blockIdx.x * 256 + threadIdx.x;   // BL*16
    int row = idx >> 4, n = idx & 15;
    float z = tmp[(size_t)row * NX + 2112 + n] + bl[n];
    lam[idx] = 1.f / (1.f + expf(-z));
}

// ======================= RoPE kr (from fused tmp cols) -> hi plane =======================
__global__ void rope_kr(const float* __restrict__ tmp, __half* __restrict__ oh)
{
    int idx = blockIdx.x * 256 + threadIdx.x;   // BL*32
    int j = idx & 31, row = idx >> 5;
    int l = row & (Lseq - 1);
    float inv = powf(10000.f, -(float)(2 * j) / 64.f);
    float ang = (float)l * inv;
    float c = cosf(ang), s = sinf(ang);
    const float* base = tmp + (size_t)row * NX + 2048;
    float x1 = base[j], x2 = base[j + 32];
    size_t o = (size_t)row * 64;
    oh[o + j]      = __float2half_rn(x1 * c - x2 * s);
    oh[o + j + 32] = __float2half_rn(x2 * c + x1 * s);
}

// ======================= RoPE qr (in-place on hi plane) =======================
__global__ void rope_qp(__half* __restrict__ ph)
{
    int idx = blockIdx.x * 256 + threadIdx.x;   // BL*32*32
    int j = idx & 31;
    int h = (idx >> 5) & 31;
    int row = idx >> 10;
    int l = row & (Lseq - 1);
    float inv = powf(10000.f, -(float)(2 * j) / 64.f);
    float ang = (float)l * inv;
    float c = cosf(ang), s = sinf(ang);
    size_t o = (size_t)row * 2048 + h * 64;
    float x1 = __half2float(ph[o + j]);
    float x2 = __half2float(ph[o + j + 32]);
    ph[o + j]      = __float2half_rn(x1 * c - x2 * s);
    ph[o + j + 32] = __float2half_rn(x2 * c + x1 * s);
}

// ======================= tensor-core flash attention (1-term fp16, fp16 out) =====
// smem words: qs 6400 | ks 3200 | vs 2176 | ps 1280 = 13056 -> 52224 B -> 4 CTAs/SM
#define FLASH_SMEM (13056 * 4)
__global__ __launch_bounds__(128)
void flash_h(const __half* __restrict__ qch,
             const __half* __restrict__ qrh,
             const __half* __restrict__ kvh,
             const __half* __restrict__ krh,
             __half* __restrict__ attn)
{
    extern __shared__ uint32_t smw[];
    uint32_t* qs = smw;            // 6400
    uint32_t* ks = smw + 6400;     // 3200
    uint32_t* vs = smw + 9600;     // 2176
    uint32_t* ps = smw + 11776;    // 1280

    const int Q0 = (gridDim.x - 1 - blockIdx.x) * 64;
    const int head2 = blockIdx.y;
    const int b = blockIdx.z;
    const int hn = head2 >> 1, hp = head2 & 1;
    const int tid = threadIdx.x;
    const int lane = tid & 31, w = tid >> 5;
    const int lr = lane >> 2, lc = lane & 3;

    const size_t tq = (size_t)(b * Lseq + Q0);

    {
        const __half* qcp = qch + tq * 4096 + head2 * 128;
        const __half* qrp = qrh + tq * 2048 + head2 * 64;
        uint32_t qb = smem_u32(qs);
        #pragma unroll
        for (int i = 0; i < 8; i++) {
            int s2 = tid + i * 128;
            int r = s2 >> 4, c = s2 & 15;
            cp16(qb + (uint32_t)(r * 100 + c * 4) * 4u, qcp + (size_t)r * 4096 + c * 8);
        }
        #pragma unroll
        for (int i = 0; i < 4; i++) {
            int s2 = tid + i * 128;
            int r = s2 >> 3, c = s2 & 7;
            cp16(qb + (uint32_t)(r * 100 + 64 + c * 4) * 4u, qrp + (size_t)r * 2048 + c * 8);
        }
        CP_COMMIT();
    }

    float o[16][4];
    #pragma unroll
    for (int i = 0; i < 16; i++) { o[i][0] = o[i][1] = o[i][2] = o[i][3] = 0.f; }
    float m0 = -INFINITY, m1 = -INFINITY, l0 = 0.f, l1 = 0.f;

    const int row0g = Q0 + 16 * w + lr;
    const int row1g = row0g + 8;
    const int prow0 = (16 * w + lr) * 20;
    const int arow0 = (16 * w + lr) * 100;

    const int ntile = (Q0 + 64) >> 5;
    for (int t = 0; t < ntile; t++) {
        const int k0 = t << 5;
        __syncthreads();
        {
            const size_t tk = (size_t)(b * Lseq + k0);
            const __half* kcp = kvh + tk * 4096 + hn * 128;
            const __half* vp  = kvh + tk * 4096 + 2048 + hn * 128;
            const __half* krp = krh + tk * 64;
            uint32_t kb = smem_u32(ks);
            uint32_t vb = smem_u32(vs);
            #pragma unroll
            for (int i = 0; i < 4; i++) {
                int s2 = tid + i * 128;
                int r = s2 >> 4, c = s2 & 15;
                cp16(kb + (uint32_t)(r * 100 + c * 4) * 4u, kcp + (size_t)r * 4096 + c * 8);
                cp16(vb + (uint32_t)(r * 68 + c * 4) * 4u,  vp  + (size_t)r * 4096 + c * 8);
            }
            #pragma unroll
            for (int i = 0; i < 2; i++) {
                int s2 = tid + i * 128;
                int r = s2 >> 3, c = s2 & 7;
                cp16(kb + (uint32_t)(r * 100 + 64 + c * 4) * 4u, krp + (size_t)r * 64 + c * 8);
            }
            CP_COMMIT();
            CP_WAIT0();
            __syncthreads();
        }

        // ---- S = Q @ K^T (fp16-hi) ----
        float s4[4][4];
        #pragma unroll
        for (int nt = 0; nt < 4; nt++) { s4[nt][0] = s4[nt][1] = s4[nt][2] = s4[nt][3] = 0.f; }

        #pragma unroll 4
        for (int s = 0; s < 12; s++) {
            const int ab = arow0 + s * 8 + lc;
            uint32_t ah0 = qs[ab],     ah1 = qs[ab + 800];
            uint32_t ah2 = qs[ab + 4], ah3 = qs[ab + 804];
            #pragma unroll
            for (int nt = 0; nt < 4; nt++) {
                const int cb = (nt * 8 + lr) * 100 + s * 8 + lc;
                mma_f16(s4[nt], ah0, ah1, ah2, ah3, ks[cb], ks[cb + 4]);
            }
        }

        // ---- mask + scale + online softmax ----
        float tmax0 = -INFINITY, tmax1 = -INFINITY;
        #pragma unroll
        for (int nt = 0; nt < 4; nt++) {
            const int colg = k0 + nt * 8 + 2 * lc;
            s4[nt][0] = (colg     <= row0g) ? s4[nt][0] * ATTN_SCALE : -INFINITY;
            s4[nt][1] = (colg + 1 <= row0g) ? s4[nt][1] * ATTN_SCALE : -INFINITY;
            s4[nt][2] = (colg     <= row1g) ? s4[nt][2] * ATTN_SCALE : -INFINITY;
            s4[nt][3] = (colg + 1 <= row1g) ? s4[nt][3] * ATTN_SCALE : -INFINITY;
            tmax0 = fmaxf(tmax0, fmaxf(s4[nt][0], s4[nt][1]));
            tmax1 = fmaxf(tmax1, fmaxf(s4[nt][2], s4[nt][3]));
        }
        tmax0 = fmaxf(tmax0, __shfl_xor_sync(0xffffffffu, tmax0, 1));
        tmax0 = fmaxf(tmax0, __shfl_xor_sync(0xffffffffu, tmax0, 2));
        tmax1 = fmaxf(tmax1, __shfl_xor_sync(0xffffffffu, tmax1, 1));
        tmax1 = fmaxf(tmax1, __shfl_xor_sync(0xffffffffu, tmax1, 2));

        const float mn0 = fmaxf(m0, tmax0), mn1 = fmaxf(m1, tmax1);
        const float scl0 = expf(m0 - mn0);
        const float scl1 = expf(m1 - mn1);

        float p4[4][4];
        float pr0 = 0.f, pr1 = 0.f;
        #pragma unroll
        for (int nt = 0; nt < 4; nt++) {
            p4[nt][0] = expf(s4[nt][0] - mn0);
            p4[nt][1] = expf(s4[nt][1] - mn0);
            p4[nt][2] = expf(s4[nt][2] - mn1);
            p4[nt][3] = expf(s4[nt][3] - mn1);
            pr0 += p4[nt][0] + p4[nt][1];
            pr1 += p4[nt][2] + p4[nt][3];
        }
        pr0 += __shfl_xor_sync(0xffffffffu, pr0, 1);
        pr0 += __shfl_xor_sync(0xffffffffu, pr0, 2);
        pr1 += __shfl_xor_sync(0xffffffffu, pr1, 1);
        pr1 += __shfl_xor_sync(0xffffffffu, pr1, 2);

        l0 = l0 * scl0 + pr0;
        l1 = l1 * scl1 + pr1;
        m0 = mn0; m1 = mn1;

        #pragma unroll
        for (int i = 0; i < 16; i++) {
            o[i][0] *= scl0; o[i][1] *= scl0;
            o[i][2] *= scl1; o[i][3] *= scl1;
        }

        // ---- P -> fp16 (per-warp private rows) ----
        #pragma unroll
        for (int nt = 0; nt < 4; nt++) {
            ((__half2*)ps)[prow0 + nt * 4 + lc]       = __floats2half2_rn(p4[nt][0], p4[nt][1]);
            ((__half2*)ps)[prow0 + 160 + nt * 4 + lc] = __floats2half2_rn(p4[nt][2], p4[nt][3]);
        }
        __syncwarp();

        // ---- O += P @ V (fp16-hi) ----
        const uint16_t* vhp = (const uint16_t*)vs;
        #pragma unroll
        for (int s = 0; s < 2; s++) {
            const int pb = prow0 + s * 8 + lc;
            uint32_t ah0 = ps[pb],     ah1 = ps[pb + 160];
            uint32_t ah2 = ps[pb + 4], ah3 = ps[pb + 164];
            const int kb = s * 16 + 2 * lc;
            #pragma unroll
            for (int nt2 = 0; nt2 < 16; nt2++) {
                const int d = nt2 * 8 + lr;
                uint32_t bh0 = (uint32_t)vhp[kb * 136 + d]       | ((uint32_t)vhp[(kb + 1) * 136 + d] << 16);
                uint32_t bh1 = (uint32_t)vhp[(kb + 8) * 136 + d] | ((uint32_t)vhp[(kb + 9) * 136 + d] << 16);
                mma_f16(o[nt2], ah0, ah1, ah2, ah3, bh0, bh1);
            }
        }
    }

    const float inv0 = 1.f / l0, inv1 = 1.f / l1;
    const size_t obase = ((size_t)(b * 2 + hp) * NHh + hn) * Lseq;
    __half* op0 = attn + (obase + row0g) * 128;
    __half* op1 = attn + (obase + row1g) * 128;
    #pragma unroll
    for (int nt2 = 0; nt2 < 16; nt2++) {
        *(__half2*)(op0 + nt2 * 8 + 2 * lc) = __floats2half2_rn(o[nt2][0] * inv0, o[nt2][1] * inv0);
        *(__half2*)(op1 + nt2 * 8 + 2 * lc) = __floats2half2_rn(o[nt2][2] * inv1, o[nt2][3] * inv1);
    }
}

// ======================= combine (fp16 attn in) -> fp16 hi plane =======================
__global__ void combine_h(const __half* __restrict__ attn, const float* __restrict__ lam,
                          __half* __restrict__ oh)
{
    int idx = blockIdx.x * 256 + threadIdx.x;
    int c = idx & 2047;
    int row = idx >> 11;
    int b = row >> 11;
    int l = row & 2047;
    int n = c >> 7, d = c & 127;
    size_t a1 = (((size_t)(b * 2 + 0) * NHh + n) * Lseq + l) * 128 + d;
    size_t a2 = (((size_t)(b * 2 + 1) * NHh + n) * Lseq + l) * 128 + d;
    float v = __half2float(attn[a1]) - lam[(size_t)row * 16 + n] * __half2float(attn[a2]);
    oh[idx] = __float2half_rn(v);
}

// ======================= launch =======================
extern "C" void kernel_launch(void* const* d_in, const int* in_sizes, int n_in,
                              void* d_out, int out_size)
{
    const float* x     = (const float*)d_in[0];
    const float* W_DKV = (const float*)d_in[1];
    const float* kv_w  = (const float*)d_in[2];
    const float* W_UK  = (const float*)d_in[3];
    const float* W_UV  = (const float*)d_in[4];
    const float* W_DQ  = (const float*)d_in[5];
    const float* q_w   = (const float*)d_in[6];
    const float* W_UQ  = (const float*)d_in[7];
    const float* W_QR  = (const float*)d_in[8];
    const float* W_KR  = (const float*)d_in[9];
    const float* W_lw  = (const float*)d_in[10];
    const float* W_lb  = (const float*)d_in[11];
    const float* W_out = (const float*)d_in[12];
    float* out = (float*)d_out;

    float *tmp, *lam;
    __half *attn;
    __half *xh, *xl, *ckvh, *ckvl, *cqh, *cql, *preh;
    __half *qchp, *qrhp, *krhp, *kvh;
    __half *tXh, *tXl, *tUKVh, *tUQh, *tQRh, *tOUTh;
    cudaGetSymbolAddress((void**)&tmp,  g_tmp);
    cudaGetSymbolAddress((void**)&lam,  g_lam);
    cudaGetSymbolAddress((void**)&attn, g_attn);
    cudaGetSymbolAddress((void**)&xh,   g_xh);
    cudaGetSymbolAddress((void**)&xl,   g_xl);
    cudaGetSymbolAddress((void**)&ckvh, g_ckvh);
    cudaGetSymbolAddress((void**)&ckvl, g_ckvl);
    cudaGetSymbolAddress((void**)&cqh,  g_cqh);
    cudaGetSymbolAddress((void**)&cql,  g_cql);
    cudaGetSymbolAddress((void**)&preh, g_preh);
    cudaGetSymbolAddress((void**)&qchp, g_qch);
    cudaGetSymbolAddress((void**)&qrhp, g_qrh);
    cudaGetSymbolAddress((void**)&krhp, g_krh);
    cudaGetSymbolAddress((void**)&kvh,  g_kvh);
    cudaGetSymbolAddress((void**)&tXh,  g_tXh);
    cudaGetSymbolAddress((void**)&tXl,  g_tXl);
    cudaGetSymbolAddress((void**)&tUKVh, g_tUKVh);
    cudaGetSymbolAddress((void**)&tUQh,  g_tUQh);
    cudaGetSymbolAddress((void**)&tQRh,  g_tQRh);
    cudaGetSymbolAddress((void**)&tOUTh, g_tOUTh);

    cudaFuncSetAttribute(hgemm_f<2>,  cudaFuncAttributeMaxDynamicSharedMemorySize, HGEMM_SMEM);
    cudaFuncSetAttribute(hgemm_f<1>,  cudaFuncAttributeMaxDynamicSharedMemorySize, HGEMM_SMEM);
    cudaFuncSetAttribute(hgemm_multi, cudaFuncAttributeMaxDynamicSharedMemorySize, HGEMM_SMEM);
    cudaFuncSetAttribute(flash_h,     cudaFuncAttributeMaxDynamicSharedMemorySize, FLASH_SMEM);

    dim3 tb(32, 8);
    // fused tX planes: rows [DKV 0..1023 | DQ 1024..2047 | KR 2048..2111 | lw 2112..2127 | pad]
    transpose32h<<<dim3(DCc/32, Dd/32), tb>>>(W_DKV, tXh,              tXl,              Dd, DCc);
    transpose32h<<<dim3(DCc/32, Dd/32), tb>>>(W_DQ,  tXh + 1024 * Dd,  tXl + 1024 * Dd,  Dd, DCc);
    transpose32h<<<dim3(DHRr/32, Dd/32), tb>>>(W_KR, tXh + 2048 * Dd,  tXl + 2048 * Dd,  Dd, DHRr);
    lwT_kernel<<<(Dd * 16) / 256, 256>>>(W_lw, tXh, tXl);
    // up-proj / out-proj weights: hi plane only
    transpose32h<<<dim3((NHh*DHh)/32, DCc/32), tb>>>(W_UK, tUKVh,              nullptr, DCc, NHh*DHh);
    transpose32h<<<dim3((NHh*DHh)/32, DCc/32), tb>>>(W_UV, tUKVh + 2048 * DCc, nullptr, DCc, NHh*DHh);
    transpose32h<<<dim3((2*NHh*DHh)/32, DCc/32), tb>>>(W_UQ, tUQh, nullptr, DCc, 2*NHh*DHh);
    transpose32h<<<dim3((2*NHh*DHRr)/32, DCc/32), tb>>>(W_QR, tQRh, nullptr, DCc, 2*NHh*DHRr);
    transpose32h<<<dim3(Dd/32, Dd/32), tb>>>(W_out, tOUTh, nullptr, Dd, Dd);
    split_kernel<<<(BL * Dd) / 256, 256>>>(x, xh, xl);

    // fused down-projection + kr + lambda-pre (2-term split): tmp[row][NX]
    hgemm_f<2><<<dim3(NX/128, BL/128), 512, HGEMM_SMEM>>>(NX, Dd, xh, xl, tXh, tmp);
    rms_h<<<BL, 256>>>(tmp,        NX, kv_w, ckvh, ckvl, DCc);
    rms_h<<<BL, 256>>>(tmp + 1024, NX, q_w,  cqh,  cql,  DCc);
    lam_sig<<<(BL * 16) / 256, 256>>>(tmp, W_lb, lam);
    rope_kr<<<(BL * 32) / 256, 256>>>(tmp, krhp);

    // merged up-projections (UKV + UQ + QR), K=1024, 2-term split, hi-only outputs
    hgemm_multi<<<dim3(80, BL/128), 512, HGEMM_SMEM>>>(
        ckvh, ckvl, cqh, cql,
        tUKVh, tUQh, tQRh,
        kvh, qchp, qrhp);

    // RoPE on qr hi plane (in-place)
    rope_qp<<<(BL * 1024) / 256, 256>>>(qrhp);

    // attention (1-term fp16 flash, fp16 output, longest-first)
    flash_h<<<dim3(Lseq / 64, 32, BB), 128, FLASH_SMEM>>>(
        qchp, qrhp, kvh, krhp, attn);

    // combine (fp16) + output projection (1-term)
    combine_h<<<(BL * Dd) / 256, 256>>>(attn, lam, preh);
    hgemm_f<1><<<dim3(Dd/128, BL/128), 512, HGEMM_SMEM>>>(Dd, Dd, preh, nullptr, tOUTh, out);
}